// round 1
// baseline (speedup 1.0000x reference)
#include <cuda_runtime.h>
#include <math.h>

#define T_DIM 2048
#define H_DIM 4096
#define NHEADS 32
#define HD_DIM 128
#define FF_DIM 11008
#define EPS_V 1e-6f

// ---------------- scratch (static device globals; no allocs allowed) --------
__device__ float g_xn [(size_t)T_DIM * H_DIM];
__device__ float g_q  [(size_t)T_DIM * H_DIM];
__device__ float g_k  [(size_t)T_DIM * H_DIM];
__device__ float g_v  [(size_t)T_DIM * H_DIM];
__device__ float g_att[(size_t)T_DIM * H_DIM];
__device__ float g_h  [(size_t)T_DIM * H_DIM];
__device__ float g_y  [(size_t)T_DIM * H_DIM];
__device__ float g_a1 [(size_t)T_DIM * FF_DIM];
__device__ float g_a2 [(size_t)T_DIM * FF_DIM];

// ---------------- RMSNorm ---------------------------------------------------
__global__ void rmsnorm_kernel(const float* __restrict__ x,
                               const float* __restrict__ scale,
                               float* __restrict__ out)
{
    int row = blockIdx.x;
    const float4* xr = (const float4*)(x + (size_t)row * H_DIM);
    float ss = 0.f;
    for (int i = threadIdx.x; i < H_DIM / 4; i += blockDim.x) {
        float4 v = xr[i];
        ss += v.x * v.x + v.y * v.y + v.z * v.z + v.w * v.w;
    }
    #pragma unroll
    for (int off = 16; off; off >>= 1) ss += __shfl_xor_sync(0xffffffffu, ss, off);
    __shared__ float red[32];
    int lane = threadIdx.x & 31, wid = threadIdx.x >> 5;
    if (lane == 0) red[wid] = ss;
    __syncthreads();
    if (wid == 0) {
        ss = (lane < (int)(blockDim.x >> 5)) ? red[lane] : 0.f;
        #pragma unroll
        for (int off = 16; off; off >>= 1) ss += __shfl_xor_sync(0xffffffffu, ss, off);
        if (lane == 0) red[0] = ss;
    }
    __syncthreads();
    float inv = rsqrtf(red[0] / (float)H_DIM + EPS_V);
    const float4* sc = (const float4*)scale;
    float4* o4 = (float4*)(out + (size_t)row * H_DIM);
    for (int i = threadIdx.x; i < H_DIM / 4; i += blockDim.x) {
        float4 v = xr[i], s = sc[i], r;
        r.x = v.x * inv * s.x; r.y = v.y * inv * s.y;
        r.z = v.z * inv * s.z; r.w = v.w * inv * s.w;
        o4[i] = r;
    }
}

// ---------------- RoPE (rotate-half, fp32 math matching JAX) ----------------
__global__ void rope_kernel(float* __restrict__ q, float* __restrict__ k,
                            const int* __restrict__ pos)
{
    int idx = blockIdx.x * blockDim.x + threadIdx.x;      // T*NH*64 threads
    if (idx >= T_DIM * NHEADS * (HD_DIM / 2)) return;
    int d  = idx & 63;
    int th = idx >> 6;           // t*NH + h
    int t  = th >> 5;            // NH == 32
    float invf = powf(10000.0f, -(float)d * (1.0f / 64.0f));
    float ang = (float)pos[t] * invf;
    float c, s;
    sincosf(ang, &s, &c);        // s = sin, c = cos
    size_t base = (size_t)th * HD_DIM + d;
    float q1 = q[base], q2 = q[base + 64];
    q[base]      = q1 * c - q2 * s;
    q[base + 64] = q2 * c + q1 * s;
    float k1 = k[base], k2 = k[base + 64];
    k[base]      = k1 * c - k2 * s;
    k[base + 64] = k2 * c + k1 * s;
}

// ---------------- SGEMM: C[M,N] = A[M,K] @ B[K,N] (+bias) (+residual) -------
__global__ __launch_bounds__(256, 2)
void sgemm_kernel(int M, int N, int K,
                  const float* __restrict__ A, const float* __restrict__ B,
                  const float* __restrict__ bias, const float* __restrict__ residual,
                  float* __restrict__ C)
{
    __shared__ float As[8][128];
    __shared__ float Bs[8][128];
    int tid = threadIdx.x;
    int bx = blockIdx.x, by = blockIdx.y;

    const int rowA = by * 128 + (tid >> 1);
    const int kA   = (tid & 1) * 4;
    const int kB   = tid >> 5;
    const int colB = bx * 128 + (tid & 31) * 4;

    const int tr = (tid >> 4) << 3;   // 0..120
    const int tc = (tid & 15) << 3;   // 0..120

    float acc[8][8];
    #pragma unroll
    for (int i = 0; i < 8; i++)
        #pragma unroll
        for (int j = 0; j < 8; j++) acc[i][j] = 0.f;

    const float* Aptr = A + (size_t)rowA * K + kA;
    const float* Bptr = B + (size_t)kB * N + colB;

    for (int k0 = 0; k0 < K; k0 += 8) {
        float4 a4 = *(const float4*)(Aptr + k0);
        float4 b4 = *(const float4*)(Bptr + (size_t)k0 * N);
        As[kA + 0][tid >> 1] = a4.x;
        As[kA + 1][tid >> 1] = a4.y;
        As[kA + 2][tid >> 1] = a4.z;
        As[kA + 3][tid >> 1] = a4.w;
        *(float4*)&Bs[kB][(tid & 31) * 4] = b4;
        __syncthreads();
        #pragma unroll
        for (int kk = 0; kk < 8; kk++) {
            float4 a0 = *(float4*)&As[kk][tr];
            float4 a1 = *(float4*)&As[kk][tr + 4];
            float4 b0 = *(float4*)&Bs[kk][tc];
            float4 b1 = *(float4*)&Bs[kk][tc + 4];
            float av[8] = {a0.x, a0.y, a0.z, a0.w, a1.x, a1.y, a1.z, a1.w};
            float bv[8] = {b0.x, b0.y, b0.z, b0.w, b1.x, b1.y, b1.z, b1.w};
            #pragma unroll
            for (int i = 0; i < 8; i++)
                #pragma unroll
                for (int j = 0; j < 8; j++)
                    acc[i][j] = fmaf(av[i], bv[j], acc[i][j]);
        }
        __syncthreads();
    }

    #pragma unroll
    for (int i = 0; i < 8; i++) {
        int r = by * 128 + tr + i;
        #pragma unroll
        for (int j = 0; j < 8; j += 4) {
            int c = bx * 128 + tc + j;
            float4 v = make_float4(acc[i][j], acc[i][j + 1], acc[i][j + 2], acc[i][j + 3]);
            if (bias) {
                const float4 bb = *(const float4*)&bias[c];
                v.x += bb.x; v.y += bb.y; v.z += bb.z; v.w += bb.w;
            }
            if (residual) {
                const float4 rr = *(const float4*)&residual[(size_t)r * N + c];
                v.x += rr.x; v.y += rr.y; v.z += rr.z; v.w += rr.w;
            }
            *(float4*)&C[(size_t)r * N + c] = v;
        }
    }
}

// ---------------- SiLU gate: a1 = a1 * (a2 * sigmoid(a2)) -------------------
__global__ void silu_mul_kernel(float* __restrict__ a1, const float* __restrict__ a2, int n)
{
    int i = blockIdx.x * blockDim.x + threadIdx.x;
    if (i < n) {
        float g = a2[i];
        float s = g / (1.f + expf(-g));
        a1[i] = a1[i] * s;
    }
}

// ---------------- Flash attention (causal), 64x64 tiles ---------------------
#define KS_STRIDE 129
#define ATTN_SMEM ((64 * 128 + 64 * KS_STRIDE + 64 * 128 + 64 * 64) * 4)

extern __shared__ float attn_smem[];
__global__ __launch_bounds__(256, 1)
void attn_kernel(const float* __restrict__ Q, const float* __restrict__ K,
                 const float* __restrict__ V, float* __restrict__ O)
{
    float* Qs = attn_smem;                 // 64 x 128
    float* Ks = Qs + 64 * 128;             // 64 x 129 (padded)
    float* Vs = Ks + 64 * KS_STRIDE;       // 64 x 128
    float* Ps = Vs + 64 * 128;             // 64 x 64

    const int qb = blockIdx.x;
    const int h  = blockIdx.y;
    const int q0 = qb * 64;
    const int tid = threadIdx.x;
    const int tx = tid & 15, ty = tid >> 4;

    for (int i = tid; i < 64 * 128; i += 256) {
        int r = i >> 7, c = i & 127;
        Qs[i] = Q[(size_t)(q0 + r) * H_DIM + h * HD_DIM + c];
    }

    float m[4], l[4], acc[4][8];
    #pragma unroll
    for (int i = 0; i < 4; i++) {
        m[i] = -1e30f; l[i] = 0.f;
        #pragma unroll
        for (int j = 0; j < 8; j++) acc[i][j] = 0.f;
    }
    const float scaling = 0.08838834764831845f;  // 128^-0.5

    for (int j0 = 0; j0 <= q0; j0 += 64) {
        __syncthreads();
        for (int i = tid; i < 64 * 128; i += 256) {
            int r = i >> 7, c = i & 127;
            size_t gidx = (size_t)(j0 + r) * H_DIM + h * HD_DIM + c;
            Ks[r * KS_STRIDE + c] = K[gidx];
            Vs[i] = V[gidx];
        }
        __syncthreads();

        float s[4][4];
        #pragma unroll
        for (int i = 0; i < 4; i++)
            #pragma unroll
            for (int j = 0; j < 4; j++) s[i][j] = 0.f;

        #pragma unroll 4
        for (int d = 0; d < 128; d++) {
            float qv[4], kv[4];
            #pragma unroll
            for (int i = 0; i < 4; i++) qv[i] = Qs[(ty * 4 + i) * 128 + d];
            #pragma unroll
            for (int j = 0; j < 4; j++) kv[j] = Ks[(tx * 4 + j) * KS_STRIDE + d];
            #pragma unroll
            for (int i = 0; i < 4; i++)
                #pragma unroll
                for (int j = 0; j < 4; j++)
                    s[i][j] = fmaf(qv[i], kv[j], s[i][j]);
        }

        const bool diag = (j0 == q0);
        #pragma unroll
        for (int i = 0; i < 4; i++) {
            #pragma unroll
            for (int j = 0; j < 4; j++) {
                s[i][j] *= scaling;
                if (diag && (tx * 4 + j) > (ty * 4 + i)) s[i][j] = -1e30f;
            }
        }

        // online softmax per row
        #pragma unroll
        for (int i = 0; i < 4; i++) {
            float mx = fmaxf(fmaxf(s[i][0], s[i][1]), fmaxf(s[i][2], s[i][3]));
            #pragma unroll
            for (int off = 8; off; off >>= 1)
                mx = fmaxf(mx, __shfl_xor_sync(0xffffffffu, mx, off));
            float mnew = fmaxf(m[i], mx);
            float p[4], rs = 0.f;
            #pragma unroll
            for (int j = 0; j < 4; j++) { p[j] = expf(s[i][j] - mnew); rs += p[j]; }
            #pragma unroll
            for (int off = 8; off; off >>= 1)
                rs += __shfl_xor_sync(0xffffffffu, rs, off);
            float alpha = expf(m[i] - mnew);
            l[i] = l[i] * alpha + rs;
            m[i] = mnew;
            #pragma unroll
            for (int j = 0; j < 8; j++) acc[i][j] *= alpha;
            #pragma unroll
            for (int j = 0; j < 4; j++) Ps[(ty * 4 + i) * 64 + tx * 4 + j] = p[j];
        }
        __syncthreads();

        // O += P @ V ; thread owns cols (tx + 16*jj)
        #pragma unroll 2
        for (int kk = 0; kk < 64; kk++) {
            float pv[4];
            #pragma unroll
            for (int i = 0; i < 4; i++) pv[i] = Ps[(ty * 4 + i) * 64 + kk];
            #pragma unroll
            for (int j = 0; j < 8; j++) {
                float vv = Vs[kk * 128 + tx + j * 16];
                #pragma unroll
                for (int i = 0; i < 4; i++)
                    acc[i][j] = fmaf(pv[i], vv, acc[i][j]);
            }
        }
    }

    #pragma unroll
    for (int i = 0; i < 4; i++) {
        float inv = 1.f / l[i];
        #pragma unroll
        for (int j = 0; j < 8; j++)
            O[(size_t)(q0 + ty * 4 + i) * H_DIM + h * HD_DIM + tx + j * 16] = acc[i][j] * inv;
    }
}

// ---------------- launch -----------------------------------------------------
extern "C" void kernel_launch(void* const* d_in, const int* in_sizes, int n_in,
                              void* d_out, int out_size)
{
    (void)in_sizes; (void)n_in; (void)out_size;
    const int*   positions = (const int*)  d_in[0];
    const float* hidden    = (const float*)d_in[1];
    const float* ln1       = (const float*)d_in[2];
    const float* wq = (const float*)d_in[3];
    const float* bq = (const float*)d_in[4];
    const float* wk = (const float*)d_in[5];
    const float* bk = (const float*)d_in[6];
    const float* wv = (const float*)d_in[7];
    const float* bv = (const float*)d_in[8];
    const float* wo = (const float*)d_in[9];
    const float* ln2= (const float*)d_in[10];
    const float* w1 = (const float*)d_in[11];
    const float* w2 = (const float*)d_in[12];
    const float* wc = (const float*)d_in[13];
    float* out = (float*)d_out;

    float *xn, *q, *k, *v, *att, *hbuf, *y, *a1, *a2;
    cudaGetSymbolAddress((void**)&xn,   g_xn);
    cudaGetSymbolAddress((void**)&q,    g_q);
    cudaGetSymbolAddress((void**)&k,    g_k);
    cudaGetSymbolAddress((void**)&v,    g_v);
    cudaGetSymbolAddress((void**)&att,  g_att);
    cudaGetSymbolAddress((void**)&hbuf, g_h);
    cudaGetSymbolAddress((void**)&y,    g_y);
    cudaGetSymbolAddress((void**)&a1,   g_a1);
    cudaGetSymbolAddress((void**)&a2,   g_a2);

    cudaFuncSetAttribute(attn_kernel, cudaFuncAttributeMaxDynamicSharedMemorySize, ATTN_SMEM);

    // 1) x = rmsnorm(hidden, ln1)
    rmsnorm_kernel<<<T_DIM, 256>>>(hidden, ln1, xn);

    // 2) q/k/v = x @ W + b
    dim3 g44(H_DIM / 128, T_DIM / 128);
    sgemm_kernel<<<g44, 256>>>(T_DIM, H_DIM, H_DIM, xn, wq, bq, nullptr, q);
    sgemm_kernel<<<g44, 256>>>(T_DIM, H_DIM, H_DIM, xn, wk, bk, nullptr, k);
    sgemm_kernel<<<g44, 256>>>(T_DIM, H_DIM, H_DIM, xn, wv, bv, nullptr, v);

    // 3) RoPE on q and k
    rope_kernel<<<(T_DIM * NHEADS * (HD_DIM / 2)) / 256, 256>>>(q, k, positions);

    // 4) causal attention
    attn_kernel<<<dim3(T_DIM / 64, NHEADS), 256, ATTN_SMEM>>>(q, k, v, att);

    // 5) h = hidden + attn @ wo
    sgemm_kernel<<<g44, 256>>>(T_DIM, H_DIM, H_DIM, att, wo, nullptr, hidden, hbuf);

    // 6) y = rmsnorm(h, ln2)
    rmsnorm_kernel<<<T_DIM, 256>>>(hbuf, ln2, y);

    // 7) a1 = y @ w1 ; a2 = y @ w2 ; a1 *= silu(a2)
    dim3 gff(FF_DIM / 128, T_DIM / 128);
    sgemm_kernel<<<gff, 256>>>(T_DIM, FF_DIM, H_DIM, y, w1, nullptr, nullptr, a1);
    sgemm_kernel<<<gff, 256>>>(T_DIM, FF_DIM, H_DIM, y, w2, nullptr, nullptr, a2);
    silu_mul_kernel<<<(T_DIM * FF_DIM + 255) / 256, 256>>>(a1, a2, T_DIM * FF_DIM);

    // 8) out = h + (a1) @ wc
    sgemm_kernel<<<g44, 256>>>(T_DIM, H_DIM, FF_DIM, a1, wc, nullptr, hbuf, out);
}

// round 3
// speedup vs baseline: 1.8914x; 1.8914x over previous
#include <cuda_runtime.h>
#include <cuda_bf16.h>
#include <math.h>
#include <cstdint>

#define T_DIM 2048
#define H_DIM 4096
#define NHEADS 32
#define HD_DIM 128
#define FF_DIM 11008
#define EPS_V 1e-6f

typedef __nv_bfloat16 bf16;

// ===================== device scratch (no allocs allowed) ==================
__device__ float g_q  [(size_t)T_DIM * H_DIM];
__device__ float g_k  [(size_t)T_DIM * H_DIM];
__device__ float g_v  [(size_t)T_DIM * H_DIM];
__device__ float g_att[(size_t)T_DIM * H_DIM];
__device__ float g_h  [(size_t)T_DIM * H_DIM];
__device__ float g_a1 [(size_t)T_DIM * FF_DIM];
__device__ float g_a2 [(size_t)T_DIM * FF_DIM];

__device__ bf16 g_xnh [(size_t)T_DIM * H_DIM];
__device__ bf16 g_xnl [(size_t)T_DIM * H_DIM];
__device__ bf16 g_atth[(size_t)T_DIM * H_DIM];
__device__ bf16 g_attl[(size_t)T_DIM * H_DIM];
__device__ bf16 g_yh  [(size_t)T_DIM * H_DIM];
__device__ bf16 g_yl  [(size_t)T_DIM * H_DIM];
__device__ bf16 g_gh  [(size_t)T_DIM * FF_DIM];
__device__ bf16 g_gl  [(size_t)T_DIM * FF_DIM];

__device__ bf16 g_wqh[(size_t)H_DIM * H_DIM];
__device__ bf16 g_wql[(size_t)H_DIM * H_DIM];
__device__ bf16 g_wkh[(size_t)H_DIM * H_DIM];
__device__ bf16 g_wkl[(size_t)H_DIM * H_DIM];
__device__ bf16 g_wvh[(size_t)H_DIM * H_DIM];
__device__ bf16 g_wvl[(size_t)H_DIM * H_DIM];
__device__ bf16 g_woh[(size_t)H_DIM * H_DIM];
__device__ bf16 g_wol[(size_t)H_DIM * H_DIM];
__device__ bf16 g_w1h[(size_t)FF_DIM * H_DIM];
__device__ bf16 g_w1l[(size_t)FF_DIM * H_DIM];
__device__ bf16 g_w2h[(size_t)FF_DIM * H_DIM];
__device__ bf16 g_w2l[(size_t)FF_DIM * H_DIM];
__device__ bf16 g_wch[(size_t)H_DIM * FF_DIM];
__device__ bf16 g_wcl[(size_t)H_DIM * FF_DIM];

// ===================== PTX helpers =========================================
__device__ __forceinline__ uint32_t smem_u32(const void* p) {
    uint32_t a;
    asm("{ .reg .u64 t; cvta.to.shared.u64 t, %1; cvt.u32.u64 %0, t; }"
        : "=r"(a) : "l"(p));
    return a;
}

#define CP_ASYNC16(dst, src) \
    asm volatile("cp.async.cg.shared.global [%0], [%1], 16;" :: "r"(dst), "l"(src))
#define CP_COMMIT() asm volatile("cp.async.commit_group;" ::: "memory")

__device__ __forceinline__ void ldsm_x4(uint32_t* r, uint32_t a) {
    asm volatile("ldmatrix.sync.aligned.m8n8.x4.shared.b16 {%0,%1,%2,%3}, [%4];"
        : "=r"(r[0]), "=r"(r[1]), "=r"(r[2]), "=r"(r[3]) : "r"(a));
}

__device__ __forceinline__ void mma16816(float* d, const uint32_t* a,
                                         uint32_t b0, uint32_t b1) {
    asm volatile(
        "mma.sync.aligned.m16n8k16.row.col.f32.bf16.bf16.f32 "
        "{%0,%1,%2,%3}, {%4,%5,%6,%7}, {%8,%9}, {%0,%1,%2,%3};"
        : "+f"(d[0]), "+f"(d[1]), "+f"(d[2]), "+f"(d[3])
        : "r"(a[0]), "r"(a[1]), "r"(a[2]), "r"(a[3]), "r"(b0), "r"(b1));
}

// ===================== bf16x3 GEMM via mma.sync ==============================
// C[M,N] = A[M,K] @ B[N,K]^T computed as Ah*Bh + Ah*Bl + Al*Bh, fp32 acc.
#define BM 128
#define BN 128
#define BK 64
#define SKW  72                 // halves per smem row (padded)
#define SKWB 144                // bytes per smem row
#define STG 3
#define TILE_BYTES (BM * SKWB)  // 18432 per operand tile
#define STAGE_B (2 * TILE_BYTES)
#define GEMM_SMEM (STG * STAGE_B)

__global__ __launch_bounds__(256, 1)
void gemm_mma_bf16x3(const bf16* __restrict__ Ah, const bf16* __restrict__ Al,
                     const bf16* __restrict__ Bh, const bf16* __restrict__ Bl,
                     const float* __restrict__ bias, const float* __restrict__ resid,
                     float* __restrict__ C, int Ntot, int K)
{
    extern __shared__ char dsm[];
    const int tid = threadIdx.x;
    const int wid = tid >> 5, lane = tid & 31;
    const int rowA0 = blockIdx.y * BM;
    const int colB0 = blockIdx.x * BN;
    const int kch = K >> 6;
    const int nIter = 3 * kch;
    const uint32_t sbase = smem_u32(dsm);

    auto load_stage = [&](int j) {
        const int s = j % STG;
        const int pass = j / kch;
        const int kc = j - pass * kch;
        const bf16* As = (pass < 2) ? Ah : Al;
        const bf16* Bs = (pass == 1) ? Bl : Bh;
        const size_t koff = (size_t)kc * BK;
        const uint32_t sa = sbase + s * STAGE_B;
        const uint32_t sb = sa + TILE_BYTES;
        #pragma unroll
        for (int i = 0; i < 4; i++) {
            int idx = tid + i * 256;            // 0..1023
            int r = idx >> 3, c8 = idx & 7;
            CP_ASYNC16(sa + r * SKWB + c8 * 16,
                       As + (size_t)(rowA0 + r) * K + koff + c8 * 8);
        }
        #pragma unroll
        for (int i = 0; i < 4; i++) {
            int idx = tid + i * 256;
            int r = idx >> 3, c8 = idx & 7;
            CP_ASYNC16(sb + r * SKWB + c8 * 16,
                       Bs + (size_t)(colB0 + r) * K + koff + c8 * 8);
        }
        CP_COMMIT();
    };

    // warp tiling: 4 (m) x 2 (n) warps; warp tile 32 x 64
    const int m0 = (wid >> 1) * 32;
    const int n0 = (wid & 1) * 64;

    float acc[2][8][4];
    #pragma unroll
    for (int i = 0; i < 2; i++)
        #pragma unroll
        for (int j = 0; j < 8; j++)
            #pragma unroll
            for (int c = 0; c < 4; c++) acc[i][j][c] = 0.f;

    // per-lane ldmatrix base byte offsets
    const int mi = lane >> 3, l7 = lane & 7;
    const uint32_t aoff = (uint32_t)((m0 + (mi & 1) * 8 + l7) * SKWB + ((mi >> 1) * 8) * 2);
    const uint32_t boff = (uint32_t)((n0 + (mi >> 1) * 8 + l7) * SKWB + ((mi & 1) * 8) * 2);

    // prologue
    load_stage(0);
    load_stage(1);

    for (int it = 0; it < nIter; it++) {
        if (it + STG - 1 < nIter) load_stage(it + STG - 1);
        else CP_COMMIT();
        asm volatile("cp.async.wait_group %0;" :: "n"(STG - 1));
        __syncthreads();

        const uint32_t sa = sbase + (it % STG) * STAGE_B;
        const uint32_t sb = sa + TILE_BYTES;

        #pragma unroll
        for (int kk = 0; kk < 4; kk++) {
            uint32_t a0[4], a1[4];
            ldsm_x4(a0, sa + aoff + kk * 32);
            ldsm_x4(a1, sa + aoff + 16 * SKWB + kk * 32);
            #pragma unroll
            for (int g = 0; g < 4; g++) {
                uint32_t b[4];
                ldsm_x4(b, sb + boff + g * 16 * SKWB + kk * 32);
                mma16816(acc[0][2 * g + 0], a0, b[0], b[1]);
                mma16816(acc[0][2 * g + 1], a0, b[2], b[3]);
                mma16816(acc[1][2 * g + 0], a1, b[0], b[1]);
                mma16816(acc[1][2 * g + 1], a1, b[2], b[3]);
            }
        }
        __syncthreads();
    }

    // epilogue
    const int l4 = lane >> 2, l2 = (lane & 3) * 2;
    #pragma unroll
    for (int mf = 0; mf < 2; mf++) {
        const int r = rowA0 + m0 + mf * 16 + l4;
        #pragma unroll
        for (int nf = 0; nf < 8; nf++) {
            const int c = colB0 + n0 + nf * 8 + l2;
            float2 v0 = make_float2(acc[mf][nf][0], acc[mf][nf][1]);
            float2 v1 = make_float2(acc[mf][nf][2], acc[mf][nf][3]);
            if (bias) {
                v0.x += bias[c]; v0.y += bias[c + 1];
                v1.x += bias[c]; v1.y += bias[c + 1];
            }
            if (resid) {
                const float2 r0 = *(const float2*)&resid[(size_t)r * Ntot + c];
                const float2 r1 = *(const float2*)&resid[(size_t)(r + 8) * Ntot + c];
                v0.x += r0.x; v0.y += r0.y;
                v1.x += r1.x; v1.y += r1.y;
            }
            *(float2*)&C[(size_t)r * Ntot + c] = v0;
            *(float2*)&C[(size_t)(r + 8) * Ntot + c] = v1;
        }
    }
}

// ===================== elementwise / conversion kernels =====================
__device__ __forceinline__ void split_hilo(float v, bf16& h, bf16& l) {
    h = __float2bfloat16(v);
    l = __float2bfloat16(v - __bfloat162float(h));
}

__global__ void rmsnorm_hilo_kernel(const float* __restrict__ x,
                                    const float* __restrict__ scale,
                                    bf16* __restrict__ oh, bf16* __restrict__ ol)
{
    int row = blockIdx.x;
    const float4* xr = (const float4*)(x + (size_t)row * H_DIM);
    float ss = 0.f;
    for (int i = threadIdx.x; i < H_DIM / 4; i += blockDim.x) {
        float4 v = xr[i];
        ss += v.x * v.x + v.y * v.y + v.z * v.z + v.w * v.w;
    }
    #pragma unroll
    for (int off = 16; off; off >>= 1) ss += __shfl_xor_sync(0xffffffffu, ss, off);
    __shared__ float red[32];
    int lane = threadIdx.x & 31, wid = threadIdx.x >> 5;
    if (lane == 0) red[wid] = ss;
    __syncthreads();
    if (wid == 0) {
        ss = (lane < (int)(blockDim.x >> 5)) ? red[lane] : 0.f;
        #pragma unroll
        for (int off = 16; off; off >>= 1) ss += __shfl_xor_sync(0xffffffffu, ss, off);
        if (lane == 0) red[0] = ss;
    }
    __syncthreads();
    float inv = rsqrtf(red[0] / (float)H_DIM + EPS_V);
    const float4* sc = (const float4*)scale;
    for (int i = threadIdx.x; i < H_DIM / 4; i += blockDim.x) {
        float4 v = xr[i], s = sc[i];
        float f[4] = {v.x * inv * s.x, v.y * inv * s.y, v.z * inv * s.z, v.w * inv * s.w};
        size_t base = (size_t)row * H_DIM + i * 4;
        #pragma unroll
        for (int c = 0; c < 4; c++) {
            bf16 h, l; split_hilo(f[c], h, l);
            oh[base + c] = h; ol[base + c] = l;
        }
    }
}

__global__ void hilo_kernel(const float* __restrict__ x,
                            bf16* __restrict__ oh, bf16* __restrict__ ol, int n)
{
    int i = blockIdx.x * blockDim.x + threadIdx.x;
    if (i < n) { bf16 h, l; split_hilo(x[i], h, l); oh[i] = h; ol[i] = l; }
}

__global__ void silu_hilo_kernel(const float* __restrict__ a1,
                                 const float* __restrict__ a2,
                                 bf16* __restrict__ oh, bf16* __restrict__ ol, int n)
{
    int i = blockIdx.x * blockDim.x + threadIdx.x;
    if (i < n) {
        float g = a2[i];
        float v = a1[i] * (g / (1.f + expf(-g)));
        bf16 h, l; split_hilo(v, h, l);
        oh[i] = h; ol[i] = l;
    }
}

// W[K][N] fp32  ->  Th/Tl[N][K] bf16 hi/lo (transposed)
__global__ void transpose_hilo_kernel(const float* __restrict__ W, int K, int N,
                                      bf16* __restrict__ Th, bf16* __restrict__ Tl)
{
    __shared__ float t[32][33];
    int n0 = blockIdx.x * 32, k0 = blockIdx.y * 32;
    int tx = threadIdx.x, ty = threadIdx.y;
    #pragma unroll
    for (int i = ty; i < 32; i += 8)
        t[i][tx] = W[(size_t)(k0 + i) * N + n0 + tx];
    __syncthreads();
    #pragma unroll
    for (int i = ty; i < 32; i += 8) {
        float v = t[tx][i];
        bf16 h, l; split_hilo(v, h, l);
        size_t idx = (size_t)(n0 + i) * K + k0 + tx;
        Th[idx] = h; Tl[idx] = l;
    }
}

// ===================== RoPE ==================================================
__global__ void rope_kernel(float* __restrict__ q, float* __restrict__ k,
                            const int* __restrict__ pos)
{
    int idx = blockIdx.x * blockDim.x + threadIdx.x;
    if (idx >= T_DIM * NHEADS * (HD_DIM / 2)) return;
    int d  = idx & 63;
    int th = idx >> 6;
    int t  = th >> 5;
    float invf = powf(10000.0f, -(float)d * (1.0f / 64.0f));
    float ang = (float)pos[t] * invf;
    float c, s;
    sincosf(ang, &s, &c);
    size_t base = (size_t)th * HD_DIM + d;
    float q1 = q[base], q2 = q[base + 64];
    q[base]      = q1 * c - q2 * s;
    q[base + 64] = q2 * c + q1 * s;
    float k1 = k[base], k2 = k[base + 64];
    k[base]      = k1 * c - k2 * s;
    k[base + 64] = k2 * c + k1 * s;
}

// ===================== Flash attention (causal, fp32) ========================
#define KS_STRIDE 129
#define ATTN_SMEM ((64 * 128 + 64 * KS_STRIDE + 64 * 128 + 64 * 64) * 4)

extern __shared__ float attn_smem[];
__global__ __launch_bounds__(256, 1)
void attn_kernel(const float* __restrict__ Q, const float* __restrict__ K,
                 const float* __restrict__ V, float* __restrict__ O)
{
    float* Qs = attn_smem;
    float* Ks = Qs + 64 * 128;
    float* Vs = Ks + 64 * KS_STRIDE;
    float* Ps = Vs + 64 * 128;

    const int qb = blockIdx.x;
    const int h  = blockIdx.y;
    const int q0 = qb * 64;
    const int tid = threadIdx.x;
    const int tx = tid & 15, ty = tid >> 4;

    for (int i = tid; i < 64 * 128; i += 256) {
        int r = i >> 7, c = i & 127;
        Qs[i] = Q[(size_t)(q0 + r) * H_DIM + h * HD_DIM + c];
    }

    float m[4], l[4], acc[4][8];
    #pragma unroll
    for (int i = 0; i < 4; i++) {
        m[i] = -1e30f; l[i] = 0.f;
        #pragma unroll
        for (int j = 0; j < 8; j++) acc[i][j] = 0.f;
    }
    const float scaling = 0.08838834764831845f;

    for (int j0 = 0; j0 <= q0; j0 += 64) {
        __syncthreads();
        for (int i = tid; i < 64 * 128; i += 256) {
            int r = i >> 7, c = i & 127;
            size_t gidx = (size_t)(j0 + r) * H_DIM + h * HD_DIM + c;
            Ks[r * KS_STRIDE + c] = K[gidx];
            Vs[i] = V[gidx];
        }
        __syncthreads();

        float s[4][4];
        #pragma unroll
        for (int i = 0; i < 4; i++)
            #pragma unroll
            for (int j = 0; j < 4; j++) s[i][j] = 0.f;

        #pragma unroll 4
        for (int d = 0; d < 128; d++) {
            float qv[4], kv[4];
            #pragma unroll
            for (int i = 0; i < 4; i++) qv[i] = Qs[(ty * 4 + i) * 128 + d];
            #pragma unroll
            for (int j = 0; j < 4; j++) kv[j] = Ks[(tx * 4 + j) * KS_STRIDE + d];
            #pragma unroll
            for (int i = 0; i < 4; i++)
                #pragma unroll
                for (int j = 0; j < 4; j++)
                    s[i][j] = fmaf(qv[i], kv[j], s[i][j]);
        }

        const bool diag = (j0 == q0);
        #pragma unroll
        for (int i = 0; i < 4; i++)
            #pragma unroll
            for (int j = 0; j < 4; j++) {
                s[i][j] *= scaling;
                if (diag && (tx * 4 + j) > (ty * 4 + i)) s[i][j] = -1e30f;
            }

        #pragma unroll
        for (int i = 0; i < 4; i++) {
            float mx = fmaxf(fmaxf(s[i][0], s[i][1]), fmaxf(s[i][2], s[i][3]));
            #pragma unroll
            for (int off = 8; off; off >>= 1)
                mx = fmaxf(mx, __shfl_xor_sync(0xffffffffu, mx, off));
            float mnew = fmaxf(m[i], mx);
            float p[4], rs = 0.f;
            #pragma unroll
            for (int j = 0; j < 4; j++) { p[j] = expf(s[i][j] - mnew); rs += p[j]; }
            #pragma unroll
            for (int off = 8; off; off >>= 1)
                rs += __shfl_xor_sync(0xffffffffu, rs, off);
            float alpha = expf(m[i] - mnew);
            l[i] = l[i] * alpha + rs;
            m[i] = mnew;
            #pragma unroll
            for (int j = 0; j < 8; j++) acc[i][j] *= alpha;
            #pragma unroll
            for (int j = 0; j < 4; j++) Ps[(ty * 4 + i) * 64 + tx * 4 + j] = p[j];
        }
        __syncthreads();

        #pragma unroll 2
        for (int kk = 0; kk < 64; kk++) {
            float pv[4];
            #pragma unroll
            for (int i = 0; i < 4; i++) pv[i] = Ps[(ty * 4 + i) * 64 + kk];
            #pragma unroll
            for (int j = 0; j < 8; j++) {
                float vv = Vs[kk * 128 + tx + j * 16];
                #pragma unroll
                for (int i = 0; i < 4; i++)
                    acc[i][j] = fmaf(pv[i], vv, acc[i][j]);
            }
        }
    }

    #pragma unroll
    for (int i = 0; i < 4; i++) {
        float inv = 1.f / l[i];
        #pragma unroll
        for (int j = 0; j < 8; j++)
            O[(size_t)(q0 + ty * 4 + i) * H_DIM + h * HD_DIM + tx + j * 16] = acc[i][j] * inv;
    }
}

// ===================== launch ================================================
extern "C" void kernel_launch(void* const* d_in, const int* in_sizes, int n_in,
                              void* d_out, int out_size)
{
    (void)in_sizes; (void)n_in; (void)out_size;
    const int*   positions = (const int*)  d_in[0];
    const float* hidden    = (const float*)d_in[1];
    const float* ln1       = (const float*)d_in[2];
    const float* wq = (const float*)d_in[3];
    const float* bq = (const float*)d_in[4];
    const float* wk = (const float*)d_in[5];
    const float* bk = (const float*)d_in[6];
    const float* wv = (const float*)d_in[7];
    const float* bv = (const float*)d_in[8];
    const float* wo = (const float*)d_in[9];
    const float* ln2= (const float*)d_in[10];
    const float* w1 = (const float*)d_in[11];
    const float* w2 = (const float*)d_in[12];
    const float* wc = (const float*)d_in[13];
    float* out = (float*)d_out;

    float *q, *k, *v, *att, *hbuf, *a1, *a2;
    bf16 *xnh, *xnl, *atth, *attl, *yh, *yl, *gh, *gl;
    bf16 *wqh, *wql, *wkh, *wkl, *wvh, *wvl, *woh, *wol;
    bf16 *w1h, *w1l, *w2h, *w2l, *wch, *wcl;
    cudaGetSymbolAddress((void**)&q,    g_q);
    cudaGetSymbolAddress((void**)&k,    g_k);
    cudaGetSymbolAddress((void**)&v,    g_v);
    cudaGetSymbolAddress((void**)&att,  g_att);
    cudaGetSymbolAddress((void**)&hbuf, g_h);
    cudaGetSymbolAddress((void**)&a1,   g_a1);
    cudaGetSymbolAddress((void**)&a2,   g_a2);
    cudaGetSymbolAddress((void**)&xnh,  g_xnh);
    cudaGetSymbolAddress((void**)&xnl,  g_xnl);
    cudaGetSymbolAddress((void**)&atth, g_atth);
    cudaGetSymbolAddress((void**)&attl, g_attl);
    cudaGetSymbolAddress((void**)&yh,   g_yh);
    cudaGetSymbolAddress((void**)&yl,   g_yl);
    cudaGetSymbolAddress((void**)&gh,   g_gh);
    cudaGetSymbolAddress((void**)&gl,   g_gl);
    cudaGetSymbolAddress((void**)&wqh,  g_wqh);
    cudaGetSymbolAddress((void**)&wql,  g_wql);
    cudaGetSymbolAddress((void**)&wkh,  g_wkh);
    cudaGetSymbolAddress((void**)&wkl,  g_wkl);
    cudaGetSymbolAddress((void**)&wvh,  g_wvh);
    cudaGetSymbolAddress((void**)&wvl,  g_wvl);
    cudaGetSymbolAddress((void**)&woh,  g_woh);
    cudaGetSymbolAddress((void**)&wol,  g_wol);
    cudaGetSymbolAddress((void**)&w1h,  g_w1h);
    cudaGetSymbolAddress((void**)&w1l,  g_w1l);
    cudaGetSymbolAddress((void**)&w2h,  g_w2h);
    cudaGetSymbolAddress((void**)&w2l,  g_w2l);
    cudaGetSymbolAddress((void**)&wch,  g_wch);
    cudaGetSymbolAddress((void**)&wcl,  g_wcl);

    cudaFuncSetAttribute(attn_kernel, cudaFuncAttributeMaxDynamicSharedMemorySize, ATTN_SMEM);
    cudaFuncSetAttribute(gemm_mma_bf16x3, cudaFuncAttributeMaxDynamicSharedMemorySize, GEMM_SMEM);

    dim3 tb(32, 8);
    transpose_hilo_kernel<<<dim3(H_DIM/32, H_DIM/32), tb>>>(wq, H_DIM, H_DIM, wqh, wql);
    transpose_hilo_kernel<<<dim3(H_DIM/32, H_DIM/32), tb>>>(wk, H_DIM, H_DIM, wkh, wkl);
    transpose_hilo_kernel<<<dim3(H_DIM/32, H_DIM/32), tb>>>(wv, H_DIM, H_DIM, wvh, wvl);
    transpose_hilo_kernel<<<dim3(H_DIM/32, H_DIM/32), tb>>>(wo, H_DIM, H_DIM, woh, wol);
    transpose_hilo_kernel<<<dim3(FF_DIM/32, H_DIM/32), tb>>>(w1, H_DIM, FF_DIM, w1h, w1l);
    transpose_hilo_kernel<<<dim3(FF_DIM/32, H_DIM/32), tb>>>(w2, H_DIM, FF_DIM, w2h, w2l);
    transpose_hilo_kernel<<<dim3(H_DIM/32, FF_DIM/32), tb>>>(wc, FF_DIM, H_DIM, wch, wcl);

    // 1) x = rmsnorm(hidden, ln1) -> bf16 hi/lo
    rmsnorm_hilo_kernel<<<T_DIM, 256>>>(hidden, ln1, xnh, xnl);

    // 2) q/k/v
    dim3 gH(H_DIM / BN, T_DIM / BM);
    gemm_mma_bf16x3<<<gH, 256, GEMM_SMEM>>>(xnh, xnl, wqh, wql, bq, nullptr, q, H_DIM, H_DIM);
    gemm_mma_bf16x3<<<gH, 256, GEMM_SMEM>>>(xnh, xnl, wkh, wkl, bk, nullptr, k, H_DIM, H_DIM);
    gemm_mma_bf16x3<<<gH, 256, GEMM_SMEM>>>(xnh, xnl, wvh, wvl, bv, nullptr, v, H_DIM, H_DIM);

    // 3) RoPE
    rope_kernel<<<(T_DIM * NHEADS * (HD_DIM / 2)) / 256, 256>>>(q, k, positions);

    // 4) attention
    attn_kernel<<<dim3(T_DIM / 64, NHEADS), 256, ATTN_SMEM>>>(q, k, v, att);

    // 5) h = hidden + attn @ wo
    hilo_kernel<<<(T_DIM * H_DIM) / 256, 256>>>(att, atth, attl, T_DIM * H_DIM);
    gemm_mma_bf16x3<<<gH, 256, GEMM_SMEM>>>(atth, attl, woh, wol, nullptr, hidden, hbuf, H_DIM, H_DIM);

    // 6) y = rmsnorm(h, ln2)
    rmsnorm_hilo_kernel<<<T_DIM, 256>>>(hbuf, ln2, yh, yl);

    // 7) MLP up + gate
    dim3 gF(FF_DIM / BN, T_DIM / BM);
    gemm_mma_bf16x3<<<gF, 256, GEMM_SMEM>>>(yh, yl, w1h, w1l, nullptr, nullptr, a1, FF_DIM, H_DIM);
    gemm_mma_bf16x3<<<gF, 256, GEMM_SMEM>>>(yh, yl, w2h, w2l, nullptr, nullptr, a2, FF_DIM, H_DIM);
    silu_hilo_kernel<<<(T_DIM * FF_DIM + 255) / 256, 256>>>(a1, a2, gh, gl, T_DIM * FF_DIM);

    // 8) out = h + g @ wc
    gemm_mma_bf16x3<<<gH, 256, GEMM_SMEM>>>(gh, gl, wch, wcl, nullptr, hbuf, out, H_DIM, FF_DIM);
}

// round 4
// speedup vs baseline: 2.3243x; 1.2289x over previous
#include <cuda_runtime.h>
#include <cuda_bf16.h>
#include <math.h>
#include <cstdint>

#define T_DIM 2048
#define H_DIM 4096
#define NHEADS 32
#define HD_DIM 128
#define FF_DIM 11008
#define EPS_V 1e-6f

typedef __nv_bfloat16 bf16;

// ===================== device scratch ======================================
__device__ float g_q  [(size_t)T_DIM * H_DIM];
__device__ float g_k  [(size_t)T_DIM * H_DIM];
__device__ float g_v  [(size_t)T_DIM * H_DIM];
__device__ float g_h  [(size_t)T_DIM * H_DIM];
__device__ float g_a1 [(size_t)T_DIM * FF_DIM];
__device__ float g_a2 [(size_t)T_DIM * FF_DIM];

__device__ bf16 g_xnh [(size_t)T_DIM * H_DIM];
__device__ bf16 g_xnl [(size_t)T_DIM * H_DIM];
__device__ bf16 g_atth[(size_t)T_DIM * H_DIM];
__device__ bf16 g_attl[(size_t)T_DIM * H_DIM];
__device__ bf16 g_yh  [(size_t)T_DIM * H_DIM];
__device__ bf16 g_yl  [(size_t)T_DIM * H_DIM];
__device__ bf16 g_gh  [(size_t)T_DIM * FF_DIM];
__device__ bf16 g_gl  [(size_t)T_DIM * FF_DIM];

__device__ bf16 g_wqh[(size_t)H_DIM * H_DIM];
__device__ bf16 g_wql[(size_t)H_DIM * H_DIM];
__device__ bf16 g_wkh[(size_t)H_DIM * H_DIM];
__device__ bf16 g_wkl[(size_t)H_DIM * H_DIM];
__device__ bf16 g_wvh[(size_t)H_DIM * H_DIM];
__device__ bf16 g_wvl[(size_t)H_DIM * H_DIM];
__device__ bf16 g_woh[(size_t)H_DIM * H_DIM];
__device__ bf16 g_wol[(size_t)H_DIM * H_DIM];
__device__ bf16 g_w1h[(size_t)FF_DIM * H_DIM];
__device__ bf16 g_w1l[(size_t)FF_DIM * H_DIM];
__device__ bf16 g_w2h[(size_t)FF_DIM * H_DIM];
__device__ bf16 g_w2l[(size_t)FF_DIM * H_DIM];
__device__ bf16 g_wch[(size_t)H_DIM * FF_DIM];
__device__ bf16 g_wcl[(size_t)H_DIM * FF_DIM];

// ===================== PTX helpers =========================================
__device__ __forceinline__ uint32_t smem_u32(const void* p) {
    uint32_t a;
    asm("{ .reg .u64 t; cvta.to.shared.u64 t, %1; cvt.u32.u64 %0, t; }"
        : "=r"(a) : "l"(p));
    return a;
}

#define CP_ASYNC16(dst, src) \
    asm volatile("cp.async.cg.shared.global [%0], [%1], 16;" :: "r"(dst), "l"(src))
#define CP_COMMIT() asm volatile("cp.async.commit_group;" ::: "memory")

__device__ __forceinline__ void ldsm_x4(uint32_t* r, uint32_t a) {
    asm volatile("ldmatrix.sync.aligned.m8n8.x4.shared.b16 {%0,%1,%2,%3}, [%4];"
        : "=r"(r[0]), "=r"(r[1]), "=r"(r[2]), "=r"(r[3]) : "r"(a));
}
__device__ __forceinline__ void ldsm_x4t(uint32_t* r, uint32_t a) {
    asm volatile("ldmatrix.sync.aligned.m8n8.x4.trans.shared.b16 {%0,%1,%2,%3}, [%4];"
        : "=r"(r[0]), "=r"(r[1]), "=r"(r[2]), "=r"(r[3]) : "r"(a));
}

__device__ __forceinline__ void mma16816(float* d, const uint32_t* a,
                                         uint32_t b0, uint32_t b1) {
    asm volatile(
        "mma.sync.aligned.m16n8k16.row.col.f32.bf16.bf16.f32 "
        "{%0,%1,%2,%3}, {%4,%5,%6,%7}, {%8,%9}, {%0,%1,%2,%3};"
        : "+f"(d[0]), "+f"(d[1]), "+f"(d[2]), "+f"(d[3])
        : "r"(a[0]), "r"(a[1]), "r"(a[2]), "r"(a[3]), "r"(b0), "r"(b1));
}

__device__ __forceinline__ void split_hilo(float v, bf16& h, bf16& l) {
    h = __float2bfloat16(v);
    l = __float2bfloat16(v - __bfloat162float(h));
}

// ===================== fused bf16x3 GEMM (single K sweep) ====================
// C[M,N] = A@B^T ; per BK=32 chunk loads Ah,Al,Bh,Bl and does 3 MMA combos.
#define BM 128
#define BN 128
#define GBK 32
#define GROWB 80                    // 64B data + 16B pad per row
#define GTILE (128 * GROWB)         // 10240
#define GSTG 4
#define GSTAGE_B (4 * GTILE)        // 40960
#define GEMM_SMEM (GSTG * GSTAGE_B) // 163840

__global__ __launch_bounds__(256, 1)
void gemm_mma_bf16x3(const bf16* __restrict__ Ah, const bf16* __restrict__ Al,
                     const bf16* __restrict__ Bh, const bf16* __restrict__ Bl,
                     const float* __restrict__ bias, const float* __restrict__ resid,
                     float* __restrict__ C, int Ntot, int K)
{
    extern __shared__ char dsm[];
    const int tid = threadIdx.x;
    const int wid = tid >> 5, lane = tid & 31;
    const int rowA0 = blockIdx.y * BM;
    const int colB0 = blockIdx.x * BN;
    const int nIter = K >> 5;
    const uint32_t sbase = smem_u32(dsm);

    // load row/seg for this thread (512 chunks per tile, 2 per thread)
    auto load_stage = [&](int it) {
        const int s = it & (GSTG - 1);
        const size_t koff = (size_t)it * GBK;
        const uint32_t st = sbase + s * GSTAGE_B;
        #pragma unroll
        for (int i = 0; i < 2; i++) {
            int idx = tid + i * 256;
            int r = idx >> 2, seg = idx & 3;
            uint32_t doff = r * GROWB + seg * 16;
            const size_t goff = koff + seg * 8;
            CP_ASYNC16(st + 0 * GTILE + doff, Ah + (size_t)(rowA0 + r) * K + goff);
            CP_ASYNC16(st + 1 * GTILE + doff, Al + (size_t)(rowA0 + r) * K + goff);
            CP_ASYNC16(st + 2 * GTILE + doff, Bh + (size_t)(colB0 + r) * K + goff);
            CP_ASYNC16(st + 3 * GTILE + doff, Bl + (size_t)(colB0 + r) * K + goff);
        }
        CP_COMMIT();
    };

    // warp tiling: 4 (m) x 2 (n); warp tile 32 x 64
    const int m0 = (wid >> 1) * 32;
    const int n0 = (wid & 1) * 64;

    float acc[2][8][4];
    #pragma unroll
    for (int i = 0; i < 2; i++)
        #pragma unroll
        for (int j = 0; j < 8; j++)
            #pragma unroll
            for (int c = 0; c < 4; c++) acc[i][j][c] = 0.f;

    const int mi = lane >> 3, l7 = lane & 7;
    const uint32_t aoff = (uint32_t)((m0 + (mi & 1) * 8 + l7) * GROWB + (mi >> 1) * 16);
    const uint32_t boff = (uint32_t)((n0 + (mi >> 1) * 8 + l7) * GROWB + (mi & 1) * 16);

    load_stage(0); load_stage(1); load_stage(2);

    for (int it = 0; it < nIter; it++) {
        if (it + GSTG - 1 < nIter) load_stage(it + GSTG - 1);
        else CP_COMMIT();
        asm volatile("cp.async.wait_group %0;" :: "n"(GSTG - 1));
        __syncthreads();

        const uint32_t st = sbase + (it & (GSTG - 1)) * GSTAGE_B;
        const uint32_t sah = st, sal = st + GTILE, sbh = st + 2 * GTILE, sbl = st + 3 * GTILE;

        #pragma unroll
        for (int kk = 0; kk < 2; kk++) {
            uint32_t ah0[4], ah1[4], al0[4], al1[4];
            ldsm_x4(ah0, sah + aoff + kk * 32);
            ldsm_x4(ah1, sah + aoff + 16 * GROWB + kk * 32);
            ldsm_x4(al0, sal + aoff + kk * 32);
            ldsm_x4(al1, sal + aoff + 16 * GROWB + kk * 32);
            #pragma unroll
            for (int g = 0; g < 4; g++) {
                uint32_t bh[4], bl[4];
                ldsm_x4(bh, sbh + boff + g * 16 * GROWB + kk * 32);
                ldsm_x4(bl, sbl + boff + g * 16 * GROWB + kk * 32);
                // Ah*Bh
                mma16816(acc[0][2*g+0], ah0, bh[0], bh[1]);
                mma16816(acc[0][2*g+1], ah0, bh[2], bh[3]);
                mma16816(acc[1][2*g+0], ah1, bh[0], bh[1]);
                mma16816(acc[1][2*g+1], ah1, bh[2], bh[3]);
                // Ah*Bl
                mma16816(acc[0][2*g+0], ah0, bl[0], bl[1]);
                mma16816(acc[0][2*g+1], ah0, bl[2], bl[3]);
                mma16816(acc[1][2*g+0], ah1, bl[0], bl[1]);
                mma16816(acc[1][2*g+1], ah1, bl[2], bl[3]);
                // Al*Bh
                mma16816(acc[0][2*g+0], al0, bh[0], bh[1]);
                mma16816(acc[0][2*g+1], al0, bh[2], bh[3]);
                mma16816(acc[1][2*g+0], al1, bh[0], bh[1]);
                mma16816(acc[1][2*g+1], al1, bh[2], bh[3]);
            }
        }
        __syncthreads();
    }

    const int l4 = lane >> 2, l2 = (lane & 3) * 2;
    #pragma unroll
    for (int mf = 0; mf < 2; mf++) {
        const int r = rowA0 + m0 + mf * 16 + l4;
        #pragma unroll
        for (int nf = 0; nf < 8; nf++) {
            const int c = colB0 + n0 + nf * 8 + l2;
            float2 v0 = make_float2(acc[mf][nf][0], acc[mf][nf][1]);
            float2 v1 = make_float2(acc[mf][nf][2], acc[mf][nf][3]);
            if (bias) {
                v0.x += bias[c]; v0.y += bias[c + 1];
                v1.x += bias[c]; v1.y += bias[c + 1];
            }
            if (resid) {
                const float2 r0 = *(const float2*)&resid[(size_t)r * Ntot + c];
                const float2 r1 = *(const float2*)&resid[(size_t)(r + 8) * Ntot + c];
                v0.x += r0.x; v0.y += r0.y;
                v1.x += r1.x; v1.y += r1.y;
            }
            *(float2*)&C[(size_t)r * Ntot + c] = v0;
            *(float2*)&C[(size_t)(r + 8) * Ntot + c] = v1;
        }
    }
}

// ===================== tensor-core flash attention ===========================
// BQ=64 per CTA (4 warps, warp owns 16 q-rows), kv blocks of 64.
// S via 3-pass hi/lo mma; softmax fp32; P bf16; V bf16 via ldmatrix.trans.
#define AROW 272                  // 128 bf16 * 2B + 16 pad
#define PSROW 144                 // 64 bf16 * 2B + 16 pad
#define OFF_QH 0
#define OFF_QL (OFF_QH + 64 * AROW)
#define OFF_KH (OFF_QL + 64 * AROW)
#define OFF_KL (OFF_KH + 64 * AROW)
#define OFF_VS (OFF_KL + 64 * AROW)
#define OFF_PS (OFF_VS + 64 * AROW)
#define ATTN_SMEM (OFF_PS + 64 * PSROW)   // 96256

__global__ __launch_bounds__(128, 2)
void attn_mma_kernel(const float* __restrict__ Q, const float* __restrict__ K,
                     const float* __restrict__ V,
                     bf16* __restrict__ Oh, bf16* __restrict__ Ol)
{
    extern __shared__ char asm_[];
    const uint32_t sb = smem_u32(asm_);
    const int q0 = blockIdx.x * 64;
    const int h  = blockIdx.y;
    const int tid = threadIdx.x;
    const int w = tid >> 5, lane = tid & 31;
    const int mi = lane >> 3, l7 = lane & 7;

    // load+split Q tile [64 x 128]
    for (int i = tid; i < 64 * 128; i += 128) {
        int r = i >> 7, c = i & 127;
        float v = Q[(size_t)(q0 + r) * H_DIM + h * HD_DIM + c];
        bf16 hh, ll; split_hilo(v, hh, ll);
        *(bf16*)(asm_ + OFF_QH + r * AROW + c * 2) = hh;
        *(bf16*)(asm_ + OFF_QL + r * AROW + c * 2) = ll;
    }

    float oacc[16][4];
    #pragma unroll
    for (int f = 0; f < 16; f++)
        #pragma unroll
        for (int c = 0; c < 4; c++) oacc[f][c] = 0.f;
    float m0v = -1e30f, m1v = -1e30f, l0v = 0.f, l1v = 0.f;
    const float scaling = 0.08838834764831845f;

    const uint32_t aq_off = (uint32_t)((w * 16 + (mi & 1) * 8 + l7) * AROW + (mi >> 1) * 16);
    const uint32_t bk_off = (uint32_t)(((mi >> 1) * 8 + l7) * AROW + (mi & 1) * 16);
    const uint32_t ps_off = (uint32_t)((w * 16 + (mi & 1) * 8 + l7) * PSROW + (mi >> 1) * 16);

    const int r0 = lane >> 2;                 // rows r0, r0+8 of warp's m16
    const int gq0 = q0 + w * 16 + r0;
    const int gq1 = gq0 + 8;

    for (int j0 = 0; j0 <= q0; j0 += 64) {
        __syncthreads();
        // load K (split) and V (bf16) [64 x 128]
        for (int i = tid; i < 64 * 128; i += 128) {
            int r = i >> 7, c = i & 127;
            size_t gidx = (size_t)(j0 + r) * H_DIM + h * HD_DIM + c;
            float kv = K[gidx];
            bf16 hh, ll; split_hilo(kv, hh, ll);
            *(bf16*)(asm_ + OFF_KH + r * AROW + c * 2) = hh;
            *(bf16*)(asm_ + OFF_KL + r * AROW + c * 2) = ll;
            *(bf16*)(asm_ + OFF_VS + r * AROW + c * 2) = __float2bfloat16(V[gidx]);
        }
        __syncthreads();

        // S = Qh*Kh + Qh*Kl + Ql*Kh   (m16 x n64, k=128)
        float sacc[8][4];
        #pragma unroll
        for (int f = 0; f < 8; f++)
            #pragma unroll
            for (int c = 0; c < 4; c++) sacc[f][c] = 0.f;

        #pragma unroll
        for (int pass = 0; pass < 3; pass++) {
            const uint32_t sa = sb + ((pass < 2) ? OFF_QH : OFF_QL);
            const uint32_t skb = sb + ((pass == 1) ? OFF_KL : OFF_KH);
            #pragma unroll
            for (int ks = 0; ks < 8; ks++) {
                uint32_t a[4];
                ldsm_x4(a, sa + aq_off + ks * 32);
                #pragma unroll
                for (int g = 0; g < 4; g++) {
                    uint32_t b[4];
                    ldsm_x4(b, skb + bk_off + g * 16 * AROW + ks * 32);
                    mma16816(sacc[2*g+0], a, b[0], b[1]);
                    mma16816(sacc[2*g+1], a, b[2], b[3]);
                }
            }
        }

        // scale + causal mask
        const bool diag = (j0 == q0);
        #pragma unroll
        for (int f = 0; f < 8; f++) {
            int kvc = j0 + f * 8 + (lane & 3) * 2;
            #pragma unroll
            for (int c = 0; c < 4; c++) sacc[f][c] *= scaling;
            if (diag) {
                if (kvc     > gq0) sacc[f][0] = -1e30f;
                if (kvc + 1 > gq0) sacc[f][1] = -1e30f;
                if (kvc     > gq1) sacc[f][2] = -1e30f;
                if (kvc + 1 > gq1) sacc[f][3] = -1e30f;
            }
        }

        // online softmax (rows r0, r0+8; lanes sharing a row differ in bits 0..1)
        float mx0 = -1e30f, mx1 = -1e30f;
        #pragma unroll
        for (int f = 0; f < 8; f++) {
            mx0 = fmaxf(mx0, fmaxf(sacc[f][0], sacc[f][1]));
            mx1 = fmaxf(mx1, fmaxf(sacc[f][2], sacc[f][3]));
        }
        mx0 = fmaxf(mx0, __shfl_xor_sync(0xffffffffu, mx0, 1));
        mx0 = fmaxf(mx0, __shfl_xor_sync(0xffffffffu, mx0, 2));
        mx1 = fmaxf(mx1, __shfl_xor_sync(0xffffffffu, mx1, 1));
        mx1 = fmaxf(mx1, __shfl_xor_sync(0xffffffffu, mx1, 2));
        const float mn0 = fmaxf(m0v, mx0), mn1 = fmaxf(m1v, mx1);
        float rs0 = 0.f, rs1 = 0.f;
        #pragma unroll
        for (int f = 0; f < 8; f++) {
            float p0 = expf(sacc[f][0] - mn0);
            float p1 = expf(sacc[f][1] - mn0);
            float p2 = expf(sacc[f][2] - mn1);
            float p3 = expf(sacc[f][3] - mn1);
            rs0 += p0 + p1; rs1 += p2 + p3;
            __nv_bfloat162 v01 = __floats2bfloat162_rn(p0, p1);
            __nv_bfloat162 v23 = __floats2bfloat162_rn(p2, p3);
            uint32_t col = (f * 8 + (lane & 3) * 2) * 2;
            *(uint32_t*)(asm_ + OFF_PS + (w * 16 + r0) * PSROW + col) = *(uint32_t*)&v01;
            *(uint32_t*)(asm_ + OFF_PS + (w * 16 + r0 + 8) * PSROW + col) = *(uint32_t*)&v23;
        }
        rs0 += __shfl_xor_sync(0xffffffffu, rs0, 1);
        rs0 += __shfl_xor_sync(0xffffffffu, rs0, 2);
        rs1 += __shfl_xor_sync(0xffffffffu, rs1, 1);
        rs1 += __shfl_xor_sync(0xffffffffu, rs1, 2);
        const float al0 = expf(m0v - mn0), al1 = expf(m1v - mn1);
        l0v = l0v * al0 + rs0; l1v = l1v * al1 + rs1;
        m0v = mn0; m1v = mn1;
        #pragma unroll
        for (int f = 0; f < 16; f++) {
            oacc[f][0] *= al0; oacc[f][1] *= al0;
            oacc[f][2] *= al1; oacc[f][3] *= al1;
        }
        __syncwarp();

        // O += P @ V   (m16 x n128, k=64); V via ldmatrix.trans
        #pragma unroll
        for (int ks = 0; ks < 4; ks++) {
            uint32_t a[4];
            ldsm_x4(a, sb + OFF_PS + ps_off + ks * 32);
            #pragma unroll
            for (int g = 0; g < 8; g++) {
                uint32_t b[4];
                ldsm_x4t(b, sb + OFF_VS + (ks * 16 + (mi & 1) * 8 + l7) * AROW
                               + (g * 16 + (mi >> 1) * 8) * 2);
                mma16816(oacc[2*g+0], a, b[0], b[1]);
                mma16816(oacc[2*g+1], a, b[2], b[3]);
            }
        }
    }

    // epilogue: write hi/lo bf16 directly
    const float i0 = 1.f / l0v, i1 = 1.f / l1v;
    #pragma unroll
    for (int f = 0; f < 16; f++) {
        int col = h * HD_DIM + f * 8 + (lane & 3) * 2;
        float a0 = oacc[f][0] * i0, a1 = oacc[f][1] * i0;
        float b0 = oacc[f][2] * i1, b1 = oacc[f][3] * i1;
        bf16 h0, l0, h1, l1, h2, l2, h3, l3;
        split_hilo(a0, h0, l0); split_hilo(a1, h1, l1);
        split_hilo(b0, h2, l2); split_hilo(b1, h3, l3);
        __nv_bfloat162 hh0 = {h0, h1}, ll0 = {l0, l1};
        __nv_bfloat162 hh1 = {h2, h3}, ll1 = {l2, l3};
        *(__nv_bfloat162*)&Oh[(size_t)gq0 * H_DIM + col] = hh0;
        *(__nv_bfloat162*)&Ol[(size_t)gq0 * H_DIM + col] = ll0;
        *(__nv_bfloat162*)&Oh[(size_t)gq1 * H_DIM + col] = hh1;
        *(__nv_bfloat162*)&Ol[(size_t)gq1 * H_DIM + col] = ll1;
    }
}

// ===================== elementwise / conversion kernels =====================
__global__ void rmsnorm_hilo_kernel(const float* __restrict__ x,
                                    const float* __restrict__ scale,
                                    bf16* __restrict__ oh, bf16* __restrict__ ol)
{
    int row = blockIdx.x;
    const float4* xr = (const float4*)(x + (size_t)row * H_DIM);
    float ss = 0.f;
    for (int i = threadIdx.x; i < H_DIM / 4; i += blockDim.x) {
        float4 v = xr[i];
        ss += v.x * v.x + v.y * v.y + v.z * v.z + v.w * v.w;
    }
    #pragma unroll
    for (int off = 16; off; off >>= 1) ss += __shfl_xor_sync(0xffffffffu, ss, off);
    __shared__ float red[32];
    int lane = threadIdx.x & 31, wid = threadIdx.x >> 5;
    if (lane == 0) red[wid] = ss;
    __syncthreads();
    if (wid == 0) {
        ss = (lane < (int)(blockDim.x >> 5)) ? red[lane] : 0.f;
        #pragma unroll
        for (int off = 16; off; off >>= 1) ss += __shfl_xor_sync(0xffffffffu, ss, off);
        if (lane == 0) red[0] = ss;
    }
    __syncthreads();
    float inv = rsqrtf(red[0] / (float)H_DIM + EPS_V);
    const float4* sc = (const float4*)scale;
    for (int i = threadIdx.x; i < H_DIM / 4; i += blockDim.x) {
        float4 v = xr[i], s = sc[i];
        float f[4] = {v.x * inv * s.x, v.y * inv * s.y, v.z * inv * s.z, v.w * inv * s.w};
        size_t base = (size_t)row * H_DIM + i * 4;
        #pragma unroll
        for (int c = 0; c < 4; c++) {
            bf16 h, l; split_hilo(f[c], h, l);
            oh[base + c] = h; ol[base + c] = l;
        }
    }
}

__global__ void silu_hilo_kernel(const float* __restrict__ a1,
                                 const float* __restrict__ a2,
                                 bf16* __restrict__ oh, bf16* __restrict__ ol, int n)
{
    int i = blockIdx.x * blockDim.x + threadIdx.x;
    if (i < n) {
        float g = a2[i];
        float v = a1[i] * (g / (1.f + expf(-g)));
        bf16 h, l; split_hilo(v, h, l);
        oh[i] = h; ol[i] = l;
    }
}

// W[K][N] fp32  ->  Th/Tl[N][K] bf16 hi/lo (transposed)
__global__ void transpose_hilo_kernel(const float* __restrict__ W, int K, int N,
                                      bf16* __restrict__ Th, bf16* __restrict__ Tl)
{
    __shared__ float t[32][33];
    int n0 = blockIdx.x * 32, k0 = blockIdx.y * 32;
    int tx = threadIdx.x, ty = threadIdx.y;
    #pragma unroll
    for (int i = ty; i < 32; i += 8)
        t[i][tx] = W[(size_t)(k0 + i) * N + n0 + tx];
    __syncthreads();
    #pragma unroll
    for (int i = ty; i < 32; i += 8) {
        float v = t[tx][i];
        bf16 h, l; split_hilo(v, h, l);
        size_t idx = (size_t)(n0 + i) * K + k0 + tx;
        Th[idx] = h; Tl[idx] = l;
    }
}

// ===================== RoPE ==================================================
__global__ void rope_kernel(float* __restrict__ q, float* __restrict__ k,
                            const int* __restrict__ pos)
{
    int idx = blockIdx.x * blockDim.x + threadIdx.x;
    if (idx >= T_DIM * NHEADS * (HD_DIM / 2)) return;
    int d  = idx & 63;
    int th = idx >> 6;
    int t  = th >> 5;
    float invf = powf(10000.0f, -(float)d * (1.0f / 64.0f));
    float ang = (float)pos[t] * invf;
    float c, s;
    sincosf(ang, &s, &c);
    size_t base = (size_t)th * HD_DIM + d;
    float q1 = q[base], q2 = q[base + 64];
    q[base]      = q1 * c - q2 * s;
    q[base + 64] = q2 * c + q1 * s;
    float k1 = k[base], k2 = k[base + 64];
    k[base]      = k1 * c - k2 * s;
    k[base + 64] = k2 * c + k1 * s;
}

// ===================== launch ================================================
extern "C" void kernel_launch(void* const* d_in, const int* in_sizes, int n_in,
                              void* d_out, int out_size)
{
    (void)in_sizes; (void)n_in; (void)out_size;
    const int*   positions = (const int*)  d_in[0];
    const float* hidden    = (const float*)d_in[1];
    const float* ln1       = (const float*)d_in[2];
    const float* wq = (const float*)d_in[3];
    const float* bq = (const float*)d_in[4];
    const float* wk = (const float*)d_in[5];
    const float* bk = (const float*)d_in[6];
    const float* wv = (const float*)d_in[7];
    const float* bv = (const float*)d_in[8];
    const float* wo = (const float*)d_in[9];
    const float* ln2= (const float*)d_in[10];
    const float* w1 = (const float*)d_in[11];
    const float* w2 = (const float*)d_in[12];
    const float* wc = (const float*)d_in[13];
    float* out = (float*)d_out;

    float *q, *k, *v, *hbuf, *a1, *a2;
    bf16 *xnh, *xnl, *atth, *attl, *yh, *yl, *gh, *gl;
    bf16 *wqh, *wql, *wkh, *wkl, *wvh, *wvl, *woh, *wol;
    bf16 *w1h, *w1l, *w2h, *w2l, *wch, *wcl;
    cudaGetSymbolAddress((void**)&q,    g_q);
    cudaGetSymbolAddress((void**)&k,    g_k);
    cudaGetSymbolAddress((void**)&v,    g_v);
    cudaGetSymbolAddress((void**)&hbuf, g_h);
    cudaGetSymbolAddress((void**)&a1,   g_a1);
    cudaGetSymbolAddress((void**)&a2,   g_a2);
    cudaGetSymbolAddress((void**)&xnh,  g_xnh);
    cudaGetSymbolAddress((void**)&xnl,  g_xnl);
    cudaGetSymbolAddress((void**)&atth, g_atth);
    cudaGetSymbolAddress((void**)&attl, g_attl);
    cudaGetSymbolAddress((void**)&yh,   g_yh);
    cudaGetSymbolAddress((void**)&yl,   g_yl);
    cudaGetSymbolAddress((void**)&gh,   g_gh);
    cudaGetSymbolAddress((void**)&gl,   g_gl);
    cudaGetSymbolAddress((void**)&wqh,  g_wqh);
    cudaGetSymbolAddress((void**)&wql,  g_wql);
    cudaGetSymbolAddress((void**)&wkh,  g_wkh);
    cudaGetSymbolAddress((void**)&wkl,  g_wkl);
    cudaGetSymbolAddress((void**)&wvh,  g_wvh);
    cudaGetSymbolAddress((void**)&wvl,  g_wvl);
    cudaGetSymbolAddress((void**)&woh,  g_woh);
    cudaGetSymbolAddress((void**)&wol,  g_wol);
    cudaGetSymbolAddress((void**)&w1h,  g_w1h);
    cudaGetSymbolAddress((void**)&w1l,  g_w1l);
    cudaGetSymbolAddress((void**)&w2h,  g_w2h);
    cudaGetSymbolAddress((void**)&w2l,  g_w2l);
    cudaGetSymbolAddress((void**)&wch,  g_wch);
    cudaGetSymbolAddress((void**)&wcl,  g_wcl);

    cudaFuncSetAttribute(gemm_mma_bf16x3, cudaFuncAttributeMaxDynamicSharedMemorySize, GEMM_SMEM);
    cudaFuncSetAttribute(attn_mma_kernel, cudaFuncAttributeMaxDynamicSharedMemorySize, ATTN_SMEM);

    dim3 tb(32, 8);
    transpose_hilo_kernel<<<dim3(H_DIM/32, H_DIM/32), tb>>>(wq, H_DIM, H_DIM, wqh, wql);
    transpose_hilo_kernel<<<dim3(H_DIM/32, H_DIM/32), tb>>>(wk, H_DIM, H_DIM, wkh, wkl);
    transpose_hilo_kernel<<<dim3(H_DIM/32, H_DIM/32), tb>>>(wv, H_DIM, H_DIM, wvh, wvl);
    transpose_hilo_kernel<<<dim3(H_DIM/32, H_DIM/32), tb>>>(wo, H_DIM, H_DIM, woh, wol);
    transpose_hilo_kernel<<<dim3(FF_DIM/32, H_DIM/32), tb>>>(w1, H_DIM, FF_DIM, w1h, w1l);
    transpose_hilo_kernel<<<dim3(FF_DIM/32, H_DIM/32), tb>>>(w2, H_DIM, FF_DIM, w2h, w2l);
    transpose_hilo_kernel<<<dim3(H_DIM/32, FF_DIM/32), tb>>>(wc, FF_DIM, H_DIM, wch, wcl);

    // 1) x = rmsnorm(hidden, ln1) -> bf16 hi/lo
    rmsnorm_hilo_kernel<<<T_DIM, 256>>>(hidden, ln1, xnh, xnl);

    // 2) q/k/v
    dim3 gH(H_DIM / BN, T_DIM / BM);
    gemm_mma_bf16x3<<<gH, 256, GEMM_SMEM>>>(xnh, xnl, wqh, wql, bq, nullptr, q, H_DIM, H_DIM);
    gemm_mma_bf16x3<<<gH, 256, GEMM_SMEM>>>(xnh, xnl, wkh, wkl, bk, nullptr, k, H_DIM, H_DIM);
    gemm_mma_bf16x3<<<gH, 256, GEMM_SMEM>>>(xnh, xnl, wvh, wvl, bv, nullptr, v, H_DIM, H_DIM);

    // 3) RoPE
    rope_kernel<<<(T_DIM * NHEADS * (HD_DIM / 2)) / 256, 256>>>(q, k, positions);

    // 4) attention (tensor cores) -> atth/attl directly
    attn_mma_kernel<<<dim3(T_DIM / 64, NHEADS), 128, ATTN_SMEM>>>(q, k, v, atth, attl);

    // 5) h = hidden + attn @ wo
    gemm_mma_bf16x3<<<gH, 256, GEMM_SMEM>>>(atth, attl, woh, wol, nullptr, hidden, hbuf, H_DIM, H_DIM);

    // 6) y = rmsnorm(h, ln2)
    rmsnorm_hilo_kernel<<<T_DIM, 256>>>(hbuf, ln2, yh, yl);

    // 7) MLP up + gate
    dim3 gF(FF_DIM / BN, T_DIM / BM);
    gemm_mma_bf16x3<<<gF, 256, GEMM_SMEM>>>(yh, yl, w1h, w1l, nullptr, nullptr, a1, FF_DIM, H_DIM);
    gemm_mma_bf16x3<<<gF, 256, GEMM_SMEM>>>(yh, yl, w2h, w2l, nullptr, nullptr, a2, FF_DIM, H_DIM);
    silu_hilo_kernel<<<(T_DIM * FF_DIM + 255) / 256, 256>>>(a1, a2, gh, gl, T_DIM * FF_DIM);

    // 8) out = h + g @ wc
    gemm_mma_bf16x3<<<gH, 256, GEMM_SMEM>>>(gh, gl, wch, wcl, nullptr, hbuf, out, H_DIM, FF_DIM);
}

// round 5
// speedup vs baseline: 3.3498x; 1.4412x over previous
#include <cuda_runtime.h>
#include <cuda_bf16.h>
#include <cuda_fp16.h>
#include <math.h>
#include <cstdint>

#define T_DIM 2048
#define H_DIM 4096
#define NHEADS 32
#define HD_DIM 128
#define FF_DIM 11008
#define EPS_V 1e-6f

typedef __nv_bfloat16 bf16;
typedef __half h16;

// ===================== device scratch ======================================
__device__ float g_q  [(size_t)T_DIM * H_DIM];
__device__ float g_k  [(size_t)T_DIM * H_DIM];
__device__ float g_v  [(size_t)T_DIM * H_DIM];
__device__ float g_h  [(size_t)T_DIM * H_DIM];
__device__ float g_a1 [(size_t)T_DIM * FF_DIM];
__device__ float g_a2 [(size_t)T_DIM * FF_DIM];

__device__ h16 g_xnh [(size_t)T_DIM * H_DIM];
__device__ h16 g_xnl [(size_t)T_DIM * H_DIM];
__device__ h16 g_atth[(size_t)T_DIM * H_DIM];
__device__ h16 g_attl[(size_t)T_DIM * H_DIM];
__device__ h16 g_yh  [(size_t)T_DIM * H_DIM];
__device__ h16 g_yl  [(size_t)T_DIM * H_DIM];
__device__ h16 g_gh  [(size_t)T_DIM * FF_DIM];
__device__ h16 g_gl  [(size_t)T_DIM * FF_DIM];

// weights: wq,wk hi/lo (3-pass); others single fp16
__device__ h16 g_wqh[(size_t)H_DIM * H_DIM];
__device__ h16 g_wql[(size_t)H_DIM * H_DIM];
__device__ h16 g_wkh[(size_t)H_DIM * H_DIM];
__device__ h16 g_wkl[(size_t)H_DIM * H_DIM];
__device__ h16 g_wvh[(size_t)H_DIM * H_DIM];
__device__ h16 g_woh[(size_t)H_DIM * H_DIM];
__device__ h16 g_w1h[(size_t)FF_DIM * H_DIM];
__device__ h16 g_w2h[(size_t)FF_DIM * H_DIM];
__device__ h16 g_wch[(size_t)H_DIM * FF_DIM];

// ===================== PTX helpers =========================================
__device__ __forceinline__ uint32_t smem_u32(const void* p) {
    uint32_t a;
    asm("{ .reg .u64 t; cvta.to.shared.u64 t, %1; cvt.u32.u64 %0, t; }"
        : "=r"(a) : "l"(p));
    return a;
}

#define CP_ASYNC16(dst, src) \
    asm volatile("cp.async.cg.shared.global [%0], [%1], 16;" :: "r"(dst), "l"(src))
#define CP_COMMIT() asm volatile("cp.async.commit_group;" ::: "memory")

__device__ __forceinline__ void ldsm_x4(uint32_t* r, uint32_t a) {
    asm volatile("ldmatrix.sync.aligned.m8n8.x4.shared.b16 {%0,%1,%2,%3}, [%4];"
        : "=r"(r[0]), "=r"(r[1]), "=r"(r[2]), "=r"(r[3]) : "r"(a));
}
__device__ __forceinline__ void ldsm_x4t(uint32_t* r, uint32_t a) {
    asm volatile("ldmatrix.sync.aligned.m8n8.x4.trans.shared.b16 {%0,%1,%2,%3}, [%4];"
        : "=r"(r[0]), "=r"(r[1]), "=r"(r[2]), "=r"(r[3]) : "r"(a));
}

__device__ __forceinline__ void mma_bf(float* d, const uint32_t* a,
                                       uint32_t b0, uint32_t b1) {
    asm volatile(
        "mma.sync.aligned.m16n8k16.row.col.f32.bf16.bf16.f32 "
        "{%0,%1,%2,%3}, {%4,%5,%6,%7}, {%8,%9}, {%0,%1,%2,%3};"
        : "+f"(d[0]), "+f"(d[1]), "+f"(d[2]), "+f"(d[3])
        : "r"(a[0]), "r"(a[1]), "r"(a[2]), "r"(a[3]), "r"(b0), "r"(b1));
}
__device__ __forceinline__ void mma_fp(float* d, const uint32_t* a,
                                       uint32_t b0, uint32_t b1) {
    asm volatile(
        "mma.sync.aligned.m16n8k16.row.col.f32.f16.f16.f32 "
        "{%0,%1,%2,%3}, {%4,%5,%6,%7}, {%8,%9}, {%0,%1,%2,%3};"
        : "+f"(d[0]), "+f"(d[1]), "+f"(d[2]), "+f"(d[3])
        : "r"(a[0]), "r"(a[1]), "r"(a[2]), "r"(a[3]), "r"(b0), "r"(b1));
}

__device__ __forceinline__ void split_bf(float v, bf16& h, bf16& l) {
    h = __float2bfloat16(v);
    l = __float2bfloat16(v - __bfloat162float(h));
}
__device__ __forceinline__ void split_fp(float v, h16& h, h16& l) {
    h = __float2half_rn(v);
    l = __float2half_rn(v - __half2float(h));
}

// ===================== fp16 GEMM (2- or 3-pass) ==============================
// C[M,N] = A@B^T. A fp16 hi/lo. PASSES=2: B single (Ah*B + Al*B).
// PASSES=3: B hi/lo (Ah*Bh + Ah*Bl + Al*Bh).
#define BM 128
#define BN 128
#define GROWB 80                     // 64B data + 16B pad per row
#define GTILE (128 * GROWB)          // 10240

template<int PASSES>
__global__ __launch_bounds__(256, (PASSES == 2) ? 2 : 1)
void gemm_f16(const h16* __restrict__ Ah, const h16* __restrict__ Al,
              const h16* __restrict__ Bh, const h16* __restrict__ Bl,
              const float* __restrict__ bias, const float* __restrict__ resid,
              float* __restrict__ C, int Ntot, int K)
{
    constexpr int NT = PASSES + 1;            // sub-tiles per stage
    constexpr int STAGE_B = NT * GTILE;
    extern __shared__ char dsm[];
    const int tid = threadIdx.x;
    const int wid = tid >> 5, lane = tid & 31;
    const int rowA0 = blockIdx.y * BM;
    const int colB0 = blockIdx.x * BN;
    const int nIter = K >> 5;
    const uint32_t sbase = smem_u32(dsm);

    auto load_stage = [&](int it) {
        const int s = it % 3;
        const size_t koff = (size_t)it * 32;
        const uint32_t st = sbase + s * STAGE_B;
        #pragma unroll
        for (int i = 0; i < 2; i++) {
            int idx = tid + i * 256;
            int r = idx >> 2, seg = idx & 3;
            uint32_t doff = r * GROWB + seg * 16;
            const size_t goff = koff + seg * 8;
            CP_ASYNC16(st + 0 * GTILE + doff, Ah + (size_t)(rowA0 + r) * K + goff);
            CP_ASYNC16(st + 1 * GTILE + doff, Al + (size_t)(rowA0 + r) * K + goff);
            CP_ASYNC16(st + 2 * GTILE + doff, Bh + (size_t)(colB0 + r) * K + goff);
            if (PASSES == 3)
                CP_ASYNC16(st + 3 * GTILE + doff, Bl + (size_t)(colB0 + r) * K + goff);
        }
        CP_COMMIT();
    };

    const int m0 = (wid >> 1) * 32;
    const int n0 = (wid & 1) * 64;

    float acc[2][8][4];
    #pragma unroll
    for (int i = 0; i < 2; i++)
        #pragma unroll
        for (int j = 0; j < 8; j++)
            #pragma unroll
            for (int c = 0; c < 4; c++) acc[i][j][c] = 0.f;

    const int mi = lane >> 3, l7 = lane & 7;
    const uint32_t aoff = (uint32_t)((m0 + (mi & 1) * 8 + l7) * GROWB + (mi >> 1) * 16);
    const uint32_t boff = (uint32_t)((n0 + (mi >> 1) * 8 + l7) * GROWB + (mi & 1) * 16);

    load_stage(0); load_stage(1);

    for (int it = 0; it < nIter; it++) {
        if (it + 2 < nIter) load_stage(it + 2);
        else CP_COMMIT();
        asm volatile("cp.async.wait_group %0;" :: "n"(2));
        __syncthreads();

        const uint32_t st = sbase + (it % 3) * STAGE_B;
        const uint32_t sah = st, sal = st + GTILE;
        const uint32_t sbh = st + 2 * GTILE, sbl = st + 3 * GTILE;

        #pragma unroll
        for (int kk = 0; kk < 2; kk++) {
            uint32_t ah0[4], ah1[4], al0[4], al1[4];
            ldsm_x4(ah0, sah + aoff + kk * 32);
            ldsm_x4(ah1, sah + aoff + 16 * GROWB + kk * 32);
            ldsm_x4(al0, sal + aoff + kk * 32);
            ldsm_x4(al1, sal + aoff + 16 * GROWB + kk * 32);
            #pragma unroll
            for (int g = 0; g < 4; g++) {
                uint32_t bh[4];
                ldsm_x4(bh, sbh + boff + g * 16 * GROWB + kk * 32);
                mma_fp(acc[0][2*g+0], ah0, bh[0], bh[1]);
                mma_fp(acc[0][2*g+1], ah0, bh[2], bh[3]);
                mma_fp(acc[1][2*g+0], ah1, bh[0], bh[1]);
                mma_fp(acc[1][2*g+1], ah1, bh[2], bh[3]);
                mma_fp(acc[0][2*g+0], al0, bh[0], bh[1]);
                mma_fp(acc[0][2*g+1], al0, bh[2], bh[3]);
                mma_fp(acc[1][2*g+0], al1, bh[0], bh[1]);
                mma_fp(acc[1][2*g+1], al1, bh[2], bh[3]);
                if (PASSES == 3) {
                    uint32_t bl[4];
                    ldsm_x4(bl, sbl + boff + g * 16 * GROWB + kk * 32);
                    mma_fp(acc[0][2*g+0], ah0, bl[0], bl[1]);
                    mma_fp(acc[0][2*g+1], ah0, bl[2], bl[3]);
                    mma_fp(acc[1][2*g+0], ah1, bl[0], bl[1]);
                    mma_fp(acc[1][2*g+1], ah1, bl[2], bl[3]);
                }
            }
        }
        __syncthreads();
    }

    const int l4 = lane >> 2, l2 = (lane & 3) * 2;
    #pragma unroll
    for (int mf = 0; mf < 2; mf++) {
        const int r = rowA0 + m0 + mf * 16 + l4;
        #pragma unroll
        for (int nf = 0; nf < 8; nf++) {
            const int c = colB0 + n0 + nf * 8 + l2;
            float2 v0 = make_float2(acc[mf][nf][0], acc[mf][nf][1]);
            float2 v1 = make_float2(acc[mf][nf][2], acc[mf][nf][3]);
            if (bias) {
                v0.x += bias[c]; v0.y += bias[c + 1];
                v1.x += bias[c]; v1.y += bias[c + 1];
            }
            if (resid) {
                const float2 r0 = *(const float2*)&resid[(size_t)r * Ntot + c];
                const float2 r1 = *(const float2*)&resid[(size_t)(r + 8) * Ntot + c];
                v0.x += r0.x; v0.y += r0.y;
                v1.x += r1.x; v1.y += r1.y;
            }
            *(float2*)&C[(size_t)r * Ntot + c] = v0;
            *(float2*)&C[(size_t)(r + 8) * Ntot + c] = v1;
        }
    }
}

// ===================== tensor-core flash attention ===========================
// S via 3-pass bf16 hi/lo; softmax fp32; P,V fp16; O -> fp16 hi/lo.
#define AROW 272
#define PSROW 144
#define OFF_QH 0
#define OFF_QL (OFF_QH + 64 * AROW)
#define OFF_KH (OFF_QL + 64 * AROW)
#define OFF_KL (OFF_KH + 64 * AROW)
#define OFF_VS (OFF_KL + 64 * AROW)
#define OFF_PS (OFF_VS + 64 * AROW)
#define ATTN_SMEM (OFF_PS + 64 * PSROW)

__global__ __launch_bounds__(128, 2)
void attn_mma_kernel(const float* __restrict__ Q, const float* __restrict__ K,
                     const float* __restrict__ V,
                     h16* __restrict__ Oh, h16* __restrict__ Ol)
{
    extern __shared__ char asm_[];
    const uint32_t sb = smem_u32(asm_);
    const int q0 = blockIdx.x * 64;
    const int h  = blockIdx.y;
    const int tid = threadIdx.x;
    const int w = tid >> 5, lane = tid & 31;
    const int mi = lane >> 3, l7 = lane & 7;

    for (int i = tid; i < 64 * 128; i += 128) {
        int r = i >> 7, c = i & 127;
        float v = Q[(size_t)(q0 + r) * H_DIM + h * HD_DIM + c];
        bf16 hh, ll; split_bf(v, hh, ll);
        *(bf16*)(asm_ + OFF_QH + r * AROW + c * 2) = hh;
        *(bf16*)(asm_ + OFF_QL + r * AROW + c * 2) = ll;
    }

    float oacc[16][4];
    #pragma unroll
    for (int f = 0; f < 16; f++)
        #pragma unroll
        for (int c = 0; c < 4; c++) oacc[f][c] = 0.f;
    float m0v = -1e30f, m1v = -1e30f, l0v = 0.f, l1v = 0.f;
    const float scaling = 0.08838834764831845f;

    const uint32_t aq_off = (uint32_t)((w * 16 + (mi & 1) * 8 + l7) * AROW + (mi >> 1) * 16);
    const uint32_t bk_off = (uint32_t)(((mi >> 1) * 8 + l7) * AROW + (mi & 1) * 16);
    const uint32_t ps_off = (uint32_t)((w * 16 + (mi & 1) * 8 + l7) * PSROW + (mi >> 1) * 16);

    const int r0 = lane >> 2;
    const int gq0 = q0 + w * 16 + r0;
    const int gq1 = gq0 + 8;

    for (int j0 = 0; j0 <= q0; j0 += 64) {
        __syncthreads();
        for (int i = tid; i < 64 * 128; i += 128) {
            int r = i >> 7, c = i & 127;
            size_t gidx = (size_t)(j0 + r) * H_DIM + h * HD_DIM + c;
            float kv = K[gidx];
            bf16 hh, ll; split_bf(kv, hh, ll);
            *(bf16*)(asm_ + OFF_KH + r * AROW + c * 2) = hh;
            *(bf16*)(asm_ + OFF_KL + r * AROW + c * 2) = ll;
            *(h16*)(asm_ + OFF_VS + r * AROW + c * 2) = __float2half_rn(V[gidx]);
        }
        __syncthreads();

        float sacc[8][4];
        #pragma unroll
        for (int f = 0; f < 8; f++)
            #pragma unroll
            for (int c = 0; c < 4; c++) sacc[f][c] = 0.f;

        #pragma unroll
        for (int pass = 0; pass < 3; pass++) {
            const uint32_t sa = sb + ((pass < 2) ? OFF_QH : OFF_QL);
            const uint32_t skb = sb + ((pass == 1) ? OFF_KL : OFF_KH);
            #pragma unroll
            for (int ks = 0; ks < 8; ks++) {
                uint32_t a[4];
                ldsm_x4(a, sa + aq_off + ks * 32);
                #pragma unroll
                for (int g = 0; g < 4; g++) {
                    uint32_t b[4];
                    ldsm_x4(b, skb + bk_off + g * 16 * AROW + ks * 32);
                    mma_bf(sacc[2*g+0], a, b[0], b[1]);
                    mma_bf(sacc[2*g+1], a, b[2], b[3]);
                }
            }
        }

        const bool diag = (j0 == q0);
        #pragma unroll
        for (int f = 0; f < 8; f++) {
            int kvc = j0 + f * 8 + (lane & 3) * 2;
            #pragma unroll
            for (int c = 0; c < 4; c++) sacc[f][c] *= scaling;
            if (diag) {
                if (kvc     > gq0) sacc[f][0] = -1e30f;
                if (kvc + 1 > gq0) sacc[f][1] = -1e30f;
                if (kvc     > gq1) sacc[f][2] = -1e30f;
                if (kvc + 1 > gq1) sacc[f][3] = -1e30f;
            }
        }

        float mx0 = -1e30f, mx1 = -1e30f;
        #pragma unroll
        for (int f = 0; f < 8; f++) {
            mx0 = fmaxf(mx0, fmaxf(sacc[f][0], sacc[f][1]));
            mx1 = fmaxf(mx1, fmaxf(sacc[f][2], sacc[f][3]));
        }
        mx0 = fmaxf(mx0, __shfl_xor_sync(0xffffffffu, mx0, 1));
        mx0 = fmaxf(mx0, __shfl_xor_sync(0xffffffffu, mx0, 2));
        mx1 = fmaxf(mx1, __shfl_xor_sync(0xffffffffu, mx1, 1));
        mx1 = fmaxf(mx1, __shfl_xor_sync(0xffffffffu, mx1, 2));
        const float mn0 = fmaxf(m0v, mx0), mn1 = fmaxf(m1v, mx1);
        float rs0 = 0.f, rs1 = 0.f;
        #pragma unroll
        for (int f = 0; f < 8; f++) {
            float p0 = expf(sacc[f][0] - mn0);
            float p1 = expf(sacc[f][1] - mn0);
            float p2 = expf(sacc[f][2] - mn1);
            float p3 = expf(sacc[f][3] - mn1);
            rs0 += p0 + p1; rs1 += p2 + p3;
            __half2 v01 = __floats2half2_rn(p0, p1);
            __half2 v23 = __floats2half2_rn(p2, p3);
            uint32_t col = (f * 8 + (lane & 3) * 2) * 2;
            *(uint32_t*)(asm_ + OFF_PS + (w * 16 + r0) * PSROW + col) = *(uint32_t*)&v01;
            *(uint32_t*)(asm_ + OFF_PS + (w * 16 + r0 + 8) * PSROW + col) = *(uint32_t*)&v23;
        }
        rs0 += __shfl_xor_sync(0xffffffffu, rs0, 1);
        rs0 += __shfl_xor_sync(0xffffffffu, rs0, 2);
        rs1 += __shfl_xor_sync(0xffffffffu, rs1, 1);
        rs1 += __shfl_xor_sync(0xffffffffu, rs1, 2);
        const float al0 = expf(m0v - mn0), al1 = expf(m1v - mn1);
        l0v = l0v * al0 + rs0; l1v = l1v * al1 + rs1;
        m0v = mn0; m1v = mn1;
        #pragma unroll
        for (int f = 0; f < 16; f++) {
            oacc[f][0] *= al0; oacc[f][1] *= al0;
            oacc[f][2] *= al1; oacc[f][3] *= al1;
        }
        __syncwarp();

        #pragma unroll
        for (int ks = 0; ks < 4; ks++) {
            uint32_t a[4];
            ldsm_x4(a, sb + OFF_PS + ps_off + ks * 32);
            #pragma unroll
            for (int g = 0; g < 8; g++) {
                uint32_t b[4];
                ldsm_x4t(b, sb + OFF_VS + (ks * 16 + (mi & 1) * 8 + l7) * AROW
                               + (g * 16 + (mi >> 1) * 8) * 2);
                mma_fp(oacc[2*g+0], a, b[0], b[1]);
                mma_fp(oacc[2*g+1], a, b[2], b[3]);
            }
        }
    }

    const float i0 = 1.f / l0v, i1 = 1.f / l1v;
    #pragma unroll
    for (int f = 0; f < 16; f++) {
        int col = h * HD_DIM + f * 8 + (lane & 3) * 2;
        float a0 = oacc[f][0] * i0, a1 = oacc[f][1] * i0;
        float b0 = oacc[f][2] * i1, b1 = oacc[f][3] * i1;
        h16 h0, l0, h1, l1, h2, l2, h3, l3;
        split_fp(a0, h0, l0); split_fp(a1, h1, l1);
        split_fp(b0, h2, l2); split_fp(b1, h3, l3);
        __half2 hh0 = {h0, h1}, ll0 = {l0, l1};
        __half2 hh1 = {h2, h3}, ll1 = {l2, l3};
        *(__half2*)&Oh[(size_t)gq0 * H_DIM + col] = hh0;
        *(__half2*)&Ol[(size_t)gq0 * H_DIM + col] = ll0;
        *(__half2*)&Oh[(size_t)gq1 * H_DIM + col] = hh1;
        *(__half2*)&Ol[(size_t)gq1 * H_DIM + col] = ll1;
    }
}

// ===================== elementwise / conversion kernels =====================
__global__ void rmsnorm_hilo_kernel(const float* __restrict__ x,
                                    const float* __restrict__ scale,
                                    h16* __restrict__ oh, h16* __restrict__ ol)
{
    int row = blockIdx.x;
    const float4* xr = (const float4*)(x + (size_t)row * H_DIM);
    float ss = 0.f;
    for (int i = threadIdx.x; i < H_DIM / 4; i += blockDim.x) {
        float4 v = xr[i];
        ss += v.x * v.x + v.y * v.y + v.z * v.z + v.w * v.w;
    }
    #pragma unroll
    for (int off = 16; off; off >>= 1) ss += __shfl_xor_sync(0xffffffffu, ss, off);
    __shared__ float red[32];
    int lane = threadIdx.x & 31, wid = threadIdx.x >> 5;
    if (lane == 0) red[wid] = ss;
    __syncthreads();
    if (wid == 0) {
        ss = (lane < (int)(blockDim.x >> 5)) ? red[lane] : 0.f;
        #pragma unroll
        for (int off = 16; off; off >>= 1) ss += __shfl_xor_sync(0xffffffffu, ss, off);
        if (lane == 0) red[0] = ss;
    }
    __syncthreads();
    float inv = rsqrtf(red[0] / (float)H_DIM + EPS_V);
    const float4* sc = (const float4*)scale;
    for (int i = threadIdx.x; i < H_DIM / 4; i += blockDim.x) {
        float4 v = xr[i], s = sc[i];
        float f[4] = {v.x * inv * s.x, v.y * inv * s.y, v.z * inv * s.z, v.w * inv * s.w};
        size_t base = (size_t)row * H_DIM + i * 4;
        #pragma unroll
        for (int c = 0; c < 4; c++) {
            h16 h, l; split_fp(f[c], h, l);
            oh[base + c] = h; ol[base + c] = l;
        }
    }
}

__global__ void silu_hilo_kernel(const float* __restrict__ a1,
                                 const float* __restrict__ a2,
                                 h16* __restrict__ oh, h16* __restrict__ ol, int n)
{
    int i = blockIdx.x * blockDim.x + threadIdx.x;
    if (i < n) {
        float g = a2[i];
        float v = a1[i] * (g / (1.f + expf(-g)));
        h16 h, l; split_fp(v, h, l);
        oh[i] = h; ol[i] = l;
    }
}

// W[K][N] fp32 -> Th[N][K] fp16 (+ optional Tl)
__global__ void transpose_f16_kernel(const float* __restrict__ W, int K, int N,
                                     h16* __restrict__ Th, h16* __restrict__ Tl)
{
    __shared__ float t[32][33];
    int n0 = blockIdx.x * 32, k0 = blockIdx.y * 32;
    int tx = threadIdx.x, ty = threadIdx.y;
    #pragma unroll
    for (int i = ty; i < 32; i += 8)
        t[i][tx] = W[(size_t)(k0 + i) * N + n0 + tx];
    __syncthreads();
    #pragma unroll
    for (int i = ty; i < 32; i += 8) {
        float v = t[tx][i];
        size_t idx = (size_t)(n0 + i) * K + k0 + tx;
        if (Tl) {
            h16 h, l; split_fp(v, h, l);
            Th[idx] = h; Tl[idx] = l;
        } else {
            Th[idx] = __float2half_rn(v);
        }
    }
}

// ===================== RoPE ==================================================
__global__ void rope_kernel(float* __restrict__ q, float* __restrict__ k,
                            const int* __restrict__ pos)
{
    int idx = blockIdx.x * blockDim.x + threadIdx.x;
    if (idx >= T_DIM * NHEADS * (HD_DIM / 2)) return;
    int d  = idx & 63;
    int th = idx >> 6;
    int t  = th >> 5;
    float invf = powf(10000.0f, -(float)d * (1.0f / 64.0f));
    float ang = (float)pos[t] * invf;
    float c, s;
    sincosf(ang, &s, &c);
    size_t base = (size_t)th * HD_DIM + d;
    float q1 = q[base], q2 = q[base + 64];
    q[base]      = q1 * c - q2 * s;
    q[base + 64] = q2 * c + q1 * s;
    float k1 = k[base], k2 = k[base + 64];
    k[base]      = k1 * c - k2 * s;
    k[base + 64] = k2 * c + k1 * s;
}

// ===================== launch ================================================
extern "C" void kernel_launch(void* const* d_in, const int* in_sizes, int n_in,
                              void* d_out, int out_size)
{
    (void)in_sizes; (void)n_in; (void)out_size;
    const int*   positions = (const int*)  d_in[0];
    const float* hidden    = (const float*)d_in[1];
    const float* ln1       = (const float*)d_in[2];
    const float* wq = (const float*)d_in[3];
    const float* bq = (const float*)d_in[4];
    const float* wk = (const float*)d_in[5];
    const float* bk = (const float*)d_in[6];
    const float* wv = (const float*)d_in[7];
    const float* bv = (const float*)d_in[8];
    const float* wo = (const float*)d_in[9];
    const float* ln2= (const float*)d_in[10];
    const float* w1 = (const float*)d_in[11];
    const float* w2 = (const float*)d_in[12];
    const float* wc = (const float*)d_in[13];
    float* out = (float*)d_out;

    float *q, *k, *v, *hbuf, *a1, *a2;
    h16 *xnh, *xnl, *atth, *attl, *yh, *yl, *gh, *gl;
    h16 *wqh, *wql, *wkh, *wkl, *wvh, *woh, *w1h, *w2h, *wch;
    cudaGetSymbolAddress((void**)&q,    g_q);
    cudaGetSymbolAddress((void**)&k,    g_k);
    cudaGetSymbolAddress((void**)&v,    g_v);
    cudaGetSymbolAddress((void**)&hbuf, g_h);
    cudaGetSymbolAddress((void**)&a1,   g_a1);
    cudaGetSymbolAddress((void**)&a2,   g_a2);
    cudaGetSymbolAddress((void**)&xnh,  g_xnh);
    cudaGetSymbolAddress((void**)&xnl,  g_xnl);
    cudaGetSymbolAddress((void**)&atth, g_atth);
    cudaGetSymbolAddress((void**)&attl, g_attl);
    cudaGetSymbolAddress((void**)&yh,   g_yh);
    cudaGetSymbolAddress((void**)&yl,   g_yl);
    cudaGetSymbolAddress((void**)&gh,   g_gh);
    cudaGetSymbolAddress((void**)&gl,   g_gl);
    cudaGetSymbolAddress((void**)&wqh,  g_wqh);
    cudaGetSymbolAddress((void**)&wql,  g_wql);
    cudaGetSymbolAddress((void**)&wkh,  g_wkh);
    cudaGetSymbolAddress((void**)&wkl,  g_wkl);
    cudaGetSymbolAddress((void**)&wvh,  g_wvh);
    cudaGetSymbolAddress((void**)&woh,  g_woh);
    cudaGetSymbolAddress((void**)&w1h,  g_w1h);
    cudaGetSymbolAddress((void**)&w2h,  g_w2h);
    cudaGetSymbolAddress((void**)&wch,  g_wch);

    const int SMEM_P2 = 3 * 3 * GTILE;   // 92160
    const int SMEM_P3 = 3 * 4 * GTILE;   // 122880
    cudaFuncSetAttribute(gemm_f16<2>, cudaFuncAttributeMaxDynamicSharedMemorySize, SMEM_P2);
    cudaFuncSetAttribute(gemm_f16<3>, cudaFuncAttributeMaxDynamicSharedMemorySize, SMEM_P3);
    cudaFuncSetAttribute(attn_mma_kernel, cudaFuncAttributeMaxDynamicSharedMemorySize, ATTN_SMEM);

    dim3 tb(32, 8);
    transpose_f16_kernel<<<dim3(H_DIM/32, H_DIM/32), tb>>>(wq, H_DIM, H_DIM, wqh, wql);
    transpose_f16_kernel<<<dim3(H_DIM/32, H_DIM/32), tb>>>(wk, H_DIM, H_DIM, wkh, wkl);
    transpose_f16_kernel<<<dim3(H_DIM/32, H_DIM/32), tb>>>(wv, H_DIM, H_DIM, wvh, nullptr);
    transpose_f16_kernel<<<dim3(H_DIM/32, H_DIM/32), tb>>>(wo, H_DIM, H_DIM, woh, nullptr);
    transpose_f16_kernel<<<dim3(FF_DIM/32, H_DIM/32), tb>>>(w1, H_DIM, FF_DIM, w1h, nullptr);
    transpose_f16_kernel<<<dim3(FF_DIM/32, H_DIM/32), tb>>>(w2, H_DIM, FF_DIM, w2h, nullptr);
    transpose_f16_kernel<<<dim3(H_DIM/32, FF_DIM/32), tb>>>(wc, FF_DIM, H_DIM, wch, nullptr);

    // 1) x = rmsnorm(hidden, ln1) -> fp16 hi/lo
    rmsnorm_hilo_kernel<<<T_DIM, 256>>>(hidden, ln1, xnh, xnl);

    // 2) q/k/v  (q,k 3-pass for softmax-amplified precision; v 2-pass)
    dim3 gH(H_DIM / BN, T_DIM / BM);
    gemm_f16<3><<<gH, 256, SMEM_P3>>>(xnh, xnl, wqh, wql, bq, nullptr, q, H_DIM, H_DIM);
    gemm_f16<3><<<gH, 256, SMEM_P3>>>(xnh, xnl, wkh, wkl, bk, nullptr, k, H_DIM, H_DIM);
    gemm_f16<2><<<gH, 256, SMEM_P2>>>(xnh, xnl, wvh, nullptr, bv, nullptr, v, H_DIM, H_DIM);

    // 3) RoPE
    rope_kernel<<<(T_DIM * NHEADS * (HD_DIM / 2)) / 256, 256>>>(q, k, positions);

    // 4) attention -> atth/attl (fp16 hi/lo)
    attn_mma_kernel<<<dim3(T_DIM / 64, NHEADS), 128, ATTN_SMEM>>>(q, k, v, atth, attl);

    // 5) h = hidden + attn @ wo
    gemm_f16<2><<<gH, 256, SMEM_P2>>>(atth, attl, woh, nullptr, nullptr, hidden, hbuf, H_DIM, H_DIM);

    // 6) y = rmsnorm(h, ln2)
    rmsnorm_hilo_kernel<<<T_DIM, 256>>>(hbuf, ln2, yh, yl);

    // 7) MLP up + gate
    dim3 gF(FF_DIM / BN, T_DIM / BM);
    gemm_f16<2><<<gF, 256, SMEM_P2>>>(yh, yl, w1h, nullptr, nullptr, nullptr, a1, FF_DIM, H_DIM);
    gemm_f16<2><<<gF, 256, SMEM_P2>>>(yh, yl, w2h, nullptr, nullptr, nullptr, a2, FF_DIM, H_DIM);
    silu_hilo_kernel<<<(T_DIM * FF_DIM + 255) / 256, 256>>>(a1, a2, gh, gl, T_DIM * FF_DIM);

    // 8) out = h + g @ wc
    gemm_f16<2><<<gH, 256, SMEM_P2>>>(gh, gl, wch, nullptr, nullptr, hbuf, out, H_DIM, FF_DIM);
}

// round 6
// speedup vs baseline: 4.0490x; 1.2087x over previous
#include <cuda_runtime.h>
#include <cuda_bf16.h>
#include <cuda_fp16.h>
#include <math.h>
#include <cstdint>

#define T_DIM 2048
#define H_DIM 4096
#define NHEADS 32
#define HD_DIM 128
#define FF_DIM 11008
#define EPS_V 1e-6f

typedef __nv_bfloat16 bf16;
typedef __half h16;

// ===================== device scratch ======================================
__device__ float g_q  [(size_t)T_DIM * H_DIM];
__device__ float g_k  [(size_t)T_DIM * H_DIM];
__device__ float g_v  [(size_t)T_DIM * H_DIM];
__device__ float g_h  [(size_t)T_DIM * H_DIM];
__device__ float g_a1 [(size_t)T_DIM * FF_DIM];
__device__ float g_a2 [(size_t)T_DIM * FF_DIM];

__device__ h16 g_xnh [(size_t)T_DIM * H_DIM];
__device__ h16 g_xnl [(size_t)T_DIM * H_DIM];
__device__ h16 g_atth[(size_t)T_DIM * H_DIM];
__device__ h16 g_yh  [(size_t)T_DIM * H_DIM];
__device__ h16 g_gh  [(size_t)T_DIM * FF_DIM];
__device__ h16 g_gl  [(size_t)T_DIM * FF_DIM];

// weights: wq,wk hi/lo (3-pass); others single fp16
__device__ h16 g_wqh[(size_t)H_DIM * H_DIM];
__device__ h16 g_wql[(size_t)H_DIM * H_DIM];
__device__ h16 g_wkh[(size_t)H_DIM * H_DIM];
__device__ h16 g_wkl[(size_t)H_DIM * H_DIM];
__device__ h16 g_wvh[(size_t)H_DIM * H_DIM];
__device__ h16 g_woh[(size_t)H_DIM * H_DIM];
__device__ h16 g_w1h[(size_t)FF_DIM * H_DIM];
__device__ h16 g_w2h[(size_t)FF_DIM * H_DIM];
__device__ h16 g_wch[(size_t)H_DIM * FF_DIM];

// ===================== PTX helpers =========================================
__device__ __forceinline__ uint32_t smem_u32(const void* p) {
    uint32_t a;
    asm("{ .reg .u64 t; cvta.to.shared.u64 t, %1; cvt.u32.u64 %0, t; }"
        : "=r"(a) : "l"(p));
    return a;
}

#define CP_ASYNC16(dst, src) \
    asm volatile("cp.async.cg.shared.global [%0], [%1], 16;" :: "r"(dst), "l"(src))
#define CP_COMMIT() asm volatile("cp.async.commit_group;" ::: "memory")

__device__ __forceinline__ void ldsm_x4(uint32_t* r, uint32_t a) {
    asm volatile("ldmatrix.sync.aligned.m8n8.x4.shared.b16 {%0,%1,%2,%3}, [%4];"
        : "=r"(r[0]), "=r"(r[1]), "=r"(r[2]), "=r"(r[3]) : "r"(a));
}
__device__ __forceinline__ void ldsm_x4t(uint32_t* r, uint32_t a) {
    asm volatile("ldmatrix.sync.aligned.m8n8.x4.trans.shared.b16 {%0,%1,%2,%3}, [%4];"
        : "=r"(r[0]), "=r"(r[1]), "=r"(r[2]), "=r"(r[3]) : "r"(a));
}

__device__ __forceinline__ void mma_bf(float* d, const uint32_t* a,
                                       uint32_t b0, uint32_t b1) {
    asm volatile(
        "mma.sync.aligned.m16n8k16.row.col.f32.bf16.bf16.f32 "
        "{%0,%1,%2,%3}, {%4,%5,%6,%7}, {%8,%9}, {%0,%1,%2,%3};"
        : "+f"(d[0]), "+f"(d[1]), "+f"(d[2]), "+f"(d[3])
        : "r"(a[0]), "r"(a[1]), "r"(a[2]), "r"(a[3]), "r"(b0), "r"(b1));
}
__device__ __forceinline__ void mma_fp(float* d, const uint32_t* a,
                                       uint32_t b0, uint32_t b1) {
    asm volatile(
        "mma.sync.aligned.m16n8k16.row.col.f32.f16.f16.f32 "
        "{%0,%1,%2,%3}, {%4,%5,%6,%7}, {%8,%9}, {%0,%1,%2,%3};"
        : "+f"(d[0]), "+f"(d[1]), "+f"(d[2]), "+f"(d[3])
        : "r"(a[0]), "r"(a[1]), "r"(a[2]), "r"(a[3]), "r"(b0), "r"(b1));
}

__device__ __forceinline__ void split_bf(float v, bf16& h, bf16& l) {
    h = __float2bfloat16(v);
    l = __float2bfloat16(v - __bfloat162float(h));
}
__device__ __forceinline__ void split_fp(float v, h16& h, h16& l) {
    h = __float2half_rn(v);
    l = __float2half_rn(v - __half2float(h));
}

// ===================== fp16 GEMM (1/2/3-pass via AS/BS) =====================
// C[M,N] = A@B^T. AS: A hi/lo. BS: B hi/lo (implies AS for the Ah*Bl term).
#define BM 128
#define BN 128
#define GROWB 80                     // 64B data + 16B pad per row
#define GTILE (128 * GROWB)          // 10240

template<bool AS, bool BS>
__global__ __launch_bounds__(256, (AS && BS) ? 1 : 2)
void gemm_f16(const h16* __restrict__ Ah, const h16* __restrict__ Al,
              const h16* __restrict__ Bh, const h16* __restrict__ Bl,
              const float* __restrict__ bias, const float* __restrict__ resid,
              float* __restrict__ C, int Ntot, int K)
{
    constexpr int NT = 2 + (AS ? 1 : 0) + (BS ? 1 : 0);
    constexpr int STAGE_B = NT * GTILE;
    constexpr uint32_t T_A0 = 0;
    constexpr uint32_t T_A1 = GTILE;                       // valid if AS
    constexpr uint32_t T_B0 = (AS ? 2 : 1) * GTILE;
    constexpr uint32_t T_B1 = T_B0 + GTILE;                // valid if BS
    extern __shared__ char dsm[];
    const int tid = threadIdx.x;
    const int wid = tid >> 5, lane = tid & 31;
    const int rowA0 = blockIdx.y * BM;
    const int colB0 = blockIdx.x * BN;
    const int nIter = K >> 5;
    const uint32_t sbase = smem_u32(dsm);

    auto load_stage = [&](int it) {
        const int s = it % 3;
        const size_t koff = (size_t)it * 32;
        const uint32_t st = sbase + s * STAGE_B;
        #pragma unroll
        for (int i = 0; i < 2; i++) {
            int idx = tid + i * 256;
            int r = idx >> 2, seg = idx & 3;
            uint32_t doff = r * GROWB + seg * 16;
            const size_t goff = koff + seg * 8;
            CP_ASYNC16(st + T_A0 + doff, Ah + (size_t)(rowA0 + r) * K + goff);
            if (AS) CP_ASYNC16(st + T_A1 + doff, Al + (size_t)(rowA0 + r) * K + goff);
            CP_ASYNC16(st + T_B0 + doff, Bh + (size_t)(colB0 + r) * K + goff);
            if (BS) CP_ASYNC16(st + T_B1 + doff, Bl + (size_t)(colB0 + r) * K + goff);
        }
        CP_COMMIT();
    };

    const int m0 = (wid >> 1) * 32;
    const int n0 = (wid & 1) * 64;

    float acc[2][8][4];
    #pragma unroll
    for (int i = 0; i < 2; i++)
        #pragma unroll
        for (int j = 0; j < 8; j++)
            #pragma unroll
            for (int c = 0; c < 4; c++) acc[i][j][c] = 0.f;

    const int mi = lane >> 3, l7 = lane & 7;
    const uint32_t aoff = (uint32_t)((m0 + (mi & 1) * 8 + l7) * GROWB + (mi >> 1) * 16);
    const uint32_t boff = (uint32_t)((n0 + (mi >> 1) * 8 + l7) * GROWB + (mi & 1) * 16);

    load_stage(0); load_stage(1);

    for (int it = 0; it < nIter; it++) {
        if (it + 2 < nIter) load_stage(it + 2);
        else CP_COMMIT();
        asm volatile("cp.async.wait_group %0;" :: "n"(2));
        __syncthreads();

        const uint32_t st = sbase + (it % 3) * STAGE_B;

        #pragma unroll
        for (int kk = 0; kk < 2; kk++) {
            uint32_t ah0[4], ah1[4], al0[4], al1[4];
            ldsm_x4(ah0, st + T_A0 + aoff + kk * 32);
            ldsm_x4(ah1, st + T_A0 + aoff + 16 * GROWB + kk * 32);
            if (AS) {
                ldsm_x4(al0, st + T_A1 + aoff + kk * 32);
                ldsm_x4(al1, st + T_A1 + aoff + 16 * GROWB + kk * 32);
            }
            #pragma unroll
            for (int g = 0; g < 4; g++) {
                uint32_t bh[4];
                ldsm_x4(bh, st + T_B0 + boff + g * 16 * GROWB + kk * 32);
                mma_fp(acc[0][2*g+0], ah0, bh[0], bh[1]);
                mma_fp(acc[0][2*g+1], ah0, bh[2], bh[3]);
                mma_fp(acc[1][2*g+0], ah1, bh[0], bh[1]);
                mma_fp(acc[1][2*g+1], ah1, bh[2], bh[3]);
                if (AS) {
                    mma_fp(acc[0][2*g+0], al0, bh[0], bh[1]);
                    mma_fp(acc[0][2*g+1], al0, bh[2], bh[3]);
                    mma_fp(acc[1][2*g+0], al1, bh[0], bh[1]);
                    mma_fp(acc[1][2*g+1], al1, bh[2], bh[3]);
                }
                if (BS) {
                    uint32_t bl[4];
                    ldsm_x4(bl, st + T_B1 + boff + g * 16 * GROWB + kk * 32);
                    mma_fp(acc[0][2*g+0], ah0, bl[0], bl[1]);
                    mma_fp(acc[0][2*g+1], ah0, bl[2], bl[3]);
                    mma_fp(acc[1][2*g+0], ah1, bl[0], bl[1]);
                    mma_fp(acc[1][2*g+1], ah1, bl[2], bl[3]);
                }
            }
        }
        __syncthreads();
    }

    const int l4 = lane >> 2, l2 = (lane & 3) * 2;
    #pragma unroll
    for (int mf = 0; mf < 2; mf++) {
        const int r = rowA0 + m0 + mf * 16 + l4;
        #pragma unroll
        for (int nf = 0; nf < 8; nf++) {
            const int c = colB0 + n0 + nf * 8 + l2;
            float2 v0 = make_float2(acc[mf][nf][0], acc[mf][nf][1]);
            float2 v1 = make_float2(acc[mf][nf][2], acc[mf][nf][3]);
            if (bias) {
                v0.x += bias[c]; v0.y += bias[c + 1];
                v1.x += bias[c]; v1.y += bias[c + 1];
            }
            if (resid) {
                const float2 r0 = *(const float2*)&resid[(size_t)r * Ntot + c];
                const float2 r1 = *(const float2*)&resid[(size_t)(r + 8) * Ntot + c];
                v0.x += r0.x; v0.y += r0.y;
                v1.x += r1.x; v1.y += r1.y;
            }
            *(float2*)&C[(size_t)r * Ntot + c] = v0;
            *(float2*)&C[(size_t)(r + 8) * Ntot + c] = v1;
        }
    }
}

// ===================== tensor-core flash attention ===========================
// S via 3-pass bf16 hi/lo; softmax fp32; P,V fp16; O -> single fp16.
#define AROW 272
#define PSROW 144
#define OFF_QH 0
#define OFF_QL (OFF_QH + 64 * AROW)
#define OFF_KH (OFF_QL + 64 * AROW)
#define OFF_KL (OFF_KH + 64 * AROW)
#define OFF_VS (OFF_KL + 64 * AROW)
#define OFF_PS (OFF_VS + 64 * AROW)
#define ATTN_SMEM (OFF_PS + 64 * PSROW)

__global__ __launch_bounds__(128, 2)
void attn_mma_kernel(const float* __restrict__ Q, const float* __restrict__ K,
                     const float* __restrict__ V, h16* __restrict__ Oh)
{
    extern __shared__ char asm_[];
    const uint32_t sb = smem_u32(asm_);
    const int q0 = blockIdx.x * 64;
    const int h  = blockIdx.y;
    const int tid = threadIdx.x;
    const int w = tid >> 5, lane = tid & 31;
    const int mi = lane >> 3, l7 = lane & 7;

    for (int i = tid; i < 64 * 128; i += 128) {
        int r = i >> 7, c = i & 127;
        float v = Q[(size_t)(q0 + r) * H_DIM + h * HD_DIM + c];
        bf16 hh, ll; split_bf(v, hh, ll);
        *(bf16*)(asm_ + OFF_QH + r * AROW + c * 2) = hh;
        *(bf16*)(asm_ + OFF_QL + r * AROW + c * 2) = ll;
    }

    float oacc[16][4];
    #pragma unroll
    for (int f = 0; f < 16; f++)
        #pragma unroll
        for (int c = 0; c < 4; c++) oacc[f][c] = 0.f;
    float m0v = -1e30f, m1v = -1e30f, l0v = 0.f, l1v = 0.f;
    const float scaling = 0.08838834764831845f;

    const uint32_t aq_off = (uint32_t)((w * 16 + (mi & 1) * 8 + l7) * AROW + (mi >> 1) * 16);
    const uint32_t bk_off = (uint32_t)(((mi >> 1) * 8 + l7) * AROW + (mi & 1) * 16);
    const uint32_t ps_off = (uint32_t)((w * 16 + (mi & 1) * 8 + l7) * PSROW + (mi >> 1) * 16);

    const int r0 = lane >> 2;
    const int gq0 = q0 + w * 16 + r0;
    const int gq1 = gq0 + 8;

    for (int j0 = 0; j0 <= q0; j0 += 64) {
        __syncthreads();
        for (int i = tid; i < 64 * 128; i += 128) {
            int r = i >> 7, c = i & 127;
            size_t gidx = (size_t)(j0 + r) * H_DIM + h * HD_DIM + c;
            float kv = K[gidx];
            bf16 hh, ll; split_bf(kv, hh, ll);
            *(bf16*)(asm_ + OFF_KH + r * AROW + c * 2) = hh;
            *(bf16*)(asm_ + OFF_KL + r * AROW + c * 2) = ll;
            *(h16*)(asm_ + OFF_VS + r * AROW + c * 2) = __float2half_rn(V[gidx]);
        }
        __syncthreads();

        float sacc[8][4];
        #pragma unroll
        for (int f = 0; f < 8; f++)
            #pragma unroll
            for (int c = 0; c < 4; c++) sacc[f][c] = 0.f;

        #pragma unroll
        for (int pass = 0; pass < 3; pass++) {
            const uint32_t sa = sb + ((pass < 2) ? OFF_QH : OFF_QL);
            const uint32_t skb = sb + ((pass == 1) ? OFF_KL : OFF_KH);
            #pragma unroll
            for (int ks = 0; ks < 8; ks++) {
                uint32_t a[4];
                ldsm_x4(a, sa + aq_off + ks * 32);
                #pragma unroll
                for (int g = 0; g < 4; g++) {
                    uint32_t b[4];
                    ldsm_x4(b, skb + bk_off + g * 16 * AROW + ks * 32);
                    mma_bf(sacc[2*g+0], a, b[0], b[1]);
                    mma_bf(sacc[2*g+1], a, b[2], b[3]);
                }
            }
        }

        const bool diag = (j0 == q0);
        #pragma unroll
        for (int f = 0; f < 8; f++) {
            int kvc = j0 + f * 8 + (lane & 3) * 2;
            #pragma unroll
            for (int c = 0; c < 4; c++) sacc[f][c] *= scaling;
            if (diag) {
                if (kvc     > gq0) sacc[f][0] = -1e30f;
                if (kvc + 1 > gq0) sacc[f][1] = -1e30f;
                if (kvc     > gq1) sacc[f][2] = -1e30f;
                if (kvc + 1 > gq1) sacc[f][3] = -1e30f;
            }
        }

        float mx0 = -1e30f, mx1 = -1e30f;
        #pragma unroll
        for (int f = 0; f < 8; f++) {
            mx0 = fmaxf(mx0, fmaxf(sacc[f][0], sacc[f][1]));
            mx1 = fmaxf(mx1, fmaxf(sacc[f][2], sacc[f][3]));
        }
        mx0 = fmaxf(mx0, __shfl_xor_sync(0xffffffffu, mx0, 1));
        mx0 = fmaxf(mx0, __shfl_xor_sync(0xffffffffu, mx0, 2));
        mx1 = fmaxf(mx1, __shfl_xor_sync(0xffffffffu, mx1, 1));
        mx1 = fmaxf(mx1, __shfl_xor_sync(0xffffffffu, mx1, 2));
        const float mn0 = fmaxf(m0v, mx0), mn1 = fmaxf(m1v, mx1);
        float rs0 = 0.f, rs1 = 0.f;
        #pragma unroll
        for (int f = 0; f < 8; f++) {
            float p0 = expf(sacc[f][0] - mn0);
            float p1 = expf(sacc[f][1] - mn0);
            float p2 = expf(sacc[f][2] - mn1);
            float p3 = expf(sacc[f][3] - mn1);
            rs0 += p0 + p1; rs1 += p2 + p3;
            __half2 v01 = __floats2half2_rn(p0, p1);
            __half2 v23 = __floats2half2_rn(p2, p3);
            uint32_t col = (f * 8 + (lane & 3) * 2) * 2;
            *(uint32_t*)(asm_ + OFF_PS + (w * 16 + r0) * PSROW + col) = *(uint32_t*)&v01;
            *(uint32_t*)(asm_ + OFF_PS + (w * 16 + r0 + 8) * PSROW + col) = *(uint32_t*)&v23;
        }
        rs0 += __shfl_xor_sync(0xffffffffu, rs0, 1);
        rs0 += __shfl_xor_sync(0xffffffffu, rs0, 2);
        rs1 += __shfl_xor_sync(0xffffffffu, rs1, 1);
        rs1 += __shfl_xor_sync(0xffffffffu, rs1, 2);
        const float al0 = expf(m0v - mn0), al1 = expf(m1v - mn1);
        l0v = l0v * al0 + rs0; l1v = l1v * al1 + rs1;
        m0v = mn0; m1v = mn1;
        #pragma unroll
        for (int f = 0; f < 16; f++) {
            oacc[f][0] *= al0; oacc[f][1] *= al0;
            oacc[f][2] *= al1; oacc[f][3] *= al1;
        }
        __syncwarp();

        #pragma unroll
        for (int ks = 0; ks < 4; ks++) {
            uint32_t a[4];
            ldsm_x4(a, sb + OFF_PS + ps_off + ks * 32);
            #pragma unroll
            for (int g = 0; g < 8; g++) {
                uint32_t b[4];
                ldsm_x4t(b, sb + OFF_VS + (ks * 16 + (mi & 1) * 8 + l7) * AROW
                               + (g * 16 + (mi >> 1) * 8) * 2);
                mma_fp(oacc[2*g+0], a, b[0], b[1]);
                mma_fp(oacc[2*g+1], a, b[2], b[3]);
            }
        }
    }

    const float i0 = 1.f / l0v, i1 = 1.f / l1v;
    #pragma unroll
    for (int f = 0; f < 16; f++) {
        int col = h * HD_DIM + f * 8 + (lane & 3) * 2;
        __half2 hh0 = __floats2half2_rn(oacc[f][0] * i0, oacc[f][1] * i0);
        __half2 hh1 = __floats2half2_rn(oacc[f][2] * i1, oacc[f][3] * i1);
        *(__half2*)&Oh[(size_t)gq0 * H_DIM + col] = hh0;
        *(__half2*)&Oh[(size_t)gq1 * H_DIM + col] = hh1;
    }
}

// ===================== elementwise / conversion kernels =====================
__global__ void rmsnorm_f16_kernel(const float* __restrict__ x,
                                   const float* __restrict__ scale,
                                   h16* __restrict__ oh, h16* __restrict__ ol)
{
    int row = blockIdx.x;
    const float4* xr = (const float4*)(x + (size_t)row * H_DIM);
    float ss = 0.f;
    for (int i = threadIdx.x; i < H_DIM / 4; i += blockDim.x) {
        float4 v = xr[i];
        ss += v.x * v.x + v.y * v.y + v.z * v.z + v.w * v.w;
    }
    #pragma unroll
    for (int off = 16; off; off >>= 1) ss += __shfl_xor_sync(0xffffffffu, ss, off);
    __shared__ float red[32];
    int lane = threadIdx.x & 31, wid = threadIdx.x >> 5;
    if (lane == 0) red[wid] = ss;
    __syncthreads();
    if (wid == 0) {
        ss = (lane < (int)(blockDim.x >> 5)) ? red[lane] : 0.f;
        #pragma unroll
        for (int off = 16; off; off >>= 1) ss += __shfl_xor_sync(0xffffffffu, ss, off);
        if (lane == 0) red[0] = ss;
    }
    __syncthreads();
    float inv = rsqrtf(red[0] / (float)H_DIM + EPS_V);
    const float4* sc = (const float4*)scale;
    for (int i = threadIdx.x; i < H_DIM / 4; i += blockDim.x) {
        float4 v = xr[i], s = sc[i];
        float f[4] = {v.x * inv * s.x, v.y * inv * s.y, v.z * inv * s.z, v.w * inv * s.w};
        size_t base = (size_t)row * H_DIM + i * 4;
        #pragma unroll
        for (int c = 0; c < 4; c++) {
            if (ol) {
                h16 h, l; split_fp(f[c], h, l);
                oh[base + c] = h; ol[base + c] = l;
            } else {
                oh[base + c] = __float2half_rn(f[c]);
            }
        }
    }
}

__global__ void silu_hilo_kernel(const float* __restrict__ a1,
                                 const float* __restrict__ a2,
                                 h16* __restrict__ oh, h16* __restrict__ ol, int n)
{
    int i = blockIdx.x * blockDim.x + threadIdx.x;
    if (i < n) {
        float g = a2[i];
        float v = a1[i] * (g / (1.f + expf(-g)));
        h16 h, l; split_fp(v, h, l);
        oh[i] = h; ol[i] = l;
    }
}

// W[K][N] fp32 -> Th[N][K] fp16 (+ optional Tl)
__global__ void transpose_f16_kernel(const float* __restrict__ W, int K, int N,
                                     h16* __restrict__ Th, h16* __restrict__ Tl)
{
    __shared__ float t[32][33];
    int n0 = blockIdx.x * 32, k0 = blockIdx.y * 32;
    int tx = threadIdx.x, ty = threadIdx.y;
    #pragma unroll
    for (int i = ty; i < 32; i += 8)
        t[i][tx] = W[(size_t)(k0 + i) * N + n0 + tx];
    __syncthreads();
    #pragma unroll
    for (int i = ty; i < 32; i += 8) {
        float v = t[tx][i];
        size_t idx = (size_t)(n0 + i) * K + k0 + tx;
        if (Tl) {
            h16 h, l; split_fp(v, h, l);
            Th[idx] = h; Tl[idx] = l;
        } else {
            Th[idx] = __float2half_rn(v);
        }
    }
}

// ===================== RoPE ==================================================
__global__ void rope_kernel(float* __restrict__ q, float* __restrict__ k,
                            const int* __restrict__ pos)
{
    int idx = blockIdx.x * blockDim.x + threadIdx.x;
    if (idx >= T_DIM * NHEADS * (HD_DIM / 2)) return;
    int d  = idx & 63;
    int th = idx >> 6;
    int t  = th >> 5;
    float invf = powf(10000.0f, -(float)d * (1.0f / 64.0f));
    float ang = (float)pos[t] * invf;
    float c, s;
    sincosf(ang, &s, &c);
    size_t base = (size_t)th * HD_DIM + d;
    float q1 = q[base], q2 = q[base + 64];
    q[base]      = q1 * c - q2 * s;
    q[base + 64] = q2 * c + q1 * s;
    float k1 = k[base], k2 = k[base + 64];
    k[base]      = k1 * c - k2 * s;
    k[base + 64] = k2 * c + k1 * s;
}

// ===================== launch ================================================
extern "C" void kernel_launch(void* const* d_in, const int* in_sizes, int n_in,
                              void* d_out, int out_size)
{
    (void)in_sizes; (void)n_in; (void)out_size;
    const int*   positions = (const int*)  d_in[0];
    const float* hidden    = (const float*)d_in[1];
    const float* ln1       = (const float*)d_in[2];
    const float* wq = (const float*)d_in[3];
    const float* bq = (const float*)d_in[4];
    const float* wk = (const float*)d_in[5];
    const float* bk = (const float*)d_in[6];
    const float* wv = (const float*)d_in[7];
    const float* bv = (const float*)d_in[8];
    const float* wo = (const float*)d_in[9];
    const float* ln2= (const float*)d_in[10];
    const float* w1 = (const float*)d_in[11];
    const float* w2 = (const float*)d_in[12];
    const float* wc = (const float*)d_in[13];
    float* out = (float*)d_out;

    float *q, *k, *v, *hbuf, *a1, *a2;
    h16 *xnh, *xnl, *atth, *yh, *gh, *gl;
    h16 *wqh, *wql, *wkh, *wkl, *wvh, *woh, *w1h, *w2h, *wch;
    cudaGetSymbolAddress((void**)&q,    g_q);
    cudaGetSymbolAddress((void**)&k,    g_k);
    cudaGetSymbolAddress((void**)&v,    g_v);
    cudaGetSymbolAddress((void**)&hbuf, g_h);
    cudaGetSymbolAddress((void**)&a1,   g_a1);
    cudaGetSymbolAddress((void**)&a2,   g_a2);
    cudaGetSymbolAddress((void**)&xnh,  g_xnh);
    cudaGetSymbolAddress((void**)&xnl,  g_xnl);
    cudaGetSymbolAddress((void**)&atth, g_atth);
    cudaGetSymbolAddress((void**)&yh,   g_yh);
    cudaGetSymbolAddress((void**)&gh,   g_gh);
    cudaGetSymbolAddress((void**)&gl,   g_gl);
    cudaGetSymbolAddress((void**)&wqh,  g_wqh);
    cudaGetSymbolAddress((void**)&wql,  g_wql);
    cudaGetSymbolAddress((void**)&wkh,  g_wkh);
    cudaGetSymbolAddress((void**)&wkl,  g_wkl);
    cudaGetSymbolAddress((void**)&wvh,  g_wvh);
    cudaGetSymbolAddress((void**)&woh,  g_woh);
    cudaGetSymbolAddress((void**)&w1h,  g_w1h);
    cudaGetSymbolAddress((void**)&w2h,  g_w2h);
    cudaGetSymbolAddress((void**)&wch,  g_wch);

    const int SMEM_11 = 3 * 4 * GTILE;   // 122880 (q,k 3-pass)
    const int SMEM_10 = 3 * 3 * GTILE;   // 92160  (wc 2-pass)
    const int SMEM_00 = 3 * 2 * GTILE;   // 61440  (1-pass)
    cudaFuncSetAttribute((gemm_f16<true,true>),   cudaFuncAttributeMaxDynamicSharedMemorySize, SMEM_11);
    cudaFuncSetAttribute((gemm_f16<true,false>),  cudaFuncAttributeMaxDynamicSharedMemorySize, SMEM_10);
    cudaFuncSetAttribute((gemm_f16<false,false>), cudaFuncAttributeMaxDynamicSharedMemorySize, SMEM_00);
    cudaFuncSetAttribute(attn_mma_kernel, cudaFuncAttributeMaxDynamicSharedMemorySize, ATTN_SMEM);

    dim3 tb(32, 8);
    transpose_f16_kernel<<<dim3(H_DIM/32, H_DIM/32), tb>>>(wq, H_DIM, H_DIM, wqh, wql);
    transpose_f16_kernel<<<dim3(H_DIM/32, H_DIM/32), tb>>>(wk, H_DIM, H_DIM, wkh, wkl);
    transpose_f16_kernel<<<dim3(H_DIM/32, H_DIM/32), tb>>>(wv, H_DIM, H_DIM, wvh, nullptr);
    transpose_f16_kernel<<<dim3(H_DIM/32, H_DIM/32), tb>>>(wo, H_DIM, H_DIM, woh, nullptr);
    transpose_f16_kernel<<<dim3(FF_DIM/32, H_DIM/32), tb>>>(w1, H_DIM, FF_DIM, w1h, nullptr);
    transpose_f16_kernel<<<dim3(FF_DIM/32, H_DIM/32), tb>>>(w2, H_DIM, FF_DIM, w2h, nullptr);
    transpose_f16_kernel<<<dim3(H_DIM/32, FF_DIM/32), tb>>>(wc, FF_DIM, H_DIM, wch, nullptr);

    // 1) x = rmsnorm(hidden, ln1) -> fp16 hi/lo
    rmsnorm_f16_kernel<<<T_DIM, 256>>>(hidden, ln1, xnh, xnl);

    // 2) q/k (3-pass), v (1-pass)
    dim3 gH(H_DIM / BN, T_DIM / BM);
    gemm_f16<true,true><<<gH, 256, SMEM_11>>>(xnh, xnl, wqh, wql, bq, nullptr, q, H_DIM, H_DIM);
    gemm_f16<true,true><<<gH, 256, SMEM_11>>>(xnh, xnl, wkh, wkl, bk, nullptr, k, H_DIM, H_DIM);
    gemm_f16<false,false><<<gH, 256, SMEM_00>>>(xnh, nullptr, wvh, nullptr, bv, nullptr, v, H_DIM, H_DIM);

    // 3) RoPE
    rope_kernel<<<(T_DIM * NHEADS * (HD_DIM / 2)) / 256, 256>>>(q, k, positions);

    // 4) attention -> atth (single fp16)
    attn_mma_kernel<<<dim3(T_DIM / 64, NHEADS), 128, ATTN_SMEM>>>(q, k, v, atth);

    // 5) h = hidden + attn @ wo  (1-pass)
    gemm_f16<false,false><<<gH, 256, SMEM_00>>>(atth, nullptr, woh, nullptr, nullptr, hidden, hbuf, H_DIM, H_DIM);

    // 6) y = rmsnorm(h, ln2) -> single fp16
    rmsnorm_f16_kernel<<<T_DIM, 256>>>(hbuf, ln2, yh, nullptr);

    // 7) MLP up + gate (1-pass each)
    dim3 gF(FF_DIM / BN, T_DIM / BM);
    gemm_f16<false,false><<<gF, 256, SMEM_00>>>(yh, nullptr, w1h, nullptr, nullptr, nullptr, a1, FF_DIM, H_DIM);
    gemm_f16<false,false><<<gF, 256, SMEM_00>>>(yh, nullptr, w2h, nullptr, nullptr, nullptr, a2, FF_DIM, H_DIM);
    silu_hilo_kernel<<<(T_DIM * FF_DIM + 255) / 256, 256>>>(a1, a2, gh, gl, T_DIM * FF_DIM);

    // 8) out = h + g @ wc  (2-pass: A hi/lo x B single)
    gemm_f16<true,false><<<gH, 256, SMEM_10>>>(gh, gl, wch, nullptr, nullptr, hbuf, out, H_DIM, FF_DIM);
}

// round 7
// speedup vs baseline: 4.9531x; 1.2233x over previous
#include <cuda_runtime.h>
#include <cuda_bf16.h>
#include <cuda_fp16.h>
#include <math.h>
#include <cstdint>

#define T_DIM 2048
#define H_DIM 4096
#define NHEADS 32
#define HD_DIM 128
#define FF_DIM 11008
#define EPS_V 1e-6f

typedef __nv_bfloat16 bf16;
typedef __half h16;

// ===================== device scratch ======================================
__device__ float g_q  [(size_t)T_DIM * H_DIM];
__device__ float g_k  [(size_t)T_DIM * H_DIM];
__device__ float g_v  [(size_t)T_DIM * H_DIM];
__device__ float g_h  [(size_t)T_DIM * H_DIM];
__device__ float g_a1 [(size_t)T_DIM * FF_DIM];
__device__ float g_a2 [(size_t)T_DIM * FF_DIM];

__device__ h16 g_xnh [(size_t)T_DIM * H_DIM];
__device__ h16 g_xnl [(size_t)T_DIM * H_DIM];
__device__ h16 g_atth[(size_t)T_DIM * H_DIM];
__device__ h16 g_yh  [(size_t)T_DIM * H_DIM];
__device__ h16 g_gh  [(size_t)T_DIM * FF_DIM];

// attention operand buffers (pre-split / converted)
__device__ bf16 g_qhb[(size_t)T_DIM * H_DIM];
__device__ bf16 g_qlb[(size_t)T_DIM * H_DIM];
__device__ bf16 g_khb[(size_t)T_DIM * H_DIM];
__device__ bf16 g_klb[(size_t)T_DIM * H_DIM];
__device__ h16  g_vhb[(size_t)T_DIM * H_DIM];

// weights: wq,wk hi/lo (3-pass); others single fp16
__device__ h16 g_wqh[(size_t)H_DIM * H_DIM];
__device__ h16 g_wql[(size_t)H_DIM * H_DIM];
__device__ h16 g_wkh[(size_t)H_DIM * H_DIM];
__device__ h16 g_wkl[(size_t)H_DIM * H_DIM];
__device__ h16 g_wvh[(size_t)H_DIM * H_DIM];
__device__ h16 g_woh[(size_t)H_DIM * H_DIM];
__device__ h16 g_w1h[(size_t)FF_DIM * H_DIM];
__device__ h16 g_w2h[(size_t)FF_DIM * H_DIM];
__device__ h16 g_wch[(size_t)H_DIM * FF_DIM];

// ===================== PTX helpers =========================================
__device__ __forceinline__ uint32_t smem_u32(const void* p) {
    uint32_t a;
    asm("{ .reg .u64 t; cvta.to.shared.u64 t, %1; cvt.u32.u64 %0, t; }"
        : "=r"(a) : "l"(p));
    return a;
}

#define CP_ASYNC16(dst, src) \
    asm volatile("cp.async.cg.shared.global [%0], [%1], 16;" :: "r"(dst), "l"(src))
#define CP_COMMIT() asm volatile("cp.async.commit_group;" ::: "memory")

__device__ __forceinline__ void ldsm_x4(uint32_t* r, uint32_t a) {
    asm volatile("ldmatrix.sync.aligned.m8n8.x4.shared.b16 {%0,%1,%2,%3}, [%4];"
        : "=r"(r[0]), "=r"(r[1]), "=r"(r[2]), "=r"(r[3]) : "r"(a));
}
__device__ __forceinline__ void ldsm_x4t(uint32_t* r, uint32_t a) {
    asm volatile("ldmatrix.sync.aligned.m8n8.x4.trans.shared.b16 {%0,%1,%2,%3}, [%4];"
        : "=r"(r[0]), "=r"(r[1]), "=r"(r[2]), "=r"(r[3]) : "r"(a));
}

__device__ __forceinline__ void mma_bf(float* d, const uint32_t* a,
                                       uint32_t b0, uint32_t b1) {
    asm volatile(
        "mma.sync.aligned.m16n8k16.row.col.f32.bf16.bf16.f32 "
        "{%0,%1,%2,%3}, {%4,%5,%6,%7}, {%8,%9}, {%0,%1,%2,%3};"
        : "+f"(d[0]), "+f"(d[1]), "+f"(d[2]), "+f"(d[3])
        : "r"(a[0]), "r"(a[1]), "r"(a[2]), "r"(a[3]), "r"(b0), "r"(b1));
}
__device__ __forceinline__ void mma_fp(float* d, const uint32_t* a,
                                       uint32_t b0, uint32_t b1) {
    asm volatile(
        "mma.sync.aligned.m16n8k16.row.col.f32.f16.f16.f32 "
        "{%0,%1,%2,%3}, {%4,%5,%6,%7}, {%8,%9}, {%0,%1,%2,%3};"
        : "+f"(d[0]), "+f"(d[1]), "+f"(d[2]), "+f"(d[3])
        : "r"(a[0]), "r"(a[1]), "r"(a[2]), "r"(a[3]), "r"(b0), "r"(b1));
}

__device__ __forceinline__ void split_bf(float v, bf16& h, bf16& l) {
    h = __float2bfloat16(v);
    l = __float2bfloat16(v - __bfloat162float(h));
}
__device__ __forceinline__ void split_fp(float v, h16& h, h16& l) {
    h = __float2half_rn(v);
    l = __float2half_rn(v - __half2float(h));
}

// ===================== fp16 GEMM (1/2/3-pass via AS/BS) =====================
#define BM 128
#define BN 128
#define GROWB 80
#define GTILE (128 * GROWB)

template<bool AS, bool BS>
__global__ __launch_bounds__(256, (AS && BS) ? 1 : 2)
void gemm_f16(const h16* __restrict__ Ah, const h16* __restrict__ Al,
              const h16* __restrict__ Bh, const h16* __restrict__ Bl,
              const float* __restrict__ bias, const float* __restrict__ resid,
              float* __restrict__ C, int Ntot, int K)
{
    constexpr int NT = 2 + (AS ? 1 : 0) + (BS ? 1 : 0);
    constexpr int STAGE_B = NT * GTILE;
    constexpr uint32_t T_A0 = 0;
    constexpr uint32_t T_A1 = GTILE;
    constexpr uint32_t T_B0 = (AS ? 2 : 1) * GTILE;
    constexpr uint32_t T_B1 = T_B0 + GTILE;
    extern __shared__ char dsm[];
    const int tid = threadIdx.x;
    const int wid = tid >> 5, lane = tid & 31;
    const int rowA0 = blockIdx.y * BM;
    const int colB0 = blockIdx.x * BN;
    const int nIter = K >> 5;
    const uint32_t sbase = smem_u32(dsm);

    auto load_stage = [&](int it) {
        const int s = it % 3;
        const size_t koff = (size_t)it * 32;
        const uint32_t st = sbase + s * STAGE_B;
        #pragma unroll
        for (int i = 0; i < 2; i++) {
            int idx = tid + i * 256;
            int r = idx >> 2, seg = idx & 3;
            uint32_t doff = r * GROWB + seg * 16;
            const size_t goff = koff + seg * 8;
            CP_ASYNC16(st + T_A0 + doff, Ah + (size_t)(rowA0 + r) * K + goff);
            if (AS) CP_ASYNC16(st + T_A1 + doff, Al + (size_t)(rowA0 + r) * K + goff);
            CP_ASYNC16(st + T_B0 + doff, Bh + (size_t)(colB0 + r) * K + goff);
            if (BS) CP_ASYNC16(st + T_B1 + doff, Bl + (size_t)(colB0 + r) * K + goff);
        }
        CP_COMMIT();
    };

    const int m0 = (wid >> 1) * 32;
    const int n0 = (wid & 1) * 64;

    float acc[2][8][4];
    #pragma unroll
    for (int i = 0; i < 2; i++)
        #pragma unroll
        for (int j = 0; j < 8; j++)
            #pragma unroll
            for (int c = 0; c < 4; c++) acc[i][j][c] = 0.f;

    const int mi = lane >> 3, l7 = lane & 7;
    const uint32_t aoff = (uint32_t)((m0 + (mi & 1) * 8 + l7) * GROWB + (mi >> 1) * 16);
    const uint32_t boff = (uint32_t)((n0 + (mi >> 1) * 8 + l7) * GROWB + (mi & 1) * 16);

    load_stage(0); load_stage(1);

    for (int it = 0; it < nIter; it++) {
        if (it + 2 < nIter) load_stage(it + 2);
        else CP_COMMIT();
        asm volatile("cp.async.wait_group %0;" :: "n"(2));
        __syncthreads();

        const uint32_t st = sbase + (it % 3) * STAGE_B;

        #pragma unroll
        for (int kk = 0; kk < 2; kk++) {
            uint32_t ah0[4], ah1[4], al0[4], al1[4];
            ldsm_x4(ah0, st + T_A0 + aoff + kk * 32);
            ldsm_x4(ah1, st + T_A0 + aoff + 16 * GROWB + kk * 32);
            if (AS) {
                ldsm_x4(al0, st + T_A1 + aoff + kk * 32);
                ldsm_x4(al1, st + T_A1 + aoff + 16 * GROWB + kk * 32);
            }
            #pragma unroll
            for (int g = 0; g < 4; g++) {
                uint32_t bh[4];
                ldsm_x4(bh, st + T_B0 + boff + g * 16 * GROWB + kk * 32);
                mma_fp(acc[0][2*g+0], ah0, bh[0], bh[1]);
                mma_fp(acc[0][2*g+1], ah0, bh[2], bh[3]);
                mma_fp(acc[1][2*g+0], ah1, bh[0], bh[1]);
                mma_fp(acc[1][2*g+1], ah1, bh[2], bh[3]);
                if (AS) {
                    mma_fp(acc[0][2*g+0], al0, bh[0], bh[1]);
                    mma_fp(acc[0][2*g+1], al0, bh[2], bh[3]);
                    mma_fp(acc[1][2*g+0], al1, bh[0], bh[1]);
                    mma_fp(acc[1][2*g+1], al1, bh[2], bh[3]);
                }
                if (BS) {
                    uint32_t bl[4];
                    ldsm_x4(bl, st + T_B1 + boff + g * 16 * GROWB + kk * 32);
                    mma_fp(acc[0][2*g+0], ah0, bl[0], bl[1]);
                    mma_fp(acc[0][2*g+1], ah0, bl[2], bl[3]);
                    mma_fp(acc[1][2*g+0], ah1, bl[0], bl[1]);
                    mma_fp(acc[1][2*g+1], ah1, bl[2], bl[3]);
                }
            }
        }
        __syncthreads();
    }

    const int l4 = lane >> 2, l2 = (lane & 3) * 2;
    #pragma unroll
    for (int mf = 0; mf < 2; mf++) {
        const int r = rowA0 + m0 + mf * 16 + l4;
        #pragma unroll
        for (int nf = 0; nf < 8; nf++) {
            const int c = colB0 + n0 + nf * 8 + l2;
            float2 v0 = make_float2(acc[mf][nf][0], acc[mf][nf][1]);
            float2 v1 = make_float2(acc[mf][nf][2], acc[mf][nf][3]);
            if (bias) {
                v0.x += bias[c]; v0.y += bias[c + 1];
                v1.x += bias[c]; v1.y += bias[c + 1];
            }
            if (resid) {
                const float2 r0 = *(const float2*)&resid[(size_t)r * Ntot + c];
                const float2 r1 = *(const float2*)&resid[(size_t)(r + 8) * Ntot + c];
                v0.x += r0.x; v0.y += r0.y;
                v1.x += r1.x; v1.y += r1.y;
            }
            *(float2*)&C[(size_t)r * Ntot + c] = v0;
            *(float2*)&C[(size_t)(r + 8) * Ntot + c] = v1;
        }
    }
}

// ===================== tensor-core flash attention ===========================
// Operands pre-split: Q,K bf16 hi/lo; V fp16. Mainloop = cp.async + MMA only.
#define AROW 272
#define PSROW 144
#define OFF_QH 0
#define OFF_QL (OFF_QH + 64 * AROW)
#define OFF_KH (OFF_QL + 64 * AROW)
#define OFF_KL (OFF_KH + 64 * AROW)
#define OFF_VS (OFF_KL + 64 * AROW)
#define OFF_PS (OFF_VS + 64 * AROW)
#define ATTN_SMEM (OFF_PS + 64 * PSROW)

__global__ __launch_bounds__(128, 2)
void attn_mma_kernel(const bf16* __restrict__ Qh, const bf16* __restrict__ Ql,
                     const bf16* __restrict__ Kh, const bf16* __restrict__ Kl,
                     const h16* __restrict__ Vh, h16* __restrict__ Oh)
{
    extern __shared__ char asm_[];
    const uint32_t sb = smem_u32(asm_);
    const int q0 = blockIdx.x * 64;
    const int h  = blockIdx.y;
    const int tid = threadIdx.x;
    const int w = tid >> 5, lane = tid & 31;
    const int mi = lane >> 3, l7 = lane & 7;
    const size_t hoff = (size_t)h * HD_DIM;

    // issue Q tile loads (bf16 hi/lo), 16B chunks
    #pragma unroll
    for (int i = 0; i < 8; i++) {
        int idx = tid + i * 128;
        int r = idx >> 4, c = idx & 15;
        uint32_t dst = sb + OFF_QH + r * AROW + c * 16;
        const size_t gsrc = (size_t)(q0 + r) * H_DIM + hoff + c * 8;
        CP_ASYNC16(dst, Qh + gsrc);
        CP_ASYNC16(dst + (OFF_QL - OFF_QH), Ql + gsrc);
    }
    CP_COMMIT();

    float oacc[16][4];
    #pragma unroll
    for (int f = 0; f < 16; f++)
        #pragma unroll
        for (int c = 0; c < 4; c++) oacc[f][c] = 0.f;
    float m0v = -1e30f, m1v = -1e30f, l0v = 0.f, l1v = 0.f;
    const float scaling = 0.08838834764831845f;

    const uint32_t aq_off = (uint32_t)((w * 16 + (mi & 1) * 8 + l7) * AROW + (mi >> 1) * 16);
    const uint32_t bk_off = (uint32_t)(((mi >> 1) * 8 + l7) * AROW + (mi & 1) * 16);
    const uint32_t ps_off = (uint32_t)((w * 16 + (mi & 1) * 8 + l7) * PSROW + (mi >> 1) * 16);

    const int r0 = lane >> 2;
    const int gq0 = q0 + w * 16 + r0;
    const int gq1 = gq0 + 8;

    for (int j0 = 0; j0 <= q0; j0 += 64) {
        __syncthreads();
        // K hi/lo + V loads, 16B chunks
        #pragma unroll
        for (int i = 0; i < 8; i++) {
            int idx = tid + i * 128;
            int r = idx >> 4, c = idx & 15;
            uint32_t doff = r * AROW + c * 16;
            const size_t gsrc = (size_t)(j0 + r) * H_DIM + hoff + c * 8;
            CP_ASYNC16(sb + OFF_KH + doff, Kh + gsrc);
            CP_ASYNC16(sb + OFF_KL + doff, Kl + gsrc);
            CP_ASYNC16(sb + OFF_VS + doff, Vh + gsrc);
        }
        CP_COMMIT();
        asm volatile("cp.async.wait_group 0;" ::: "memory");
        __syncthreads();

        float sacc[8][4];
        #pragma unroll
        for (int f = 0; f < 8; f++)
            #pragma unroll
            for (int c = 0; c < 4; c++) sacc[f][c] = 0.f;

        #pragma unroll
        for (int pass = 0; pass < 3; pass++) {
            const uint32_t sa = sb + ((pass < 2) ? OFF_QH : OFF_QL);
            const uint32_t skb = sb + ((pass == 1) ? OFF_KL : OFF_KH);
            #pragma unroll
            for (int ks = 0; ks < 8; ks++) {
                uint32_t a[4];
                ldsm_x4(a, sa + aq_off + ks * 32);
                #pragma unroll
                for (int g = 0; g < 4; g++) {
                    uint32_t b[4];
                    ldsm_x4(b, skb + bk_off + g * 16 * AROW + ks * 32);
                    mma_bf(sacc[2*g+0], a, b[0], b[1]);
                    mma_bf(sacc[2*g+1], a, b[2], b[3]);
                }
            }
        }

        const bool diag = (j0 == q0);
        #pragma unroll
        for (int f = 0; f < 8; f++) {
            int kvc = j0 + f * 8 + (lane & 3) * 2;
            #pragma unroll
            for (int c = 0; c < 4; c++) sacc[f][c] *= scaling;
            if (diag) {
                if (kvc     > gq0) sacc[f][0] = -1e30f;
                if (kvc + 1 > gq0) sacc[f][1] = -1e30f;
                if (kvc     > gq1) sacc[f][2] = -1e30f;
                if (kvc + 1 > gq1) sacc[f][3] = -1e30f;
            }
        }

        float mx0 = -1e30f, mx1 = -1e30f;
        #pragma unroll
        for (int f = 0; f < 8; f++) {
            mx0 = fmaxf(mx0, fmaxf(sacc[f][0], sacc[f][1]));
            mx1 = fmaxf(mx1, fmaxf(sacc[f][2], sacc[f][3]));
        }
        mx0 = fmaxf(mx0, __shfl_xor_sync(0xffffffffu, mx0, 1));
        mx0 = fmaxf(mx0, __shfl_xor_sync(0xffffffffu, mx0, 2));
        mx1 = fmaxf(mx1, __shfl_xor_sync(0xffffffffu, mx1, 1));
        mx1 = fmaxf(mx1, __shfl_xor_sync(0xffffffffu, mx1, 2));
        const float mn0 = fmaxf(m0v, mx0), mn1 = fmaxf(m1v, mx1);
        float rs0 = 0.f, rs1 = 0.f;
        #pragma unroll
        for (int f = 0; f < 8; f++) {
            float p0 = expf(sacc[f][0] - mn0);
            float p1 = expf(sacc[f][1] - mn0);
            float p2 = expf(sacc[f][2] - mn1);
            float p3 = expf(sacc[f][3] - mn1);
            rs0 += p0 + p1; rs1 += p2 + p3;
            __half2 v01 = __floats2half2_rn(p0, p1);
            __half2 v23 = __floats2half2_rn(p2, p3);
            uint32_t col = (f * 8 + (lane & 3) * 2) * 2;
            *(uint32_t*)(asm_ + OFF_PS + (w * 16 + r0) * PSROW + col) = *(uint32_t*)&v01;
            *(uint32_t*)(asm_ + OFF_PS + (w * 16 + r0 + 8) * PSROW + col) = *(uint32_t*)&v23;
        }
        rs0 += __shfl_xor_sync(0xffffffffu, rs0, 1);
        rs0 += __shfl_xor_sync(0xffffffffu, rs0, 2);
        rs1 += __shfl_xor_sync(0xffffffffu, rs1, 1);
        rs1 += __shfl_xor_sync(0xffffffffu, rs1, 2);
        const float al0 = expf(m0v - mn0), al1 = expf(m1v - mn1);
        l0v = l0v * al0 + rs0; l1v = l1v * al1 + rs1;
        m0v = mn0; m1v = mn1;
        #pragma unroll
        for (int f = 0; f < 16; f++) {
            oacc[f][0] *= al0; oacc[f][1] *= al0;
            oacc[f][2] *= al1; oacc[f][3] *= al1;
        }
        __syncwarp();

        #pragma unroll
        for (int ks = 0; ks < 4; ks++) {
            uint32_t a[4];
            ldsm_x4(a, sb + OFF_PS + ps_off + ks * 32);
            #pragma unroll
            for (int g = 0; g < 8; g++) {
                uint32_t b[4];
                ldsm_x4t(b, sb + OFF_VS + (ks * 16 + (mi & 1) * 8 + l7) * AROW
                               + (g * 16 + (mi >> 1) * 8) * 2);
                mma_fp(oacc[2*g+0], a, b[0], b[1]);
                mma_fp(oacc[2*g+1], a, b[2], b[3]);
            }
        }
    }

    const float i0 = 1.f / l0v, i1 = 1.f / l1v;
    #pragma unroll
    for (int f = 0; f < 16; f++) {
        int col = h * HD_DIM + f * 8 + (lane & 3) * 2;
        __half2 hh0 = __floats2half2_rn(oacc[f][0] * i0, oacc[f][1] * i0);
        __half2 hh1 = __floats2half2_rn(oacc[f][2] * i1, oacc[f][3] * i1);
        *(__half2*)&Oh[(size_t)gq0 * H_DIM + col] = hh0;
        *(__half2*)&Oh[(size_t)gq1 * H_DIM + col] = hh1;
    }
}

// ===================== elementwise / conversion kernels =====================
__global__ void rmsnorm_f16_kernel(const float* __restrict__ x,
                                   const float* __restrict__ scale,
                                   h16* __restrict__ oh, h16* __restrict__ ol)
{
    int row = blockIdx.x;
    const float4* xr = (const float4*)(x + (size_t)row * H_DIM);
    float ss = 0.f;
    for (int i = threadIdx.x; i < H_DIM / 4; i += blockDim.x) {
        float4 v = xr[i];
        ss += v.x * v.x + v.y * v.y + v.z * v.z + v.w * v.w;
    }
    #pragma unroll
    for (int off = 16; off; off >>= 1) ss += __shfl_xor_sync(0xffffffffu, ss, off);
    __shared__ float red[32];
    int lane = threadIdx.x & 31, wid = threadIdx.x >> 5;
    if (lane == 0) red[wid] = ss;
    __syncthreads();
    if (wid == 0) {
        ss = (lane < (int)(blockDim.x >> 5)) ? red[lane] : 0.f;
        #pragma unroll
        for (int off = 16; off; off >>= 1) ss += __shfl_xor_sync(0xffffffffu, ss, off);
        if (lane == 0) red[0] = ss;
    }
    __syncthreads();
    float inv = rsqrtf(red[0] / (float)H_DIM + EPS_V);
    const float4* sc = (const float4*)scale;
    for (int i = threadIdx.x; i < H_DIM / 4; i += blockDim.x) {
        float4 v = xr[i], s = sc[i];
        float f[4] = {v.x * inv * s.x, v.y * inv * s.y, v.z * inv * s.z, v.w * inv * s.w};
        size_t base = (size_t)row * H_DIM + i * 4;
        #pragma unroll
        for (int c = 0; c < 4; c++) {
            if (ol) {
                h16 h, l; split_fp(f[c], h, l);
                oh[base + c] = h; ol[base + c] = l;
            } else {
                oh[base + c] = __float2half_rn(f[c]);
            }
        }
    }
}

// a1 * silu(a2) -> single fp16, 4 elements/thread
__global__ void silu_f16_kernel(const float* __restrict__ a1,
                                const float* __restrict__ a2,
                                h16* __restrict__ oh, int n4)
{
    int i = blockIdx.x * blockDim.x + threadIdx.x;
    if (i < n4) {
        float4 x = ((const float4*)a1)[i];
        float4 g = ((const float4*)a2)[i];
        float v0 = x.x * (g.x / (1.f + expf(-g.x)));
        float v1 = x.y * (g.y / (1.f + expf(-g.y)));
        float v2 = x.z * (g.z / (1.f + expf(-g.z)));
        float v3 = x.w * (g.w / (1.f + expf(-g.w)));
        __half2 lo = __floats2half2_rn(v0, v1);
        __half2 hi = __floats2half2_rn(v2, v3);
        uint2 pack = {*(uint32_t*)&lo, *(uint32_t*)&hi};
        ((uint2*)oh)[i] = pack;
    }
}

// W[K][N] fp32 -> Th[N][K] fp16 (+ optional Tl)
__global__ void transpose_f16_kernel(const float* __restrict__ W, int K, int N,
                                     h16* __restrict__ Th, h16* __restrict__ Tl)
{
    __shared__ float t[32][33];
    int n0 = blockIdx.x * 32, k0 = blockIdx.y * 32;
    int tx = threadIdx.x, ty = threadIdx.y;
    #pragma unroll
    for (int i = ty; i < 32; i += 8)
        t[i][tx] = W[(size_t)(k0 + i) * N + n0 + tx];
    __syncthreads();
    #pragma unroll
    for (int i = ty; i < 32; i += 8) {
        float v = t[tx][i];
        size_t idx = (size_t)(n0 + i) * K + k0 + tx;
        if (Tl) {
            h16 h, l; split_fp(v, h, l);
            Th[idx] = h; Tl[idx] = l;
        } else {
            Th[idx] = __float2half_rn(v);
        }
    }
}

// ===================== RoPE + split (q,k fp32 -> bf16 hi/lo) =================
__global__ void rope_split_kernel(const float* __restrict__ q,
                                  const float* __restrict__ k,
                                  const int* __restrict__ pos,
                                  bf16* __restrict__ qh, bf16* __restrict__ ql,
                                  bf16* __restrict__ kh, bf16* __restrict__ kl)
{
    int idx = blockIdx.x * blockDim.x + threadIdx.x;
    if (idx >= T_DIM * NHEADS * (HD_DIM / 2)) return;
    int d  = idx & 63;
    int th = idx >> 6;
    int t  = th >> 5;
    float invf = powf(10000.0f, -(float)d * (1.0f / 64.0f));
    float ang = (float)pos[t] * invf;
    float c, s;
    sincosf(ang, &s, &c);
    size_t base = (size_t)th * HD_DIM + d;
    float q1 = q[base], q2 = q[base + 64];
    float rq1 = q1 * c - q2 * s;
    float rq2 = q2 * c + q1 * s;
    float k1 = k[base], k2 = k[base + 64];
    float rk1 = k1 * c - k2 * s;
    float rk2 = k2 * c + k1 * s;
    bf16 h, l;
    split_bf(rq1, h, l); qh[base] = h;       ql[base] = l;
    split_bf(rq2, h, l); qh[base + 64] = h;  ql[base + 64] = l;
    split_bf(rk1, h, l); kh[base] = h;       kl[base] = l;
    split_bf(rk2, h, l); kh[base + 64] = h;  kl[base + 64] = l;
}

// v fp32 -> fp16
__global__ void f32_to_f16_kernel(const float* __restrict__ x,
                                  h16* __restrict__ o, int n4)
{
    int i = blockIdx.x * blockDim.x + threadIdx.x;
    if (i < n4) {
        float4 v = ((const float4*)x)[i];
        __half2 lo = __floats2half2_rn(v.x, v.y);
        __half2 hi = __floats2half2_rn(v.z, v.w);
        uint2 pack = {*(uint32_t*)&lo, *(uint32_t*)&hi};
        ((uint2*)o)[i] = pack;
    }
}

// ===================== launch ================================================
extern "C" void kernel_launch(void* const* d_in, const int* in_sizes, int n_in,
                              void* d_out, int out_size)
{
    (void)in_sizes; (void)n_in; (void)out_size;
    const int*   positions = (const int*)  d_in[0];
    const float* hidden    = (const float*)d_in[1];
    const float* ln1       = (const float*)d_in[2];
    const float* wq = (const float*)d_in[3];
    const float* bq = (const float*)d_in[4];
    const float* wk = (const float*)d_in[5];
    const float* bk = (const float*)d_in[6];
    const float* wv = (const float*)d_in[7];
    const float* bv = (const float*)d_in[8];
    const float* wo = (const float*)d_in[9];
    const float* ln2= (const float*)d_in[10];
    const float* w1 = (const float*)d_in[11];
    const float* w2 = (const float*)d_in[12];
    const float* wc = (const float*)d_in[13];
    float* out = (float*)d_out;

    float *q, *k, *v, *hbuf, *a1, *a2;
    h16 *xnh, *xnl, *atth, *yh, *gh, *vhb;
    bf16 *qhb, *qlb, *khb, *klb;
    h16 *wqh, *wql, *wkh, *wkl, *wvh, *woh, *w1h, *w2h, *wch;
    cudaGetSymbolAddress((void**)&q,    g_q);
    cudaGetSymbolAddress((void**)&k,    g_k);
    cudaGetSymbolAddress((void**)&v,    g_v);
    cudaGetSymbolAddress((void**)&hbuf, g_h);
    cudaGetSymbolAddress((void**)&a1,   g_a1);
    cudaGetSymbolAddress((void**)&a2,   g_a2);
    cudaGetSymbolAddress((void**)&xnh,  g_xnh);
    cudaGetSymbolAddress((void**)&xnl,  g_xnl);
    cudaGetSymbolAddress((void**)&atth, g_atth);
    cudaGetSymbolAddress((void**)&yh,   g_yh);
    cudaGetSymbolAddress((void**)&gh,   g_gh);
    cudaGetSymbolAddress((void**)&qhb,  g_qhb);
    cudaGetSymbolAddress((void**)&qlb,  g_qlb);
    cudaGetSymbolAddress((void**)&khb,  g_khb);
    cudaGetSymbolAddress((void**)&klb,  g_klb);
    cudaGetSymbolAddress((void**)&vhb,  g_vhb);
    cudaGetSymbolAddress((void**)&wqh,  g_wqh);
    cudaGetSymbolAddress((void**)&wql,  g_wql);
    cudaGetSymbolAddress((void**)&wkh,  g_wkh);
    cudaGetSymbolAddress((void**)&wkl,  g_wkl);
    cudaGetSymbolAddress((void**)&wvh,  g_wvh);
    cudaGetSymbolAddress((void**)&woh,  g_woh);
    cudaGetSymbolAddress((void**)&w1h,  g_w1h);
    cudaGetSymbolAddress((void**)&w2h,  g_w2h);
    cudaGetSymbolAddress((void**)&wch,  g_wch);

    const int SMEM_11 = 3 * 4 * GTILE;   // 122880 (q,k 3-pass)
    const int SMEM_00 = 3 * 2 * GTILE;   // 61440  (1-pass)
    cudaFuncSetAttribute((gemm_f16<true,true>),   cudaFuncAttributeMaxDynamicSharedMemorySize, SMEM_11);
    cudaFuncSetAttribute((gemm_f16<false,false>), cudaFuncAttributeMaxDynamicSharedMemorySize, SMEM_00);
    cudaFuncSetAttribute(attn_mma_kernel, cudaFuncAttributeMaxDynamicSharedMemorySize, ATTN_SMEM);

    dim3 tb(32, 8);
    transpose_f16_kernel<<<dim3(H_DIM/32, H_DIM/32), tb>>>(wq, H_DIM, H_DIM, wqh, wql);
    transpose_f16_kernel<<<dim3(H_DIM/32, H_DIM/32), tb>>>(wk, H_DIM, H_DIM, wkh, wkl);
    transpose_f16_kernel<<<dim3(H_DIM/32, H_DIM/32), tb>>>(wv, H_DIM, H_DIM, wvh, nullptr);
    transpose_f16_kernel<<<dim3(H_DIM/32, H_DIM/32), tb>>>(wo, H_DIM, H_DIM, woh, nullptr);
    transpose_f16_kernel<<<dim3(FF_DIM/32, H_DIM/32), tb>>>(w1, H_DIM, FF_DIM, w1h, nullptr);
    transpose_f16_kernel<<<dim3(FF_DIM/32, H_DIM/32), tb>>>(w2, H_DIM, FF_DIM, w2h, nullptr);
    transpose_f16_kernel<<<dim3(H_DIM/32, FF_DIM/32), tb>>>(wc, FF_DIM, H_DIM, wch, nullptr);

    // 1) x = rmsnorm(hidden, ln1) -> fp16 hi/lo
    rmsnorm_f16_kernel<<<T_DIM, 256>>>(hidden, ln1, xnh, xnl);

    // 2) q/k (3-pass), v (1-pass)
    dim3 gH(H_DIM / BN, T_DIM / BM);
    gemm_f16<true,true><<<gH, 256, SMEM_11>>>(xnh, xnl, wqh, wql, bq, nullptr, q, H_DIM, H_DIM);
    gemm_f16<true,true><<<gH, 256, SMEM_11>>>(xnh, xnl, wkh, wkl, bk, nullptr, k, H_DIM, H_DIM);
    gemm_f16<false,false><<<gH, 256, SMEM_00>>>(xnh, nullptr, wvh, nullptr, bv, nullptr, v, H_DIM, H_DIM);

    // 3) RoPE + split to attention operand buffers; V convert
    rope_split_kernel<<<(T_DIM * NHEADS * (HD_DIM / 2)) / 256, 256>>>(q, k, positions,
                                                                      qhb, qlb, khb, klb);
    f32_to_f16_kernel<<<(T_DIM * H_DIM / 4 + 255) / 256, 256>>>(v, vhb, T_DIM * H_DIM / 4);

    // 4) attention -> atth (single fp16)
    attn_mma_kernel<<<dim3(T_DIM / 64, NHEADS), 128, ATTN_SMEM>>>(qhb, qlb, khb, klb, vhb, atth);

    // 5) h = hidden + attn @ wo  (1-pass)
    gemm_f16<false,false><<<gH, 256, SMEM_00>>>(atth, nullptr, woh, nullptr, nullptr, hidden, hbuf, H_DIM, H_DIM);

    // 6) y = rmsnorm(h, ln2) -> single fp16
    rmsnorm_f16_kernel<<<T_DIM, 256>>>(hbuf, ln2, yh, nullptr);

    // 7) MLP up + gate (1-pass each)
    dim3 gF(FF_DIM / BN, T_DIM / BM);
    gemm_f16<false,false><<<gF, 256, SMEM_00>>>(yh, nullptr, w1h, nullptr, nullptr, nullptr, a1, FF_DIM, H_DIM);
    gemm_f16<false,false><<<gF, 256, SMEM_00>>>(yh, nullptr, w2h, nullptr, nullptr, nullptr, a2, FF_DIM, H_DIM);
    silu_f16_kernel<<<(T_DIM * FF_DIM / 4 + 255) / 256, 256>>>(a1, a2, gh, T_DIM * FF_DIM / 4);

    // 8) out = h + g @ wc  (1-pass)
    gemm_f16<false,false><<<gH, 256, SMEM_00>>>(gh, nullptr, wch, nullptr, nullptr, hbuf, out, H_DIM, FF_DIM);
}

// round 8
// speedup vs baseline: 5.6906x; 1.1489x over previous
#include <cuda_runtime.h>
#include <cuda_bf16.h>
#include <cuda_fp16.h>
#include <math.h>
#include <cstdint>

#define T_DIM 2048
#define H_DIM 4096
#define NHEADS 32
#define HD_DIM 128
#define FF_DIM 11008
#define EPS_V 1e-6f

typedef __nv_bfloat16 bf16;
typedef __half h16;

// ===================== device scratch ======================================
__device__ float g_q  [(size_t)T_DIM * H_DIM];
__device__ float g_k  [(size_t)T_DIM * H_DIM];
__device__ float g_h  [(size_t)T_DIM * H_DIM];
__device__ float g_a2 [(size_t)T_DIM * FF_DIM];

__device__ h16 g_xnh [(size_t)T_DIM * H_DIM];
__device__ h16 g_xnl [(size_t)T_DIM * H_DIM];
__device__ h16 g_atth[(size_t)T_DIM * H_DIM];
__device__ h16 g_yh  [(size_t)T_DIM * H_DIM];
__device__ h16 g_gh  [(size_t)T_DIM * FF_DIM];

// attention operand buffers (pre-split / converted)
__device__ bf16 g_qhb[(size_t)T_DIM * H_DIM];
__device__ bf16 g_qlb[(size_t)T_DIM * H_DIM];
__device__ bf16 g_khb[(size_t)T_DIM * H_DIM];
__device__ bf16 g_klb[(size_t)T_DIM * H_DIM];
__device__ h16  g_vhb[(size_t)T_DIM * H_DIM];

// weights (single fp16, transposed [N][K])
__device__ h16 g_wqh[(size_t)H_DIM * H_DIM];
__device__ h16 g_wkh[(size_t)H_DIM * H_DIM];
__device__ h16 g_wvh[(size_t)H_DIM * H_DIM];
__device__ h16 g_woh[(size_t)H_DIM * H_DIM];
__device__ h16 g_w1h[(size_t)FF_DIM * H_DIM];
__device__ h16 g_w2h[(size_t)FF_DIM * H_DIM];
__device__ h16 g_wch[(size_t)H_DIM * FF_DIM];

// ===================== PTX helpers =========================================
__device__ __forceinline__ uint32_t smem_u32(const void* p) {
    uint32_t a;
    asm("{ .reg .u64 t; cvta.to.shared.u64 t, %1; cvt.u32.u64 %0, t; }"
        : "=r"(a) : "l"(p));
    return a;
}

#define CP_ASYNC16(dst, src) \
    asm volatile("cp.async.cg.shared.global [%0], [%1], 16;" :: "r"(dst), "l"(src))
#define CP_COMMIT() asm volatile("cp.async.commit_group;" ::: "memory")

__device__ __forceinline__ void ldsm_x4(uint32_t* r, uint32_t a) {
    asm volatile("ldmatrix.sync.aligned.m8n8.x4.shared.b16 {%0,%1,%2,%3}, [%4];"
        : "=r"(r[0]), "=r"(r[1]), "=r"(r[2]), "=r"(r[3]) : "r"(a));
}
__device__ __forceinline__ void ldsm_x4t(uint32_t* r, uint32_t a) {
    asm volatile("ldmatrix.sync.aligned.m8n8.x4.trans.shared.b16 {%0,%1,%2,%3}, [%4];"
        : "=r"(r[0]), "=r"(r[1]), "=r"(r[2]), "=r"(r[3]) : "r"(a));
}

__device__ __forceinline__ void mma_bf(float* d, const uint32_t* a,
                                       uint32_t b0, uint32_t b1) {
    asm volatile(
        "mma.sync.aligned.m16n8k16.row.col.f32.bf16.bf16.f32 "
        "{%0,%1,%2,%3}, {%4,%5,%6,%7}, {%8,%9}, {%0,%1,%2,%3};"
        : "+f"(d[0]), "+f"(d[1]), "+f"(d[2]), "+f"(d[3])
        : "r"(a[0]), "r"(a[1]), "r"(a[2]), "r"(a[3]), "r"(b0), "r"(b1));
}
__device__ __forceinline__ void mma_fp(float* d, const uint32_t* a,
                                       uint32_t b0, uint32_t b1) {
    asm volatile(
        "mma.sync.aligned.m16n8k16.row.col.f32.f16.f16.f32 "
        "{%0,%1,%2,%3}, {%4,%5,%6,%7}, {%8,%9}, {%0,%1,%2,%3};"
        : "+f"(d[0]), "+f"(d[1]), "+f"(d[2]), "+f"(d[3])
        : "r"(a[0]), "r"(a[1]), "r"(a[2]), "r"(a[3]), "r"(b0), "r"(b1));
}

__device__ __forceinline__ void split_bf(float v, bf16& h, bf16& l) {
    h = __float2bfloat16(v);
    l = __float2bfloat16(v - __bfloat162float(h));
}
__device__ __forceinline__ void split_fp(float v, h16& h, h16& l) {
    h = __float2half_rn(v);
    l = __float2half_rn(v - __half2float(h));
}
__device__ __forceinline__ float silu_f(float g) {
    return g / (1.f + expf(-g));
}

// ===================== fp16 GEMM =============================================
// C[M,N] = A@B^T (+bias). AS: A hi/lo 2-pass.
// EPI: 0 = fp32 out (+resid), 1 = fp16 out, 2 = fp16 out * silu(gate)
#define BM 128
#define BN 128
#define GROWB 80
#define GTILE (128 * GROWB)

template<bool AS, int EPI>
__global__ __launch_bounds__(256, 2)
void gemm_f16(const h16* __restrict__ Ah, const h16* __restrict__ Al,
              const h16* __restrict__ Bh,
              const float* __restrict__ bias, const float* __restrict__ resid,
              const float* __restrict__ gate,
              void* __restrict__ Cv, int Ntot, int K)
{
    constexpr int NT = AS ? 3 : 2;
    constexpr int STAGE_B = NT * GTILE;
    constexpr uint32_t T_A0 = 0;
    constexpr uint32_t T_A1 = GTILE;
    constexpr uint32_t T_B0 = (AS ? 2 : 1) * GTILE;
    extern __shared__ char dsm[];
    const int tid = threadIdx.x;
    const int wid = tid >> 5, lane = tid & 31;
    const int rowA0 = blockIdx.y * BM;
    const int colB0 = blockIdx.x * BN;
    const int nIter = K >> 5;
    const uint32_t sbase = smem_u32(dsm);

    auto load_stage = [&](int it) {
        const int s = it % 3;
        const size_t koff = (size_t)it * 32;
        const uint32_t st = sbase + s * STAGE_B;
        #pragma unroll
        for (int i = 0; i < 2; i++) {
            int idx = tid + i * 256;
            int r = idx >> 2, seg = idx & 3;
            uint32_t doff = r * GROWB + seg * 16;
            const size_t goff = koff + seg * 8;
            CP_ASYNC16(st + T_A0 + doff, Ah + (size_t)(rowA0 + r) * K + goff);
            if (AS) CP_ASYNC16(st + T_A1 + doff, Al + (size_t)(rowA0 + r) * K + goff);
            CP_ASYNC16(st + T_B0 + doff, Bh + (size_t)(colB0 + r) * K + goff);
        }
        CP_COMMIT();
    };

    const int m0 = (wid >> 1) * 32;
    const int n0 = (wid & 1) * 64;

    float acc[2][8][4];
    #pragma unroll
    for (int i = 0; i < 2; i++)
        #pragma unroll
        for (int j = 0; j < 8; j++)
            #pragma unroll
            for (int c = 0; c < 4; c++) acc[i][j][c] = 0.f;

    const int mi = lane >> 3, l7 = lane & 7;
    const uint32_t aoff = (uint32_t)((m0 + (mi & 1) * 8 + l7) * GROWB + (mi >> 1) * 16);
    const uint32_t boff = (uint32_t)((n0 + (mi >> 1) * 8 + l7) * GROWB + (mi & 1) * 16);

    load_stage(0); load_stage(1);

    for (int it = 0; it < nIter; it++) {
        if (it + 2 < nIter) load_stage(it + 2);
        else CP_COMMIT();
        asm volatile("cp.async.wait_group %0;" :: "n"(2));
        __syncthreads();

        const uint32_t st = sbase + (it % 3) * STAGE_B;

        #pragma unroll
        for (int kk = 0; kk < 2; kk++) {
            uint32_t ah0[4], ah1[4], al0[4], al1[4];
            ldsm_x4(ah0, st + T_A0 + aoff + kk * 32);
            ldsm_x4(ah1, st + T_A0 + aoff + 16 * GROWB + kk * 32);
            if (AS) {
                ldsm_x4(al0, st + T_A1 + aoff + kk * 32);
                ldsm_x4(al1, st + T_A1 + aoff + 16 * GROWB + kk * 32);
            }
            #pragma unroll
            for (int g = 0; g < 4; g++) {
                uint32_t bh[4];
                ldsm_x4(bh, st + T_B0 + boff + g * 16 * GROWB + kk * 32);
                mma_fp(acc[0][2*g+0], ah0, bh[0], bh[1]);
                mma_fp(acc[0][2*g+1], ah0, bh[2], bh[3]);
                mma_fp(acc[1][2*g+0], ah1, bh[0], bh[1]);
                mma_fp(acc[1][2*g+1], ah1, bh[2], bh[3]);
                if (AS) {
                    mma_fp(acc[0][2*g+0], al0, bh[0], bh[1]);
                    mma_fp(acc[0][2*g+1], al0, bh[2], bh[3]);
                    mma_fp(acc[1][2*g+0], al1, bh[0], bh[1]);
                    mma_fp(acc[1][2*g+1], al1, bh[2], bh[3]);
                }
            }
        }
        __syncthreads();
    }

    const int l4 = lane >> 2, l2 = (lane & 3) * 2;
    #pragma unroll
    for (int mf = 0; mf < 2; mf++) {
        const int r = rowA0 + m0 + mf * 16 + l4;
        #pragma unroll
        for (int nf = 0; nf < 8; nf++) {
            const int c = colB0 + n0 + nf * 8 + l2;
            float2 v0 = make_float2(acc[mf][nf][0], acc[mf][nf][1]);
            float2 v1 = make_float2(acc[mf][nf][2], acc[mf][nf][3]);
            if (bias) {
                v0.x += bias[c]; v0.y += bias[c + 1];
                v1.x += bias[c]; v1.y += bias[c + 1];
            }
            if (EPI == 0) {
                if (resid) {
                    const float2 r0 = *(const float2*)&resid[(size_t)r * Ntot + c];
                    const float2 r1 = *(const float2*)&resid[(size_t)(r + 8) * Ntot + c];
                    v0.x += r0.x; v0.y += r0.y;
                    v1.x += r1.x; v1.y += r1.y;
                }
                float* C = (float*)Cv;
                *(float2*)&C[(size_t)r * Ntot + c] = v0;
                *(float2*)&C[(size_t)(r + 8) * Ntot + c] = v1;
            } else {
                if (EPI == 2) {
                    const float2 g0 = *(const float2*)&gate[(size_t)r * Ntot + c];
                    const float2 g1 = *(const float2*)&gate[(size_t)(r + 8) * Ntot + c];
                    v0.x *= silu_f(g0.x); v0.y *= silu_f(g0.y);
                    v1.x *= silu_f(g1.x); v1.y *= silu_f(g1.y);
                }
                h16* C = (h16*)Cv;
                *(__half2*)&C[(size_t)r * Ntot + c] = __floats2half2_rn(v0.x, v0.y);
                *(__half2*)&C[(size_t)(r + 8) * Ntot + c] = __floats2half2_rn(v1.x, v1.y);
            }
        }
    }
}

// ===================== tensor-core flash attention ===========================
#define AROW 272
#define PSROW 144
#define OFF_QH 0
#define OFF_QL (OFF_QH + 64 * AROW)
#define OFF_KH (OFF_QL + 64 * AROW)
#define OFF_KL (OFF_KH + 64 * AROW)
#define OFF_VS (OFF_KL + 64 * AROW)
#define OFF_PS (OFF_VS + 64 * AROW)
#define ATTN_SMEM (OFF_PS + 64 * PSROW)

__global__ __launch_bounds__(128, 2)
void attn_mma_kernel(const bf16* __restrict__ Qh, const bf16* __restrict__ Ql,
                     const bf16* __restrict__ Kh, const bf16* __restrict__ Kl,
                     const h16* __restrict__ Vh, h16* __restrict__ Oh)
{
    extern __shared__ char asm_[];
    const uint32_t sb = smem_u32(asm_);
    const int q0 = blockIdx.x * 64;
    const int h  = blockIdx.y;
    const int tid = threadIdx.x;
    const int w = tid >> 5, lane = tid & 31;
    const int mi = lane >> 3, l7 = lane & 7;
    const size_t hoff = (size_t)h * HD_DIM;

    #pragma unroll
    for (int i = 0; i < 8; i++) {
        int idx = tid + i * 128;
        int r = idx >> 4, c = idx & 15;
        uint32_t dst = sb + OFF_QH + r * AROW + c * 16;
        const size_t gsrc = (size_t)(q0 + r) * H_DIM + hoff + c * 8;
        CP_ASYNC16(dst, Qh + gsrc);
        CP_ASYNC16(dst + (OFF_QL - OFF_QH), Ql + gsrc);
    }
    CP_COMMIT();

    float oacc[16][4];
    #pragma unroll
    for (int f = 0; f < 16; f++)
        #pragma unroll
        for (int c = 0; c < 4; c++) oacc[f][c] = 0.f;
    float m0v = -1e30f, m1v = -1e30f, l0v = 0.f, l1v = 0.f;
    const float scaling = 0.08838834764831845f;

    const uint32_t aq_off = (uint32_t)((w * 16 + (mi & 1) * 8 + l7) * AROW + (mi >> 1) * 16);
    const uint32_t bk_off = (uint32_t)(((mi >> 1) * 8 + l7) * AROW + (mi & 1) * 16);
    const uint32_t ps_off = (uint32_t)((w * 16 + (mi & 1) * 8 + l7) * PSROW + (mi >> 1) * 16);

    const int r0 = lane >> 2;
    const int gq0 = q0 + w * 16 + r0;
    const int gq1 = gq0 + 8;

    for (int j0 = 0; j0 <= q0; j0 += 64) {
        __syncthreads();
        #pragma unroll
        for (int i = 0; i < 8; i++) {
            int idx = tid + i * 128;
            int r = idx >> 4, c = idx & 15;
            uint32_t doff = r * AROW + c * 16;
            const size_t gsrc = (size_t)(j0 + r) * H_DIM + hoff + c * 8;
            CP_ASYNC16(sb + OFF_KH + doff, Kh + gsrc);
            CP_ASYNC16(sb + OFF_KL + doff, Kl + gsrc);
            CP_ASYNC16(sb + OFF_VS + doff, Vh + gsrc);
        }
        CP_COMMIT();
        asm volatile("cp.async.wait_group 0;" ::: "memory");
        __syncthreads();

        float sacc[8][4];
        #pragma unroll
        for (int f = 0; f < 8; f++)
            #pragma unroll
            for (int c = 0; c < 4; c++) sacc[f][c] = 0.f;

        #pragma unroll
        for (int pass = 0; pass < 3; pass++) {
            const uint32_t sa = sb + ((pass < 2) ? OFF_QH : OFF_QL);
            const uint32_t skb = sb + ((pass == 1) ? OFF_KL : OFF_KH);
            #pragma unroll
            for (int ks = 0; ks < 8; ks++) {
                uint32_t a[4];
                ldsm_x4(a, sa + aq_off + ks * 32);
                #pragma unroll
                for (int g = 0; g < 4; g++) {
                    uint32_t b[4];
                    ldsm_x4(b, skb + bk_off + g * 16 * AROW + ks * 32);
                    mma_bf(sacc[2*g+0], a, b[0], b[1]);
                    mma_bf(sacc[2*g+1], a, b[2], b[3]);
                }
            }
        }

        const bool diag = (j0 == q0);
        #pragma unroll
        for (int f = 0; f < 8; f++) {
            int kvc = j0 + f * 8 + (lane & 3) * 2;
            #pragma unroll
            for (int c = 0; c < 4; c++) sacc[f][c] *= scaling;
            if (diag) {
                if (kvc     > gq0) sacc[f][0] = -1e30f;
                if (kvc + 1 > gq0) sacc[f][1] = -1e30f;
                if (kvc     > gq1) sacc[f][2] = -1e30f;
                if (kvc + 1 > gq1) sacc[f][3] = -1e30f;
            }
        }

        float mx0 = -1e30f, mx1 = -1e30f;
        #pragma unroll
        for (int f = 0; f < 8; f++) {
            mx0 = fmaxf(mx0, fmaxf(sacc[f][0], sacc[f][1]));
            mx1 = fmaxf(mx1, fmaxf(sacc[f][2], sacc[f][3]));
        }
        mx0 = fmaxf(mx0, __shfl_xor_sync(0xffffffffu, mx0, 1));
        mx0 = fmaxf(mx0, __shfl_xor_sync(0xffffffffu, mx0, 2));
        mx1 = fmaxf(mx1, __shfl_xor_sync(0xffffffffu, mx1, 1));
        mx1 = fmaxf(mx1, __shfl_xor_sync(0xffffffffu, mx1, 2));
        const float mn0 = fmaxf(m0v, mx0), mn1 = fmaxf(m1v, mx1);
        float rs0 = 0.f, rs1 = 0.f;
        #pragma unroll
        for (int f = 0; f < 8; f++) {
            float p0 = expf(sacc[f][0] - mn0);
            float p1 = expf(sacc[f][1] - mn0);
            float p2 = expf(sacc[f][2] - mn1);
            float p3 = expf(sacc[f][3] - mn1);
            rs0 += p0 + p1; rs1 += p2 + p3;
            __half2 v01 = __floats2half2_rn(p0, p1);
            __half2 v23 = __floats2half2_rn(p2, p3);
            uint32_t col = (f * 8 + (lane & 3) * 2) * 2;
            *(uint32_t*)(asm_ + OFF_PS + (w * 16 + r0) * PSROW + col) = *(uint32_t*)&v01;
            *(uint32_t*)(asm_ + OFF_PS + (w * 16 + r0 + 8) * PSROW + col) = *(uint32_t*)&v23;
        }
        rs0 += __shfl_xor_sync(0xffffffffu, rs0, 1);
        rs0 += __shfl_xor_sync(0xffffffffu, rs0, 2);
        rs1 += __shfl_xor_sync(0xffffffffu, rs1, 1);
        rs1 += __shfl_xor_sync(0xffffffffu, rs1, 2);
        const float al0 = expf(m0v - mn0), al1 = expf(m1v - mn1);
        l0v = l0v * al0 + rs0; l1v = l1v * al1 + rs1;
        m0v = mn0; m1v = mn1;
        #pragma unroll
        for (int f = 0; f < 16; f++) {
            oacc[f][0] *= al0; oacc[f][1] *= al0;
            oacc[f][2] *= al1; oacc[f][3] *= al1;
        }
        __syncwarp();

        #pragma unroll
        for (int ks = 0; ks < 4; ks++) {
            uint32_t a[4];
            ldsm_x4(a, sb + OFF_PS + ps_off + ks * 32);
            #pragma unroll
            for (int g = 0; g < 8; g++) {
                uint32_t b[4];
                ldsm_x4t(b, sb + OFF_VS + (ks * 16 + (mi & 1) * 8 + l7) * AROW
                               + (g * 16 + (mi >> 1) * 8) * 2);
                mma_fp(oacc[2*g+0], a, b[0], b[1]);
                mma_fp(oacc[2*g+1], a, b[2], b[3]);
            }
        }
    }

    const float i0 = 1.f / l0v, i1 = 1.f / l1v;
    #pragma unroll
    for (int f = 0; f < 16; f++) {
        int col = h * HD_DIM + f * 8 + (lane & 3) * 2;
        __half2 hh0 = __floats2half2_rn(oacc[f][0] * i0, oacc[f][1] * i0);
        __half2 hh1 = __floats2half2_rn(oacc[f][2] * i1, oacc[f][3] * i1);
        *(__half2*)&Oh[(size_t)gq0 * H_DIM + col] = hh0;
        *(__half2*)&Oh[(size_t)gq1 * H_DIM + col] = hh1;
    }
}

// ===================== elementwise / conversion kernels =====================
__global__ void rmsnorm_f16_kernel(const float* __restrict__ x,
                                   const float* __restrict__ scale,
                                   h16* __restrict__ oh, h16* __restrict__ ol)
{
    int row = blockIdx.x;
    const float4* xr = (const float4*)(x + (size_t)row * H_DIM);
    float ss = 0.f;
    for (int i = threadIdx.x; i < H_DIM / 4; i += blockDim.x) {
        float4 v = xr[i];
        ss += v.x * v.x + v.y * v.y + v.z * v.z + v.w * v.w;
    }
    #pragma unroll
    for (int off = 16; off; off >>= 1) ss += __shfl_xor_sync(0xffffffffu, ss, off);
    __shared__ float red[32];
    int lane = threadIdx.x & 31, wid = threadIdx.x >> 5;
    if (lane == 0) red[wid] = ss;
    __syncthreads();
    if (wid == 0) {
        ss = (lane < (int)(blockDim.x >> 5)) ? red[lane] : 0.f;
        #pragma unroll
        for (int off = 16; off; off >>= 1) ss += __shfl_xor_sync(0xffffffffu, ss, off);
        if (lane == 0) red[0] = ss;
    }
    __syncthreads();
    float inv = rsqrtf(red[0] / (float)H_DIM + EPS_V);
    const float4* sc = (const float4*)scale;
    for (int i = threadIdx.x; i < H_DIM / 4; i += blockDim.x) {
        float4 v = xr[i], s = sc[i];
        float f[4] = {v.x * inv * s.x, v.y * inv * s.y, v.z * inv * s.z, v.w * inv * s.w};
        size_t base = (size_t)row * H_DIM + i * 4;
        #pragma unroll
        for (int c = 0; c < 4; c++) {
            if (ol) {
                h16 h, l; split_fp(f[c], h, l);
                oh[base + c] = h; ol[base + c] = l;
            } else {
                oh[base + c] = __float2half_rn(f[c]);
            }
        }
    }
}

// W[K][N] fp32 -> Th[N][K] fp16
__global__ void transpose_f16_kernel(const float* __restrict__ W, int K, int N,
                                     h16* __restrict__ Th)
{
    __shared__ float t[32][33];
    int n0 = blockIdx.x * 32, k0 = blockIdx.y * 32;
    int tx = threadIdx.x, ty = threadIdx.y;
    #pragma unroll
    for (int i = ty; i < 32; i += 8)
        t[i][tx] = W[(size_t)(k0 + i) * N + n0 + tx];
    __syncthreads();
    #pragma unroll
    for (int i = ty; i < 32; i += 8)
        Th[(size_t)(n0 + i) * K + k0 + tx] = __float2half_rn(t[tx][i]);
}

// ===================== RoPE + split (q,k fp32 -> bf16 hi/lo) =================
__global__ void rope_split_kernel(const float* __restrict__ q,
                                  const float* __restrict__ k,
                                  const int* __restrict__ pos,
                                  bf16* __restrict__ qh, bf16* __restrict__ ql,
                                  bf16* __restrict__ kh, bf16* __restrict__ kl)
{
    int idx = blockIdx.x * blockDim.x + threadIdx.x;
    if (idx >= T_DIM * NHEADS * (HD_DIM / 2)) return;
    int d  = idx & 63;
    int th = idx >> 6;
    int t  = th >> 5;
    float invf = powf(10000.0f, -(float)d * (1.0f / 64.0f));
    float ang = (float)pos[t] * invf;
    float c, s;
    sincosf(ang, &s, &c);
    size_t base = (size_t)th * HD_DIM + d;
    float q1 = q[base], q2 = q[base + 64];
    float rq1 = q1 * c - q2 * s;
    float rq2 = q2 * c + q1 * s;
    float k1 = k[base], k2 = k[base + 64];
    float rk1 = k1 * c - k2 * s;
    float rk2 = k2 * c + k1 * s;
    bf16 h, l;
    split_bf(rq1, h, l); qh[base] = h;       ql[base] = l;
    split_bf(rq2, h, l); qh[base + 64] = h;  ql[base + 64] = l;
    split_bf(rk1, h, l); kh[base] = h;       kl[base] = l;
    split_bf(rk2, h, l); kh[base + 64] = h;  kl[base + 64] = l;
}

// ===================== launch ================================================
extern "C" void kernel_launch(void* const* d_in, const int* in_sizes, int n_in,
                              void* d_out, int out_size)
{
    (void)in_sizes; (void)n_in; (void)out_size;
    const int*   positions = (const int*)  d_in[0];
    const float* hidden    = (const float*)d_in[1];
    const float* ln1       = (const float*)d_in[2];
    const float* wq = (const float*)d_in[3];
    const float* bq = (const float*)d_in[4];
    const float* wk = (const float*)d_in[5];
    const float* bk = (const float*)d_in[6];
    const float* wv = (const float*)d_in[7];
    const float* bv = (const float*)d_in[8];
    const float* wo = (const float*)d_in[9];
    const float* ln2= (const float*)d_in[10];
    const float* w1 = (const float*)d_in[11];
    const float* w2 = (const float*)d_in[12];
    const float* wc = (const float*)d_in[13];
    float* out = (float*)d_out;

    float *q, *k, *hbuf, *a2;
    h16 *xnh, *xnl, *atth, *yh, *gh, *vhb;
    bf16 *qhb, *qlb, *khb, *klb;
    h16 *wqh, *wkh, *wvh, *woh, *w1h, *w2h, *wch;
    cudaGetSymbolAddress((void**)&q,    g_q);
    cudaGetSymbolAddress((void**)&k,    g_k);
    cudaGetSymbolAddress((void**)&hbuf, g_h);
    cudaGetSymbolAddress((void**)&a2,   g_a2);
    cudaGetSymbolAddress((void**)&xnh,  g_xnh);
    cudaGetSymbolAddress((void**)&xnl,  g_xnl);
    cudaGetSymbolAddress((void**)&atth, g_atth);
    cudaGetSymbolAddress((void**)&yh,   g_yh);
    cudaGetSymbolAddress((void**)&gh,   g_gh);
    cudaGetSymbolAddress((void**)&qhb,  g_qhb);
    cudaGetSymbolAddress((void**)&qlb,  g_qlb);
    cudaGetSymbolAddress((void**)&khb,  g_khb);
    cudaGetSymbolAddress((void**)&klb,  g_klb);
    cudaGetSymbolAddress((void**)&vhb,  g_vhb);
    cudaGetSymbolAddress((void**)&wqh,  g_wqh);
    cudaGetSymbolAddress((void**)&wkh,  g_wkh);
    cudaGetSymbolAddress((void**)&wvh,  g_wvh);
    cudaGetSymbolAddress((void**)&woh,  g_woh);
    cudaGetSymbolAddress((void**)&w1h,  g_w1h);
    cudaGetSymbolAddress((void**)&w2h,  g_w2h);
    cudaGetSymbolAddress((void**)&wch,  g_wch);

    const int SMEM_A = 3 * 3 * GTILE;   // 92160 (2-pass)
    const int SMEM_1 = 3 * 2 * GTILE;   // 61440 (1-pass)
    cudaFuncSetAttribute((gemm_f16<true,0>),  cudaFuncAttributeMaxDynamicSharedMemorySize, SMEM_A);
    cudaFuncSetAttribute((gemm_f16<false,0>), cudaFuncAttributeMaxDynamicSharedMemorySize, SMEM_1);
    cudaFuncSetAttribute((gemm_f16<false,1>), cudaFuncAttributeMaxDynamicSharedMemorySize, SMEM_1);
    cudaFuncSetAttribute((gemm_f16<false,2>), cudaFuncAttributeMaxDynamicSharedMemorySize, SMEM_1);
    cudaFuncSetAttribute(attn_mma_kernel, cudaFuncAttributeMaxDynamicSharedMemorySize, ATTN_SMEM);

    dim3 tb(32, 8);
    transpose_f16_kernel<<<dim3(H_DIM/32, H_DIM/32), tb>>>(wq, H_DIM, H_DIM, wqh);
    transpose_f16_kernel<<<dim3(H_DIM/32, H_DIM/32), tb>>>(wk, H_DIM, H_DIM, wkh);
    transpose_f16_kernel<<<dim3(H_DIM/32, H_DIM/32), tb>>>(wv, H_DIM, H_DIM, wvh);
    transpose_f16_kernel<<<dim3(H_DIM/32, H_DIM/32), tb>>>(wo, H_DIM, H_DIM, woh);
    transpose_f16_kernel<<<dim3(FF_DIM/32, H_DIM/32), tb>>>(w1, H_DIM, FF_DIM, w1h);
    transpose_f16_kernel<<<dim3(FF_DIM/32, H_DIM/32), tb>>>(w2, H_DIM, FF_DIM, w2h);
    transpose_f16_kernel<<<dim3(H_DIM/32, FF_DIM/32), tb>>>(wc, FF_DIM, H_DIM, wch);

    // 1) x = rmsnorm(hidden, ln1) -> fp16 hi/lo
    rmsnorm_f16_kernel<<<T_DIM, 256>>>(hidden, ln1, xnh, xnl);

    // 2) q,k (2-pass, fp32 out); v (1-pass, fp16 out direct)
    dim3 gH(H_DIM / BN, T_DIM / BM);
    gemm_f16<true,0><<<gH, 256, SMEM_A>>>(xnh, xnl, wqh, bq, nullptr, nullptr, q, H_DIM, H_DIM);
    gemm_f16<true,0><<<gH, 256, SMEM_A>>>(xnh, xnl, wkh, bk, nullptr, nullptr, k, H_DIM, H_DIM);
    gemm_f16<false,1><<<gH, 256, SMEM_1>>>(xnh, nullptr, wvh, bv, nullptr, nullptr, vhb, H_DIM, H_DIM);

    // 3) RoPE + split to attention operand buffers
    rope_split_kernel<<<(T_DIM * NHEADS * (HD_DIM / 2)) / 256, 256>>>(q, k, positions,
                                                                      qhb, qlb, khb, klb);

    // 4) attention -> atth (single fp16)
    attn_mma_kernel<<<dim3(T_DIM / 64, NHEADS), 128, ATTN_SMEM>>>(qhb, qlb, khb, klb, vhb, atth);

    // 5) h = hidden + attn @ wo
    gemm_f16<false,0><<<gH, 256, SMEM_1>>>(atth, nullptr, woh, nullptr, hidden, nullptr, hbuf, H_DIM, H_DIM);

    // 6) y = rmsnorm(h, ln2) -> single fp16
    rmsnorm_f16_kernel<<<T_DIM, 256>>>(hbuf, ln2, yh, nullptr);

    // 7) MLP: a2 = y@w2 (fp32); gh = (y@w1) * silu(a2) fused, fp16 out
    dim3 gF(FF_DIM / BN, T_DIM / BM);
    gemm_f16<false,0><<<gF, 256, SMEM_1>>>(yh, nullptr, w2h, nullptr, nullptr, nullptr, a2, FF_DIM, H_DIM);
    gemm_f16<false,2><<<gF, 256, SMEM_1>>>(yh, nullptr, w1h, nullptr, nullptr, a2, gh, FF_DIM, H_DIM);

    // 8) out = h + gh @ wc
    gemm_f16<false,0><<<gH, 256, SMEM_1>>>(gh, nullptr, wch, nullptr, hbuf, nullptr, out, H_DIM, FF_DIM);
}

// round 9
// speedup vs baseline: 6.6103x; 1.1616x over previous
#include <cuda_runtime.h>
#include <cuda_bf16.h>
#include <cuda_fp16.h>
#include <math.h>
#include <cstdint>

#define T_DIM 2048
#define H_DIM 4096
#define NHEADS 32
#define HD_DIM 128
#define FF_DIM 11008
#define EPS_V 1e-6f

typedef __nv_bfloat16 bf16;
typedef __half h16;

// ===================== device scratch ======================================
__device__ float g_q  [(size_t)T_DIM * H_DIM];
__device__ float g_k  [(size_t)T_DIM * H_DIM];
__device__ float g_h  [(size_t)T_DIM * H_DIM];
__device__ float g_a2 [(size_t)T_DIM * FF_DIM];

__device__ h16 g_xnh [(size_t)T_DIM * H_DIM];
__device__ h16 g_atth[(size_t)T_DIM * H_DIM];
__device__ h16 g_yh  [(size_t)T_DIM * H_DIM];
__device__ h16 g_gh  [(size_t)T_DIM * FF_DIM];

// attention operand buffers (pre-split / converted)
__device__ bf16 g_qhb[(size_t)T_DIM * H_DIM];
__device__ bf16 g_qlb[(size_t)T_DIM * H_DIM];
__device__ bf16 g_khb[(size_t)T_DIM * H_DIM];
__device__ bf16 g_klb[(size_t)T_DIM * H_DIM];
__device__ h16  g_vhb[(size_t)T_DIM * H_DIM];

// weights (single fp16, transposed [N][K])
__device__ h16 g_wqh[(size_t)H_DIM * H_DIM];
__device__ h16 g_wkh[(size_t)H_DIM * H_DIM];
__device__ h16 g_wvh[(size_t)H_DIM * H_DIM];
__device__ h16 g_woh[(size_t)H_DIM * H_DIM];
__device__ h16 g_w1h[(size_t)FF_DIM * H_DIM];
__device__ h16 g_w2h[(size_t)FF_DIM * H_DIM];
__device__ h16 g_wch[(size_t)H_DIM * FF_DIM];

// ===================== PTX helpers =========================================
__device__ __forceinline__ uint32_t smem_u32(const void* p) {
    uint32_t a;
    asm("{ .reg .u64 t; cvta.to.shared.u64 t, %1; cvt.u32.u64 %0, t; }"
        : "=r"(a) : "l"(p));
    return a;
}

#define CP_ASYNC16(dst, src) \
    asm volatile("cp.async.cg.shared.global [%0], [%1], 16;" :: "r"(dst), "l"(src))
#define CP_COMMIT() asm volatile("cp.async.commit_group;" ::: "memory")

__device__ __forceinline__ void ldsm_x4(uint32_t* r, uint32_t a) {
    asm volatile("ldmatrix.sync.aligned.m8n8.x4.shared.b16 {%0,%1,%2,%3}, [%4];"
        : "=r"(r[0]), "=r"(r[1]), "=r"(r[2]), "=r"(r[3]) : "r"(a));
}
__device__ __forceinline__ void ldsm_x4t(uint32_t* r, uint32_t a) {
    asm volatile("ldmatrix.sync.aligned.m8n8.x4.trans.shared.b16 {%0,%1,%2,%3}, [%4];"
        : "=r"(r[0]), "=r"(r[1]), "=r"(r[2]), "=r"(r[3]) : "r"(a));
}

__device__ __forceinline__ void mma_bf(float* d, const uint32_t* a,
                                       uint32_t b0, uint32_t b1) {
    asm volatile(
        "mma.sync.aligned.m16n8k16.row.col.f32.bf16.bf16.f32 "
        "{%0,%1,%2,%3}, {%4,%5,%6,%7}, {%8,%9}, {%0,%1,%2,%3};"
        : "+f"(d[0]), "+f"(d[1]), "+f"(d[2]), "+f"(d[3])
        : "r"(a[0]), "r"(a[1]), "r"(a[2]), "r"(a[3]), "r"(b0), "r"(b1));
}
__device__ __forceinline__ void mma_fp(float* d, const uint32_t* a,
                                       uint32_t b0, uint32_t b1) {
    asm volatile(
        "mma.sync.aligned.m16n8k16.row.col.f32.f16.f16.f32 "
        "{%0,%1,%2,%3}, {%4,%5,%6,%7}, {%8,%9}, {%0,%1,%2,%3};"
        : "+f"(d[0]), "+f"(d[1]), "+f"(d[2]), "+f"(d[3])
        : "r"(a[0]), "r"(a[1]), "r"(a[2]), "r"(a[3]), "r"(b0), "r"(b1));
}

__device__ __forceinline__ void split_bf(float v, bf16& h, bf16& l) {
    h = __float2bfloat16(v);
    l = __float2bfloat16(v - __bfloat162float(h));
}
__device__ __forceinline__ float silu_f(float g) {
    return g / (1.f + expf(-g));
}

// ===================== fp16 GEMM (single-pass) ===============================
// C[M,N] = A@B^T (+bias). EPI: 0 = fp32 out (+resid), 1 = fp16, 2 = fp16*silu(gate)
#define BM 128
#define BN 128
#define GROWB 80
#define GTILE (128 * GROWB)
#define GSMEM (3 * 2 * GTILE)

template<int EPI>
__global__ __launch_bounds__(256, 2)
void gemm_f16(const h16* __restrict__ Ah, const h16* __restrict__ Bh,
              const float* __restrict__ bias, const float* __restrict__ resid,
              const float* __restrict__ gate,
              void* __restrict__ Cv, int Ntot, int K)
{
    constexpr int STAGE_B = 2 * GTILE;
    extern __shared__ char dsm[];
    const int tid = threadIdx.x;
    const int wid = tid >> 5, lane = tid & 31;
    const int rowA0 = blockIdx.y * BM;
    const int colB0 = blockIdx.x * BN;
    const int nIter = K >> 5;
    const uint32_t sbase = smem_u32(dsm);

    auto load_stage = [&](int it) {
        const int s = it % 3;
        const size_t koff = (size_t)it * 32;
        const uint32_t st = sbase + s * STAGE_B;
        #pragma unroll
        for (int i = 0; i < 2; i++) {
            int idx = tid + i * 256;
            int r = idx >> 2, seg = idx & 3;
            uint32_t doff = r * GROWB + seg * 16;
            const size_t goff = koff + seg * 8;
            CP_ASYNC16(st + doff, Ah + (size_t)(rowA0 + r) * K + goff);
            CP_ASYNC16(st + GTILE + doff, Bh + (size_t)(colB0 + r) * K + goff);
        }
        CP_COMMIT();
    };

    const int m0 = (wid >> 1) * 32;
    const int n0 = (wid & 1) * 64;

    float acc[2][8][4];
    #pragma unroll
    for (int i = 0; i < 2; i++)
        #pragma unroll
        for (int j = 0; j < 8; j++)
            #pragma unroll
            for (int c = 0; c < 4; c++) acc[i][j][c] = 0.f;

    const int mi = lane >> 3, l7 = lane & 7;
    const uint32_t aoff = (uint32_t)((m0 + (mi & 1) * 8 + l7) * GROWB + (mi >> 1) * 16);
    const uint32_t boff = (uint32_t)((n0 + (mi >> 1) * 8 + l7) * GROWB + (mi & 1) * 16);

    load_stage(0); load_stage(1);

    for (int it = 0; it < nIter; it++) {
        if (it + 2 < nIter) load_stage(it + 2);
        else CP_COMMIT();
        asm volatile("cp.async.wait_group %0;" :: "n"(2));
        __syncthreads();

        const uint32_t st = sbase + (it % 3) * STAGE_B;

        #pragma unroll
        for (int kk = 0; kk < 2; kk++) {
            uint32_t ah0[4], ah1[4];
            ldsm_x4(ah0, st + aoff + kk * 32);
            ldsm_x4(ah1, st + aoff + 16 * GROWB + kk * 32);
            #pragma unroll
            for (int g = 0; g < 4; g++) {
                uint32_t bh[4];
                ldsm_x4(bh, st + GTILE + boff + g * 16 * GROWB + kk * 32);
                mma_fp(acc[0][2*g+0], ah0, bh[0], bh[1]);
                mma_fp(acc[0][2*g+1], ah0, bh[2], bh[3]);
                mma_fp(acc[1][2*g+0], ah1, bh[0], bh[1]);
                mma_fp(acc[1][2*g+1], ah1, bh[2], bh[3]);
            }
        }
        __syncthreads();
    }

    const int l4 = lane >> 2, l2 = (lane & 3) * 2;
    #pragma unroll
    for (int mf = 0; mf < 2; mf++) {
        const int r = rowA0 + m0 + mf * 16 + l4;
        #pragma unroll
        for (int nf = 0; nf < 8; nf++) {
            const int c = colB0 + n0 + nf * 8 + l2;
            float2 v0 = make_float2(acc[mf][nf][0], acc[mf][nf][1]);
            float2 v1 = make_float2(acc[mf][nf][2], acc[mf][nf][3]);
            if (bias) {
                v0.x += bias[c]; v0.y += bias[c + 1];
                v1.x += bias[c]; v1.y += bias[c + 1];
            }
            if (EPI == 0) {
                if (resid) {
                    const float2 r0 = *(const float2*)&resid[(size_t)r * Ntot + c];
                    const float2 r1 = *(const float2*)&resid[(size_t)(r + 8) * Ntot + c];
                    v0.x += r0.x; v0.y += r0.y;
                    v1.x += r1.x; v1.y += r1.y;
                }
                float* C = (float*)Cv;
                *(float2*)&C[(size_t)r * Ntot + c] = v0;
                *(float2*)&C[(size_t)(r + 8) * Ntot + c] = v1;
            } else {
                if (EPI == 2) {
                    const float2 g0 = *(const float2*)&gate[(size_t)r * Ntot + c];
                    const float2 g1 = *(const float2*)&gate[(size_t)(r + 8) * Ntot + c];
                    v0.x *= silu_f(g0.x); v0.y *= silu_f(g0.y);
                    v1.x *= silu_f(g1.x); v1.y *= silu_f(g1.y);
                }
                h16* C = (h16*)Cv;
                *(__half2*)&C[(size_t)r * Ntot + c] = __floats2half2_rn(v0.x, v0.y);
                *(__half2*)&C[(size_t)(r + 8) * Ntot + c] = __floats2half2_rn(v1.x, v1.y);
            }
        }
    }
}

// ===================== tensor-core flash attention ===========================
#define AROW 272
#define PSROW 144
#define OFF_QH 0
#define OFF_QL (OFF_QH + 64 * AROW)
#define OFF_KH (OFF_QL + 64 * AROW)
#define OFF_KL (OFF_KH + 64 * AROW)
#define OFF_VS (OFF_KL + 64 * AROW)
#define OFF_PS (OFF_VS + 64 * AROW)
#define ATTN_SMEM (OFF_PS + 64 * PSROW)

__global__ __launch_bounds__(128, 2)
void attn_mma_kernel(const bf16* __restrict__ Qh, const bf16* __restrict__ Ql,
                     const bf16* __restrict__ Kh, const bf16* __restrict__ Kl,
                     const h16* __restrict__ Vh, h16* __restrict__ Oh)
{
    extern __shared__ char asm_[];
    const uint32_t sb = smem_u32(asm_);
    const int q0 = blockIdx.x * 64;
    const int h  = blockIdx.y;
    const int tid = threadIdx.x;
    const int w = tid >> 5, lane = tid & 31;
    const int mi = lane >> 3, l7 = lane & 7;
    const size_t hoff = (size_t)h * HD_DIM;

    #pragma unroll
    for (int i = 0; i < 8; i++) {
        int idx = tid + i * 128;
        int r = idx >> 4, c = idx & 15;
        uint32_t dst = sb + OFF_QH + r * AROW + c * 16;
        const size_t gsrc = (size_t)(q0 + r) * H_DIM + hoff + c * 8;
        CP_ASYNC16(dst, Qh + gsrc);
        CP_ASYNC16(dst + (OFF_QL - OFF_QH), Ql + gsrc);
    }
    CP_COMMIT();

    float oacc[16][4];
    #pragma unroll
    for (int f = 0; f < 16; f++)
        #pragma unroll
        for (int c = 0; c < 4; c++) oacc[f][c] = 0.f;
    float m0v = -1e30f, m1v = -1e30f, l0v = 0.f, l1v = 0.f;
    const float scaling = 0.08838834764831845f;

    const uint32_t aq_off = (uint32_t)((w * 16 + (mi & 1) * 8 + l7) * AROW + (mi >> 1) * 16);
    const uint32_t bk_off = (uint32_t)(((mi >> 1) * 8 + l7) * AROW + (mi & 1) * 16);
    const uint32_t ps_off = (uint32_t)((w * 16 + (mi & 1) * 8 + l7) * PSROW + (mi >> 1) * 16);

    const int r0 = lane >> 2;
    const int gq0 = q0 + w * 16 + r0;
    const int gq1 = gq0 + 8;

    for (int j0 = 0; j0 <= q0; j0 += 64) {
        __syncthreads();
        #pragma unroll
        for (int i = 0; i < 8; i++) {
            int idx = tid + i * 128;
            int r = idx >> 4, c = idx & 15;
            uint32_t doff = r * AROW + c * 16;
            const size_t gsrc = (size_t)(j0 + r) * H_DIM + hoff + c * 8;
            CP_ASYNC16(sb + OFF_KH + doff, Kh + gsrc);
            CP_ASYNC16(sb + OFF_KL + doff, Kl + gsrc);
            CP_ASYNC16(sb + OFF_VS + doff, Vh + gsrc);
        }
        CP_COMMIT();
        asm volatile("cp.async.wait_group 0;" ::: "memory");
        __syncthreads();

        float sacc[8][4];
        #pragma unroll
        for (int f = 0; f < 8; f++)
            #pragma unroll
            for (int c = 0; c < 4; c++) sacc[f][c] = 0.f;

        #pragma unroll
        for (int pass = 0; pass < 3; pass++) {
            const uint32_t sa = sb + ((pass < 2) ? OFF_QH : OFF_QL);
            const uint32_t skb = sb + ((pass == 1) ? OFF_KL : OFF_KH);
            #pragma unroll
            for (int ks = 0; ks < 8; ks++) {
                uint32_t a[4];
                ldsm_x4(a, sa + aq_off + ks * 32);
                #pragma unroll
                for (int g = 0; g < 4; g++) {
                    uint32_t b[4];
                    ldsm_x4(b, skb + bk_off + g * 16 * AROW + ks * 32);
                    mma_bf(sacc[2*g+0], a, b[0], b[1]);
                    mma_bf(sacc[2*g+1], a, b[2], b[3]);
                }
            }
        }

        const bool diag = (j0 == q0);
        #pragma unroll
        for (int f = 0; f < 8; f++) {
            int kvc = j0 + f * 8 + (lane & 3) * 2;
            #pragma unroll
            for (int c = 0; c < 4; c++) sacc[f][c] *= scaling;
            if (diag) {
                if (kvc     > gq0) sacc[f][0] = -1e30f;
                if (kvc + 1 > gq0) sacc[f][1] = -1e30f;
                if (kvc     > gq1) sacc[f][2] = -1e30f;
                if (kvc + 1 > gq1) sacc[f][3] = -1e30f;
            }
        }

        float mx0 = -1e30f, mx1 = -1e30f;
        #pragma unroll
        for (int f = 0; f < 8; f++) {
            mx0 = fmaxf(mx0, fmaxf(sacc[f][0], sacc[f][1]));
            mx1 = fmaxf(mx1, fmaxf(sacc[f][2], sacc[f][3]));
        }
        mx0 = fmaxf(mx0, __shfl_xor_sync(0xffffffffu, mx0, 1));
        mx0 = fmaxf(mx0, __shfl_xor_sync(0xffffffffu, mx0, 2));
        mx1 = fmaxf(mx1, __shfl_xor_sync(0xffffffffu, mx1, 1));
        mx1 = fmaxf(mx1, __shfl_xor_sync(0xffffffffu, mx1, 2));
        const float mn0 = fmaxf(m0v, mx0), mn1 = fmaxf(m1v, mx1);
        float rs0 = 0.f, rs1 = 0.f;
        #pragma unroll
        for (int f = 0; f < 8; f++) {
            float p0 = expf(sacc[f][0] - mn0);
            float p1 = expf(sacc[f][1] - mn0);
            float p2 = expf(sacc[f][2] - mn1);
            float p3 = expf(sacc[f][3] - mn1);
            rs0 += p0 + p1; rs1 += p2 + p3;
            __half2 v01 = __floats2half2_rn(p0, p1);
            __half2 v23 = __floats2half2_rn(p2, p3);
            uint32_t col = (f * 8 + (lane & 3) * 2) * 2;
            *(uint32_t*)(asm_ + OFF_PS + (w * 16 + r0) * PSROW + col) = *(uint32_t*)&v01;
            *(uint32_t*)(asm_ + OFF_PS + (w * 16 + r0 + 8) * PSROW + col) = *(uint32_t*)&v23;
        }
        rs0 += __shfl_xor_sync(0xffffffffu, rs0, 1);
        rs0 += __shfl_xor_sync(0xffffffffu, rs0, 2);
        rs1 += __shfl_xor_sync(0xffffffffu, rs1, 1);
        rs1 += __shfl_xor_sync(0xffffffffu, rs1, 2);
        const float al0 = expf(m0v - mn0), al1 = expf(m1v - mn1);
        l0v = l0v * al0 + rs0; l1v = l1v * al1 + rs1;
        m0v = mn0; m1v = mn1;
        #pragma unroll
        for (int f = 0; f < 16; f++) {
            oacc[f][0] *= al0; oacc[f][1] *= al0;
            oacc[f][2] *= al1; oacc[f][3] *= al1;
        }
        __syncwarp();

        #pragma unroll
        for (int ks = 0; ks < 4; ks++) {
            uint32_t a[4];
            ldsm_x4(a, sb + OFF_PS + ps_off + ks * 32);
            #pragma unroll
            for (int g = 0; g < 8; g++) {
                uint32_t b[4];
                ldsm_x4t(b, sb + OFF_VS + (ks * 16 + (mi & 1) * 8 + l7) * AROW
                               + (g * 16 + (mi >> 1) * 8) * 2);
                mma_fp(oacc[2*g+0], a, b[0], b[1]);
                mma_fp(oacc[2*g+1], a, b[2], b[3]);
            }
        }
    }

    const float i0 = 1.f / l0v, i1 = 1.f / l1v;
    #pragma unroll
    for (int f = 0; f < 16; f++) {
        int col = h * HD_DIM + f * 8 + (lane & 3) * 2;
        __half2 hh0 = __floats2half2_rn(oacc[f][0] * i0, oacc[f][1] * i0);
        __half2 hh1 = __floats2half2_rn(oacc[f][2] * i1, oacc[f][3] * i1);
        *(__half2*)&Oh[(size_t)gq0 * H_DIM + col] = hh0;
        *(__half2*)&Oh[(size_t)gq1 * H_DIM + col] = hh1;
    }
}

// ===================== elementwise / conversion kernels =====================
__global__ void rmsnorm_f16_kernel(const float* __restrict__ x,
                                   const float* __restrict__ scale,
                                   h16* __restrict__ oh)
{
    int row = blockIdx.x;
    const float4* xr = (const float4*)(x + (size_t)row * H_DIM);
    float ss = 0.f;
    for (int i = threadIdx.x; i < H_DIM / 4; i += blockDim.x) {
        float4 v = xr[i];
        ss += v.x * v.x + v.y * v.y + v.z * v.z + v.w * v.w;
    }
    #pragma unroll
    for (int off = 16; off; off >>= 1) ss += __shfl_xor_sync(0xffffffffu, ss, off);
    __shared__ float red[32];
    int lane = threadIdx.x & 31, wid = threadIdx.x >> 5;
    if (lane == 0) red[wid] = ss;
    __syncthreads();
    if (wid == 0) {
        ss = (lane < (int)(blockDim.x >> 5)) ? red[lane] : 0.f;
        #pragma unroll
        for (int off = 16; off; off >>= 1) ss += __shfl_xor_sync(0xffffffffu, ss, off);
        if (lane == 0) red[0] = ss;
    }
    __syncthreads();
    float inv = rsqrtf(red[0] / (float)H_DIM + EPS_V);
    const float4* sc = (const float4*)scale;
    for (int i = threadIdx.x; i < H_DIM / 4; i += blockDim.x) {
        float4 v = xr[i], s = sc[i];
        __half2 lo = __floats2half2_rn(v.x * inv * s.x, v.y * inv * s.y);
        __half2 hi = __floats2half2_rn(v.z * inv * s.z, v.w * inv * s.w);
        uint2 pack = {*(uint32_t*)&lo, *(uint32_t*)&hi};
        ((uint2*)(oh + (size_t)row * H_DIM))[i] = pack;
    }
}

// W[K][N] fp32 -> Th[N][K] fp16. Tile 64K x 32N, coalesced half2 stores.
__global__ void transpose_f16_kernel(const float* __restrict__ W, int K, int N,
                                     h16* __restrict__ Th)
{
    __shared__ float t[64][33];
    const int n0 = blockIdx.x * 32, k0 = blockIdx.y * 64;
    const int lane = threadIdx.x & 31;
    const int w = threadIdx.x >> 5;          // 0..7
    #pragma unroll
    for (int i = 0; i < 8; i++) {
        int kk = w + i * 8;
        t[kk][lane] = W[(size_t)(k0 + kk) * N + n0 + lane];
    }
    __syncthreads();
    #pragma unroll
    for (int j = 0; j < 4; j++) {
        int n = w * 4 + j;
        __half2 v = __floats2half2_rn(t[2 * lane][n], t[2 * lane + 1][n]);
        *(__half2*)&Th[(size_t)(n0 + n) * K + k0 + 2 * lane] = v;
    }
}

// ===================== RoPE + split (q,k fp32 -> bf16 hi/lo) =================
__global__ void rope_split_kernel(const float* __restrict__ q,
                                  const float* __restrict__ k,
                                  const int* __restrict__ pos,
                                  bf16* __restrict__ qh, bf16* __restrict__ ql,
                                  bf16* __restrict__ kh, bf16* __restrict__ kl)
{
    int idx = blockIdx.x * blockDim.x + threadIdx.x;
    if (idx >= T_DIM * NHEADS * (HD_DIM / 2)) return;
    int d  = idx & 63;
    int th = idx >> 6;
    int t  = th >> 5;
    float invf = powf(10000.0f, -(float)d * (1.0f / 64.0f));
    float ang = (float)pos[t] * invf;
    float c, s;
    sincosf(ang, &s, &c);
    size_t base = (size_t)th * HD_DIM + d;
    float q1 = q[base], q2 = q[base + 64];
    float rq1 = q1 * c - q2 * s;
    float rq2 = q2 * c + q1 * s;
    float k1 = k[base], k2 = k[base + 64];
    float rk1 = k1 * c - k2 * s;
    float rk2 = k2 * c + k1 * s;
    bf16 h, l;
    split_bf(rq1, h, l); qh[base] = h;       ql[base] = l;
    split_bf(rq2, h, l); qh[base + 64] = h;  ql[base + 64] = l;
    split_bf(rk1, h, l); kh[base] = h;       kl[base] = l;
    split_bf(rk2, h, l); kh[base + 64] = h;  kl[base + 64] = l;
}

// ===================== launch ================================================
extern "C" void kernel_launch(void* const* d_in, const int* in_sizes, int n_in,
                              void* d_out, int out_size)
{
    (void)in_sizes; (void)n_in; (void)out_size;
    const int*   positions = (const int*)  d_in[0];
    const float* hidden    = (const float*)d_in[1];
    const float* ln1       = (const float*)d_in[2];
    const float* wq = (const float*)d_in[3];
    const float* bq = (const float*)d_in[4];
    const float* wk = (const float*)d_in[5];
    const float* bk = (const float*)d_in[6];
    const float* wv = (const float*)d_in[7];
    const float* bv = (const float*)d_in[8];
    const float* wo = (const float*)d_in[9];
    const float* ln2= (const float*)d_in[10];
    const float* w1 = (const float*)d_in[11];
    const float* w2 = (const float*)d_in[12];
    const float* wc = (const float*)d_in[13];
    float* out = (float*)d_out;

    float *q, *k, *hbuf, *a2;
    h16 *xnh, *atth, *yh, *gh, *vhb;
    bf16 *qhb, *qlb, *khb, *klb;
    h16 *wqh, *wkh, *wvh, *woh, *w1h, *w2h, *wch;
    cudaGetSymbolAddress((void**)&q,    g_q);
    cudaGetSymbolAddress((void**)&k,    g_k);
    cudaGetSymbolAddress((void**)&hbuf, g_h);
    cudaGetSymbolAddress((void**)&a2,   g_a2);
    cudaGetSymbolAddress((void**)&xnh,  g_xnh);
    cudaGetSymbolAddress((void**)&atth, g_atth);
    cudaGetSymbolAddress((void**)&yh,   g_yh);
    cudaGetSymbolAddress((void**)&gh,   g_gh);
    cudaGetSymbolAddress((void**)&qhb,  g_qhb);
    cudaGetSymbolAddress((void**)&qlb,  g_qlb);
    cudaGetSymbolAddress((void**)&khb,  g_khb);
    cudaGetSymbolAddress((void**)&klb,  g_klb);
    cudaGetSymbolAddress((void**)&vhb,  g_vhb);
    cudaGetSymbolAddress((void**)&wqh,  g_wqh);
    cudaGetSymbolAddress((void**)&wkh,  g_wkh);
    cudaGetSymbolAddress((void**)&wvh,  g_wvh);
    cudaGetSymbolAddress((void**)&woh,  g_woh);
    cudaGetSymbolAddress((void**)&w1h,  g_w1h);
    cudaGetSymbolAddress((void**)&w2h,  g_w2h);
    cudaGetSymbolAddress((void**)&wch,  g_wch);

    cudaFuncSetAttribute((gemm_f16<0>), cudaFuncAttributeMaxDynamicSharedMemorySize, GSMEM);
    cudaFuncSetAttribute((gemm_f16<1>), cudaFuncAttributeMaxDynamicSharedMemorySize, GSMEM);
    cudaFuncSetAttribute((gemm_f16<2>), cudaFuncAttributeMaxDynamicSharedMemorySize, GSMEM);
    cudaFuncSetAttribute(attn_mma_kernel, cudaFuncAttributeMaxDynamicSharedMemorySize, ATTN_SMEM);

    // weight transposes (fp32 [K,N] -> fp16 [N,K])
    transpose_f16_kernel<<<dim3(H_DIM/32, H_DIM/64), 256>>>(wq, H_DIM, H_DIM, wqh);
    transpose_f16_kernel<<<dim3(H_DIM/32, H_DIM/64), 256>>>(wk, H_DIM, H_DIM, wkh);
    transpose_f16_kernel<<<dim3(H_DIM/32, H_DIM/64), 256>>>(wv, H_DIM, H_DIM, wvh);
    transpose_f16_kernel<<<dim3(H_DIM/32, H_DIM/64), 256>>>(wo, H_DIM, H_DIM, woh);
    transpose_f16_kernel<<<dim3(FF_DIM/32, H_DIM/64), 256>>>(w1, H_DIM, FF_DIM, w1h);
    transpose_f16_kernel<<<dim3(FF_DIM/32, H_DIM/64), 256>>>(w2, H_DIM, FF_DIM, w2h);
    transpose_f16_kernel<<<dim3(H_DIM/32, FF_DIM/64), 256>>>(wc, FF_DIM, H_DIM, wch);

    // 1) x = rmsnorm(hidden, ln1) -> single fp16
    rmsnorm_f16_kernel<<<T_DIM, 256>>>(hidden, ln1, xnh);

    // 2) q,k (1-pass, fp32 out); v (1-pass, fp16 out)
    dim3 gH(H_DIM / BN, T_DIM / BM);
    gemm_f16<0><<<gH, 256, GSMEM>>>(xnh, wqh, bq, nullptr, nullptr, q, H_DIM, H_DIM);
    gemm_f16<0><<<gH, 256, GSMEM>>>(xnh, wkh, bk, nullptr, nullptr, k, H_DIM, H_DIM);
    gemm_f16<1><<<gH, 256, GSMEM>>>(xnh, wvh, bv, nullptr, nullptr, vhb, H_DIM, H_DIM);

    // 3) RoPE + split to attention operand buffers
    rope_split_kernel<<<(T_DIM * NHEADS * (HD_DIM / 2)) / 256, 256>>>(q, k, positions,
                                                                      qhb, qlb, khb, klb);

    // 4) attention -> atth (single fp16)
    attn_mma_kernel<<<dim3(T_DIM / 64, NHEADS), 128, ATTN_SMEM>>>(qhb, qlb, khb, klb, vhb, atth);

    // 5) h = hidden + attn @ wo
    gemm_f16<0><<<gH, 256, GSMEM>>>(atth, woh, nullptr, hidden, nullptr, hbuf, H_DIM, H_DIM);

    // 6) y = rmsnorm(h, ln2) -> single fp16
    rmsnorm_f16_kernel<<<T_DIM, 256>>>(hbuf, ln2, yh);

    // 7) MLP: a2 = y@w2 (fp32); gh = (y@w1) * silu(a2) fused, fp16 out
    dim3 gF(FF_DIM / BN, T_DIM / BM);
    gemm_f16<0><<<gF, 256, GSMEM>>>(yh, w2h, nullptr, nullptr, nullptr, a2, FF_DIM, H_DIM);
    gemm_f16<2><<<gF, 256, GSMEM>>>(yh, w1h, nullptr, nullptr, a2, gh, FF_DIM, H_DIM);

    // 8) out = h + gh @ wc
    gemm_f16<0><<<gH, 256, GSMEM>>>(gh, wch, nullptr, hbuf, nullptr, out, H_DIM, FF_DIM);
}

// round 11
// speedup vs baseline: 6.8161x; 1.0311x over previous
#include <cuda_runtime.h>
#include <cuda_bf16.h>
#include <cuda_fp16.h>
#include <math.h>
#include <cstdint>

#define T_DIM 2048
#define H_DIM 4096
#define NHEADS 32
#define HD_DIM 128
#define FF_DIM 11008
#define EPS_V 1e-6f

typedef __nv_bfloat16 bf16;
typedef __half h16;

// ===================== device scratch ======================================
__device__ float g_q  [(size_t)T_DIM * H_DIM];
__device__ float g_k  [(size_t)T_DIM * H_DIM];
__device__ float g_h  [(size_t)T_DIM * H_DIM];
__device__ float g_a2 [(size_t)T_DIM * FF_DIM];

__device__ h16 g_xnh [(size_t)T_DIM * H_DIM];
__device__ h16 g_atth[(size_t)T_DIM * H_DIM];
__device__ h16 g_yh  [(size_t)T_DIM * H_DIM];
__device__ h16 g_gh  [(size_t)T_DIM * FF_DIM];

// attention operand buffers (pre-split / converted; q pre-scaled)
__device__ bf16 g_qhb[(size_t)T_DIM * H_DIM];
__device__ bf16 g_qlb[(size_t)T_DIM * H_DIM];
__device__ bf16 g_khb[(size_t)T_DIM * H_DIM];
__device__ bf16 g_klb[(size_t)T_DIM * H_DIM];
__device__ h16  g_vhb[(size_t)T_DIM * H_DIM];

// weights (single fp16, transposed [N][K])
__device__ h16 g_wqh[(size_t)H_DIM * H_DIM];
__device__ h16 g_wkh[(size_t)H_DIM * H_DIM];
__device__ h16 g_wvh[(size_t)H_DIM * H_DIM];
__device__ h16 g_woh[(size_t)H_DIM * H_DIM];
__device__ h16 g_w1h[(size_t)FF_DIM * H_DIM];
__device__ h16 g_w2h[(size_t)FF_DIM * H_DIM];
__device__ h16 g_wch[(size_t)H_DIM * FF_DIM];

// ===================== PTX helpers =========================================
__device__ __forceinline__ uint32_t smem_u32(const void* p) {
    uint32_t a;
    asm("{ .reg .u64 t; cvta.to.shared.u64 t, %1; cvt.u32.u64 %0, t; }"
        : "=r"(a) : "l"(p));
    return a;
}

#define CP_ASYNC16(dst, src) \
    asm volatile("cp.async.cg.shared.global [%0], [%1], 16;" :: "r"(dst), "l"(src))
#define CP_COMMIT() asm volatile("cp.async.commit_group;" ::: "memory")
#define CP_WAIT(n)  asm volatile("cp.async.wait_group %0;" :: "n"(n) : "memory")

__device__ __forceinline__ void ldsm_x4(uint32_t* r, uint32_t a) {
    asm volatile("ldmatrix.sync.aligned.m8n8.x4.shared.b16 {%0,%1,%2,%3}, [%4];"
        : "=r"(r[0]), "=r"(r[1]), "=r"(r[2]), "=r"(r[3]) : "r"(a));
}
__device__ __forceinline__ void ldsm_x4t(uint32_t* r, uint32_t a) {
    asm volatile("ldmatrix.sync.aligned.m8n8.x4.trans.shared.b16 {%0,%1,%2,%3}, [%4];"
        : "=r"(r[0]), "=r"(r[1]), "=r"(r[2]), "=r"(r[3]) : "r"(a));
}

__device__ __forceinline__ void mma_bf(float* d, const uint32_t* a,
                                       uint32_t b0, uint32_t b1) {
    asm volatile(
        "mma.sync.aligned.m16n8k16.row.col.f32.bf16.bf16.f32 "
        "{%0,%1,%2,%3}, {%4,%5,%6,%7}, {%8,%9}, {%0,%1,%2,%3};"
        : "+f"(d[0]), "+f"(d[1]), "+f"(d[2]), "+f"(d[3])
        : "r"(a[0]), "r"(a[1]), "r"(a[2]), "r"(a[3]), "r"(b0), "r"(b1));
}
__device__ __forceinline__ void mma_fp(float* d, const uint32_t* a,
                                       uint32_t b0, uint32_t b1) {
    asm volatile(
        "mma.sync.aligned.m16n8k16.row.col.f32.f16.f16.f32 "
        "{%0,%1,%2,%3}, {%4,%5,%6,%7}, {%8,%9}, {%0,%1,%2,%3};"
        : "+f"(d[0]), "+f"(d[1]), "+f"(d[2]), "+f"(d[3])
        : "r"(a[0]), "r"(a[1]), "r"(a[2]), "r"(a[3]), "r"(b0), "r"(b1));
}

__device__ __forceinline__ void split_bf(float v, bf16& h, bf16& l) {
    h = __float2bfloat16(v);
    l = __float2bfloat16(v - __bfloat162float(h));
}
__device__ __forceinline__ float silu_f(float g) {
    return g / (1.f + expf(-g));
}

// ===================== fp16 GEMM (single-pass, 4-stage, paired iters) ========
// C[M,N] = A@B^T (+bias). EPI: 0 = fp32 out (+resid), 1 = fp16, 2 = fp16*silu(gate)
#define BM 128
#define BN 128
#define GROWB 80
#define GTILE (128 * GROWB)
#define GSMEM (4 * 2 * GTILE)      // 81920

template<int EPI>
__global__ __launch_bounds__(256, 2)
void gemm_f16(const h16* __restrict__ Ah, const h16* __restrict__ Bh,
              const float* __restrict__ bias, const float* __restrict__ resid,
              const float* __restrict__ gate,
              void* __restrict__ Cv, int Ntot, int K)
{
    constexpr int STAGE_B = 2 * GTILE;
    extern __shared__ char dsm[];
    const int tid = threadIdx.x;
    const int wid = tid >> 5, lane = tid & 31;
    const int rowA0 = blockIdx.y * BM;
    const int colB0 = blockIdx.x * BN;
    const int nIter = K >> 5;           // always even (128 or 344)
    const uint32_t sbase = smem_u32(dsm);

    auto load_stage = [&](int it) {
        const int s = it & 3;
        const size_t koff = (size_t)it * 32;
        const uint32_t st = sbase + s * STAGE_B;
        #pragma unroll
        for (int i = 0; i < 2; i++) {
            int idx = tid + i * 256;
            int r = idx >> 2, seg = idx & 3;
            uint32_t doff = r * GROWB + seg * 16;
            const size_t goff = koff + seg * 8;
            CP_ASYNC16(st + doff, Ah + (size_t)(rowA0 + r) * K + goff);
            CP_ASYNC16(st + GTILE + doff, Bh + (size_t)(colB0 + r) * K + goff);
        }
        CP_COMMIT();
    };

    const int m0 = (wid >> 1) * 32;
    const int n0 = (wid & 1) * 64;

    float acc[2][8][4];
    #pragma unroll
    for (int i = 0; i < 2; i++)
        #pragma unroll
        for (int j = 0; j < 8; j++)
            #pragma unroll
            for (int c = 0; c < 4; c++) acc[i][j][c] = 0.f;

    const int mi = lane >> 3, l7 = lane & 7;
    const uint32_t aoff = (uint32_t)((m0 + (mi & 1) * 8 + l7) * GROWB + (mi >> 1) * 16);
    const uint32_t boff = (uint32_t)((n0 + (mi >> 1) * 8 + l7) * GROWB + (mi & 1) * 16);

    auto compute = [&](int it) {
        const uint32_t st = sbase + (it & 3) * STAGE_B;
        #pragma unroll
        for (int kk = 0; kk < 2; kk++) {
            uint32_t ah0[4], ah1[4];
            ldsm_x4(ah0, st + aoff + kk * 32);
            ldsm_x4(ah1, st + aoff + 16 * GROWB + kk * 32);
            #pragma unroll
            for (int g = 0; g < 4; g++) {
                uint32_t bh[4];
                ldsm_x4(bh, st + GTILE + boff + g * 16 * GROWB + kk * 32);
                mma_fp(acc[0][2*g+0], ah0, bh[0], bh[1]);
                mma_fp(acc[0][2*g+1], ah0, bh[2], bh[3]);
                mma_fp(acc[1][2*g+0], ah1, bh[0], bh[1]);
                mma_fp(acc[1][2*g+1], ah1, bh[2], bh[3]);
            }
        }
    };

    load_stage(0); load_stage(1);

    for (int it = 0; it < nIter; it += 2) {
        // WAR safety: stage (it+2)&3 / (it+3)&3 were last read by
        // compute(it-2)/compute(it-1), both before the previous bottom sync.
        if (it + 2 < nIter) load_stage(it + 2); else CP_COMMIT();
        if (it + 3 < nIter) load_stage(it + 3); else CP_COMMIT();
        CP_WAIT(2);           // this thread's groups it, it+1 landed
        __syncthreads();      // all threads' groups landed -> visible
        compute(it);
        compute(it + 1);
        __syncthreads();      // reads done before next iteration's writes
    }

    const int l4 = lane >> 2, l2 = (lane & 3) * 2;
    #pragma unroll
    for (int mf = 0; mf < 2; mf++) {
        const int r = rowA0 + m0 + mf * 16 + l4;
        #pragma unroll
        for (int nf = 0; nf < 8; nf++) {
            const int c = colB0 + n0 + nf * 8 + l2;
            float2 v0 = make_float2(acc[mf][nf][0], acc[mf][nf][1]);
            float2 v1 = make_float2(acc[mf][nf][2], acc[mf][nf][3]);
            if (bias) {
                v0.x += bias[c]; v0.y += bias[c + 1];
                v1.x += bias[c]; v1.y += bias[c + 1];
            }
            if (EPI == 0) {
                if (resid) {
                    const float2 r0 = *(const float2*)&resid[(size_t)r * Ntot + c];
                    const float2 r1 = *(const float2*)&resid[(size_t)(r + 8) * Ntot + c];
                    v0.x += r0.x; v0.y += r0.y;
                    v1.x += r1.x; v1.y += r1.y;
                }
                float* C = (float*)Cv;
                *(float2*)&C[(size_t)r * Ntot + c] = v0;
                *(float2*)&C[(size_t)(r + 8) * Ntot + c] = v1;
            } else {
                if (EPI == 2) {
                    const float2 g0 = *(const float2*)&gate[(size_t)r * Ntot + c];
                    const float2 g1 = *(const float2*)&gate[(size_t)(r + 8) * Ntot + c];
                    v0.x *= silu_f(g0.x); v0.y *= silu_f(g0.y);
                    v1.x *= silu_f(g1.x); v1.y *= silu_f(g1.y);
                }
                h16* C = (h16*)Cv;
                *(__half2*)&C[(size_t)r * Ntot + c] = __floats2half2_rn(v0.x, v0.y);
                *(__half2*)&C[(size_t)(r + 8) * Ntot + c] = __floats2half2_rn(v1.x, v1.y);
            }
        }
    }
}

// ===================== tensor-core flash attention (pipelined) ===============
// Q pre-scaled by 1/sqrt(HD). K single-buffered (prefetch overlaps PV),
// V double-buffered (prefetch overlaps S+softmax).
#define AROW 272
#define PSROW 144
#define OFF_QH 0
#define OFF_QL (OFF_QH + 64 * AROW)
#define OFF_KH (OFF_QL + 64 * AROW)
#define OFF_KL (OFF_KH + 64 * AROW)
#define OFF_V0 (OFF_KL + 64 * AROW)
#define OFF_V1 (OFF_V0 + 64 * AROW)
#define OFF_PS (OFF_V1 + 64 * AROW)
#define ATTN_SMEM (OFF_PS + 64 * PSROW)   // 113664

__global__ __launch_bounds__(128, 2)
void attn_mma_kernel(const bf16* __restrict__ Qh, const bf16* __restrict__ Ql,
                     const bf16* __restrict__ Kh, const bf16* __restrict__ Kl,
                     const h16* __restrict__ Vh, h16* __restrict__ Oh)
{
    extern __shared__ char asm_[];
    const uint32_t sb = smem_u32(asm_);
    const int q0 = blockIdx.x * 64;
    const int h  = blockIdx.y;
    const int tid = threadIdx.x;
    const int w = tid >> 5, lane = tid & 31;
    const int mi = lane >> 3, l7 = lane & 7;
    const size_t hoff = (size_t)h * HD_DIM;
    const int nIter = blockIdx.x + 1;

    auto load_K = [&](int jj) {
        const int j0 = jj * 64;
        #pragma unroll
        for (int i = 0; i < 8; i++) {
            int idx = tid + i * 128;
            int r = idx >> 4, c = idx & 15;
            uint32_t doff = r * AROW + c * 16;
            const size_t gsrc = (size_t)(j0 + r) * H_DIM + hoff + c * 8;
            CP_ASYNC16(sb + OFF_KH + doff, Kh + gsrc);
            CP_ASYNC16(sb + OFF_KL + doff, Kl + gsrc);
        }
        CP_COMMIT();
    };
    auto load_V = [&](int jj) {
        const int j0 = jj * 64;
        const uint32_t vb = sb + ((jj & 1) ? OFF_V1 : OFF_V0);
        #pragma unroll
        for (int i = 0; i < 8; i++) {
            int idx = tid + i * 128;
            int r = idx >> 4, c = idx & 15;
            const size_t gsrc = (size_t)(j0 + r) * H_DIM + hoff + c * 8;
            CP_ASYNC16(vb + r * AROW + c * 16, Vh + gsrc);
        }
        CP_COMMIT();
    };

    // prologue: Q (group), K0 (group), V0 (group)
    #pragma unroll
    for (int i = 0; i < 8; i++) {
        int idx = tid + i * 128;
        int r = idx >> 4, c = idx & 15;
        uint32_t dst = sb + OFF_QH + r * AROW + c * 16;
        const size_t gsrc = (size_t)(q0 + r) * H_DIM + hoff + c * 8;
        CP_ASYNC16(dst, Qh + gsrc);
        CP_ASYNC16(dst + (OFF_QL - OFF_QH), Ql + gsrc);
    }
    CP_COMMIT();
    load_K(0);
    load_V(0);

    float oacc[16][4];
    #pragma unroll
    for (int f = 0; f < 16; f++)
        #pragma unroll
        for (int c = 0; c < 4; c++) oacc[f][c] = 0.f;
    float m0v = -1e30f, m1v = -1e30f, l0v = 0.f, l1v = 0.f;

    const uint32_t aq_off = (uint32_t)((w * 16 + (mi & 1) * 8 + l7) * AROW + (mi >> 1) * 16);
    const uint32_t bk_off = (uint32_t)(((mi >> 1) * 8 + l7) * AROW + (mi & 1) * 16);
    const uint32_t ps_off = (uint32_t)((w * 16 + (mi & 1) * 8 + l7) * PSROW + (mi >> 1) * 16);

    const int r0 = lane >> 2;
    const int gq0 = q0 + w * 16 + r0;
    const int gq1 = gq0 + 8;

    for (int jj = 0; jj < nIter; jj++) {
        const int j0 = jj * 64;
        CP_WAIT(1);               // this thread's Q + K_jj landed (V_jj may pend)
        __syncthreads();          // all threads' Q/K landed -> visible

        // S = Qh*Kh + Qh*Kl + Ql*Kh  (Q pre-scaled)
        float sacc[8][4];
        #pragma unroll
        for (int f = 0; f < 8; f++)
            #pragma unroll
            for (int c = 0; c < 4; c++) sacc[f][c] = 0.f;

        #pragma unroll
        for (int pass = 0; pass < 3; pass++) {
            const uint32_t sa = sb + ((pass < 2) ? OFF_QH : OFF_QL);
            const uint32_t skb = sb + ((pass == 1) ? OFF_KL : OFF_KH);
            #pragma unroll
            for (int ks = 0; ks < 8; ks++) {
                uint32_t a[4];
                ldsm_x4(a, sa + aq_off + ks * 32);
                #pragma unroll
                for (int g = 0; g < 4; g++) {
                    uint32_t b[4];
                    ldsm_x4(b, skb + bk_off + g * 16 * AROW + ks * 32);
                    mma_bf(sacc[2*g+0], a, b[0], b[1]);
                    mma_bf(sacc[2*g+1], a, b[2], b[3]);
                }
            }
        }

        const bool diag = (j0 == q0);
        if (diag) {
            #pragma unroll
            for (int f = 0; f < 8; f++) {
                int kvc = j0 + f * 8 + (lane & 3) * 2;
                if (kvc     > gq0) sacc[f][0] = -1e30f;
                if (kvc + 1 > gq0) sacc[f][1] = -1e30f;
                if (kvc     > gq1) sacc[f][2] = -1e30f;
                if (kvc + 1 > gq1) sacc[f][3] = -1e30f;
            }
        }

        float mx0 = -1e30f, mx1 = -1e30f;
        #pragma unroll
        for (int f = 0; f < 8; f++) {
            mx0 = fmaxf(mx0, fmaxf(sacc[f][0], sacc[f][1]));
            mx1 = fmaxf(mx1, fmaxf(sacc[f][2], sacc[f][3]));
        }
        mx0 = fmaxf(mx0, __shfl_xor_sync(0xffffffffu, mx0, 1));
        mx0 = fmaxf(mx0, __shfl_xor_sync(0xffffffffu, mx0, 2));
        mx1 = fmaxf(mx1, __shfl_xor_sync(0xffffffffu, mx1, 1));
        mx1 = fmaxf(mx1, __shfl_xor_sync(0xffffffffu, mx1, 2));
        const float mn0 = fmaxf(m0v, mx0), mn1 = fmaxf(m1v, mx1);
        float rs0 = 0.f, rs1 = 0.f;
        #pragma unroll
        for (int f = 0; f < 8; f++) {
            float p0 = expf(sacc[f][0] - mn0);
            float p1 = expf(sacc[f][1] - mn0);
            float p2 = expf(sacc[f][2] - mn1);
            float p3 = expf(sacc[f][3] - mn1);
            rs0 += p0 + p1; rs1 += p2 + p3;
            __half2 v01 = __floats2half2_rn(p0, p1);
            __half2 v23 = __floats2half2_rn(p2, p3);
            uint32_t col = (f * 8 + (lane & 3) * 2) * 2;
            *(uint32_t*)(asm_ + OFF_PS + (w * 16 + r0) * PSROW + col) = *(uint32_t*)&v01;
            *(uint32_t*)(asm_ + OFF_PS + (w * 16 + r0 + 8) * PSROW + col) = *(uint32_t*)&v23;
        }
        rs0 += __shfl_xor_sync(0xffffffffu, rs0, 1);
        rs0 += __shfl_xor_sync(0xffffffffu, rs0, 2);
        rs1 += __shfl_xor_sync(0xffffffffu, rs1, 1);
        rs1 += __shfl_xor_sync(0xffffffffu, rs1, 2);
        const float al0 = expf(m0v - mn0), al1 = expf(m1v - mn1);
        l0v = l0v * al0 + rs0; l1v = l1v * al1 + rs1;
        m0v = mn0; m1v = mn1;
        #pragma unroll
        for (int f = 0; f < 16; f++) {
            oacc[f][0] *= al0; oacc[f][1] *= al0;
            oacc[f][2] *= al1; oacc[f][3] *= al1;
        }
        __syncthreads();          // K reads done; PS visible to all

        // prefetch next K (overlaps PV) and next V (double-buffered)
        if (jj + 1 < nIter) { load_K(jj + 1); load_V(jj + 1); }
        else                { CP_COMMIT(); CP_COMMIT(); }

        CP_WAIT(2);               // this thread's V_jj landed
        __syncthreads();          // all threads' V_jj landed -> visible

        const uint32_t vb = sb + ((jj & 1) ? OFF_V1 : OFF_V0);
        #pragma unroll
        for (int ks = 0; ks < 4; ks++) {
            uint32_t a[4];
            ldsm_x4(a, sb + OFF_PS + ps_off + ks * 32);
            #pragma unroll
            for (int g = 0; g < 8; g++) {
                uint32_t b[4];
                ldsm_x4t(b, vb + (ks * 16 + (mi & 1) * 8 + l7) * AROW
                               + (g * 16 + (mi >> 1) * 8) * 2);
                mma_fp(oacc[2*g+0], a, b[0], b[1]);
                mma_fp(oacc[2*g+1], a, b[2], b[3]);
            }
        }
    }

    const float i0 = 1.f / l0v, i1 = 1.f / l1v;
    #pragma unroll
    for (int f = 0; f < 16; f++) {
        int col = h * HD_DIM + f * 8 + (lane & 3) * 2;
        __half2 hh0 = __floats2half2_rn(oacc[f][0] * i0, oacc[f][1] * i0);
        __half2 hh1 = __floats2half2_rn(oacc[f][2] * i1, oacc[f][3] * i1);
        *(__half2*)&Oh[(size_t)gq0 * H_DIM + col] = hh0;
        *(__half2*)&Oh[(size_t)gq1 * H_DIM + col] = hh1;
    }
}

// ===================== elementwise / conversion kernels =====================
__global__ void rmsnorm_f16_kernel(const float* __restrict__ x,
                                   const float* __restrict__ scale,
                                   h16* __restrict__ oh)
{
    int row = blockIdx.x;
    const float4* xr = (const float4*)(x + (size_t)row * H_DIM);
    float ss = 0.f;
    for (int i = threadIdx.x; i < H_DIM / 4; i += blockDim.x) {
        float4 v = xr[i];
        ss += v.x * v.x + v.y * v.y + v.z * v.z + v.w * v.w;
    }
    #pragma unroll
    for (int off = 16; off; off >>= 1) ss += __shfl_xor_sync(0xffffffffu, ss, off);
    __shared__ float red[32];
    int lane = threadIdx.x & 31, wid = threadIdx.x >> 5;
    if (lane == 0) red[wid] = ss;
    __syncthreads();
    if (wid == 0) {
        ss = (lane < (int)(blockDim.x >> 5)) ? red[lane] : 0.f;
        #pragma unroll
        for (int off = 16; off; off >>= 1) ss += __shfl_xor_sync(0xffffffffu, ss, off);
        if (lane == 0) red[0] = ss;
    }
    __syncthreads();
    float inv = rsqrtf(red[0] / (float)H_DIM + EPS_V);
    const float4* sc = (const float4*)scale;
    for (int i = threadIdx.x; i < H_DIM / 4; i += blockDim.x) {
        float4 v = xr[i], s = sc[i];
        __half2 lo = __floats2half2_rn(v.x * inv * s.x, v.y * inv * s.y);
        __half2 hi = __floats2half2_rn(v.z * inv * s.z, v.w * inv * s.w);
        uint2 pack = {*(uint32_t*)&lo, *(uint32_t*)&hi};
        ((uint2*)(oh + (size_t)row * H_DIM))[i] = pack;
    }
}

// W[K][N] fp32 -> Th[N][K] fp16
__global__ void transpose_f16_kernel(const float* __restrict__ W, int K, int N,
                                     h16* __restrict__ Th)
{
    __shared__ float t[64][33];
    const int n0 = blockIdx.x * 32, k0 = blockIdx.y * 64;
    const int lane = threadIdx.x & 31;
    const int w = threadIdx.x >> 5;
    #pragma unroll
    for (int i = 0; i < 8; i++) {
        int kk = w + i * 8;
        t[kk][lane] = W[(size_t)(k0 + kk) * N + n0 + lane];
    }
    __syncthreads();
    #pragma unroll
    for (int j = 0; j < 4; j++) {
        int n = w * 4 + j;
        __half2 v = __floats2half2_rn(t[2 * lane][n], t[2 * lane + 1][n]);
        *(__half2*)&Th[(size_t)(n0 + n) * K + k0 + 2 * lane] = v;
    }
}

// ===================== RoPE + split (q pre-scaled) ===========================
__global__ void rope_split_kernel(const float* __restrict__ q,
                                  const float* __restrict__ k,
                                  const int* __restrict__ pos,
                                  bf16* __restrict__ qh, bf16* __restrict__ ql,
                                  bf16* __restrict__ kh, bf16* __restrict__ kl)
{
    int idx = blockIdx.x * blockDim.x + threadIdx.x;
    if (idx >= T_DIM * NHEADS * (HD_DIM / 2)) return;
    int d  = idx & 63;
    int th = idx >> 6;
    int t  = th >> 5;
    const float scaling = 0.08838834764831845f;   // 128^-0.5
    float invf = powf(10000.0f, -(float)d * (1.0f / 64.0f));
    float ang = (float)pos[t] * invf;
    float c, s;
    sincosf(ang, &s, &c);
    size_t base = (size_t)th * HD_DIM + d;
    float q1 = q[base], q2 = q[base + 64];
    float rq1 = (q1 * c - q2 * s) * scaling;
    float rq2 = (q2 * c + q1 * s) * scaling;
    float k1 = k[base], k2 = k[base + 64];
    float rk1 = k1 * c - k2 * s;
    float rk2 = k2 * c + k1 * s;
    bf16 h, l;
    split_bf(rq1, h, l); qh[base] = h;       ql[base] = l;
    split_bf(rq2, h, l); qh[base + 64] = h;  ql[base + 64] = l;
    split_bf(rk1, h, l); kh[base] = h;       kl[base] = l;
    split_bf(rk2, h, l); kh[base + 64] = h;  kl[base + 64] = l;
}

// ===================== launch ================================================
extern "C" void kernel_launch(void* const* d_in, const int* in_sizes, int n_in,
                              void* d_out, int out_size)
{
    (void)in_sizes; (void)n_in; (void)out_size;
    const int*   positions = (const int*)  d_in[0];
    const float* hidden    = (const float*)d_in[1];
    const float* ln1       = (const float*)d_in[2];
    const float* wq = (const float*)d_in[3];
    const float* bq = (const float*)d_in[4];
    const float* wk = (const float*)d_in[5];
    const float* bk = (const float*)d_in[6];
    const float* wv = (const float*)d_in[7];
    const float* bv = (const float*)d_in[8];
    const float* wo = (const float*)d_in[9];
    const float* ln2= (const float*)d_in[10];
    const float* w1 = (const float*)d_in[11];
    const float* w2 = (const float*)d_in[12];
    const float* wc = (const float*)d_in[13];
    float* out = (float*)d_out;

    float *q, *k, *hbuf, *a2;
    h16 *xnh, *atth, *yh, *gh, *vhb;
    bf16 *qhb, *qlb, *khb, *klb;
    h16 *wqh, *wkh, *wvh, *woh, *w1h, *w2h, *wch;
    cudaGetSymbolAddress((void**)&q,    g_q);
    cudaGetSymbolAddress((void**)&k,    g_k);
    cudaGetSymbolAddress((void**)&hbuf, g_h);
    cudaGetSymbolAddress((void**)&a2,   g_a2);
    cudaGetSymbolAddress((void**)&xnh,  g_xnh);
    cudaGetSymbolAddress((void**)&atth, g_atth);
    cudaGetSymbolAddress((void**)&yh,   g_yh);
    cudaGetSymbolAddress((void**)&gh,   g_gh);
    cudaGetSymbolAddress((void**)&qhb,  g_qhb);
    cudaGetSymbolAddress((void**)&qlb,  g_qlb);
    cudaGetSymbolAddress((void**)&khb,  g_khb);
    cudaGetSymbolAddress((void**)&klb,  g_klb);
    cudaGetSymbolAddress((void**)&vhb,  g_vhb);
    cudaGetSymbolAddress((void**)&wqh,  g_wqh);
    cudaGetSymbolAddress((void**)&wkh,  g_wkh);
    cudaGetSymbolAddress((void**)&wvh,  g_wvh);
    cudaGetSymbolAddress((void**)&woh,  g_woh);
    cudaGetSymbolAddress((void**)&w1h,  g_w1h);
    cudaGetSymbolAddress((void**)&w2h,  g_w2h);
    cudaGetSymbolAddress((void**)&wch,  g_wch);

    cudaFuncSetAttribute((gemm_f16<0>), cudaFuncAttributeMaxDynamicSharedMemorySize, GSMEM);
    cudaFuncSetAttribute((gemm_f16<1>), cudaFuncAttributeMaxDynamicSharedMemorySize, GSMEM);
    cudaFuncSetAttribute((gemm_f16<2>), cudaFuncAttributeMaxDynamicSharedMemorySize, GSMEM);
    cudaFuncSetAttribute(attn_mma_kernel, cudaFuncAttributeMaxDynamicSharedMemorySize, ATTN_SMEM);

    // weight transposes (fp32 [K,N] -> fp16 [N,K])
    transpose_f16_kernel<<<dim3(H_DIM/32, H_DIM/64), 256>>>(wq, H_DIM, H_DIM, wqh);
    transpose_f16_kernel<<<dim3(H_DIM/32, H_DIM/64), 256>>>(wk, H_DIM, H_DIM, wkh);
    transpose_f16_kernel<<<dim3(H_DIM/32, H_DIM/64), 256>>>(wv, H_DIM, H_DIM, wvh);
    transpose_f16_kernel<<<dim3(H_DIM/32, H_DIM/64), 256>>>(wo, H_DIM, H_DIM, woh);
    transpose_f16_kernel<<<dim3(FF_DIM/32, H_DIM/64), 256>>>(w1, H_DIM, FF_DIM, w1h);
    transpose_f16_kernel<<<dim3(FF_DIM/32, H_DIM/64), 256>>>(w2, H_DIM, FF_DIM, w2h);
    transpose_f16_kernel<<<dim3(H_DIM/32, FF_DIM/64), 256>>>(wc, FF_DIM, H_DIM, wch);

    // 1) x = rmsnorm(hidden, ln1) -> single fp16
    rmsnorm_f16_kernel<<<T_DIM, 256>>>(hidden, ln1, xnh);

    // 2) q,k (fp32 out); v (fp16 out)
    dim3 gH(H_DIM / BN, T_DIM / BM);
    gemm_f16<0><<<gH, 256, GSMEM>>>(xnh, wqh, bq, nullptr, nullptr, q, H_DIM, H_DIM);
    gemm_f16<0><<<gH, 256, GSMEM>>>(xnh, wkh, bk, nullptr, nullptr, k, H_DIM, H_DIM);
    gemm_f16<1><<<gH, 256, GSMEM>>>(xnh, wvh, bv, nullptr, nullptr, vhb, H_DIM, H_DIM);

    // 3) RoPE + split (q pre-scaled)
    rope_split_kernel<<<(T_DIM * NHEADS * (HD_DIM / 2)) / 256, 256>>>(q, k, positions,
                                                                      qhb, qlb, khb, klb);

    // 4) attention -> atth (single fp16)
    attn_mma_kernel<<<dim3(T_DIM / 64, NHEADS), 128, ATTN_SMEM>>>(qhb, qlb, khb, klb, vhb, atth);

    // 5) h = hidden + attn @ wo
    gemm_f16<0><<<gH, 256, GSMEM>>>(atth, woh, nullptr, hidden, nullptr, hbuf, H_DIM, H_DIM);

    // 6) y = rmsnorm(h, ln2) -> single fp16
    rmsnorm_f16_kernel<<<T_DIM, 256>>>(hbuf, ln2, yh);

    // 7) MLP: a2 = y@w2 (fp32); gh = (y@w1) * silu(a2) fused, fp16 out
    dim3 gF(FF_DIM / BN, T_DIM / BM);
    gemm_f16<0><<<gF, 256, GSMEM>>>(yh, w2h, nullptr, nullptr, nullptr, a2, FF_DIM, H_DIM);
    gemm_f16<2><<<gF, 256, GSMEM>>>(yh, w1h, nullptr, nullptr, a2, gh, FF_DIM, H_DIM);

    // 8) out = h + gh @ wc
    gemm_f16<0><<<gH, 256, GSMEM>>>(gh, wch, nullptr, hbuf, nullptr, out, H_DIM, FF_DIM);
}

// round 12
// speedup vs baseline: 7.1680x; 1.0516x over previous
#include <cuda_runtime.h>
#include <cuda_bf16.h>
#include <cuda_fp16.h>
#include <math.h>
#include <cstdint>

#define T_DIM 2048
#define H_DIM 4096
#define NHEADS 32
#define HD_DIM 128
#define FF_DIM 11008
#define EPS_V 1e-6f

typedef __half h16;

// ===================== device scratch ======================================
__device__ float g_h  [(size_t)T_DIM * H_DIM];
__device__ float g_a2 [(size_t)T_DIM * FF_DIM];

__device__ h16 g_xnh [(size_t)T_DIM * H_DIM];
__device__ h16 g_atth[(size_t)T_DIM * H_DIM];
__device__ h16 g_yh  [(size_t)T_DIM * H_DIM];
__device__ h16 g_gh  [(size_t)T_DIM * FF_DIM];

// attention operands (fp16; q pre-scaled, RoPE applied in place)
__device__ h16 g_q16[(size_t)T_DIM * H_DIM];
__device__ h16 g_k16[(size_t)T_DIM * H_DIM];
__device__ h16 g_vhb[(size_t)T_DIM * H_DIM];

// weights (single fp16, transposed [N][K])
__device__ h16 g_wqh[(size_t)H_DIM * H_DIM];
__device__ h16 g_wkh[(size_t)H_DIM * H_DIM];
__device__ h16 g_wvh[(size_t)H_DIM * H_DIM];
__device__ h16 g_woh[(size_t)H_DIM * H_DIM];
__device__ h16 g_w1h[(size_t)FF_DIM * H_DIM];
__device__ h16 g_w2h[(size_t)FF_DIM * H_DIM];
__device__ h16 g_wch[(size_t)H_DIM * FF_DIM];

// ===================== PTX helpers =========================================
__device__ __forceinline__ uint32_t smem_u32(const void* p) {
    uint32_t a;
    asm("{ .reg .u64 t; cvta.to.shared.u64 t, %1; cvt.u32.u64 %0, t; }"
        : "=r"(a) : "l"(p));
    return a;
}

#define CP_ASYNC16(dst, src) \
    asm volatile("cp.async.cg.shared.global [%0], [%1], 16;" :: "r"(dst), "l"(src))
#define CP_COMMIT() asm volatile("cp.async.commit_group;" ::: "memory")
#define CP_WAIT(n)  asm volatile("cp.async.wait_group %0;" :: "n"(n) : "memory")

__device__ __forceinline__ void ldsm_x4(uint32_t* r, uint32_t a) {
    asm volatile("ldmatrix.sync.aligned.m8n8.x4.shared.b16 {%0,%1,%2,%3}, [%4];"
        : "=r"(r[0]), "=r"(r[1]), "=r"(r[2]), "=r"(r[3]) : "r"(a));
}
__device__ __forceinline__ void ldsm_x4t(uint32_t* r, uint32_t a) {
    asm volatile("ldmatrix.sync.aligned.m8n8.x4.trans.shared.b16 {%0,%1,%2,%3}, [%4];"
        : "=r"(r[0]), "=r"(r[1]), "=r"(r[2]), "=r"(r[3]) : "r"(a));
}

__device__ __forceinline__ void mma_fp(float* d, const uint32_t* a,
                                       uint32_t b0, uint32_t b1) {
    asm volatile(
        "mma.sync.aligned.m16n8k16.row.col.f32.f16.f16.f32 "
        "{%0,%1,%2,%3}, {%4,%5,%6,%7}, {%8,%9}, {%0,%1,%2,%3};"
        : "+f"(d[0]), "+f"(d[1]), "+f"(d[2]), "+f"(d[3])
        : "r"(a[0]), "r"(a[1]), "r"(a[2]), "r"(a[3]), "r"(b0), "r"(b1));
}

__device__ __forceinline__ float silu_f(float g) {
    return g / (1.f + expf(-g));
}

// ===================== fp16 GEMM (single-pass, 4-stage, paired iters) ========
// C[M,N] = A@B^T (+bias). EPI: 0 = fp32 out (+resid), 1 = fp16, 2 = fp16*silu(gate)
#define BM 128
#define BN 128
#define GROWB 80
#define GTILE (128 * GROWB)
#define GSMEM (4 * 2 * GTILE)      // 81920

template<int EPI>
__global__ __launch_bounds__(256, 2)
void gemm_f16(const h16* __restrict__ Ah, const h16* __restrict__ Bh,
              const float* __restrict__ bias, const float* __restrict__ resid,
              const float* __restrict__ gate,
              void* __restrict__ Cv, int Ntot, int K)
{
    constexpr int STAGE_B = 2 * GTILE;
    extern __shared__ char dsm[];
    const int tid = threadIdx.x;
    const int wid = tid >> 5, lane = tid & 31;
    const int rowA0 = blockIdx.y * BM;
    const int colB0 = blockIdx.x * BN;
    const int nIter = K >> 5;           // always even (128 or 344)
    const uint32_t sbase = smem_u32(dsm);

    auto load_stage = [&](int it) {
        const int s = it & 3;
        const size_t koff = (size_t)it * 32;
        const uint32_t st = sbase + s * STAGE_B;
        #pragma unroll
        for (int i = 0; i < 2; i++) {
            int idx = tid + i * 256;
            int r = idx >> 2, seg = idx & 3;
            uint32_t doff = r * GROWB + seg * 16;
            const size_t goff = koff + seg * 8;
            CP_ASYNC16(st + doff, Ah + (size_t)(rowA0 + r) * K + goff);
            CP_ASYNC16(st + GTILE + doff, Bh + (size_t)(colB0 + r) * K + goff);
        }
        CP_COMMIT();
    };

    const int m0 = (wid >> 1) * 32;
    const int n0 = (wid & 1) * 64;

    float acc[2][8][4];
    #pragma unroll
    for (int i = 0; i < 2; i++)
        #pragma unroll
        for (int j = 0; j < 8; j++)
            #pragma unroll
            for (int c = 0; c < 4; c++) acc[i][j][c] = 0.f;

    const int mi = lane >> 3, l7 = lane & 7;
    const uint32_t aoff = (uint32_t)((m0 + (mi & 1) * 8 + l7) * GROWB + (mi >> 1) * 16);
    const uint32_t boff = (uint32_t)((n0 + (mi >> 1) * 8 + l7) * GROWB + (mi & 1) * 16);

    auto compute = [&](int it) {
        const uint32_t st = sbase + (it & 3) * STAGE_B;
        #pragma unroll
        for (int kk = 0; kk < 2; kk++) {
            uint32_t ah0[4], ah1[4];
            ldsm_x4(ah0, st + aoff + kk * 32);
            ldsm_x4(ah1, st + aoff + 16 * GROWB + kk * 32);
            #pragma unroll
            for (int g = 0; g < 4; g++) {
                uint32_t bh[4];
                ldsm_x4(bh, st + GTILE + boff + g * 16 * GROWB + kk * 32);
                mma_fp(acc[0][2*g+0], ah0, bh[0], bh[1]);
                mma_fp(acc[0][2*g+1], ah0, bh[2], bh[3]);
                mma_fp(acc[1][2*g+0], ah1, bh[0], bh[1]);
                mma_fp(acc[1][2*g+1], ah1, bh[2], bh[3]);
            }
        }
    };

    load_stage(0); load_stage(1);

    for (int it = 0; it < nIter; it += 2) {
        if (it + 2 < nIter) load_stage(it + 2); else CP_COMMIT();
        if (it + 3 < nIter) load_stage(it + 3); else CP_COMMIT();
        CP_WAIT(2);
        __syncthreads();
        compute(it);
        compute(it + 1);
        __syncthreads();
    }

    const int l4 = lane >> 2, l2 = (lane & 3) * 2;
    #pragma unroll
    for (int mf = 0; mf < 2; mf++) {
        const int r = rowA0 + m0 + mf * 16 + l4;
        #pragma unroll
        for (int nf = 0; nf < 8; nf++) {
            const int c = colB0 + n0 + nf * 8 + l2;
            float2 v0 = make_float2(acc[mf][nf][0], acc[mf][nf][1]);
            float2 v1 = make_float2(acc[mf][nf][2], acc[mf][nf][3]);
            if (bias) {
                v0.x += bias[c]; v0.y += bias[c + 1];
                v1.x += bias[c]; v1.y += bias[c + 1];
            }
            if (EPI == 0) {
                if (resid) {
                    const float2 r0 = *(const float2*)&resid[(size_t)r * Ntot + c];
                    const float2 r1 = *(const float2*)&resid[(size_t)(r + 8) * Ntot + c];
                    v0.x += r0.x; v0.y += r0.y;
                    v1.x += r1.x; v1.y += r1.y;
                }
                float* C = (float*)Cv;
                *(float2*)&C[(size_t)r * Ntot + c] = v0;
                *(float2*)&C[(size_t)(r + 8) * Ntot + c] = v1;
            } else {
                if (EPI == 2) {
                    const float2 g0 = *(const float2*)&gate[(size_t)r * Ntot + c];
                    const float2 g1 = *(const float2*)&gate[(size_t)(r + 8) * Ntot + c];
                    v0.x *= silu_f(g0.x); v0.y *= silu_f(g0.y);
                    v1.x *= silu_f(g1.x); v1.y *= silu_f(g1.y);
                }
                h16* C = (h16*)Cv;
                *(__half2*)&C[(size_t)r * Ntot + c] = __floats2half2_rn(v0.x, v0.y);
                *(__half2*)&C[(size_t)(r + 8) * Ntot + c] = __floats2half2_rn(v1.x, v1.y);
            }
        }
    }
}

// ===================== tensor-core flash attention (fp16, pipelined) =========
// Q pre-scaled. S = Q@K^T single-pass fp16. V double-buffered; K prefetch
// overlaps PV.
#define AROW 272
#define PSROW 144
#define OFF_Q  0
#define OFF_K  (OFF_Q + 64 * AROW)
#define OFF_V0 (OFF_K + 64 * AROW)
#define OFF_V1 (OFF_V0 + 64 * AROW)
#define OFF_PS (OFF_V1 + 64 * AROW)
#define ATTN_SMEM (OFF_PS + 64 * PSROW)   // 78848

__global__ __launch_bounds__(128, 2)
void attn_mma_kernel(const h16* __restrict__ Q, const h16* __restrict__ K,
                     const h16* __restrict__ V, h16* __restrict__ Oh)
{
    extern __shared__ char asm_[];
    const uint32_t sb = smem_u32(asm_);
    const int q0 = blockIdx.x * 64;
    const int h  = blockIdx.y;
    const int tid = threadIdx.x;
    const int w = tid >> 5, lane = tid & 31;
    const int mi = lane >> 3, l7 = lane & 7;
    const size_t hoff = (size_t)h * HD_DIM;
    const int nIter = blockIdx.x + 1;

    auto load_K = [&](int jj) {
        const int j0 = jj * 64;
        #pragma unroll
        for (int i = 0; i < 8; i++) {
            int idx = tid + i * 128;
            int r = idx >> 4, c = idx & 15;
            const size_t gsrc = (size_t)(j0 + r) * H_DIM + hoff + c * 8;
            CP_ASYNC16(sb + OFF_K + r * AROW + c * 16, K + gsrc);
        }
        CP_COMMIT();
    };
    auto load_V = [&](int jj) {
        const int j0 = jj * 64;
        const uint32_t vb = sb + ((jj & 1) ? OFF_V1 : OFF_V0);
        #pragma unroll
        for (int i = 0; i < 8; i++) {
            int idx = tid + i * 128;
            int r = idx >> 4, c = idx & 15;
            const size_t gsrc = (size_t)(j0 + r) * H_DIM + hoff + c * 8;
            CP_ASYNC16(vb + r * AROW + c * 16, V + gsrc);
        }
        CP_COMMIT();
    };

    // prologue: Q (group), K0 (group), V0 (group)
    #pragma unroll
    for (int i = 0; i < 8; i++) {
        int idx = tid + i * 128;
        int r = idx >> 4, c = idx & 15;
        const size_t gsrc = (size_t)(q0 + r) * H_DIM + hoff + c * 8;
        CP_ASYNC16(sb + OFF_Q + r * AROW + c * 16, Q + gsrc);
    }
    CP_COMMIT();
    load_K(0);
    load_V(0);

    float oacc[16][4];
    #pragma unroll
    for (int f = 0; f < 16; f++)
        #pragma unroll
        for (int c = 0; c < 4; c++) oacc[f][c] = 0.f;
    float m0v = -1e30f, m1v = -1e30f, l0v = 0.f, l1v = 0.f;

    const uint32_t aq_off = (uint32_t)((w * 16 + (mi & 1) * 8 + l7) * AROW + (mi >> 1) * 16);
    const uint32_t bk_off = (uint32_t)(((mi >> 1) * 8 + l7) * AROW + (mi & 1) * 16);
    const uint32_t ps_off = (uint32_t)((w * 16 + (mi & 1) * 8 + l7) * PSROW + (mi >> 1) * 16);

    const int r0 = lane >> 2;
    const int gq0 = q0 + w * 16 + r0;
    const int gq1 = gq0 + 8;

    for (int jj = 0; jj < nIter; jj++) {
        const int j0 = jj * 64;
        CP_WAIT(1);               // this thread's Q + K_jj landed
        __syncthreads();          // all threads' -> visible

        // S = Q@K^T (single fp16 pass; Q pre-scaled)
        float sacc[8][4];
        #pragma unroll
        for (int f = 0; f < 8; f++)
            #pragma unroll
            for (int c = 0; c < 4; c++) sacc[f][c] = 0.f;

        #pragma unroll
        for (int ks = 0; ks < 8; ks++) {
            uint32_t a[4];
            ldsm_x4(a, sb + OFF_Q + aq_off + ks * 32);
            #pragma unroll
            for (int g = 0; g < 4; g++) {
                uint32_t b[4];
                ldsm_x4(b, sb + OFF_K + bk_off + g * 16 * AROW + ks * 32);
                mma_fp(sacc[2*g+0], a, b[0], b[1]);
                mma_fp(sacc[2*g+1], a, b[2], b[3]);
            }
        }

        const bool diag = (j0 == q0);
        if (diag) {
            #pragma unroll
            for (int f = 0; f < 8; f++) {
                int kvc = j0 + f * 8 + (lane & 3) * 2;
                if (kvc     > gq0) sacc[f][0] = -1e30f;
                if (kvc + 1 > gq0) sacc[f][1] = -1e30f;
                if (kvc     > gq1) sacc[f][2] = -1e30f;
                if (kvc + 1 > gq1) sacc[f][3] = -1e30f;
            }
        }

        float mx0 = -1e30f, mx1 = -1e30f;
        #pragma unroll
        for (int f = 0; f < 8; f++) {
            mx0 = fmaxf(mx0, fmaxf(sacc[f][0], sacc[f][1]));
            mx1 = fmaxf(mx1, fmaxf(sacc[f][2], sacc[f][3]));
        }
        mx0 = fmaxf(mx0, __shfl_xor_sync(0xffffffffu, mx0, 1));
        mx0 = fmaxf(mx0, __shfl_xor_sync(0xffffffffu, mx0, 2));
        mx1 = fmaxf(mx1, __shfl_xor_sync(0xffffffffu, mx1, 1));
        mx1 = fmaxf(mx1, __shfl_xor_sync(0xffffffffu, mx1, 2));
        const float mn0 = fmaxf(m0v, mx0), mn1 = fmaxf(m1v, mx1);
        float rs0 = 0.f, rs1 = 0.f;
        #pragma unroll
        for (int f = 0; f < 8; f++) {
            float p0 = expf(sacc[f][0] - mn0);
            float p1 = expf(sacc[f][1] - mn0);
            float p2 = expf(sacc[f][2] - mn1);
            float p3 = expf(sacc[f][3] - mn1);
            rs0 += p0 + p1; rs1 += p2 + p3;
            __half2 v01 = __floats2half2_rn(p0, p1);
            __half2 v23 = __floats2half2_rn(p2, p3);
            uint32_t col = (f * 8 + (lane & 3) * 2) * 2;
            *(uint32_t*)(asm_ + OFF_PS + (w * 16 + r0) * PSROW + col) = *(uint32_t*)&v01;
            *(uint32_t*)(asm_ + OFF_PS + (w * 16 + r0 + 8) * PSROW + col) = *(uint32_t*)&v23;
        }
        rs0 += __shfl_xor_sync(0xffffffffu, rs0, 1);
        rs0 += __shfl_xor_sync(0xffffffffu, rs0, 2);
        rs1 += __shfl_xor_sync(0xffffffffu, rs1, 1);
        rs1 += __shfl_xor_sync(0xffffffffu, rs1, 2);
        const float al0 = expf(m0v - mn0), al1 = expf(m1v - mn1);
        l0v = l0v * al0 + rs0; l1v = l1v * al1 + rs1;
        m0v = mn0; m1v = mn1;
        #pragma unroll
        for (int f = 0; f < 16; f++) {
            oacc[f][0] *= al0; oacc[f][1] *= al0;
            oacc[f][2] *= al1; oacc[f][3] *= al1;
        }
        __syncthreads();          // K reads done; PS visible to all

        // prefetch next K (overlaps PV) and next V (double-buffered)
        if (jj + 1 < nIter) { load_K(jj + 1); load_V(jj + 1); }
        else                { CP_COMMIT(); CP_COMMIT(); }

        CP_WAIT(2);               // this thread's V_jj landed
        __syncthreads();          // all threads' V_jj landed -> visible

        const uint32_t vb = sb + ((jj & 1) ? OFF_V1 : OFF_V0);
        #pragma unroll
        for (int ks = 0; ks < 4; ks++) {
            uint32_t a[4];
            ldsm_x4(a, sb + OFF_PS + ps_off + ks * 32);
            #pragma unroll
            for (int g = 0; g < 8; g++) {
                uint32_t b[4];
                ldsm_x4t(b, vb + (ks * 16 + (mi & 1) * 8 + l7) * AROW
                               + (g * 16 + (mi >> 1) * 8) * 2);
                mma_fp(oacc[2*g+0], a, b[0], b[1]);
                mma_fp(oacc[2*g+1], a, b[2], b[3]);
            }
        }
    }

    const float i0 = 1.f / l0v, i1 = 1.f / l1v;
    #pragma unroll
    for (int f = 0; f < 16; f++) {
        int col = h * HD_DIM + f * 8 + (lane & 3) * 2;
        __half2 hh0 = __floats2half2_rn(oacc[f][0] * i0, oacc[f][1] * i0);
        __half2 hh1 = __floats2half2_rn(oacc[f][2] * i1, oacc[f][3] * i1);
        *(__half2*)&Oh[(size_t)gq0 * H_DIM + col] = hh0;
        *(__half2*)&Oh[(size_t)gq1 * H_DIM + col] = hh1;
    }
}

// ===================== elementwise / conversion kernels =====================
__global__ void rmsnorm_f16_kernel(const float* __restrict__ x,
                                   const float* __restrict__ scale,
                                   h16* __restrict__ oh)
{
    int row = blockIdx.x;
    const float4* xr = (const float4*)(x + (size_t)row * H_DIM);
    float ss = 0.f;
    for (int i = threadIdx.x; i < H_DIM / 4; i += blockDim.x) {
        float4 v = xr[i];
        ss += v.x * v.x + v.y * v.y + v.z * v.z + v.w * v.w;
    }
    #pragma unroll
    for (int off = 16; off; off >>= 1) ss += __shfl_xor_sync(0xffffffffu, ss, off);
    __shared__ float red[32];
    int lane = threadIdx.x & 31, wid = threadIdx.x >> 5;
    if (lane == 0) red[wid] = ss;
    __syncthreads();
    if (wid == 0) {
        ss = (lane < (int)(blockDim.x >> 5)) ? red[lane] : 0.f;
        #pragma unroll
        for (int off = 16; off; off >>= 1) ss += __shfl_xor_sync(0xffffffffu, ss, off);
        if (lane == 0) red[0] = ss;
    }
    __syncthreads();
    float inv = rsqrtf(red[0] / (float)H_DIM + EPS_V);
    const float4* sc = (const float4*)scale;
    for (int i = threadIdx.x; i < H_DIM / 4; i += blockDim.x) {
        float4 v = xr[i], s = sc[i];
        __half2 lo = __floats2half2_rn(v.x * inv * s.x, v.y * inv * s.y);
        __half2 hi = __floats2half2_rn(v.z * inv * s.z, v.w * inv * s.w);
        uint2 pack = {*(uint32_t*)&lo, *(uint32_t*)&hi};
        ((uint2*)(oh + (size_t)row * H_DIM))[i] = pack;
    }
}

// W[K][N] fp32 -> Th[N][K] fp16
__global__ void transpose_f16_kernel(const float* __restrict__ W, int K, int N,
                                     h16* __restrict__ Th)
{
    __shared__ float t[64][33];
    const int n0 = blockIdx.x * 32, k0 = blockIdx.y * 64;
    const int lane = threadIdx.x & 31;
    const int w = threadIdx.x >> 5;
    #pragma unroll
    for (int i = 0; i < 8; i++) {
        int kk = w + i * 8;
        t[kk][lane] = W[(size_t)(k0 + kk) * N + n0 + lane];
    }
    __syncthreads();
    #pragma unroll
    for (int j = 0; j < 4; j++) {
        int n = w * 4 + j;
        __half2 v = __floats2half2_rn(t[2 * lane][n], t[2 * lane + 1][n]);
        *(__half2*)&Th[(size_t)(n0 + n) * K + k0 + 2 * lane] = v;
    }
}

// ===================== RoPE in-place on fp16 q,k (q pre-scaled) ==============
__global__ void rope_f16_kernel(h16* __restrict__ q, h16* __restrict__ k,
                                const int* __restrict__ pos)
{
    int idx = blockIdx.x * blockDim.x + threadIdx.x;
    if (idx >= T_DIM * NHEADS * (HD_DIM / 2)) return;
    int d  = idx & 63;
    int th = idx >> 6;
    int t  = th >> 5;
    const float scaling = 0.08838834764831845f;   // 128^-0.5
    float invf = powf(10000.0f, -(float)d * (1.0f / 64.0f));
    float ang = (float)pos[t] * invf;
    float c, s;
    sincosf(ang, &s, &c);
    size_t base = (size_t)th * HD_DIM + d;
    float q1 = __half2float(q[base]), q2 = __half2float(q[base + 64]);
    q[base]      = __float2half_rn((q1 * c - q2 * s) * scaling);
    q[base + 64] = __float2half_rn((q2 * c + q1 * s) * scaling);
    float k1 = __half2float(k[base]), k2 = __half2float(k[base + 64]);
    k[base]      = __float2half_rn(k1 * c - k2 * s);
    k[base + 64] = __float2half_rn(k2 * c + k1 * s);
}

// ===================== launch ================================================
extern "C" void kernel_launch(void* const* d_in, const int* in_sizes, int n_in,
                              void* d_out, int out_size)
{
    (void)in_sizes; (void)n_in; (void)out_size;
    const int*   positions = (const int*)  d_in[0];
    const float* hidden    = (const float*)d_in[1];
    const float* ln1       = (const float*)d_in[2];
    const float* wq = (const float*)d_in[3];
    const float* bq = (const float*)d_in[4];
    const float* wk = (const float*)d_in[5];
    const float* bk = (const float*)d_in[6];
    const float* wv = (const float*)d_in[7];
    const float* bv = (const float*)d_in[8];
    const float* wo = (const float*)d_in[9];
    const float* ln2= (const float*)d_in[10];
    const float* w1 = (const float*)d_in[11];
    const float* w2 = (const float*)d_in[12];
    const float* wc = (const float*)d_in[13];
    float* out = (float*)d_out;

    float *hbuf, *a2;
    h16 *xnh, *atth, *yh, *gh, *q16, *k16, *vhb;
    h16 *wqh, *wkh, *wvh, *woh, *w1h, *w2h, *wch;
    cudaGetSymbolAddress((void**)&hbuf, g_h);
    cudaGetSymbolAddress((void**)&a2,   g_a2);
    cudaGetSymbolAddress((void**)&xnh,  g_xnh);
    cudaGetSymbolAddress((void**)&atth, g_atth);
    cudaGetSymbolAddress((void**)&yh,   g_yh);
    cudaGetSymbolAddress((void**)&gh,   g_gh);
    cudaGetSymbolAddress((void**)&q16,  g_q16);
    cudaGetSymbolAddress((void**)&k16,  g_k16);
    cudaGetSymbolAddress((void**)&vhb,  g_vhb);
    cudaGetSymbolAddress((void**)&wqh,  g_wqh);
    cudaGetSymbolAddress((void**)&wkh,  g_wkh);
    cudaGetSymbolAddress((void**)&wvh,  g_wvh);
    cudaGetSymbolAddress((void**)&woh,  g_woh);
    cudaGetSymbolAddress((void**)&w1h,  g_w1h);
    cudaGetSymbolAddress((void**)&w2h,  g_w2h);
    cudaGetSymbolAddress((void**)&wch,  g_wch);

    cudaFuncSetAttribute((gemm_f16<0>), cudaFuncAttributeMaxDynamicSharedMemorySize, GSMEM);
    cudaFuncSetAttribute((gemm_f16<1>), cudaFuncAttributeMaxDynamicSharedMemorySize, GSMEM);
    cudaFuncSetAttribute((gemm_f16<2>), cudaFuncAttributeMaxDynamicSharedMemorySize, GSMEM);
    cudaFuncSetAttribute(attn_mma_kernel, cudaFuncAttributeMaxDynamicSharedMemorySize, ATTN_SMEM);

    // weight transposes (fp32 [K,N] -> fp16 [N,K])
    transpose_f16_kernel<<<dim3(H_DIM/32, H_DIM/64), 256>>>(wq, H_DIM, H_DIM, wqh);
    transpose_f16_kernel<<<dim3(H_DIM/32, H_DIM/64), 256>>>(wk, H_DIM, H_DIM, wkh);
    transpose_f16_kernel<<<dim3(H_DIM/32, H_DIM/64), 256>>>(wv, H_DIM, H_DIM, wvh);
    transpose_f16_kernel<<<dim3(H_DIM/32, H_DIM/64), 256>>>(wo, H_DIM, H_DIM, woh);
    transpose_f16_kernel<<<dim3(FF_DIM/32, H_DIM/64), 256>>>(w1, H_DIM, FF_DIM, w1h);
    transpose_f16_kernel<<<dim3(FF_DIM/32, H_DIM/64), 256>>>(w2, H_DIM, FF_DIM, w2h);
    transpose_f16_kernel<<<dim3(H_DIM/32, FF_DIM/64), 256>>>(wc, FF_DIM, H_DIM, wch);

    // 1) x = rmsnorm(hidden, ln1) -> fp16
    rmsnorm_f16_kernel<<<T_DIM, 256>>>(hidden, ln1, xnh);

    // 2) q,k,v (all fp16 out)
    dim3 gH(H_DIM / BN, T_DIM / BM);
    gemm_f16<1><<<gH, 256, GSMEM>>>(xnh, wqh, bq, nullptr, nullptr, q16, H_DIM, H_DIM);
    gemm_f16<1><<<gH, 256, GSMEM>>>(xnh, wkh, bk, nullptr, nullptr, k16, H_DIM, H_DIM);
    gemm_f16<1><<<gH, 256, GSMEM>>>(xnh, wvh, bv, nullptr, nullptr, vhb, H_DIM, H_DIM);

    // 3) RoPE in place (q pre-scaled)
    rope_f16_kernel<<<(T_DIM * NHEADS * (HD_DIM / 2)) / 256, 256>>>(q16, k16, positions);

    // 4) attention -> atth (fp16)
    attn_mma_kernel<<<dim3(T_DIM / 64, NHEADS), 128, ATTN_SMEM>>>(q16, k16, vhb, atth);

    // 5) h = hidden + attn @ wo
    gemm_f16<0><<<gH, 256, GSMEM>>>(atth, woh, nullptr, hidden, nullptr, hbuf, H_DIM, H_DIM);

    // 6) y = rmsnorm(h, ln2) -> fp16
    rmsnorm_f16_kernel<<<T_DIM, 256>>>(hbuf, ln2, yh);

    // 7) MLP: a2 = y@w2 (fp32); gh = (y@w1) * silu(a2) fused, fp16 out
    dim3 gF(FF_DIM / BN, T_DIM / BM);
    gemm_f16<0><<<gF, 256, GSMEM>>>(yh, w2h, nullptr, nullptr, nullptr, a2, FF_DIM, H_DIM);
    gemm_f16<2><<<gF, 256, GSMEM>>>(yh, w1h, nullptr, nullptr, a2, gh, FF_DIM, H_DIM);

    // 8) out = h + gh @ wc
    gemm_f16<0><<<gH, 256, GSMEM>>>(gh, wch, nullptr, hbuf, nullptr, out, H_DIM, FF_DIM);
}

// round 13
// speedup vs baseline: 7.6602x; 1.0687x over previous
#include <cuda_runtime.h>
#include <cuda_fp16.h>
#include <math.h>
#include <cstdint>

#define T_DIM 2048
#define H_DIM 4096
#define NHEADS 32
#define HD_DIM 128
#define FF_DIM 11008
#define QKV_N (3 * H_DIM)          // 12288
#define EPS_V 1e-6f

typedef __half h16;

// ===================== device scratch ======================================
__device__ float g_h   [(size_t)T_DIM * H_DIM];
__device__ float g_a2  [(size_t)T_DIM * FF_DIM];
__device__ float g_bqkv[QKV_N];

__device__ h16 g_xnh  [(size_t)T_DIM * H_DIM];
__device__ h16 g_atth [(size_t)T_DIM * H_DIM];
__device__ h16 g_yh   [(size_t)T_DIM * H_DIM];
__device__ h16 g_gh   [(size_t)T_DIM * FF_DIM];
__device__ h16 g_qkv16[(size_t)T_DIM * QKV_N];

// weights fp16, SAME layout as input ([K][N] row-major)
__device__ h16 g_wqkv[(size_t)H_DIM * QKV_N];
__device__ h16 g_woh [(size_t)H_DIM * H_DIM];
__device__ h16 g_w1h [(size_t)H_DIM * FF_DIM];
__device__ h16 g_w2h [(size_t)H_DIM * FF_DIM];
__device__ h16 g_wch [(size_t)FF_DIM * H_DIM];

// ===================== PTX helpers =========================================
__device__ __forceinline__ uint32_t smem_u32(const void* p) {
    uint32_t a;
    asm("{ .reg .u64 t; cvta.to.shared.u64 t, %1; cvt.u32.u64 %0, t; }"
        : "=r"(a) : "l"(p));
    return a;
}

#define CP_ASYNC16(dst, src) \
    asm volatile("cp.async.cg.shared.global [%0], [%1], 16;" :: "r"(dst), "l"(src))
#define CP_COMMIT() asm volatile("cp.async.commit_group;" ::: "memory")
#define CP_WAIT(n)  asm volatile("cp.async.wait_group %0;" :: "n"(n) : "memory")

__device__ __forceinline__ void ldsm_x4(uint32_t* r, uint32_t a) {
    asm volatile("ldmatrix.sync.aligned.m8n8.x4.shared.b16 {%0,%1,%2,%3}, [%4];"
        : "=r"(r[0]), "=r"(r[1]), "=r"(r[2]), "=r"(r[3]) : "r"(a));
}
__device__ __forceinline__ void ldsm_x4t(uint32_t* r, uint32_t a) {
    asm volatile("ldmatrix.sync.aligned.m8n8.x4.trans.shared.b16 {%0,%1,%2,%3}, [%4];"
        : "=r"(r[0]), "=r"(r[1]), "=r"(r[2]), "=r"(r[3]) : "r"(a));
}

__device__ __forceinline__ void mma_fp(float* d, const uint32_t* a,
                                       uint32_t b0, uint32_t b1) {
    asm volatile(
        "mma.sync.aligned.m16n8k16.row.col.f32.f16.f16.f32 "
        "{%0,%1,%2,%3}, {%4,%5,%6,%7}, {%8,%9}, {%0,%1,%2,%3};"
        : "+f"(d[0]), "+f"(d[1]), "+f"(d[2]), "+f"(d[3])
        : "r"(a[0]), "r"(a[1]), "r"(a[2]), "r"(a[3]), "r"(b0), "r"(b1));
}

__device__ __forceinline__ float silu_f(float g) {
    return g / (1.f + expf(-g));
}

// ===================== fp16 GEMM: C = A[M,K] @ B[K,N] (+bias) ================
// B in natural [K][N] layout; fragments via ldmatrix.trans.
// EPI: 0 = fp32 out (+resid), 1 = fp16 out, 2 = fp16 out * silu(gate)
#define BM 128
#define BN 128
#define GROWB 80                       // A row: 64 B data + 16 pad
#define GTILE_A (128 * GROWB)          // 10240
#define BROWB 272                      // B row: 256 B data + 16 pad
#define GTILE_B (32 * BROWB)           // 8704
#define STAGE_B (GTILE_A + GTILE_B)    // 18944
#define GSMEM (4 * STAGE_B)            // 75776

template<int EPI>
__global__ __launch_bounds__(256, 2)
void gemm_f16(const h16* __restrict__ Ah, const h16* __restrict__ Bh,
              const float* __restrict__ bias, const float* __restrict__ resid,
              const float* __restrict__ gate,
              void* __restrict__ Cv, int Ntot, int K)
{
    extern __shared__ char dsm[];
    const int tid = threadIdx.x;
    const int wid = tid >> 5, lane = tid & 31;
    const int rowA0 = blockIdx.y * BM;
    const int colB0 = blockIdx.x * BN;
    const int nIter = K >> 5;           // even (128 or 344)
    const uint32_t sbase = smem_u32(dsm);

    auto load_stage = [&](int it) {
        const int s = it & 3;
        const size_t koff = (size_t)it * 32;
        const uint32_t sa = sbase + s * STAGE_B;
        const uint32_t sbt = sa + GTILE_A;
        #pragma unroll
        for (int i = 0; i < 2; i++) {
            int idx = tid + i * 256;
            // A: 128 rows x 4 chunks (64 B/row)
            int ra = idx >> 2, sega = idx & 3;
            CP_ASYNC16(sa + ra * GROWB + sega * 16,
                       Ah + (size_t)(rowA0 + ra) * K + koff + sega * 8);
            // B: 32 rows x 16 chunks (256 B/row)
            int rb = idx >> 4, segb = idx & 15;
            CP_ASYNC16(sbt + rb * BROWB + segb * 16,
                       Bh + (koff + rb) * (size_t)Ntot + colB0 + segb * 8);
        }
        CP_COMMIT();
    };

    const int m0 = (wid >> 1) * 32;
    const int n0 = (wid & 1) * 64;

    float acc[2][8][4];
    #pragma unroll
    for (int i = 0; i < 2; i++)
        #pragma unroll
        for (int j = 0; j < 8; j++)
            #pragma unroll
            for (int c = 0; c < 4; c++) acc[i][j][c] = 0.f;

    const int mi = lane >> 3, l7 = lane & 7;
    const uint32_t aoff = (uint32_t)((m0 + (mi & 1) * 8 + l7) * GROWB + (mi >> 1) * 16);
    const uint32_t boff = (uint32_t)(((mi & 1) * 8 + l7) * BROWB + (n0 + (mi >> 1) * 8) * 2);

    auto compute = [&](int it) {
        const uint32_t sa = sbase + (it & 3) * STAGE_B;
        const uint32_t sbt = sa + GTILE_A;
        #pragma unroll
        for (int kk = 0; kk < 2; kk++) {
            uint32_t ah0[4], ah1[4];
            ldsm_x4(ah0, sa + aoff + kk * 32);
            ldsm_x4(ah1, sa + aoff + 16 * GROWB + kk * 32);
            #pragma unroll
            for (int g = 0; g < 4; g++) {
                uint32_t bh[4];
                ldsm_x4t(bh, sbt + boff + kk * 16 * BROWB + g * 32);
                mma_fp(acc[0][2*g+0], ah0, bh[0], bh[1]);
                mma_fp(acc[0][2*g+1], ah0, bh[2], bh[3]);
                mma_fp(acc[1][2*g+0], ah1, bh[0], bh[1]);
                mma_fp(acc[1][2*g+1], ah1, bh[2], bh[3]);
            }
        }
    };

    load_stage(0); load_stage(1);

    for (int it = 0; it < nIter; it += 2) {
        if (it + 2 < nIter) load_stage(it + 2); else CP_COMMIT();
        if (it + 3 < nIter) load_stage(it + 3); else CP_COMMIT();
        CP_WAIT(2);
        __syncthreads();
        compute(it);
        compute(it + 1);
        __syncthreads();
    }

    const int l4 = lane >> 2, l2 = (lane & 3) * 2;
    #pragma unroll
    for (int mf = 0; mf < 2; mf++) {
        const int r = rowA0 + m0 + mf * 16 + l4;
        #pragma unroll
        for (int nf = 0; nf < 8; nf++) {
            const int c = colB0 + n0 + nf * 8 + l2;
            float2 v0 = make_float2(acc[mf][nf][0], acc[mf][nf][1]);
            float2 v1 = make_float2(acc[mf][nf][2], acc[mf][nf][3]);
            if (bias) {
                v0.x += bias[c]; v0.y += bias[c + 1];
                v1.x += bias[c]; v1.y += bias[c + 1];
            }
            if (EPI == 0) {
                if (resid) {
                    const float2 r0 = *(const float2*)&resid[(size_t)r * Ntot + c];
                    const float2 r1 = *(const float2*)&resid[(size_t)(r + 8) * Ntot + c];
                    v0.x += r0.x; v0.y += r0.y;
                    v1.x += r1.x; v1.y += r1.y;
                }
                float* C = (float*)Cv;
                *(float2*)&C[(size_t)r * Ntot + c] = v0;
                *(float2*)&C[(size_t)(r + 8) * Ntot + c] = v1;
            } else {
                if (EPI == 2) {
                    const float2 g0 = *(const float2*)&gate[(size_t)r * Ntot + c];
                    const float2 g1 = *(const float2*)&gate[(size_t)(r + 8) * Ntot + c];
                    v0.x *= silu_f(g0.x); v0.y *= silu_f(g0.y);
                    v1.x *= silu_f(g1.x); v1.y *= silu_f(g1.y);
                }
                h16* C = (h16*)Cv;
                *(__half2*)&C[(size_t)r * Ntot + c] = __floats2half2_rn(v0.x, v0.y);
                *(__half2*)&C[(size_t)(r + 8) * Ntot + c] = __floats2half2_rn(v1.x, v1.y);
            }
        }
    }
}

// ===================== tensor-core flash attention (fp16, pipelined) =========
// Q pre-scaled. S = Q@K^T single-pass fp16. V double-buffered; K prefetch
// overlaps PV. QS = row stride of Q/K/V. Heavy tiles launch first.
#define AROW 272
#define PSROW 144
#define OFF_Q  0
#define OFF_K  (OFF_Q + 64 * AROW)
#define OFF_V0 (OFF_K + 64 * AROW)
#define OFF_V1 (OFF_V0 + 64 * AROW)
#define OFF_PS (OFF_V1 + 64 * AROW)
#define ATTN_SMEM (OFF_PS + 64 * PSROW)   // 78848

__global__ __launch_bounds__(128, 2)
void attn_mma_kernel(const h16* __restrict__ Q, const h16* __restrict__ K,
                     const h16* __restrict__ V, h16* __restrict__ Oh, int QS)
{
    extern __shared__ char asm_[];
    const uint32_t sb = smem_u32(asm_);
    const int qb = gridDim.x - 1 - blockIdx.x;   // longest first
    const int q0 = qb * 64;
    const int h  = blockIdx.y;
    const int tid = threadIdx.x;
    const int w = tid >> 5, lane = tid & 31;
    const int mi = lane >> 3, l7 = lane & 7;
    const size_t hoff = (size_t)h * HD_DIM;
    const int nIter = qb + 1;

    auto load_K = [&](int jj) {
        const int j0 = jj * 64;
        #pragma unroll
        for (int i = 0; i < 8; i++) {
            int idx = tid + i * 128;
            int r = idx >> 4, c = idx & 15;
            const size_t gsrc = (size_t)(j0 + r) * QS + hoff + c * 8;
            CP_ASYNC16(sb + OFF_K + r * AROW + c * 16, K + gsrc);
        }
        CP_COMMIT();
    };
    auto load_V = [&](int jj) {
        const int j0 = jj * 64;
        const uint32_t vb = sb + ((jj & 1) ? OFF_V1 : OFF_V0);
        #pragma unroll
        for (int i = 0; i < 8; i++) {
            int idx = tid + i * 128;
            int r = idx >> 4, c = idx & 15;
            const size_t gsrc = (size_t)(j0 + r) * QS + hoff + c * 8;
            CP_ASYNC16(vb + r * AROW + c * 16, V + gsrc);
        }
        CP_COMMIT();
    };

    #pragma unroll
    for (int i = 0; i < 8; i++) {
        int idx = tid + i * 128;
        int r = idx >> 4, c = idx & 15;
        const size_t gsrc = (size_t)(q0 + r) * QS + hoff + c * 8;
        CP_ASYNC16(sb + OFF_Q + r * AROW + c * 16, Q + gsrc);
    }
    CP_COMMIT();
    load_K(0);
    load_V(0);

    float oacc[16][4];
    #pragma unroll
    for (int f = 0; f < 16; f++)
        #pragma unroll
        for (int c = 0; c < 4; c++) oacc[f][c] = 0.f;
    float m0v = -1e30f, m1v = -1e30f, l0v = 0.f, l1v = 0.f;

    const uint32_t aq_off = (uint32_t)((w * 16 + (mi & 1) * 8 + l7) * AROW + (mi >> 1) * 16);
    const uint32_t bk_off = (uint32_t)(((mi >> 1) * 8 + l7) * AROW + (mi & 1) * 16);
    const uint32_t ps_off = (uint32_t)((w * 16 + (mi & 1) * 8 + l7) * PSROW + (mi >> 1) * 16);

    const int r0 = lane >> 2;
    const int gq0 = q0 + w * 16 + r0;
    const int gq1 = gq0 + 8;

    for (int jj = 0; jj < nIter; jj++) {
        const int j0 = jj * 64;
        CP_WAIT(1);
        __syncthreads();

        float sacc[8][4];
        #pragma unroll
        for (int f = 0; f < 8; f++)
            #pragma unroll
            for (int c = 0; c < 4; c++) sacc[f][c] = 0.f;

        #pragma unroll
        for (int ks = 0; ks < 8; ks++) {
            uint32_t a[4];
            ldsm_x4(a, sb + OFF_Q + aq_off + ks * 32);
            #pragma unroll
            for (int g = 0; g < 4; g++) {
                uint32_t b[4];
                ldsm_x4(b, sb + OFF_K + bk_off + g * 16 * AROW + ks * 32);
                mma_fp(sacc[2*g+0], a, b[0], b[1]);
                mma_fp(sacc[2*g+1], a, b[2], b[3]);
            }
        }

        if (j0 == q0) {
            #pragma unroll
            for (int f = 0; f < 8; f++) {
                int kvc = j0 + f * 8 + (lane & 3) * 2;
                if (kvc     > gq0) sacc[f][0] = -1e30f;
                if (kvc + 1 > gq0) sacc[f][1] = -1e30f;
                if (kvc     > gq1) sacc[f][2] = -1e30f;
                if (kvc + 1 > gq1) sacc[f][3] = -1e30f;
            }
        }

        float mx0 = -1e30f, mx1 = -1e30f;
        #pragma unroll
        for (int f = 0; f < 8; f++) {
            mx0 = fmaxf(mx0, fmaxf(sacc[f][0], sacc[f][1]));
            mx1 = fmaxf(mx1, fmaxf(sacc[f][2], sacc[f][3]));
        }
        mx0 = fmaxf(mx0, __shfl_xor_sync(0xffffffffu, mx0, 1));
        mx0 = fmaxf(mx0, __shfl_xor_sync(0xffffffffu, mx0, 2));
        mx1 = fmaxf(mx1, __shfl_xor_sync(0xffffffffu, mx1, 1));
        mx1 = fmaxf(mx1, __shfl_xor_sync(0xffffffffu, mx1, 2));
        const float mn0 = fmaxf(m0v, mx0), mn1 = fmaxf(m1v, mx1);
        float rs0 = 0.f, rs1 = 0.f;
        #pragma unroll
        for (int f = 0; f < 8; f++) {
            float p0 = expf(sacc[f][0] - mn0);
            float p1 = expf(sacc[f][1] - mn0);
            float p2 = expf(sacc[f][2] - mn1);
            float p3 = expf(sacc[f][3] - mn1);
            rs0 += p0 + p1; rs1 += p2 + p3;
            __half2 v01 = __floats2half2_rn(p0, p1);
            __half2 v23 = __floats2half2_rn(p2, p3);
            uint32_t col = (f * 8 + (lane & 3) * 2) * 2;
            *(uint32_t*)(asm_ + OFF_PS + (w * 16 + r0) * PSROW + col) = *(uint32_t*)&v01;
            *(uint32_t*)(asm_ + OFF_PS + (w * 16 + r0 + 8) * PSROW + col) = *(uint32_t*)&v23;
        }
        rs0 += __shfl_xor_sync(0xffffffffu, rs0, 1);
        rs0 += __shfl_xor_sync(0xffffffffu, rs0, 2);
        rs1 += __shfl_xor_sync(0xffffffffu, rs1, 1);
        rs1 += __shfl_xor_sync(0xffffffffu, rs1, 2);
        const float al0 = expf(m0v - mn0), al1 = expf(m1v - mn1);
        l0v = l0v * al0 + rs0; l1v = l1v * al1 + rs1;
        m0v = mn0; m1v = mn1;
        #pragma unroll
        for (int f = 0; f < 16; f++) {
            oacc[f][0] *= al0; oacc[f][1] *= al0;
            oacc[f][2] *= al1; oacc[f][3] *= al1;
        }
        __syncthreads();          // K reads done; PS visible

        if (jj + 1 < nIter) { load_K(jj + 1); load_V(jj + 1); }
        else                { CP_COMMIT(); CP_COMMIT(); }

        CP_WAIT(2);
        __syncthreads();

        const uint32_t vb = sb + ((jj & 1) ? OFF_V1 : OFF_V0);
        #pragma unroll
        for (int ks = 0; ks < 4; ks++) {
            uint32_t a[4];
            ldsm_x4(a, sb + OFF_PS + ps_off + ks * 32);
            #pragma unroll
            for (int g = 0; g < 8; g++) {
                uint32_t b[4];
                ldsm_x4t(b, vb + (ks * 16 + (mi & 1) * 8 + l7) * AROW
                               + (g * 16 + (mi >> 1) * 8) * 2);
                mma_fp(oacc[2*g+0], a, b[0], b[1]);
                mma_fp(oacc[2*g+1], a, b[2], b[3]);
            }
        }
    }

    const float i0 = 1.f / l0v, i1 = 1.f / l1v;
    #pragma unroll
    for (int f = 0; f < 16; f++) {
        int col = h * HD_DIM + f * 8 + (lane & 3) * 2;
        __half2 hh0 = __floats2half2_rn(oacc[f][0] * i0, oacc[f][1] * i0);
        __half2 hh1 = __floats2half2_rn(oacc[f][2] * i1, oacc[f][3] * i1);
        *(__half2*)&Oh[(size_t)gq0 * H_DIM + col] = hh0;
        *(__half2*)&Oh[(size_t)gq1 * H_DIM + col] = hh1;
    }
}

// ===================== elementwise / conversion kernels =====================
__global__ void rmsnorm_f16_kernel(const float* __restrict__ x,
                                   const float* __restrict__ scale,
                                   h16* __restrict__ oh)
{
    int row = blockIdx.x;
    const float4* xr = (const float4*)(x + (size_t)row * H_DIM);
    float ss = 0.f;
    for (int i = threadIdx.x; i < H_DIM / 4; i += blockDim.x) {
        float4 v = xr[i];
        ss += v.x * v.x + v.y * v.y + v.z * v.z + v.w * v.w;
    }
    #pragma unroll
    for (int off = 16; off; off >>= 1) ss += __shfl_xor_sync(0xffffffffu, ss, off);
    __shared__ float red[32];
    int lane = threadIdx.x & 31, wid = threadIdx.x >> 5;
    if (lane == 0) red[wid] = ss;
    __syncthreads();
    if (wid == 0) {
        ss = (lane < (int)(blockDim.x >> 5)) ? red[lane] : 0.f;
        #pragma unroll
        for (int off = 16; off; off >>= 1) ss += __shfl_xor_sync(0xffffffffu, ss, off);
        if (lane == 0) red[0] = ss;
    }
    __syncthreads();
    float inv = rsqrtf(red[0] / (float)H_DIM + EPS_V);
    const float4* sc = (const float4*)scale;
    for (int i = threadIdx.x; i < H_DIM / 4; i += blockDim.x) {
        float4 v = xr[i], s = sc[i];
        __half2 lo = __floats2half2_rn(v.x * inv * s.x, v.y * inv * s.y);
        __half2 hi = __floats2half2_rn(v.z * inv * s.z, v.w * inv * s.w);
        uint2 pack = {*(uint32_t*)&lo, *(uint32_t*)&hi};
        ((uint2*)(oh + (size_t)row * H_DIM))[i] = pack;
    }
}

// streaming fp32 -> fp16, same [K][N] layout; output row stride OS.
// N8 = N/8, i indexes groups of 8 elements.
__global__ void convert_f16_kernel(const float* __restrict__ W,
                                   h16* __restrict__ out,
                                   int N8, int OS, int total8)
{
    int i = blockIdx.x * blockDim.x + threadIdx.x;
    if (i >= total8) return;
    const float4* src = (const float4*)W + (size_t)i * 2;
    float4 a = src[0], b = src[1];
    __half2 h0 = __floats2half2_rn(a.x, a.y);
    __half2 h1 = __floats2half2_rn(a.z, a.w);
    __half2 h2 = __floats2half2_rn(b.x, b.y);
    __half2 h3 = __floats2half2_rn(b.z, b.w);
    int k = i / N8, n8 = i - k * N8;
    uint4 pack = {*(uint32_t*)&h0, *(uint32_t*)&h1, *(uint32_t*)&h2, *(uint32_t*)&h3};
    *(uint4*)(out + (size_t)k * OS + (size_t)n8 * 8) = pack;
}

__global__ void bias_cat_kernel(const float* __restrict__ bq,
                                const float* __restrict__ bk,
                                const float* __restrict__ bv,
                                float* __restrict__ cat)
{
    int i = blockIdx.x * blockDim.x + threadIdx.x;
    if (i < H_DIM)          cat[i] = bq[i];
    else if (i < 2 * H_DIM) cat[i] = bk[i - H_DIM];
    else if (i < 3 * H_DIM) cat[i] = bv[i - 2 * H_DIM];
}

// RoPE in-place on fp16 q,k inside the qkv buffer (row stride QS); q pre-scaled.
__global__ void rope_f16_kernel(h16* __restrict__ q, h16* __restrict__ k,
                                const int* __restrict__ pos, int QS)
{
    int idx = blockIdx.x * blockDim.x + threadIdx.x;
    if (idx >= T_DIM * NHEADS * (HD_DIM / 2)) return;
    int d  = idx & 63;
    int th = idx >> 6;
    int t  = th >> 5;
    int hh = th & 31;
    const float scaling = 0.08838834764831845f;
    float invf = powf(10000.0f, -(float)d * (1.0f / 64.0f));
    float ang = (float)pos[t] * invf;
    float c, s;
    sincosf(ang, &s, &c);
    size_t base = (size_t)t * QS + hh * HD_DIM + d;
    float q1 = __half2float(q[base]), q2 = __half2float(q[base + 64]);
    q[base]      = __float2half_rn((q1 * c - q2 * s) * scaling);
    q[base + 64] = __float2half_rn((q2 * c + q1 * s) * scaling);
    float k1 = __half2float(k[base]), k2 = __half2float(k[base + 64]);
    k[base]      = __float2half_rn(k1 * c - k2 * s);
    k[base + 64] = __float2half_rn(k2 * c + k1 * s);
}

// ===================== launch ================================================
extern "C" void kernel_launch(void* const* d_in, const int* in_sizes, int n_in,
                              void* d_out, int out_size)
{
    (void)in_sizes; (void)n_in; (void)out_size;
    const int*   positions = (const int*)  d_in[0];
    const float* hidden    = (const float*)d_in[1];
    const float* ln1       = (const float*)d_in[2];
    const float* wq = (const float*)d_in[3];
    const float* bq = (const float*)d_in[4];
    const float* wk = (const float*)d_in[5];
    const float* bk = (const float*)d_in[6];
    const float* wv = (const float*)d_in[7];
    const float* bv = (const float*)d_in[8];
    const float* wo = (const float*)d_in[9];
    const float* ln2= (const float*)d_in[10];
    const float* w1 = (const float*)d_in[11];
    const float* w2 = (const float*)d_in[12];
    const float* wc = (const float*)d_in[13];
    float* out = (float*)d_out;

    float *hbuf, *a2, *bqkv;
    h16 *xnh, *atth, *yh, *gh, *qkv16;
    h16 *wqkv, *woh, *w1h, *w2h, *wch;
    cudaGetSymbolAddress((void**)&hbuf,  g_h);
    cudaGetSymbolAddress((void**)&a2,    g_a2);
    cudaGetSymbolAddress((void**)&bqkv,  g_bqkv);
    cudaGetSymbolAddress((void**)&xnh,   g_xnh);
    cudaGetSymbolAddress((void**)&atth,  g_atth);
    cudaGetSymbolAddress((void**)&yh,    g_yh);
    cudaGetSymbolAddress((void**)&gh,    g_gh);
    cudaGetSymbolAddress((void**)&qkv16, g_qkv16);
    cudaGetSymbolAddress((void**)&wqkv,  g_wqkv);
    cudaGetSymbolAddress((void**)&woh,   g_woh);
    cudaGetSymbolAddress((void**)&w1h,   g_w1h);
    cudaGetSymbolAddress((void**)&w2h,   g_w2h);
    cudaGetSymbolAddress((void**)&wch,   g_wch);

    cudaFuncSetAttribute((gemm_f16<0>), cudaFuncAttributeMaxDynamicSharedMemorySize, GSMEM);
    cudaFuncSetAttribute((gemm_f16<1>), cudaFuncAttributeMaxDynamicSharedMemorySize, GSMEM);
    cudaFuncSetAttribute((gemm_f16<2>), cudaFuncAttributeMaxDynamicSharedMemorySize, GSMEM);
    cudaFuncSetAttribute(attn_mma_kernel, cudaFuncAttributeMaxDynamicSharedMemorySize, ATTN_SMEM);

    // weight conversions (streaming fp32->fp16, layout preserved)
    const int HH8 = H_DIM * H_DIM / 8;          // 2M groups
    const int HF8 = H_DIM * FF_DIM / 8;         // ~5.6M groups
    convert_f16_kernel<<<(HH8 + 255) / 256, 256>>>(wq, wqkv + 0,          H_DIM/8, QKV_N, HH8);
    convert_f16_kernel<<<(HH8 + 255) / 256, 256>>>(wk, wqkv + H_DIM,     H_DIM/8, QKV_N, HH8);
    convert_f16_kernel<<<(HH8 + 255) / 256, 256>>>(wv, wqkv + 2 * H_DIM, H_DIM/8, QKV_N, HH8);
    convert_f16_kernel<<<(HH8 + 255) / 256, 256>>>(wo, woh, H_DIM/8, H_DIM, HH8);
    convert_f16_kernel<<<(HF8 + 255) / 256, 256>>>(w1, w1h, FF_DIM/8, FF_DIM, HF8);
    convert_f16_kernel<<<(HF8 + 255) / 256, 256>>>(w2, w2h, FF_DIM/8, FF_DIM, HF8);
    convert_f16_kernel<<<(HF8 + 255) / 256, 256>>>(wc, wch, H_DIM/8, H_DIM, HF8);
    bias_cat_kernel<<<(QKV_N + 255) / 256, 256>>>(bq, bk, bv, bqkv);

    // 1) x = rmsnorm(hidden, ln1) -> fp16
    rmsnorm_f16_kernel<<<T_DIM, 256>>>(hidden, ln1, xnh);

    // 2) fused qkv GEMM (fp16 out)
    dim3 gQKV(QKV_N / BN, T_DIM / BM);
    gemm_f16<1><<<gQKV, 256, GSMEM>>>(xnh, wqkv, bqkv, nullptr, nullptr, qkv16, QKV_N, H_DIM);

    // 3) RoPE in place (q pre-scaled)
    rope_f16_kernel<<<(T_DIM * NHEADS * (HD_DIM / 2)) / 256, 256>>>(
        qkv16, qkv16 + H_DIM, positions, QKV_N);

    // 4) attention -> atth (fp16)
    attn_mma_kernel<<<dim3(T_DIM / 64, NHEADS), 128, ATTN_SMEM>>>(
        qkv16, qkv16 + H_DIM, qkv16 + 2 * H_DIM, atth, QKV_N);

    // 5) h = hidden + attn @ wo
    dim3 gH(H_DIM / BN, T_DIM / BM);
    gemm_f16<0><<<gH, 256, GSMEM>>>(atth, woh, nullptr, hidden, nullptr, hbuf, H_DIM, H_DIM);

    // 6) y = rmsnorm(h, ln2) -> fp16
    rmsnorm_f16_kernel<<<T_DIM, 256>>>(hbuf, ln2, yh);

    // 7) MLP: a2 = y@w2 (fp32); gh = (y@w1) * silu(a2) fused, fp16 out
    dim3 gF(FF_DIM / BN, T_DIM / BM);
    gemm_f16<0><<<gF, 256, GSMEM>>>(yh, w2h, nullptr, nullptr, nullptr, a2, FF_DIM, H_DIM);
    gemm_f16<2><<<gF, 256, GSMEM>>>(yh, w1h, nullptr, nullptr, a2, gh, FF_DIM, H_DIM);

    // 8) out = h + gh @ wc
    gemm_f16<0><<<gH, 256, GSMEM>>>(gh, wch, nullptr, hbuf, nullptr, out, H_DIM, FF_DIM);
}

// round 14
// speedup vs baseline: 7.8782x; 1.0284x over previous
#include <cuda_runtime.h>
#include <cuda_fp16.h>
#include <math.h>
#include <cstdint>

#define T_DIM 2048
#define H_DIM 4096
#define NHEADS 32
#define HD_DIM 128
#define FF_DIM 11008
#define QKV_N (3 * H_DIM)          // 12288
#define MLP_N (2 * FF_DIM)         // 22016 (interleaved w1|w2)
#define EPS_V 1e-6f

typedef __half h16;

// ===================== device scratch ======================================
__device__ float g_h   [(size_t)T_DIM * H_DIM];
__device__ float g_bqkv[QKV_N];

__device__ h16 g_xnh  [(size_t)T_DIM * H_DIM];
__device__ h16 g_atth [(size_t)T_DIM * H_DIM];
__device__ h16 g_yh   [(size_t)T_DIM * H_DIM];
__device__ h16 g_gh   [(size_t)T_DIM * FF_DIM];
__device__ h16 g_qkv16[(size_t)T_DIM * QKV_N];

// weights fp16, [K][N] row-major (same layout as input)
__device__ h16 g_wqkv[(size_t)H_DIM * QKV_N];
__device__ h16 g_woh [(size_t)H_DIM * H_DIM];
__device__ h16 g_w12 [(size_t)H_DIM * MLP_N];   // interleaved w1/w2
__device__ h16 g_wch [(size_t)FF_DIM * H_DIM];

// ===================== PTX helpers =========================================
__device__ __forceinline__ uint32_t smem_u32(const void* p) {
    uint32_t a;
    asm("{ .reg .u64 t; cvta.to.shared.u64 t, %1; cvt.u32.u64 %0, t; }"
        : "=r"(a) : "l"(p));
    return a;
}

#define CP_ASYNC16(dst, src) \
    asm volatile("cp.async.cg.shared.global [%0], [%1], 16;" :: "r"(dst), "l"(src))
#define CP_COMMIT() asm volatile("cp.async.commit_group;" ::: "memory")
#define CP_WAIT(n)  asm volatile("cp.async.wait_group %0;" :: "n"(n) : "memory")

__device__ __forceinline__ void ldsm_x4(uint32_t* r, uint32_t a) {
    asm volatile("ldmatrix.sync.aligned.m8n8.x4.shared.b16 {%0,%1,%2,%3}, [%4];"
        : "=r"(r[0]), "=r"(r[1]), "=r"(r[2]), "=r"(r[3]) : "r"(a));
}
__device__ __forceinline__ void ldsm_x4t(uint32_t* r, uint32_t a) {
    asm volatile("ldmatrix.sync.aligned.m8n8.x4.trans.shared.b16 {%0,%1,%2,%3}, [%4];"
        : "=r"(r[0]), "=r"(r[1]), "=r"(r[2]), "=r"(r[3]) : "r"(a));
}

__device__ __forceinline__ void mma_fp(float* d, const uint32_t* a,
                                       uint32_t b0, uint32_t b1) {
    asm volatile(
        "mma.sync.aligned.m16n8k16.row.col.f32.f16.f16.f32 "
        "{%0,%1,%2,%3}, {%4,%5,%6,%7}, {%8,%9}, {%0,%1,%2,%3};"
        : "+f"(d[0]), "+f"(d[1]), "+f"(d[2]), "+f"(d[3])
        : "r"(a[0]), "r"(a[1]), "r"(a[2]), "r"(a[3]), "r"(b0), "r"(b1));
}

__device__ __forceinline__ float silu_f(float g) {
    return g / (1.f + expf(-g));
}

// ===================== fp16 GEMM: C = A[M,K] @ B[K,N] (+bias) ================
// B in natural [K][N] layout; fragments via ldmatrix.trans.
// EPI: 0 = fp32 out (+resid), 1 = fp16 out,
//      3 = interleaved gated MLP: acc pairs (a1,a2) -> fp16 a1*silu(a2),
//          output width Ntot/2.
#define BM 128
#define BN 128
#define GROWB 80
#define GTILE_A (128 * GROWB)
#define BROWB 272
#define GTILE_B (32 * BROWB)
#define STAGE_B (GTILE_A + GTILE_B)
#define GSMEM (4 * STAGE_B)            // 75776

template<int EPI>
__global__ __launch_bounds__(256, 2)
void gemm_f16(const h16* __restrict__ Ah, const h16* __restrict__ Bh,
              const float* __restrict__ bias, const float* __restrict__ resid,
              void* __restrict__ Cv, int Ntot, int K)
{
    extern __shared__ char dsm[];
    const int tid = threadIdx.x;
    const int wid = tid >> 5, lane = tid & 31;
    const int rowA0 = blockIdx.y * BM;
    const int colB0 = blockIdx.x * BN;
    const int nIter = K >> 5;
    const uint32_t sbase = smem_u32(dsm);

    auto load_stage = [&](int it) {
        const int s = it & 3;
        const size_t koff = (size_t)it * 32;
        const uint32_t sa = sbase + s * STAGE_B;
        const uint32_t sbt = sa + GTILE_A;
        #pragma unroll
        for (int i = 0; i < 2; i++) {
            int idx = tid + i * 256;
            int ra = idx >> 2, sega = idx & 3;
            CP_ASYNC16(sa + ra * GROWB + sega * 16,
                       Ah + (size_t)(rowA0 + ra) * K + koff + sega * 8);
            int rb = idx >> 4, segb = idx & 15;
            CP_ASYNC16(sbt + rb * BROWB + segb * 16,
                       Bh + (koff + rb) * (size_t)Ntot + colB0 + segb * 8);
        }
        CP_COMMIT();
    };

    const int m0 = (wid >> 1) * 32;
    const int n0 = (wid & 1) * 64;

    float acc[2][8][4];
    #pragma unroll
    for (int i = 0; i < 2; i++)
        #pragma unroll
        for (int j = 0; j < 8; j++)
            #pragma unroll
            for (int c = 0; c < 4; c++) acc[i][j][c] = 0.f;

    const int mi = lane >> 3, l7 = lane & 7;
    const uint32_t aoff = (uint32_t)((m0 + (mi & 1) * 8 + l7) * GROWB + (mi >> 1) * 16);
    const uint32_t boff = (uint32_t)(((mi & 1) * 8 + l7) * BROWB + (n0 + (mi >> 1) * 8) * 2);

    auto compute = [&](int it) {
        const uint32_t sa = sbase + (it & 3) * STAGE_B;
        const uint32_t sbt = sa + GTILE_A;
        #pragma unroll
        for (int kk = 0; kk < 2; kk++) {
            uint32_t ah0[4], ah1[4];
            ldsm_x4(ah0, sa + aoff + kk * 32);
            ldsm_x4(ah1, sa + aoff + 16 * GROWB + kk * 32);
            #pragma unroll
            for (int g = 0; g < 4; g++) {
                uint32_t bh[4];
                ldsm_x4t(bh, sbt + boff + kk * 16 * BROWB + g * 32);
                mma_fp(acc[0][2*g+0], ah0, bh[0], bh[1]);
                mma_fp(acc[0][2*g+1], ah0, bh[2], bh[3]);
                mma_fp(acc[1][2*g+0], ah1, bh[0], bh[1]);
                mma_fp(acc[1][2*g+1], ah1, bh[2], bh[3]);
            }
        }
    };

    load_stage(0); load_stage(1);

    for (int it = 0; it < nIter; it += 2) {
        if (it + 2 < nIter) load_stage(it + 2); else CP_COMMIT();
        if (it + 3 < nIter) load_stage(it + 3); else CP_COMMIT();
        CP_WAIT(2);
        __syncthreads();
        compute(it);
        compute(it + 1);
        __syncthreads();
    }

    const int l4 = lane >> 2, l2 = (lane & 3) * 2;
    #pragma unroll
    for (int mf = 0; mf < 2; mf++) {
        const int r = rowA0 + m0 + mf * 16 + l4;
        #pragma unroll
        for (int nf = 0; nf < 8; nf++) {
            const int c = colB0 + n0 + nf * 8 + l2;
            float2 v0 = make_float2(acc[mf][nf][0], acc[mf][nf][1]);
            float2 v1 = make_float2(acc[mf][nf][2], acc[mf][nf][3]);
            if (bias) {
                v0.x += bias[c]; v0.y += bias[c + 1];
                v1.x += bias[c]; v1.y += bias[c + 1];
            }
            if (EPI == 0) {
                if (resid) {
                    const float2 r0 = *(const float2*)&resid[(size_t)r * Ntot + c];
                    const float2 r1 = *(const float2*)&resid[(size_t)(r + 8) * Ntot + c];
                    v0.x += r0.x; v0.y += r0.y;
                    v1.x += r1.x; v1.y += r1.y;
                }
                float* C = (float*)Cv;
                *(float2*)&C[(size_t)r * Ntot + c] = v0;
                *(float2*)&C[(size_t)(r + 8) * Ntot + c] = v1;
            } else if (EPI == 1) {
                h16* C = (h16*)Cv;
                *(__half2*)&C[(size_t)r * Ntot + c] = __floats2half2_rn(v0.x, v0.y);
                *(__half2*)&C[(size_t)(r + 8) * Ntot + c] = __floats2half2_rn(v1.x, v1.y);
            } else { // EPI == 3: acc pair = (a1, a2) interleaved; out width Ntot/2
                const int No = Ntot >> 1;
                const int j = c >> 1;
                h16* C = (h16*)Cv;
                C[(size_t)r * No + j]       = __float2half_rn(v0.x * silu_f(v0.y));
                C[(size_t)(r + 8) * No + j] = __float2half_rn(v1.x * silu_f(v1.y));
            }
        }
    }
}

// ===================== tensor-core flash attention (fp16, pipelined) =========
#define AROW 272
#define PSROW 144
#define OFF_Q  0
#define OFF_K  (OFF_Q + 64 * AROW)
#define OFF_V0 (OFF_K + 64 * AROW)
#define OFF_V1 (OFF_V0 + 64 * AROW)
#define OFF_PS (OFF_V1 + 64 * AROW)
#define ATTN_SMEM (OFF_PS + 64 * PSROW)   // 78848

__global__ __launch_bounds__(128, 2)
void attn_mma_kernel(const h16* __restrict__ Q, const h16* __restrict__ K,
                     const h16* __restrict__ V, h16* __restrict__ Oh, int QS)
{
    extern __shared__ char asm_[];
    const uint32_t sb = smem_u32(asm_);
    const int qb = gridDim.x - 1 - blockIdx.x;   // longest first
    const int q0 = qb * 64;
    const int h  = blockIdx.y;
    const int tid = threadIdx.x;
    const int w = tid >> 5, lane = tid & 31;
    const int mi = lane >> 3, l7 = lane & 7;
    const size_t hoff = (size_t)h * HD_DIM;
    const int nIter = qb + 1;

    auto load_K = [&](int jj) {
        const int j0 = jj * 64;
        #pragma unroll
        for (int i = 0; i < 8; i++) {
            int idx = tid + i * 128;
            int r = idx >> 4, c = idx & 15;
            const size_t gsrc = (size_t)(j0 + r) * QS + hoff + c * 8;
            CP_ASYNC16(sb + OFF_K + r * AROW + c * 16, K + gsrc);
        }
        CP_COMMIT();
    };
    auto load_V = [&](int jj) {
        const int j0 = jj * 64;
        const uint32_t vb = sb + ((jj & 1) ? OFF_V1 : OFF_V0);
        #pragma unroll
        for (int i = 0; i < 8; i++) {
            int idx = tid + i * 128;
            int r = idx >> 4, c = idx & 15;
            const size_t gsrc = (size_t)(j0 + r) * QS + hoff + c * 8;
            CP_ASYNC16(vb + r * AROW + c * 16, V + gsrc);
        }
        CP_COMMIT();
    };

    #pragma unroll
    for (int i = 0; i < 8; i++) {
        int idx = tid + i * 128;
        int r = idx >> 4, c = idx & 15;
        const size_t gsrc = (size_t)(q0 + r) * QS + hoff + c * 8;
        CP_ASYNC16(sb + OFF_Q + r * AROW + c * 16, Q + gsrc);
    }
    CP_COMMIT();
    load_K(0);
    load_V(0);

    float oacc[16][4];
    #pragma unroll
    for (int f = 0; f < 16; f++)
        #pragma unroll
        for (int c = 0; c < 4; c++) oacc[f][c] = 0.f;
    float m0v = -1e30f, m1v = -1e30f, l0v = 0.f, l1v = 0.f;

    const uint32_t aq_off = (uint32_t)((w * 16 + (mi & 1) * 8 + l7) * AROW + (mi >> 1) * 16);
    const uint32_t bk_off = (uint32_t)(((mi >> 1) * 8 + l7) * AROW + (mi & 1) * 16);
    const uint32_t ps_off = (uint32_t)((w * 16 + (mi & 1) * 8 + l7) * PSROW + (mi >> 1) * 16);

    const int r0 = lane >> 2;
    const int gq0 = q0 + w * 16 + r0;
    const int gq1 = gq0 + 8;

    for (int jj = 0; jj < nIter; jj++) {
        const int j0 = jj * 64;
        CP_WAIT(1);
        __syncthreads();

        float sacc[8][4];
        #pragma unroll
        for (int f = 0; f < 8; f++)
            #pragma unroll
            for (int c = 0; c < 4; c++) sacc[f][c] = 0.f;

        #pragma unroll
        for (int ks = 0; ks < 8; ks++) {
            uint32_t a[4];
            ldsm_x4(a, sb + OFF_Q + aq_off + ks * 32);
            #pragma unroll
            for (int g = 0; g < 4; g++) {
                uint32_t b[4];
                ldsm_x4(b, sb + OFF_K + bk_off + g * 16 * AROW + ks * 32);
                mma_fp(sacc[2*g+0], a, b[0], b[1]);
                mma_fp(sacc[2*g+1], a, b[2], b[3]);
            }
        }

        if (j0 == q0) {
            #pragma unroll
            for (int f = 0; f < 8; f++) {
                int kvc = j0 + f * 8 + (lane & 3) * 2;
                if (kvc     > gq0) sacc[f][0] = -1e30f;
                if (kvc + 1 > gq0) sacc[f][1] = -1e30f;
                if (kvc     > gq1) sacc[f][2] = -1e30f;
                if (kvc + 1 > gq1) sacc[f][3] = -1e30f;
            }
        }

        float mx0 = -1e30f, mx1 = -1e30f;
        #pragma unroll
        for (int f = 0; f < 8; f++) {
            mx0 = fmaxf(mx0, fmaxf(sacc[f][0], sacc[f][1]));
            mx1 = fmaxf(mx1, fmaxf(sacc[f][2], sacc[f][3]));
        }
        mx0 = fmaxf(mx0, __shfl_xor_sync(0xffffffffu, mx0, 1));
        mx0 = fmaxf(mx0, __shfl_xor_sync(0xffffffffu, mx0, 2));
        mx1 = fmaxf(mx1, __shfl_xor_sync(0xffffffffu, mx1, 1));
        mx1 = fmaxf(mx1, __shfl_xor_sync(0xffffffffu, mx1, 2));
        const float mn0 = fmaxf(m0v, mx0), mn1 = fmaxf(m1v, mx1);
        float rs0 = 0.f, rs1 = 0.f;
        #pragma unroll
        for (int f = 0; f < 8; f++) {
            float p0 = expf(sacc[f][0] - mn0);
            float p1 = expf(sacc[f][1] - mn0);
            float p2 = expf(sacc[f][2] - mn1);
            float p3 = expf(sacc[f][3] - mn1);
            rs0 += p0 + p1; rs1 += p2 + p3;
            __half2 v01 = __floats2half2_rn(p0, p1);
            __half2 v23 = __floats2half2_rn(p2, p3);
            uint32_t col = (f * 8 + (lane & 3) * 2) * 2;
            *(uint32_t*)(asm_ + OFF_PS + (w * 16 + r0) * PSROW + col) = *(uint32_t*)&v01;
            *(uint32_t*)(asm_ + OFF_PS + (w * 16 + r0 + 8) * PSROW + col) = *(uint32_t*)&v23;
        }
        rs0 += __shfl_xor_sync(0xffffffffu, rs0, 1);
        rs0 += __shfl_xor_sync(0xffffffffu, rs0, 2);
        rs1 += __shfl_xor_sync(0xffffffffu, rs1, 1);
        rs1 += __shfl_xor_sync(0xffffffffu, rs1, 2);
        const float al0 = expf(m0v - mn0), al1 = expf(m1v - mn1);
        l0v = l0v * al0 + rs0; l1v = l1v * al1 + rs1;
        m0v = mn0; m1v = mn1;
        #pragma unroll
        for (int f = 0; f < 16; f++) {
            oacc[f][0] *= al0; oacc[f][1] *= al0;
            oacc[f][2] *= al1; oacc[f][3] *= al1;
        }
        __syncthreads();

        if (jj + 1 < nIter) { load_K(jj + 1); load_V(jj + 1); }
        else                { CP_COMMIT(); CP_COMMIT(); }

        CP_WAIT(2);
        __syncthreads();

        const uint32_t vb = sb + ((jj & 1) ? OFF_V1 : OFF_V0);
        #pragma unroll
        for (int ks = 0; ks < 4; ks++) {
            uint32_t a[4];
            ldsm_x4(a, sb + OFF_PS + ps_off + ks * 32);
            #pragma unroll
            for (int g = 0; g < 8; g++) {
                uint32_t b[4];
                ldsm_x4t(b, vb + (ks * 16 + (mi & 1) * 8 + l7) * AROW
                               + (g * 16 + (mi >> 1) * 8) * 2);
                mma_fp(oacc[2*g+0], a, b[0], b[1]);
                mma_fp(oacc[2*g+1], a, b[2], b[3]);
            }
        }
    }

    const float i0 = 1.f / l0v, i1 = 1.f / l1v;
    #pragma unroll
    for (int f = 0; f < 16; f++) {
        int col = h * HD_DIM + f * 8 + (lane & 3) * 2;
        __half2 hh0 = __floats2half2_rn(oacc[f][0] * i0, oacc[f][1] * i0);
        __half2 hh1 = __floats2half2_rn(oacc[f][2] * i1, oacc[f][3] * i1);
        *(__half2*)&Oh[(size_t)gq0 * H_DIM + col] = hh0;
        *(__half2*)&Oh[(size_t)gq1 * H_DIM + col] = hh1;
    }
}

// ===================== elementwise / conversion kernels =====================
__global__ void rmsnorm_f16_kernel(const float* __restrict__ x,
                                   const float* __restrict__ scale,
                                   h16* __restrict__ oh)
{
    int row = blockIdx.x;
    const float4* xr = (const float4*)(x + (size_t)row * H_DIM);
    float ss = 0.f;
    for (int i = threadIdx.x; i < H_DIM / 4; i += blockDim.x) {
        float4 v = xr[i];
        ss += v.x * v.x + v.y * v.y + v.z * v.z + v.w * v.w;
    }
    #pragma unroll
    for (int off = 16; off; off >>= 1) ss += __shfl_xor_sync(0xffffffffu, ss, off);
    __shared__ float red[32];
    int lane = threadIdx.x & 31, wid = threadIdx.x >> 5;
    if (lane == 0) red[wid] = ss;
    __syncthreads();
    if (wid == 0) {
        ss = (lane < (int)(blockDim.x >> 5)) ? red[lane] : 0.f;
        #pragma unroll
        for (int off = 16; off; off >>= 1) ss += __shfl_xor_sync(0xffffffffu, ss, off);
        if (lane == 0) red[0] = ss;
    }
    __syncthreads();
    float inv = rsqrtf(red[0] / (float)H_DIM + EPS_V);
    const float4* sc = (const float4*)scale;
    for (int i = threadIdx.x; i < H_DIM / 4; i += blockDim.x) {
        float4 v = xr[i], s = sc[i];
        __half2 lo = __floats2half2_rn(v.x * inv * s.x, v.y * inv * s.y);
        __half2 hi = __floats2half2_rn(v.z * inv * s.z, v.w * inv * s.w);
        uint2 pack = {*(uint32_t*)&lo, *(uint32_t*)&hi};
        ((uint2*)(oh + (size_t)row * H_DIM))[i] = pack;
    }
}

// streaming fp32 -> fp16, same [K][N] layout; output row stride OS.
__global__ void convert_f16_kernel(const float* __restrict__ W,
                                   h16* __restrict__ out,
                                   int N8, int OS, int total8)
{
    int i = blockIdx.x * blockDim.x + threadIdx.x;
    if (i >= total8) return;
    const float4* src = (const float4*)W + (size_t)i * 2;
    float4 a = src[0], b = src[1];
    __half2 h0 = __floats2half2_rn(a.x, a.y);
    __half2 h1 = __floats2half2_rn(a.z, a.w);
    __half2 h2 = __floats2half2_rn(b.x, b.y);
    __half2 h3 = __floats2half2_rn(b.z, b.w);
    int k = i / N8, n8 = i - k * N8;
    uint4 pack = {*(uint32_t*)&h0, *(uint32_t*)&h1, *(uint32_t*)&h2, *(uint32_t*)&h3};
    *(uint4*)(out + (size_t)k * OS + (size_t)n8 * 8) = pack;
}

// w1,w2 fp32 [K][FF] -> interleaved fp16 [K][2*FF]: out[k][2j]=w1, out[k][2j+1]=w2
__global__ void convert_pair_kernel(const float* __restrict__ W1,
                                    const float* __restrict__ W2,
                                    h16* __restrict__ out, int total8)
{
    int i = blockIdx.x * blockDim.x + threadIdx.x;
    if (i >= total8) return;    // i indexes groups of 8 source elements
    const float4* s1 = (const float4*)W1 + (size_t)i * 2;
    const float4* s2 = (const float4*)W2 + (size_t)i * 2;
    float4 a1 = s1[0], b1 = s1[1];
    float4 a2 = s2[0], b2 = s2[1];
    __half2 p0 = __floats2half2_rn(a1.x, a2.x);
    __half2 p1 = __floats2half2_rn(a1.y, a2.y);
    __half2 p2 = __floats2half2_rn(a1.z, a2.z);
    __half2 p3 = __floats2half2_rn(a1.w, a2.w);
    __half2 p4 = __floats2half2_rn(b1.x, b2.x);
    __half2 p5 = __floats2half2_rn(b1.y, b2.y);
    __half2 p6 = __floats2half2_rn(b1.z, b2.z);
    __half2 p7 = __floats2half2_rn(b1.w, b2.w);
    uint4 lo = {*(uint32_t*)&p0, *(uint32_t*)&p1, *(uint32_t*)&p2, *(uint32_t*)&p3};
    uint4 hi = {*(uint32_t*)&p4, *(uint32_t*)&p5, *(uint32_t*)&p6, *(uint32_t*)&p7};
    uint4* dst = (uint4*)(out + (size_t)i * 16);
    dst[0] = lo;
    dst[1] = hi;
}

__global__ void bias_cat_kernel(const float* __restrict__ bq,
                                const float* __restrict__ bk,
                                const float* __restrict__ bv,
                                float* __restrict__ cat)
{
    int i = blockIdx.x * blockDim.x + threadIdx.x;
    if (i < H_DIM)          cat[i] = bq[i];
    else if (i < 2 * H_DIM) cat[i] = bk[i - H_DIM];
    else if (i < 3 * H_DIM) cat[i] = bv[i - 2 * H_DIM];
}

// RoPE in-place on fp16 q,k inside the qkv buffer (row stride QS); q pre-scaled.
__global__ void rope_f16_kernel(h16* __restrict__ q, h16* __restrict__ k,
                                const int* __restrict__ pos, int QS)
{
    int idx = blockIdx.x * blockDim.x + threadIdx.x;
    if (idx >= T_DIM * NHEADS * (HD_DIM / 2)) return;
    int d  = idx & 63;
    int th = idx >> 6;
    int t  = th >> 5;
    int hh = th & 31;
    const float scaling = 0.08838834764831845f;
    float invf = powf(10000.0f, -(float)d * (1.0f / 64.0f));
    float ang = (float)pos[t] * invf;
    float c, s;
    sincosf(ang, &s, &c);
    size_t base = (size_t)t * QS + hh * HD_DIM + d;
    float q1 = __half2float(q[base]), q2 = __half2float(q[base + 64]);
    q[base]      = __float2half_rn((q1 * c - q2 * s) * scaling);
    q[base + 64] = __float2half_rn((q2 * c + q1 * s) * scaling);
    float k1 = __half2float(k[base]), k2 = __half2float(k[base + 64]);
    k[base]      = __float2half_rn(k1 * c - k2 * s);
    k[base + 64] = __float2half_rn(k2 * c + k1 * s);
}

// ===================== launch ================================================
extern "C" void kernel_launch(void* const* d_in, const int* in_sizes, int n_in,
                              void* d_out, int out_size)
{
    (void)in_sizes; (void)n_in; (void)out_size;
    const int*   positions = (const int*)  d_in[0];
    const float* hidden    = (const float*)d_in[1];
    const float* ln1       = (const float*)d_in[2];
    const float* wq = (const float*)d_in[3];
    const float* bq = (const float*)d_in[4];
    const float* wk = (const float*)d_in[5];
    const float* bk = (const float*)d_in[6];
    const float* wv = (const float*)d_in[7];
    const float* bv = (const float*)d_in[8];
    const float* wo = (const float*)d_in[9];
    const float* ln2= (const float*)d_in[10];
    const float* w1 = (const float*)d_in[11];
    const float* w2 = (const float*)d_in[12];
    const float* wc = (const float*)d_in[13];
    float* out = (float*)d_out;

    float *hbuf, *bqkv;
    h16 *xnh, *atth, *yh, *gh, *qkv16;
    h16 *wqkv, *woh, *w12, *wch;
    cudaGetSymbolAddress((void**)&hbuf,  g_h);
    cudaGetSymbolAddress((void**)&bqkv,  g_bqkv);
    cudaGetSymbolAddress((void**)&xnh,   g_xnh);
    cudaGetSymbolAddress((void**)&atth,  g_atth);
    cudaGetSymbolAddress((void**)&yh,    g_yh);
    cudaGetSymbolAddress((void**)&gh,    g_gh);
    cudaGetSymbolAddress((void**)&qkv16, g_qkv16);
    cudaGetSymbolAddress((void**)&wqkv,  g_wqkv);
    cudaGetSymbolAddress((void**)&woh,   g_woh);
    cudaGetSymbolAddress((void**)&w12,   g_w12);
    cudaGetSymbolAddress((void**)&wch,   g_wch);

    cudaFuncSetAttribute((gemm_f16<0>), cudaFuncAttributeMaxDynamicSharedMemorySize, GSMEM);
    cudaFuncSetAttribute((gemm_f16<1>), cudaFuncAttributeMaxDynamicSharedMemorySize, GSMEM);
    cudaFuncSetAttribute((gemm_f16<3>), cudaFuncAttributeMaxDynamicSharedMemorySize, GSMEM);
    cudaFuncSetAttribute(attn_mma_kernel, cudaFuncAttributeMaxDynamicSharedMemorySize, ATTN_SMEM);

    // weight conversions (streaming fp32->fp16)
    const int HH8 = H_DIM * H_DIM / 8;
    const int HF8 = H_DIM * FF_DIM / 8;
    convert_f16_kernel<<<(HH8 + 255) / 256, 256>>>(wq, wqkv + 0,         H_DIM/8, QKV_N, HH8);
    convert_f16_kernel<<<(HH8 + 255) / 256, 256>>>(wk, wqkv + H_DIM,     H_DIM/8, QKV_N, HH8);
    convert_f16_kernel<<<(HH8 + 255) / 256, 256>>>(wv, wqkv + 2 * H_DIM, H_DIM/8, QKV_N, HH8);
    convert_f16_kernel<<<(HH8 + 255) / 256, 256>>>(wo, woh, H_DIM/8, H_DIM, HH8);
    convert_pair_kernel<<<(HF8 + 255) / 256, 256>>>(w1, w2, w12, HF8);
    convert_f16_kernel<<<(HF8 + 255) / 256, 256>>>(wc, wch, H_DIM/8, H_DIM, HF8);
    bias_cat_kernel<<<(QKV_N + 255) / 256, 256>>>(bq, bk, bv, bqkv);

    // 1) x = rmsnorm(hidden, ln1) -> fp16
    rmsnorm_f16_kernel<<<T_DIM, 256>>>(hidden, ln1, xnh);

    // 2) fused qkv GEMM (fp16 out)
    dim3 gQKV(QKV_N / BN, T_DIM / BM);
    gemm_f16<1><<<gQKV, 256, GSMEM>>>(xnh, wqkv, bqkv, nullptr, qkv16, QKV_N, H_DIM);

    // 3) RoPE in place (q pre-scaled)
    rope_f16_kernel<<<(T_DIM * NHEADS * (HD_DIM / 2)) / 256, 256>>>(
        qkv16, qkv16 + H_DIM, positions, QKV_N);

    // 4) attention -> atth (fp16)
    attn_mma_kernel<<<dim3(T_DIM / 64, NHEADS), 128, ATTN_SMEM>>>(
        qkv16, qkv16 + H_DIM, qkv16 + 2 * H_DIM, atth, QKV_N);

    // 5) h = hidden + attn @ wo
    dim3 gH(H_DIM / BN, T_DIM / BM);
    gemm_f16<0><<<gH, 256, GSMEM>>>(atth, woh, nullptr, hidden, hbuf, H_DIM, H_DIM);

    // 6) y = rmsnorm(h, ln2) -> fp16
    rmsnorm_f16_kernel<<<T_DIM, 256>>>(hbuf, ln2, yh);

    // 7) fused gated MLP: gh = (y@w1) * silu(y@w2), single interleaved GEMM
    dim3 gF2(MLP_N / BN, T_DIM / BM);
    gemm_f16<3><<<gF2, 256, GSMEM>>>(yh, w12, nullptr, nullptr, gh, MLP_N, H_DIM);

    // 8) out = h + gh @ wc
    gemm_f16<0><<<gH, 256, GSMEM>>>(gh, wch, nullptr, hbuf, out, H_DIM, FF_DIM);
}

// round 15
// speedup vs baseline: 7.9210x; 1.0054x over previous
#include <cuda_runtime.h>
#include <cuda_fp16.h>
#include <math.h>
#include <cstdint>

#define T_DIM 2048
#define H_DIM 4096
#define NHEADS 32
#define HD_DIM 128
#define FF_DIM 11008
#define QKV_N (3 * H_DIM)          // 12288
#define MLP_N (2 * FF_DIM)         // 22016 (interleaved w1|w2)
#define EPS_V 1e-6f

typedef __half h16;

// ===================== device scratch ======================================
__device__ float g_h   [(size_t)T_DIM * H_DIM];
__device__ float g_bqkv[QKV_N];

__device__ h16 g_xnh  [(size_t)T_DIM * H_DIM];
__device__ h16 g_atth [(size_t)T_DIM * H_DIM];
__device__ h16 g_yh   [(size_t)T_DIM * H_DIM];
__device__ h16 g_gh   [(size_t)T_DIM * FF_DIM];
__device__ h16 g_qkv16[(size_t)T_DIM * QKV_N];

// weights fp16, [K][N] row-major (same layout as input)
__device__ h16 g_wqkv[(size_t)H_DIM * QKV_N];
__device__ h16 g_woh [(size_t)H_DIM * H_DIM];
__device__ h16 g_w12 [(size_t)H_DIM * MLP_N];   // interleaved w1/w2
__device__ h16 g_wch [(size_t)FF_DIM * H_DIM];

// ===================== PTX helpers =========================================
__device__ __forceinline__ uint32_t smem_u32(const void* p) {
    uint32_t a;
    asm("{ .reg .u64 t; cvta.to.shared.u64 t, %1; cvt.u32.u64 %0, t; }"
        : "=r"(a) : "l"(p));
    return a;
}

#define CP_ASYNC16(dst, src) \
    asm volatile("cp.async.cg.shared.global [%0], [%1], 16;" :: "r"(dst), "l"(src))
#define CP_COMMIT() asm volatile("cp.async.commit_group;" ::: "memory")
#define CP_WAIT(n)  asm volatile("cp.async.wait_group %0;" :: "n"(n) : "memory")

__device__ __forceinline__ void ldsm_x4(uint32_t* r, uint32_t a) {
    asm volatile("ldmatrix.sync.aligned.m8n8.x4.shared.b16 {%0,%1,%2,%3}, [%4];"
        : "=r"(r[0]), "=r"(r[1]), "=r"(r[2]), "=r"(r[3]) : "r"(a));
}
__device__ __forceinline__ void ldsm_x4t(uint32_t* r, uint32_t a) {
    asm volatile("ldmatrix.sync.aligned.m8n8.x4.trans.shared.b16 {%0,%1,%2,%3}, [%4];"
        : "=r"(r[0]), "=r"(r[1]), "=r"(r[2]), "=r"(r[3]) : "r"(a));
}

__device__ __forceinline__ void mma_fp(float* d, const uint32_t* a,
                                       uint32_t b0, uint32_t b1) {
    asm volatile(
        "mma.sync.aligned.m16n8k16.row.col.f32.f16.f16.f32 "
        "{%0,%1,%2,%3}, {%4,%5,%6,%7}, {%8,%9}, {%0,%1,%2,%3};"
        : "+f"(d[0]), "+f"(d[1]), "+f"(d[2]), "+f"(d[3])
        : "r"(a[0]), "r"(a[1]), "r"(a[2]), "r"(a[3]), "r"(b0), "r"(b1));
}

__device__ __forceinline__ float silu_f(float g) {
    return g / (1.f + expf(-g));
}

// ===================== fp16 GEMM: C = A[M,K] @ B[K,N] (+bias) ================
// B in natural [K][N] layout; fragments via ldmatrix.trans.
// EPI: 0 = fp32 out (+resid), 1 = fp16 out,
//      3 = interleaved gated MLP: acc pairs (a1,a2) -> fp16 a1*silu(a2),
//          output width Ntot/2.
#define BM 128
#define BN 128
#define GROWB 80
#define GTILE_A (128 * GROWB)
#define BROWB 272
#define GTILE_B (32 * BROWB)
#define STAGE_B (GTILE_A + GTILE_B)
#define GSMEM (4 * STAGE_B)            // 75776

template<int EPI>
__global__ __launch_bounds__(256, 2)
void gemm_f16(const h16* __restrict__ Ah, const h16* __restrict__ Bh,
              const float* __restrict__ bias, const float* __restrict__ resid,
              void* __restrict__ Cv, int Ntot, int K)
{
    extern __shared__ char dsm[];
    const int tid = threadIdx.x;
    const int wid = tid >> 5, lane = tid & 31;
    const int rowA0 = blockIdx.y * BM;
    const int colB0 = blockIdx.x * BN;
    const int nIter = K >> 5;
    const uint32_t sbase = smem_u32(dsm);

    auto load_stage = [&](int it) {
        const int s = it & 3;
        const size_t koff = (size_t)it * 32;
        const uint32_t sa = sbase + s * STAGE_B;
        const uint32_t sbt = sa + GTILE_A;
        #pragma unroll
        for (int i = 0; i < 2; i++) {
            int idx = tid + i * 256;
            int ra = idx >> 2, sega = idx & 3;
            CP_ASYNC16(sa + ra * GROWB + sega * 16,
                       Ah + (size_t)(rowA0 + ra) * K + koff + sega * 8);
            int rb = idx >> 4, segb = idx & 15;
            CP_ASYNC16(sbt + rb * BROWB + segb * 16,
                       Bh + (koff + rb) * (size_t)Ntot + colB0 + segb * 8);
        }
        CP_COMMIT();
    };

    const int m0 = (wid >> 1) * 32;
    const int n0 = (wid & 1) * 64;

    float acc[2][8][4];
    #pragma unroll
    for (int i = 0; i < 2; i++)
        #pragma unroll
        for (int j = 0; j < 8; j++)
            #pragma unroll
            for (int c = 0; c < 4; c++) acc[i][j][c] = 0.f;

    const int mi = lane >> 3, l7 = lane & 7;
    const uint32_t aoff = (uint32_t)((m0 + (mi & 1) * 8 + l7) * GROWB + (mi >> 1) * 16);
    const uint32_t boff = (uint32_t)(((mi & 1) * 8 + l7) * BROWB + (n0 + (mi >> 1) * 8) * 2);

    auto compute = [&](int it) {
        const uint32_t sa = sbase + (it & 3) * STAGE_B;
        const uint32_t sbt = sa + GTILE_A;
        #pragma unroll
        for (int kk = 0; kk < 2; kk++) {
            uint32_t ah0[4], ah1[4];
            ldsm_x4(ah0, sa + aoff + kk * 32);
            ldsm_x4(ah1, sa + aoff + 16 * GROWB + kk * 32);
            #pragma unroll
            for (int g = 0; g < 4; g++) {
                uint32_t bh[4];
                ldsm_x4t(bh, sbt + boff + kk * 16 * BROWB + g * 32);
                mma_fp(acc[0][2*g+0], ah0, bh[0], bh[1]);
                mma_fp(acc[0][2*g+1], ah0, bh[2], bh[3]);
                mma_fp(acc[1][2*g+0], ah1, bh[0], bh[1]);
                mma_fp(acc[1][2*g+1], ah1, bh[2], bh[3]);
            }
        }
    };

    load_stage(0); load_stage(1);

    for (int it = 0; it < nIter; it += 2) {
        if (it + 2 < nIter) load_stage(it + 2); else CP_COMMIT();
        if (it + 3 < nIter) load_stage(it + 3); else CP_COMMIT();
        CP_WAIT(2);
        __syncthreads();
        compute(it);
        compute(it + 1);
        __syncthreads();
    }

    const int l4 = lane >> 2, l2 = (lane & 3) * 2;
    #pragma unroll
    for (int mf = 0; mf < 2; mf++) {
        const int r = rowA0 + m0 + mf * 16 + l4;
        #pragma unroll
        for (int nf = 0; nf < 8; nf++) {
            const int c = colB0 + n0 + nf * 8 + l2;
            float2 v0 = make_float2(acc[mf][nf][0], acc[mf][nf][1]);
            float2 v1 = make_float2(acc[mf][nf][2], acc[mf][nf][3]);
            if (bias) {
                v0.x += bias[c]; v0.y += bias[c + 1];
                v1.x += bias[c]; v1.y += bias[c + 1];
            }
            if (EPI == 0) {
                if (resid) {
                    const float2 r0 = *(const float2*)&resid[(size_t)r * Ntot + c];
                    const float2 r1 = *(const float2*)&resid[(size_t)(r + 8) * Ntot + c];
                    v0.x += r0.x; v0.y += r0.y;
                    v1.x += r1.x; v1.y += r1.y;
                }
                float* C = (float*)Cv;
                *(float2*)&C[(size_t)r * Ntot + c] = v0;
                *(float2*)&C[(size_t)(r + 8) * Ntot + c] = v1;
            } else if (EPI == 1) {
                h16* C = (h16*)Cv;
                *(__half2*)&C[(size_t)r * Ntot + c] = __floats2half2_rn(v0.x, v0.y);
                *(__half2*)&C[(size_t)(r + 8) * Ntot + c] = __floats2half2_rn(v1.x, v1.y);
            } else { // EPI == 3
                const int No = Ntot >> 1;
                const int j = c >> 1;
                h16* C = (h16*)Cv;
                C[(size_t)r * No + j]       = __float2half_rn(v0.x * silu_f(v0.y));
                C[(size_t)(r + 8) * No + j] = __float2half_rn(v1.x * silu_f(v1.y));
            }
        }
    }
}

// ===================== tensor-core flash attention (fp16, base-2 softmax) ====
// Q pre-scaled by log2(e)/sqrt(HD): logits land in log2 domain; exp2f used.
#define AROW 272
#define PSROW 144
#define OFF_Q  0
#define OFF_K  (OFF_Q + 64 * AROW)
#define OFF_V0 (OFF_K + 64 * AROW)
#define OFF_V1 (OFF_V0 + 64 * AROW)
#define OFF_PS (OFF_V1 + 64 * AROW)
#define ATTN_SMEM (OFF_PS + 64 * PSROW)   // 78848

__global__ __launch_bounds__(128, 2)
void attn_mma_kernel(const h16* __restrict__ Q, const h16* __restrict__ K,
                     const h16* __restrict__ V, h16* __restrict__ Oh, int QS)
{
    extern __shared__ char asm_[];
    const uint32_t sb = smem_u32(asm_);
    const int qb = gridDim.x - 1 - blockIdx.x;   // longest first
    const int q0 = qb * 64;
    const int h  = blockIdx.y;
    const int tid = threadIdx.x;
    const int w = tid >> 5, lane = tid & 31;
    const int mi = lane >> 3, l7 = lane & 7;
    const size_t hoff = (size_t)h * HD_DIM;
    const int nIter = qb + 1;

    auto load_K = [&](int jj) {
        const int j0 = jj * 64;
        #pragma unroll
        for (int i = 0; i < 8; i++) {
            int idx = tid + i * 128;
            int r = idx >> 4, c = idx & 15;
            const size_t gsrc = (size_t)(j0 + r) * QS + hoff + c * 8;
            CP_ASYNC16(sb + OFF_K + r * AROW + c * 16, K + gsrc);
        }
        CP_COMMIT();
    };
    auto load_V = [&](int jj) {
        const int j0 = jj * 64;
        const uint32_t vb = sb + ((jj & 1) ? OFF_V1 : OFF_V0);
        #pragma unroll
        for (int i = 0; i < 8; i++) {
            int idx = tid + i * 128;
            int r = idx >> 4, c = idx & 15;
            const size_t gsrc = (size_t)(j0 + r) * QS + hoff + c * 8;
            CP_ASYNC16(vb + r * AROW + c * 16, V + gsrc);
        }
        CP_COMMIT();
    };

    #pragma unroll
    for (int i = 0; i < 8; i++) {
        int idx = tid + i * 128;
        int r = idx >> 4, c = idx & 15;
        const size_t gsrc = (size_t)(q0 + r) * QS + hoff + c * 8;
        CP_ASYNC16(sb + OFF_Q + r * AROW + c * 16, Q + gsrc);
    }
    CP_COMMIT();
    load_K(0);
    load_V(0);

    float oacc[16][4];
    #pragma unroll
    for (int f = 0; f < 16; f++)
        #pragma unroll
        for (int c = 0; c < 4; c++) oacc[f][c] = 0.f;
    float m0v = -1e30f, m1v = -1e30f, l0v = 0.f, l1v = 0.f;

    const uint32_t aq_off = (uint32_t)((w * 16 + (mi & 1) * 8 + l7) * AROW + (mi >> 1) * 16);
    const uint32_t bk_off = (uint32_t)(((mi >> 1) * 8 + l7) * AROW + (mi & 1) * 16);
    const uint32_t ps_off = (uint32_t)((w * 16 + (mi & 1) * 8 + l7) * PSROW + (mi >> 1) * 16);

    const int r0 = lane >> 2;
    const int gq0 = q0 + w * 16 + r0;
    const int gq1 = gq0 + 8;

    for (int jj = 0; jj < nIter; jj++) {
        const int j0 = jj * 64;
        CP_WAIT(1);
        __syncthreads();

        float sacc[8][4];
        #pragma unroll
        for (int f = 0; f < 8; f++)
            #pragma unroll
            for (int c = 0; c < 4; c++) sacc[f][c] = 0.f;

        #pragma unroll
        for (int ks = 0; ks < 8; ks++) {
            uint32_t a[4];
            ldsm_x4(a, sb + OFF_Q + aq_off + ks * 32);
            #pragma unroll
            for (int g = 0; g < 4; g++) {
                uint32_t b[4];
                ldsm_x4(b, sb + OFF_K + bk_off + g * 16 * AROW + ks * 32);
                mma_fp(sacc[2*g+0], a, b[0], b[1]);
                mma_fp(sacc[2*g+1], a, b[2], b[3]);
            }
        }

        if (j0 == q0) {
            #pragma unroll
            for (int f = 0; f < 8; f++) {
                int kvc = j0 + f * 8 + (lane & 3) * 2;
                if (kvc     > gq0) sacc[f][0] = -1e30f;
                if (kvc + 1 > gq0) sacc[f][1] = -1e30f;
                if (kvc     > gq1) sacc[f][2] = -1e30f;
                if (kvc + 1 > gq1) sacc[f][3] = -1e30f;
            }
        }

        float mx0 = -1e30f, mx1 = -1e30f;
        #pragma unroll
        for (int f = 0; f < 8; f++) {
            mx0 = fmaxf(mx0, fmaxf(sacc[f][0], sacc[f][1]));
            mx1 = fmaxf(mx1, fmaxf(sacc[f][2], sacc[f][3]));
        }
        mx0 = fmaxf(mx0, __shfl_xor_sync(0xffffffffu, mx0, 1));
        mx0 = fmaxf(mx0, __shfl_xor_sync(0xffffffffu, mx0, 2));
        mx1 = fmaxf(mx1, __shfl_xor_sync(0xffffffffu, mx1, 1));
        mx1 = fmaxf(mx1, __shfl_xor_sync(0xffffffffu, mx1, 2));
        const float mn0 = fmaxf(m0v, mx0), mn1 = fmaxf(m1v, mx1);
        float rs0 = 0.f, rs1 = 0.f;
        #pragma unroll
        for (int f = 0; f < 8; f++) {
            float p0 = exp2f(sacc[f][0] - mn0);
            float p1 = exp2f(sacc[f][1] - mn0);
            float p2 = exp2f(sacc[f][2] - mn1);
            float p3 = exp2f(sacc[f][3] - mn1);
            rs0 += p0 + p1; rs1 += p2 + p3;
            __half2 v01 = __floats2half2_rn(p0, p1);
            __half2 v23 = __floats2half2_rn(p2, p3);
            uint32_t col = (f * 8 + (lane & 3) * 2) * 2;
            *(uint32_t*)(asm_ + OFF_PS + (w * 16 + r0) * PSROW + col) = *(uint32_t*)&v01;
            *(uint32_t*)(asm_ + OFF_PS + (w * 16 + r0 + 8) * PSROW + col) = *(uint32_t*)&v23;
        }
        rs0 += __shfl_xor_sync(0xffffffffu, rs0, 1);
        rs0 += __shfl_xor_sync(0xffffffffu, rs0, 2);
        rs1 += __shfl_xor_sync(0xffffffffu, rs1, 1);
        rs1 += __shfl_xor_sync(0xffffffffu, rs1, 2);
        const float al0 = exp2f(m0v - mn0), al1 = exp2f(m1v - mn1);
        l0v = l0v * al0 + rs0; l1v = l1v * al1 + rs1;
        m0v = mn0; m1v = mn1;
        #pragma unroll
        for (int f = 0; f < 16; f++) {
            oacc[f][0] *= al0; oacc[f][1] *= al0;
            oacc[f][2] *= al1; oacc[f][3] *= al1;
        }
        __syncthreads();

        if (jj + 1 < nIter) { load_K(jj + 1); load_V(jj + 1); }
        else                { CP_COMMIT(); CP_COMMIT(); }

        CP_WAIT(2);
        __syncthreads();

        const uint32_t vb = sb + ((jj & 1) ? OFF_V1 : OFF_V0);
        #pragma unroll
        for (int ks = 0; ks < 4; ks++) {
            uint32_t a[4];
            ldsm_x4(a, sb + OFF_PS + ps_off + ks * 32);
            #pragma unroll
            for (int g = 0; g < 8; g++) {
                uint32_t b[4];
                ldsm_x4t(b, vb + (ks * 16 + (mi & 1) * 8 + l7) * AROW
                               + (g * 16 + (mi >> 1) * 8) * 2);
                mma_fp(oacc[2*g+0], a, b[0], b[1]);
                mma_fp(oacc[2*g+1], a, b[2], b[3]);
            }
        }
    }

    const float i0 = 1.f / l0v, i1 = 1.f / l1v;
    #pragma unroll
    for (int f = 0; f < 16; f++) {
        int col = h * HD_DIM + f * 8 + (lane & 3) * 2;
        __half2 hh0 = __floats2half2_rn(oacc[f][0] * i0, oacc[f][1] * i0);
        __half2 hh1 = __floats2half2_rn(oacc[f][2] * i1, oacc[f][3] * i1);
        *(__half2*)&Oh[(size_t)gq0 * H_DIM + col] = hh0;
        *(__half2*)&Oh[(size_t)gq1 * H_DIM + col] = hh1;
    }
}

// ===================== elementwise / conversion kernels =====================
__global__ void rmsnorm_f16_kernel(const float* __restrict__ x,
                                   const float* __restrict__ scale,
                                   h16* __restrict__ oh)
{
    int row = blockIdx.x;
    const float4* xr = (const float4*)(x + (size_t)row * H_DIM);
    float ss = 0.f;
    for (int i = threadIdx.x; i < H_DIM / 4; i += blockDim.x) {
        float4 v = xr[i];
        ss += v.x * v.x + v.y * v.y + v.z * v.z + v.w * v.w;
    }
    #pragma unroll
    for (int off = 16; off; off >>= 1) ss += __shfl_xor_sync(0xffffffffu, ss, off);
    __shared__ float red[32];
    int lane = threadIdx.x & 31, wid = threadIdx.x >> 5;
    if (lane == 0) red[wid] = ss;
    __syncthreads();
    if (wid == 0) {
        ss = (lane < (int)(blockDim.x >> 5)) ? red[lane] : 0.f;
        #pragma unroll
        for (int off = 16; off; off >>= 1) ss += __shfl_xor_sync(0xffffffffu, ss, off);
        if (lane == 0) red[0] = ss;
    }
    __syncthreads();
    float inv = rsqrtf(red[0] / (float)H_DIM + EPS_V);
    const float4* sc = (const float4*)scale;
    for (int i = threadIdx.x; i < H_DIM / 4; i += blockDim.x) {
        float4 v = xr[i], s = sc[i];
        __half2 lo = __floats2half2_rn(v.x * inv * s.x, v.y * inv * s.y);
        __half2 hi = __floats2half2_rn(v.z * inv * s.z, v.w * inv * s.w);
        uint2 pack = {*(uint32_t*)&lo, *(uint32_t*)&hi};
        ((uint2*)(oh + (size_t)row * H_DIM))[i] = pack;
    }
}

// streaming fp32 -> fp16, same [K][N] layout; output row stride OS.
__global__ void convert_f16_kernel(const float* __restrict__ W,
                                   h16* __restrict__ out,
                                   int N8, int OS, int total8)
{
    int i = blockIdx.x * blockDim.x + threadIdx.x;
    if (i >= total8) return;
    const float4* src = (const float4*)W + (size_t)i * 2;
    float4 a = src[0], b = src[1];
    __half2 h0 = __floats2half2_rn(a.x, a.y);
    __half2 h1 = __floats2half2_rn(a.z, a.w);
    __half2 h2 = __floats2half2_rn(b.x, b.y);
    __half2 h3 = __floats2half2_rn(b.z, b.w);
    int k = i / N8, n8 = i - k * N8;
    uint4 pack = {*(uint32_t*)&h0, *(uint32_t*)&h1, *(uint32_t*)&h2, *(uint32_t*)&h3};
    *(uint4*)(out + (size_t)k * OS + (size_t)n8 * 8) = pack;
}

// merged qkv convert: sections 0..2 pull from wq/wk/wv into g_wqkv columns.
__global__ void convert_qkv_kernel(const float* __restrict__ Wq,
                                   const float* __restrict__ Wk,
                                   const float* __restrict__ Wv,
                                   h16* __restrict__ out, int per8)
{
    int i = blockIdx.x * blockDim.x + threadIdx.x;
    if (i >= 3 * per8) return;
    int sec = i / per8, j = i - sec * per8;
    const float* W = (sec == 0) ? Wq : (sec == 1) ? Wk : Wv;
    const float4* src = (const float4*)W + (size_t)j * 2;
    float4 a = src[0], b = src[1];
    __half2 h0 = __floats2half2_rn(a.x, a.y);
    __half2 h1 = __floats2half2_rn(a.z, a.w);
    __half2 h2 = __floats2half2_rn(b.x, b.y);
    __half2 h3 = __floats2half2_rn(b.z, b.w);
    const int N8 = H_DIM / 8;
    int k = j / N8, n8 = j - k * N8;
    uint4 pack = {*(uint32_t*)&h0, *(uint32_t*)&h1, *(uint32_t*)&h2, *(uint32_t*)&h3};
    *(uint4*)(out + (size_t)k * QKV_N + sec * H_DIM + (size_t)n8 * 8) = pack;
}

// w1,w2 fp32 [K][FF] -> interleaved fp16 [K][2*FF]
__global__ void convert_pair_kernel(const float* __restrict__ W1,
                                    const float* __restrict__ W2,
                                    h16* __restrict__ out, int total8)
{
    int i = blockIdx.x * blockDim.x + threadIdx.x;
    if (i >= total8) return;
    const float4* s1 = (const float4*)W1 + (size_t)i * 2;
    const float4* s2 = (const float4*)W2 + (size_t)i * 2;
    float4 a1 = s1[0], b1 = s1[1];
    float4 a2 = s2[0], b2 = s2[1];
    __half2 p0 = __floats2half2_rn(a1.x, a2.x);
    __half2 p1 = __floats2half2_rn(a1.y, a2.y);
    __half2 p2 = __floats2half2_rn(a1.z, a2.z);
    __half2 p3 = __floats2half2_rn(a1.w, a2.w);
    __half2 p4 = __floats2half2_rn(b1.x, b2.x);
    __half2 p5 = __floats2half2_rn(b1.y, b2.y);
    __half2 p6 = __floats2half2_rn(b1.z, b2.z);
    __half2 p7 = __floats2half2_rn(b1.w, b2.w);
    uint4 lo = {*(uint32_t*)&p0, *(uint32_t*)&p1, *(uint32_t*)&p2, *(uint32_t*)&p3};
    uint4 hi = {*(uint32_t*)&p4, *(uint32_t*)&p5, *(uint32_t*)&p6, *(uint32_t*)&p7};
    uint4* dst = (uint4*)(out + (size_t)i * 16);
    dst[0] = lo;
    dst[1] = hi;
}

__global__ void bias_cat_kernel(const float* __restrict__ bq,
                                const float* __restrict__ bk,
                                const float* __restrict__ bv,
                                float* __restrict__ cat)
{
    int i = blockIdx.x * blockDim.x + threadIdx.x;
    if (i < H_DIM)          cat[i] = bq[i];
    else if (i < 2 * H_DIM) cat[i] = bk[i - H_DIM];
    else if (i < 3 * H_DIM) cat[i] = bv[i - 2 * H_DIM];
}

// RoPE in-place on fp16 q,k (row stride QS); q pre-scaled by log2(e)/sqrt(HD).
__global__ void rope_f16_kernel(h16* __restrict__ q, h16* __restrict__ k,
                                const int* __restrict__ pos, int QS)
{
    int idx = blockIdx.x * blockDim.x + threadIdx.x;
    if (idx >= T_DIM * NHEADS * (HD_DIM / 2)) return;
    int d  = idx & 63;
    int th = idx >> 6;
    int t  = th >> 5;
    int hh = th & 31;
    const float scaling = 0.08838834764831845f * 1.4426950408889634f; // 128^-.5 * log2(e)
    float invf = powf(10000.0f, -(float)d * (1.0f / 64.0f));
    float ang = (float)pos[t] * invf;
    float c, s;
    sincosf(ang, &s, &c);
    size_t base = (size_t)t * QS + hh * HD_DIM + d;
    float q1 = __half2float(q[base]), q2 = __half2float(q[base + 64]);
    q[base]      = __float2half_rn((q1 * c - q2 * s) * scaling);
    q[base + 64] = __float2half_rn((q2 * c + q1 * s) * scaling);
    float k1 = __half2float(k[base]), k2 = __half2float(k[base + 64]);
    k[base]      = __float2half_rn(k1 * c - k2 * s);
    k[base + 64] = __float2half_rn(k2 * c + k1 * s);
}

// ===================== launch ================================================
extern "C" void kernel_launch(void* const* d_in, const int* in_sizes, int n_in,
                              void* d_out, int out_size)
{
    (void)in_sizes; (void)n_in; (void)out_size;
    const int*   positions = (const int*)  d_in[0];
    const float* hidden    = (const float*)d_in[1];
    const float* ln1       = (const float*)d_in[2];
    const float* wq = (const float*)d_in[3];
    const float* bq = (const float*)d_in[4];
    const float* wk = (const float*)d_in[5];
    const float* bk = (const float*)d_in[6];
    const float* wv = (const float*)d_in[7];
    const float* bv = (const float*)d_in[8];
    const float* wo = (const float*)d_in[9];
    const float* ln2= (const float*)d_in[10];
    const float* w1 = (const float*)d_in[11];
    const float* w2 = (const float*)d_in[12];
    const float* wc = (const float*)d_in[13];
    float* out = (float*)d_out;

    float *hbuf, *bqkv;
    h16 *xnh, *atth, *yh, *gh, *qkv16;
    h16 *wqkv, *woh, *w12, *wch;
    cudaGetSymbolAddress((void**)&hbuf,  g_h);
    cudaGetSymbolAddress((void**)&bqkv,  g_bqkv);
    cudaGetSymbolAddress((void**)&xnh,   g_xnh);
    cudaGetSymbolAddress((void**)&atth,  g_atth);
    cudaGetSymbolAddress((void**)&yh,    g_yh);
    cudaGetSymbolAddress((void**)&gh,    g_gh);
    cudaGetSymbolAddress((void**)&qkv16, g_qkv16);
    cudaGetSymbolAddress((void**)&wqkv,  g_wqkv);
    cudaGetSymbolAddress((void**)&woh,   g_woh);
    cudaGetSymbolAddress((void**)&w12,   g_w12);
    cudaGetSymbolAddress((void**)&wch,   g_wch);

    cudaFuncSetAttribute((gemm_f16<0>), cudaFuncAttributeMaxDynamicSharedMemorySize, GSMEM);
    cudaFuncSetAttribute((gemm_f16<1>), cudaFuncAttributeMaxDynamicSharedMemorySize, GSMEM);
    cudaFuncSetAttribute((gemm_f16<3>), cudaFuncAttributeMaxDynamicSharedMemorySize, GSMEM);
    cudaFuncSetAttribute(attn_mma_kernel, cudaFuncAttributeMaxDynamicSharedMemorySize, ATTN_SMEM);

    // weight conversions (streaming fp32->fp16)
    const int HH8 = H_DIM * H_DIM / 8;
    const int HF8 = H_DIM * FF_DIM / 8;
    convert_qkv_kernel<<<(3 * HH8 + 255) / 256, 256>>>(wq, wk, wv, wqkv, HH8);
    convert_f16_kernel<<<(HH8 + 255) / 256, 256>>>(wo, woh, H_DIM/8, H_DIM, HH8);
    convert_pair_kernel<<<(HF8 + 255) / 256, 256>>>(w1, w2, w12, HF8);
    convert_f16_kernel<<<(HF8 + 255) / 256, 256>>>(wc, wch, H_DIM/8, H_DIM, HF8);
    bias_cat_kernel<<<(QKV_N + 255) / 256, 256>>>(bq, bk, bv, bqkv);

    // 1) x = rmsnorm(hidden, ln1) -> fp16
    rmsnorm_f16_kernel<<<T_DIM, 256>>>(hidden, ln1, xnh);

    // 2) fused qkv GEMM (fp16 out)
    dim3 gQKV(QKV_N / BN, T_DIM / BM);
    gemm_f16<1><<<gQKV, 256, GSMEM>>>(xnh, wqkv, bqkv, nullptr, qkv16, QKV_N, H_DIM);

    // 3) RoPE in place (q pre-scaled into log2 domain)
    rope_f16_kernel<<<(T_DIM * NHEADS * (HD_DIM / 2)) / 256, 256>>>(
        qkv16, qkv16 + H_DIM, positions, QKV_N);

    // 4) attention -> atth (fp16)
    attn_mma_kernel<<<dim3(T_DIM / 64, NHEADS), 128, ATTN_SMEM>>>(
        qkv16, qkv16 + H_DIM, qkv16 + 2 * H_DIM, atth, QKV_N);

    // 5) h = hidden + attn @ wo
    dim3 gH(H_DIM / BN, T_DIM / BM);
    gemm_f16<0><<<gH, 256, GSMEM>>>(atth, woh, nullptr, hidden, hbuf, H_DIM, H_DIM);

    // 6) y = rmsnorm(h, ln2) -> fp16
    rmsnorm_f16_kernel<<<T_DIM, 256>>>(hbuf, ln2, yh);

    // 7) fused gated MLP: gh = (y@w1) * silu(y@w2), single interleaved GEMM
    dim3 gF2(MLP_N / BN, T_DIM / BM);
    gemm_f16<3><<<gF2, 256, GSMEM>>>(yh, w12, nullptr, nullptr, gh, MLP_N, H_DIM);

    // 8) out = h + gh @ wc
    gemm_f16<0><<<gH, 256, GSMEM>>>(gh, wch, nullptr, hbuf, out, H_DIM, FF_DIM);
}

// round 16
// speedup vs baseline: 7.9409x; 1.0025x over previous
#include <cuda_runtime.h>
#include <cuda_fp16.h>
#include <math.h>
#include <cstdint>

#define T_DIM 2048
#define H_DIM 4096
#define NHEADS 32
#define HD_DIM 128
#define FF_DIM 11008
#define QKV_N (3 * H_DIM)          // 12288
#define MLP_N (2 * FF_DIM)         // 22016 (interleaved w1|w2)
#define EPS_V 1e-6f

typedef __half h16;

// ===================== device scratch ======================================
__device__ float g_h   [(size_t)T_DIM * H_DIM];
__device__ float g_bqkv[QKV_N];

__device__ h16 g_xnh  [(size_t)T_DIM * H_DIM];
__device__ h16 g_atth [(size_t)T_DIM * H_DIM];
__device__ h16 g_yh   [(size_t)T_DIM * H_DIM];
__device__ h16 g_gh   [(size_t)T_DIM * FF_DIM];
__device__ h16 g_qkv16[(size_t)T_DIM * QKV_N];

// weights fp16, [K][N] row-major (same layout as input)
__device__ h16 g_wqkv[(size_t)H_DIM * QKV_N];
__device__ h16 g_woh [(size_t)H_DIM * H_DIM];
__device__ h16 g_w12 [(size_t)H_DIM * MLP_N];   // interleaved w1/w2
__device__ h16 g_wch [(size_t)FF_DIM * H_DIM];

// ===================== PTX helpers =========================================
__device__ __forceinline__ uint32_t smem_u32(const void* p) {
    uint32_t a;
    asm("{ .reg .u64 t; cvta.to.shared.u64 t, %1; cvt.u32.u64 %0, t; }"
        : "=r"(a) : "l"(p));
    return a;
}

#define CP_ASYNC16(dst, src) \
    asm volatile("cp.async.cg.shared.global [%0], [%1], 16;" :: "r"(dst), "l"(src))
#define CP_COMMIT() asm volatile("cp.async.commit_group;" ::: "memory")
#define CP_WAIT(n)  asm volatile("cp.async.wait_group %0;" :: "n"(n) : "memory")

__device__ __forceinline__ void ldsm_x4(uint32_t* r, uint32_t a) {
    asm volatile("ldmatrix.sync.aligned.m8n8.x4.shared.b16 {%0,%1,%2,%3}, [%4];"
        : "=r"(r[0]), "=r"(r[1]), "=r"(r[2]), "=r"(r[3]) : "r"(a));
}
__device__ __forceinline__ void ldsm_x4t(uint32_t* r, uint32_t a) {
    asm volatile("ldmatrix.sync.aligned.m8n8.x4.trans.shared.b16 {%0,%1,%2,%3}, [%4];"
        : "=r"(r[0]), "=r"(r[1]), "=r"(r[2]), "=r"(r[3]) : "r"(a));
}

__device__ __forceinline__ void mma_fp(float* d, const uint32_t* a,
                                       uint32_t b0, uint32_t b1) {
    asm volatile(
        "mma.sync.aligned.m16n8k16.row.col.f32.f16.f16.f32 "
        "{%0,%1,%2,%3}, {%4,%5,%6,%7}, {%8,%9}, {%0,%1,%2,%3};"
        : "+f"(d[0]), "+f"(d[1]), "+f"(d[2]), "+f"(d[3])
        : "r"(a[0]), "r"(a[1]), "r"(a[2]), "r"(a[3]), "r"(b0), "r"(b1));
}

__device__ __forceinline__ float silu_f(float g) {
    return g / (1.f + expf(-g));
}

// ===================== fp16 GEMM: C = A[M,K] @ B[K,N] (+bias) ================
// EPI: 0 = fp32 out (+resid), 1 = fp16 out, 3 = interleaved gated MLP.
#define BM 128
#define BN 128
#define GROWB 80
#define GTILE_A (128 * GROWB)
#define BROWB 272
#define GTILE_B (32 * BROWB)
#define STAGE_B (GTILE_A + GTILE_B)
#define GSMEM (4 * STAGE_B)            // 75776

template<int EPI>
__global__ __launch_bounds__(256, 2)
void gemm_f16(const h16* __restrict__ Ah, const h16* __restrict__ Bh,
              const float* __restrict__ bias, const float* __restrict__ resid,
              void* __restrict__ Cv, int Ntot, int K)
{
    extern __shared__ char dsm[];
    const int tid = threadIdx.x;
    const int wid = tid >> 5, lane = tid & 31;
    const int rowA0 = blockIdx.y * BM;
    const int colB0 = blockIdx.x * BN;
    const int nIter = K >> 5;
    const uint32_t sbase = smem_u32(dsm);

    auto load_stage = [&](int it) {
        const int s = it & 3;
        const size_t koff = (size_t)it * 32;
        const uint32_t sa = sbase + s * STAGE_B;
        const uint32_t sbt = sa + GTILE_A;
        #pragma unroll
        for (int i = 0; i < 2; i++) {
            int idx = tid + i * 256;
            int ra = idx >> 2, sega = idx & 3;
            CP_ASYNC16(sa + ra * GROWB + sega * 16,
                       Ah + (size_t)(rowA0 + ra) * K + koff + sega * 8);
            int rb = idx >> 4, segb = idx & 15;
            CP_ASYNC16(sbt + rb * BROWB + segb * 16,
                       Bh + (koff + rb) * (size_t)Ntot + colB0 + segb * 8);
        }
        CP_COMMIT();
    };

    const int m0 = (wid >> 1) * 32;
    const int n0 = (wid & 1) * 64;

    float acc[2][8][4];
    #pragma unroll
    for (int i = 0; i < 2; i++)
        #pragma unroll
        for (int j = 0; j < 8; j++)
            #pragma unroll
            for (int c = 0; c < 4; c++) acc[i][j][c] = 0.f;

    const int mi = lane >> 3, l7 = lane & 7;
    const uint32_t aoff = (uint32_t)((m0 + (mi & 1) * 8 + l7) * GROWB + (mi >> 1) * 16);
    const uint32_t boff = (uint32_t)(((mi & 1) * 8 + l7) * BROWB + (n0 + (mi >> 1) * 8) * 2);

    auto compute = [&](int it) {
        const uint32_t sa = sbase + (it & 3) * STAGE_B;
        const uint32_t sbt = sa + GTILE_A;
        #pragma unroll
        for (int kk = 0; kk < 2; kk++) {
            uint32_t ah0[4], ah1[4];
            ldsm_x4(ah0, sa + aoff + kk * 32);
            ldsm_x4(ah1, sa + aoff + 16 * GROWB + kk * 32);
            #pragma unroll
            for (int g = 0; g < 4; g++) {
                uint32_t bh[4];
                ldsm_x4t(bh, sbt + boff + kk * 16 * BROWB + g * 32);
                mma_fp(acc[0][2*g+0], ah0, bh[0], bh[1]);
                mma_fp(acc[0][2*g+1], ah0, bh[2], bh[3]);
                mma_fp(acc[1][2*g+0], ah1, bh[0], bh[1]);
                mma_fp(acc[1][2*g+1], ah1, bh[2], bh[3]);
            }
        }
    };

    load_stage(0); load_stage(1);

    for (int it = 0; it < nIter; it += 2) {
        if (it + 2 < nIter) load_stage(it + 2); else CP_COMMIT();
        if (it + 3 < nIter) load_stage(it + 3); else CP_COMMIT();
        CP_WAIT(2);
        __syncthreads();
        compute(it);
        compute(it + 1);
        __syncthreads();
    }

    const int l4 = lane >> 2, l2 = (lane & 3) * 2;
    #pragma unroll
    for (int mf = 0; mf < 2; mf++) {
        const int r = rowA0 + m0 + mf * 16 + l4;
        #pragma unroll
        for (int nf = 0; nf < 8; nf++) {
            const int c = colB0 + n0 + nf * 8 + l2;
            float2 v0 = make_float2(acc[mf][nf][0], acc[mf][nf][1]);
            float2 v1 = make_float2(acc[mf][nf][2], acc[mf][nf][3]);
            if (bias) {
                v0.x += bias[c]; v0.y += bias[c + 1];
                v1.x += bias[c]; v1.y += bias[c + 1];
            }
            if (EPI == 0) {
                if (resid) {
                    const float2 r0 = *(const float2*)&resid[(size_t)r * Ntot + c];
                    const float2 r1 = *(const float2*)&resid[(size_t)(r + 8) * Ntot + c];
                    v0.x += r0.x; v0.y += r0.y;
                    v1.x += r1.x; v1.y += r1.y;
                }
                float* C = (float*)Cv;
                *(float2*)&C[(size_t)r * Ntot + c] = v0;
                *(float2*)&C[(size_t)(r + 8) * Ntot + c] = v1;
            } else if (EPI == 1) {
                h16* C = (h16*)Cv;
                *(__half2*)&C[(size_t)r * Ntot + c] = __floats2half2_rn(v0.x, v0.y);
                *(__half2*)&C[(size_t)(r + 8) * Ntot + c] = __floats2half2_rn(v1.x, v1.y);
            } else { // EPI == 3
                const int No = Ntot >> 1;
                const int j = c >> 1;
                h16* C = (h16*)Cv;
                C[(size_t)r * No + j]       = __float2half_rn(v0.x * silu_f(v0.y));
                C[(size_t)(r + 8) * No + j] = __float2half_rn(v1.x * silu_f(v1.y));
            }
        }
    }
}

// ===================== tensor-core flash attention (fp16, base-2 softmax) ====
#define AROW 272
#define PSROW 144
#define OFF_Q  0
#define OFF_K  (OFF_Q + 64 * AROW)
#define OFF_V0 (OFF_K + 64 * AROW)
#define OFF_V1 (OFF_V0 + 64 * AROW)
#define OFF_PS (OFF_V1 + 64 * AROW)
#define ATTN_SMEM (OFF_PS + 64 * PSROW)   // 78848

__global__ __launch_bounds__(128, 2)
void attn_mma_kernel(const h16* __restrict__ Q, const h16* __restrict__ K,
                     const h16* __restrict__ V, h16* __restrict__ Oh, int QS)
{
    extern __shared__ char asm_[];
    const uint32_t sb = smem_u32(asm_);
    const int qb = gridDim.x - 1 - blockIdx.x;   // longest first
    const int q0 = qb * 64;
    const int h  = blockIdx.y;
    const int tid = threadIdx.x;
    const int w = tid >> 5, lane = tid & 31;
    const int mi = lane >> 3, l7 = lane & 7;
    const size_t hoff = (size_t)h * HD_DIM;
    const int nIter = qb + 1;

    auto load_K = [&](int jj) {
        const int j0 = jj * 64;
        #pragma unroll
        for (int i = 0; i < 8; i++) {
            int idx = tid + i * 128;
            int r = idx >> 4, c = idx & 15;
            const size_t gsrc = (size_t)(j0 + r) * QS + hoff + c * 8;
            CP_ASYNC16(sb + OFF_K + r * AROW + c * 16, K + gsrc);
        }
        CP_COMMIT();
    };
    auto load_V = [&](int jj) {
        const int j0 = jj * 64;
        const uint32_t vb = sb + ((jj & 1) ? OFF_V1 : OFF_V0);
        #pragma unroll
        for (int i = 0; i < 8; i++) {
            int idx = tid + i * 128;
            int r = idx >> 4, c = idx & 15;
            const size_t gsrc = (size_t)(j0 + r) * QS + hoff + c * 8;
            CP_ASYNC16(vb + r * AROW + c * 16, V + gsrc);
        }
        CP_COMMIT();
    };

    #pragma unroll
    for (int i = 0; i < 8; i++) {
        int idx = tid + i * 128;
        int r = idx >> 4, c = idx & 15;
        const size_t gsrc = (size_t)(q0 + r) * QS + hoff + c * 8;
        CP_ASYNC16(sb + OFF_Q + r * AROW + c * 16, Q + gsrc);
    }
    CP_COMMIT();
    load_K(0);
    load_V(0);

    float oacc[16][4];
    #pragma unroll
    for (int f = 0; f < 16; f++)
        #pragma unroll
        for (int c = 0; c < 4; c++) oacc[f][c] = 0.f;
    float m0v = -1e30f, m1v = -1e30f, l0v = 0.f, l1v = 0.f;

    const uint32_t aq_off = (uint32_t)((w * 16 + (mi & 1) * 8 + l7) * AROW + (mi >> 1) * 16);
    const uint32_t bk_off = (uint32_t)(((mi >> 1) * 8 + l7) * AROW + (mi & 1) * 16);
    const uint32_t ps_off = (uint32_t)((w * 16 + (mi & 1) * 8 + l7) * PSROW + (mi >> 1) * 16);

    const int r0 = lane >> 2;
    const int gq0 = q0 + w * 16 + r0;
    const int gq1 = gq0 + 8;

    for (int jj = 0; jj < nIter; jj++) {
        const int j0 = jj * 64;
        CP_WAIT(1);
        __syncthreads();

        float sacc[8][4];
        #pragma unroll
        for (int f = 0; f < 8; f++)
            #pragma unroll
            for (int c = 0; c < 4; c++) sacc[f][c] = 0.f;

        #pragma unroll
        for (int ks = 0; ks < 8; ks++) {
            uint32_t a[4];
            ldsm_x4(a, sb + OFF_Q + aq_off + ks * 32);
            #pragma unroll
            for (int g = 0; g < 4; g++) {
                uint32_t b[4];
                ldsm_x4(b, sb + OFF_K + bk_off + g * 16 * AROW + ks * 32);
                mma_fp(sacc[2*g+0], a, b[0], b[1]);
                mma_fp(sacc[2*g+1], a, b[2], b[3]);
            }
        }

        if (j0 == q0) {
            #pragma unroll
            for (int f = 0; f < 8; f++) {
                int kvc = j0 + f * 8 + (lane & 3) * 2;
                if (kvc     > gq0) sacc[f][0] = -1e30f;
                if (kvc + 1 > gq0) sacc[f][1] = -1e30f;
                if (kvc     > gq1) sacc[f][2] = -1e30f;
                if (kvc + 1 > gq1) sacc[f][3] = -1e30f;
            }
        }

        float mx0 = -1e30f, mx1 = -1e30f;
        #pragma unroll
        for (int f = 0; f < 8; f++) {
            mx0 = fmaxf(mx0, fmaxf(sacc[f][0], sacc[f][1]));
            mx1 = fmaxf(mx1, fmaxf(sacc[f][2], sacc[f][3]));
        }
        mx0 = fmaxf(mx0, __shfl_xor_sync(0xffffffffu, mx0, 1));
        mx0 = fmaxf(mx0, __shfl_xor_sync(0xffffffffu, mx0, 2));
        mx1 = fmaxf(mx1, __shfl_xor_sync(0xffffffffu, mx1, 1));
        mx1 = fmaxf(mx1, __shfl_xor_sync(0xffffffffu, mx1, 2));
        const float mn0 = fmaxf(m0v, mx0), mn1 = fmaxf(m1v, mx1);
        float rs0 = 0.f, rs1 = 0.f;
        #pragma unroll
        for (int f = 0; f < 8; f++) {
            float p0 = exp2f(sacc[f][0] - mn0);
            float p1 = exp2f(sacc[f][1] - mn0);
            float p2 = exp2f(sacc[f][2] - mn1);
            float p3 = exp2f(sacc[f][3] - mn1);
            rs0 += p0 + p1; rs1 += p2 + p3;
            __half2 v01 = __floats2half2_rn(p0, p1);
            __half2 v23 = __floats2half2_rn(p2, p3);
            uint32_t col = (f * 8 + (lane & 3) * 2) * 2;
            *(uint32_t*)(asm_ + OFF_PS + (w * 16 + r0) * PSROW + col) = *(uint32_t*)&v01;
            *(uint32_t*)(asm_ + OFF_PS + (w * 16 + r0 + 8) * PSROW + col) = *(uint32_t*)&v23;
        }
        rs0 += __shfl_xor_sync(0xffffffffu, rs0, 1);
        rs0 += __shfl_xor_sync(0xffffffffu, rs0, 2);
        rs1 += __shfl_xor_sync(0xffffffffu, rs1, 1);
        rs1 += __shfl_xor_sync(0xffffffffu, rs1, 2);
        const float al0 = exp2f(m0v - mn0), al1 = exp2f(m1v - mn1);
        l0v = l0v * al0 + rs0; l1v = l1v * al1 + rs1;
        m0v = mn0; m1v = mn1;
        #pragma unroll
        for (int f = 0; f < 16; f++) {
            oacc[f][0] *= al0; oacc[f][1] *= al0;
            oacc[f][2] *= al1; oacc[f][3] *= al1;
        }
        __syncthreads();

        if (jj + 1 < nIter) { load_K(jj + 1); load_V(jj + 1); }
        else                { CP_COMMIT(); CP_COMMIT(); }

        CP_WAIT(2);
        __syncthreads();

        const uint32_t vb = sb + ((jj & 1) ? OFF_V1 : OFF_V0);
        #pragma unroll
        for (int ks = 0; ks < 4; ks++) {
            uint32_t a[4];
            ldsm_x4(a, sb + OFF_PS + ps_off + ks * 32);
            #pragma unroll
            for (int g = 0; g < 8; g++) {
                uint32_t b[4];
                ldsm_x4t(b, vb + (ks * 16 + (mi & 1) * 8 + l7) * AROW
                               + (g * 16 + (mi >> 1) * 8) * 2);
                mma_fp(oacc[2*g+0], a, b[0], b[1]);
                mma_fp(oacc[2*g+1], a, b[2], b[3]);
            }
        }
    }

    const float i0 = 1.f / l0v, i1 = 1.f / l1v;
    #pragma unroll
    for (int f = 0; f < 16; f++) {
        int col = h * HD_DIM + f * 8 + (lane & 3) * 2;
        __half2 hh0 = __floats2half2_rn(oacc[f][0] * i0, oacc[f][1] * i0);
        __half2 hh1 = __floats2half2_rn(oacc[f][2] * i1, oacc[f][3] * i1);
        *(__half2*)&Oh[(size_t)gq0 * H_DIM + col] = hh0;
        *(__half2*)&Oh[(size_t)gq1 * H_DIM + col] = hh1;
    }
}

// ===================== elementwise / conversion kernels =====================
__global__ void rmsnorm_f16_kernel(const float* __restrict__ x,
                                   const float* __restrict__ scale,
                                   h16* __restrict__ oh)
{
    int row = blockIdx.x;
    const float4* xr = (const float4*)(x + (size_t)row * H_DIM);
    float ss = 0.f;
    for (int i = threadIdx.x; i < H_DIM / 4; i += blockDim.x) {
        float4 v = xr[i];
        ss += v.x * v.x + v.y * v.y + v.z * v.z + v.w * v.w;
    }
    #pragma unroll
    for (int off = 16; off; off >>= 1) ss += __shfl_xor_sync(0xffffffffu, ss, off);
    __shared__ float red[32];
    int lane = threadIdx.x & 31, wid = threadIdx.x >> 5;
    if (lane == 0) red[wid] = ss;
    __syncthreads();
    if (wid == 0) {
        ss = (lane < (int)(blockDim.x >> 5)) ? red[lane] : 0.f;
        #pragma unroll
        for (int off = 16; off; off >>= 1) ss += __shfl_xor_sync(0xffffffffu, ss, off);
        if (lane == 0) red[0] = ss;
    }
    __syncthreads();
    float inv = rsqrtf(red[0] / (float)H_DIM + EPS_V);
    const float4* sc = (const float4*)scale;
    for (int i = threadIdx.x; i < H_DIM / 4; i += blockDim.x) {
        float4 v = xr[i], s = sc[i];
        __half2 lo = __floats2half2_rn(v.x * inv * s.x, v.y * inv * s.y);
        __half2 hi = __floats2half2_rn(v.z * inv * s.z, v.w * inv * s.w);
        uint2 pack = {*(uint32_t*)&lo, *(uint32_t*)&hi};
        ((uint2*)(oh + (size_t)row * H_DIM))[i] = pack;
    }
}

// streaming fp32 -> fp16, same [K][N] layout; output row stride OS.
__global__ void convert_f16_kernel(const float* __restrict__ W,
                                   h16* __restrict__ out,
                                   int N8, int OS, int total8)
{
    int i = blockIdx.x * blockDim.x + threadIdx.x;
    if (i >= total8) return;
    const float4* src = (const float4*)W + (size_t)i * 2;
    float4 a = src[0], b = src[1];
    __half2 h0 = __floats2half2_rn(a.x, a.y);
    __half2 h1 = __floats2half2_rn(a.z, a.w);
    __half2 h2 = __floats2half2_rn(b.x, b.y);
    __half2 h3 = __floats2half2_rn(b.z, b.w);
    int k = i / N8, n8 = i - k * N8;
    uint4 pack = {*(uint32_t*)&h0, *(uint32_t*)&h1, *(uint32_t*)&h2, *(uint32_t*)&h3};
    *(uint4*)(out + (size_t)k * OS + (size_t)n8 * 8) = pack;
}

// merged qkv convert: sections 0..2 pull from wq/wk/wv into g_wqkv columns.
__global__ void convert_qkv_kernel(const float* __restrict__ Wq,
                                   const float* __restrict__ Wk,
                                   const float* __restrict__ Wv,
                                   h16* __restrict__ out, int per8)
{
    int i = blockIdx.x * blockDim.x + threadIdx.x;
    if (i >= 3 * per8) return;
    int sec = i / per8, j = i - sec * per8;
    const float* W = (sec == 0) ? Wq : (sec == 1) ? Wk : Wv;
    const float4* src = (const float4*)W + (size_t)j * 2;
    float4 a = src[0], b = src[1];
    __half2 h0 = __floats2half2_rn(a.x, a.y);
    __half2 h1 = __floats2half2_rn(a.z, a.w);
    __half2 h2 = __floats2half2_rn(b.x, b.y);
    __half2 h3 = __floats2half2_rn(b.z, b.w);
    const int N8 = H_DIM / 8;
    int k = j / N8, n8 = j - k * N8;
    uint4 pack = {*(uint32_t*)&h0, *(uint32_t*)&h1, *(uint32_t*)&h2, *(uint32_t*)&h3};
    *(uint4*)(out + (size_t)k * QKV_N + sec * H_DIM + (size_t)n8 * 8) = pack;
}

// w1,w2 fp32 [K][FF] -> interleaved fp16 [K][2*FF]
__global__ void convert_pair_kernel(const float* __restrict__ W1,
                                    const float* __restrict__ W2,
                                    h16* __restrict__ out, int total8)
{
    int i = blockIdx.x * blockDim.x + threadIdx.x;
    if (i >= total8) return;
    const float4* s1 = (const float4*)W1 + (size_t)i * 2;
    const float4* s2 = (const float4*)W2 + (size_t)i * 2;
    float4 a1 = s1[0], b1 = s1[1];
    float4 a2 = s2[0], b2 = s2[1];
    __half2 p0 = __floats2half2_rn(a1.x, a2.x);
    __half2 p1 = __floats2half2_rn(a1.y, a2.y);
    __half2 p2 = __floats2half2_rn(a1.z, a2.z);
    __half2 p3 = __floats2half2_rn(a1.w, a2.w);
    __half2 p4 = __floats2half2_rn(b1.x, b2.x);
    __half2 p5 = __floats2half2_rn(b1.y, b2.y);
    __half2 p6 = __floats2half2_rn(b1.z, b2.z);
    __half2 p7 = __floats2half2_rn(b1.w, b2.w);
    uint4 lo = {*(uint32_t*)&p0, *(uint32_t*)&p1, *(uint32_t*)&p2, *(uint32_t*)&p3};
    uint4 hi = {*(uint32_t*)&p4, *(uint32_t*)&p5, *(uint32_t*)&p6, *(uint32_t*)&p7};
    uint4* dst = (uint4*)(out + (size_t)i * 16);
    dst[0] = lo;
    dst[1] = hi;
}

__global__ void bias_cat_kernel(const float* __restrict__ bq,
                                const float* __restrict__ bk,
                                const float* __restrict__ bv,
                                float* __restrict__ cat)
{
    int i = blockIdx.x * blockDim.x + threadIdx.x;
    if (i < H_DIM)          cat[i] = bq[i];
    else if (i < 2 * H_DIM) cat[i] = bk[i - H_DIM];
    else if (i < 3 * H_DIM) cat[i] = bv[i - 2 * H_DIM];
}

// RoPE in-place on fp16 q,k (row stride QS); q pre-scaled by log2(e)/sqrt(HD).
__global__ void rope_f16_kernel(h16* __restrict__ q, h16* __restrict__ k,
                                const int* __restrict__ pos, int QS)
{
    int idx = blockIdx.x * blockDim.x + threadIdx.x;
    if (idx >= T_DIM * NHEADS * (HD_DIM / 2)) return;
    int d  = idx & 63;
    int th = idx >> 6;
    int t  = th >> 5;
    int hh = th & 31;
    const float scaling = 0.08838834764831845f * 1.4426950408889634f;
    float invf = powf(10000.0f, -(float)d * (1.0f / 64.0f));
    float ang = (float)pos[t] * invf;
    float c, s;
    sincosf(ang, &s, &c);
    size_t base = (size_t)t * QS + hh * HD_DIM + d;
    float q1 = __half2float(q[base]), q2 = __half2float(q[base + 64]);
    q[base]      = __float2half_rn((q1 * c - q2 * s) * scaling);
    q[base + 64] = __float2half_rn((q2 * c + q1 * s) * scaling);
    float k1 = __half2float(k[base]), k2 = __half2float(k[base + 64]);
    k[base]      = __float2half_rn(k1 * c - k2 * s);
    k[base + 64] = __float2half_rn(k2 * c + k1 * s);
}

// ===================== launch ================================================
extern "C" void kernel_launch(void* const* d_in, const int* in_sizes, int n_in,
                              void* d_out, int out_size)
{
    (void)in_sizes; (void)n_in; (void)out_size;
    const int*   positions = (const int*)  d_in[0];
    const float* hidden    = (const float*)d_in[1];
    const float* ln1       = (const float*)d_in[2];
    const float* wq = (const float*)d_in[3];
    const float* bq = (const float*)d_in[4];
    const float* wk = (const float*)d_in[5];
    const float* bk = (const float*)d_in[6];
    const float* wv = (const float*)d_in[7];
    const float* bv = (const float*)d_in[8];
    const float* wo = (const float*)d_in[9];
    const float* ln2= (const float*)d_in[10];
    const float* w1 = (const float*)d_in[11];
    const float* w2 = (const float*)d_in[12];
    const float* wc = (const float*)d_in[13];
    float* out = (float*)d_out;

    float *hbuf, *bqkv;
    h16 *xnh, *atth, *yh, *gh, *qkv16;
    h16 *wqkv, *woh, *w12, *wch;
    cudaGetSymbolAddress((void**)&hbuf,  g_h);
    cudaGetSymbolAddress((void**)&bqkv,  g_bqkv);
    cudaGetSymbolAddress((void**)&xnh,   g_xnh);
    cudaGetSymbolAddress((void**)&atth,  g_atth);
    cudaGetSymbolAddress((void**)&yh,    g_yh);
    cudaGetSymbolAddress((void**)&gh,    g_gh);
    cudaGetSymbolAddress((void**)&qkv16, g_qkv16);
    cudaGetSymbolAddress((void**)&wqkv,  g_wqkv);
    cudaGetSymbolAddress((void**)&woh,   g_woh);
    cudaGetSymbolAddress((void**)&w12,   g_w12);
    cudaGetSymbolAddress((void**)&wch,   g_wch);

    cudaFuncSetAttribute((gemm_f16<0>), cudaFuncAttributeMaxDynamicSharedMemorySize, GSMEM);
    cudaFuncSetAttribute((gemm_f16<1>), cudaFuncAttributeMaxDynamicSharedMemorySize, GSMEM);
    cudaFuncSetAttribute((gemm_f16<3>), cudaFuncAttributeMaxDynamicSharedMemorySize, GSMEM);
    cudaFuncSetAttribute(attn_mma_kernel, cudaFuncAttributeMaxDynamicSharedMemorySize, ATTN_SMEM);

    // side stream + fork/join events (host resources; created once, reused —
    // device work per call is identical and deterministic)
    static cudaStream_t s_cvt = nullptr;
    static cudaEvent_t ev_fork = nullptr, ev_join = nullptr;
    if (s_cvt == nullptr) {
        cudaStreamCreateWithFlags(&s_cvt, cudaStreamNonBlocking);
        cudaEventCreateWithFlags(&ev_fork, cudaEventDisableTiming);
        cudaEventCreateWithFlags(&ev_join, cudaEventDisableTiming);
    }

    const int HH8 = H_DIM * H_DIM / 8;
    const int HF8 = H_DIM * FF_DIM / 8;

    // ---- fork: wo/w12/wc converts run on side stream, overlapping the
    //      qkv convert + rmsnorm + qkv GEMM + rope + attention span.
    cudaEventRecord(ev_fork, 0);
    cudaStreamWaitEvent(s_cvt, ev_fork, 0);
    convert_f16_kernel<<<(HH8 + 255) / 256, 256, 0, s_cvt>>>(wo, woh, H_DIM/8, H_DIM, HH8);
    convert_pair_kernel<<<(HF8 + 255) / 256, 256, 0, s_cvt>>>(w1, w2, w12, HF8);
    convert_f16_kernel<<<(HF8 + 255) / 256, 256, 0, s_cvt>>>(wc, wch, H_DIM/8, H_DIM, HF8);
    cudaEventRecord(ev_join, s_cvt);

    // ---- main stream: critical path
    convert_qkv_kernel<<<(3 * HH8 + 255) / 256, 256>>>(wq, wk, wv, wqkv, HH8);
    bias_cat_kernel<<<(QKV_N + 255) / 256, 256>>>(bq, bk, bv, bqkv);

    // 1) x = rmsnorm(hidden, ln1) -> fp16
    rmsnorm_f16_kernel<<<T_DIM, 256>>>(hidden, ln1, xnh);

    // 2) fused qkv GEMM (fp16 out)
    dim3 gQKV(QKV_N / BN, T_DIM / BM);
    gemm_f16<1><<<gQKV, 256, GSMEM>>>(xnh, wqkv, bqkv, nullptr, qkv16, QKV_N, H_DIM);

    // 3) RoPE in place (q pre-scaled into log2 domain)
    rope_f16_kernel<<<(T_DIM * NHEADS * (HD_DIM / 2)) / 256, 256>>>(
        qkv16, qkv16 + H_DIM, positions, QKV_N);

    // 4) attention -> atth (fp16)
    attn_mma_kernel<<<dim3(T_DIM / 64, NHEADS), 128, ATTN_SMEM>>>(
        qkv16, qkv16 + H_DIM, qkv16 + 2 * H_DIM, atth, QKV_N);

    // ---- join: weight converts must be done before wo GEMM
    cudaStreamWaitEvent(0, ev_join, 0);

    // 5) h = hidden + attn @ wo
    dim3 gH(H_DIM / BN, T_DIM / BM);
    gemm_f16<0><<<gH, 256, GSMEM>>>(atth, woh, nullptr, hidden, hbuf, H_DIM, H_DIM);

    // 6) y = rmsnorm(h, ln2) -> fp16
    rmsnorm_f16_kernel<<<T_DIM, 256>>>(hbuf, ln2, yh);

    // 7) fused gated MLP: gh = (y@w1) * silu(y@w2), single interleaved GEMM
    dim3 gF2(MLP_N / BN, T_DIM / BM);
    gemm_f16<3><<<gF2, 256, GSMEM>>>(yh, w12, nullptr, nullptr, gh, MLP_N, H_DIM);

    // 8) out = h + gh @ wc
    gemm_f16<0><<<gH, 256, GSMEM>>>(gh, wch, nullptr, hbuf, out, H_DIM, FF_DIM);
}